// round 7
// baseline (speedup 1.0000x reference)
#include <cuda_runtime.h>
#include <cuda_bf16.h>
#include <cstdint>
#include <math.h>

// Problem constants
#define B_  4
#define T_  2048
#define C_  1024
#define H_  16
#define N_  64
#define DMIX 32

#define CHUNK 64
#define G_ 32                     // chunks per (b,h)
#define NCHUNK (B_*H_*G_)         // 2048
#define STRD 68                   // padded row stride for chunk smem tiles

static const long BTC = (long)B_ * T_ * C_;   // 8388608

// ---------------- scratch (device globals; no runtime allocation) -------------
__device__ float g_xx [ (long)B_*T_*C_ ];
__device__ float g_xxx[ (long)B_*T_*C_ ];
__device__ float g_xw [ (long)B_*T_*C_ ];
__device__ float g_xk [ (long)B_*T_*C_ ];
__device__ float g_xv [ (long)B_*T_*C_ ];
__device__ float g_xr [ (long)B_*T_*C_ ];
__device__ float g_xg [ (long)B_*T_*C_ ];
__device__ float g_r  [ (long)B_*T_*C_ ];
__device__ float g_k  [ (long)B_*T_*C_ ];
__device__ float g_v  [ (long)B_*T_*C_ ];
__device__ float g_w  [ (long)B_*T_*C_ ];   // lw = log(decay)
__device__ float g_g  [ (long)B_*T_*C_ ];
__device__ float g_y  [ (long)B_*T_*C_ ];
__device__ float g_z  [ (long)B_*T_*C_ ];
__device__ float g_lora [ (long)B_*T_*5*DMIX ];
__device__ float g_small[ (long)B_*T_*64 ];
__device__ float g_D  [ (long)NCHUNK*64*64 ];
__device__ float g_Sc [ (long)NCHUNK*64*64 ];
__device__ float g_rp [ (long)NCHUNK*64*64 ];
__device__ float g_pL [ (long)NCHUNK*64 ];
// transposed weights [N, K] K-major
__device__ float g_WrT[ (long)C_*C_ ];
__device__ float g_WkT[ (long)C_*C_ ];
__device__ float g_WvT[ (long)C_*C_ ];
__device__ float g_WoT[ (long)C_*C_ ];
__device__ float g_w1T[ (long)160*C_ ];
__device__ float g_w2T[ (long)C_*160 ];
__device__ float g_dw1T[ (long)64*C_ ];
__device__ float g_gw1T[ (long)64*C_ ];
__device__ float g_dw2T[ (long)C_*64 ];
__device__ float g_gw2T[ (long)C_*64 ];

// ================= tf32 mma.sync GEMM ========================================
// Permuted-k smem layout: within each k-8-group, slots hold [k0,k4,k1,k5,k2,k6,k3,k7]
// so fragment pairs (k, k+4) are adjacent -> LDS.64 fragment loads.
#define TSTR 20   // smem row stride in words

__device__ __forceinline__ uint32_t f2tf32(float f) {
    uint32_t o;
    asm("cvt.rna.tf32.f32 %0, %1;" : "=r"(o) : "f"(f));
    return o;
}
__device__ __forceinline__ void mma1688(float* d, const uint32_t* a, const uint32_t* b) {
    asm volatile(
        "mma.sync.aligned.m16n8k8.row.col.f32.tf32.tf32.f32 "
        "{%0,%1,%2,%3}, {%4,%5,%6,%7}, {%8,%9}, {%0,%1,%2,%3};"
        : "+f"(d[0]), "+f"(d[1]), "+f"(d[2]), "+f"(d[3])
        : "r"(a[0]), "r"(a[1]), "r"(a[2]), "r"(a[3]), "r"(b[0]), "r"(b[1]));
}

// ---- shared 128x128 body ----------------------------------------------------
// EPI: 0 none, 1 tanh, 2 -exp(acc + bias[col]), 3 xin + xxin*(bias[col] + acc)
template<int EPI>
__device__ __forceinline__ void gemm128_body(
    uint32_t (*As)[128 * TSTR], uint32_t (*Bs)[128 * TSTR],
    const float* __restrict__ A, int lda,
    const float* __restrict__ Bt, int ldb,
    float* __restrict__ Cm, int ldc,
    int K, int Nn, const float* __restrict__ bias,
    const float* __restrict__ xin, const float* __restrict__ xxin,
    int row0, int col0)
{
    const int tid = threadIdx.x;
    const int lane = tid & 31;
    const int wid = tid >> 5;
    const int wr = wid >> 2;
    const int wc = wid & 3;

    float4 ra[2], rb[2];

    auto loadAB = [&](int kc) {
        const int k0 = kc * 16;
        #pragma unroll
        for (int l = 0; l < 2; l++) {
            int e = tid + (l << 8);
            int r = e >> 2, c = e & 3;
            ra[l] = *(const float4*)&A[(long)(row0 + r) * lda + k0 + (c << 2)];
            int br = col0 + r;
            if (br < Nn)
                rb[l] = *(const float4*)&Bt[(long)br * ldb + k0 + (c << 2)];
            else
                rb[l] = make_float4(0.f, 0.f, 0.f, 0.f);
        }
    };
    auto storeAB = [&](int buf) {
        #pragma unroll
        for (int l = 0; l < 2; l++) {
            int e = tid + (l << 8);
            int r = e >> 2, c = e & 3;
            int slot = ((c >> 1) << 3) + (c & 1);   // 0,1,8,9
            uint32_t* ap = &As[buf][r * TSTR + slot];
            ap[0] = f2tf32(ra[l].x); ap[2] = f2tf32(ra[l].y);
            ap[4] = f2tf32(ra[l].z); ap[6] = f2tf32(ra[l].w);
            uint32_t* bp = &Bs[buf][r * TSTR + slot];
            bp[0] = f2tf32(rb[l].x); bp[2] = f2tf32(rb[l].y);
            bp[4] = f2tf32(rb[l].z); bp[6] = f2tf32(rb[l].w);
        }
    };

    float acc[4][4][4];
    #pragma unroll
    for (int mi = 0; mi < 4; mi++)
        #pragma unroll
        for (int ni = 0; ni < 4; ni++)
            #pragma unroll
            for (int e = 0; e < 4; e++) acc[mi][ni][e] = 0.f;

    const int NKT = K >> 4;
    loadAB(0);
    storeAB(0);
    __syncthreads();

    const int lg = lane >> 2;
    const int lt = lane & 3;

    for (int kc = 0; kc < NKT; kc++) {
        const int cur = kc & 1;
        if (kc + 1 < NKT) loadAB(kc + 1);

        #pragma unroll
        for (int ks = 0; ks < 2; ks++) {
            const int ko = (ks << 3) + (lt << 1);   // slot offset
            uint32_t af[4][4], bf[4][2];
            #pragma unroll
            for (int mi = 0; mi < 4; mi++) {
                int rm = wr * 64 + mi * 16 + lg;
                uint2 lo = *(const uint2*)&As[cur][rm * TSTR + ko];
                uint2 hi = *(const uint2*)&As[cur][(rm + 8) * TSTR + ko];
                af[mi][0] = lo.x; af[mi][1] = hi.x;
                af[mi][2] = lo.y; af[mi][3] = hi.y;
            }
            #pragma unroll
            for (int ni = 0; ni < 4; ni++) {
                int cn = wc * 32 + ni * 8 + lg;
                uint2 bb = *(const uint2*)&Bs[cur][cn * TSTR + ko];
                bf[ni][0] = bb.x; bf[ni][1] = bb.y;
            }
            #pragma unroll
            for (int mi = 0; mi < 4; mi++)
                #pragma unroll
                for (int ni = 0; ni < 4; ni++)
                    mma1688(acc[mi][ni], af[mi], bf[ni]);
        }

        if (kc + 1 < NKT) storeAB(cur ^ 1);
        __syncthreads();
    }

    #pragma unroll
    for (int mi = 0; mi < 4; mi++) {
        int gr0 = row0 + wr * 64 + mi * 16 + lg;
        #pragma unroll
        for (int ni = 0; ni < 4; ni++) {
            int gc = col0 + wc * 32 + ni * 8 + 2 * lt;
            if (gc < Nn) {
                float v0 = acc[mi][ni][0], v1 = acc[mi][ni][1];
                float v2 = acc[mi][ni][2], v3 = acc[mi][ni][3];
                long o0 = (long)gr0 * ldc + gc;
                long o1 = (long)(gr0 + 8) * ldc + gc;
                if (EPI == 1) {
                    v0 = tanhf(v0); v1 = tanhf(v1); v2 = tanhf(v2); v3 = tanhf(v3);
                } else if (EPI == 2) {
                    float b0 = bias[gc], b1 = bias[gc + 1];
                    v0 = -expf(v0 + b0); v1 = -expf(v1 + b1);
                    v2 = -expf(v2 + b0); v3 = -expf(v3 + b1);
                } else if (EPI == 3) {
                    float b0 = bias[gc], b1 = bias[gc + 1];
                    float2 x0 = *(const float2*)&xin[o0];
                    float2 x1 = *(const float2*)&xin[o1];
                    float2 d0 = *(const float2*)&xxin[o0];
                    float2 d1 = *(const float2*)&xxin[o1];
                    v0 = fmaf(d0.x, b0 + v0, x0.x);
                    v1 = fmaf(d0.y, b1 + v1, x0.y);
                    v2 = fmaf(d1.x, b0 + v2, x1.x);
                    v3 = fmaf(d1.y, b1 + v3, x1.y);
                }
                *(float2*)&Cm[o0] = make_float2(v0, v1);
                *(float2*)&Cm[o1] = make_float2(v2, v3);
            }
        }
    }
}

template<int EPI>
__global__ __launch_bounds__(256) void gemm_tc(
    const float* __restrict__ A, int lda,
    const float* __restrict__ Bt, int ldb,
    float* __restrict__ Cm, int ldc,
    int K, int Nn, const float* __restrict__ bias)
{
    __shared__ uint32_t As[2][128 * TSTR];
    __shared__ uint32_t Bs[2][128 * TSTR];
    gemm128_body<EPI>(As, Bs, A, lda, Bt, ldb, Cm, ldc, K, Nn, bias,
                      nullptr, nullptr, blockIdx.y * 128, blockIdx.x * 128);
}

// merged 5-branch mix GEMM: z selects branch
__global__ __launch_bounds__(256) void gemm_mix(
    const float* __restrict__ lora, const float* __restrict__ w2T,
    const float* __restrict__ x, const float* __restrict__ xx,
    const float* m0, const float* m1, const float* m2, const float* m3, const float* m4,
    float* o0, float* o1, float* o2, float* o3, float* o4)
{
    __shared__ uint32_t As[2][128 * TSTR];
    __shared__ uint32_t Bs[2][128 * TSTR];
    const int z = blockIdx.z;
    const float* bias = (z == 0) ? m0 : (z == 1) ? m1 : (z == 2) ? m2 : (z == 3) ? m3 : m4;
    float* out = (z == 0) ? o0 : (z == 1) ? o1 : (z == 2) ? o2 : (z == 3) ? o3 : o4;
    gemm128_body<3>(As, Bs, lora + z * DMIX, 160, w2T + z * DMIX, 160,
                    out, C_, DMIX, C_, bias, x, xx,
                    blockIdx.y * 128, blockIdx.x * 128);
}

// ---- small tile: BM=64, BN=64, 128 threads (4 warps 2x2, warp 32x32) ---------
template<int EPI>
__global__ __launch_bounds__(128) void gemm_tc64(
    const float* __restrict__ A, int lda,
    const float* __restrict__ Bt, int ldb,
    float* __restrict__ Cm, int ldc,
    int K, int Nn, const float* __restrict__ bias)
{
    __shared__ uint32_t As[2][64 * TSTR];
    __shared__ uint32_t Bs[2][64 * TSTR];

    const int tid = threadIdx.x;
    const int lane = tid & 31;
    const int wid = tid >> 5;
    const int wr = wid >> 1;
    const int wc = wid & 1;
    const int row0 = blockIdx.y * 64;
    const int col0 = blockIdx.x * 64;

    float4 ra[2], rb[2];

    auto loadAB = [&](int kc) {
        const int k0 = kc * 16;
        #pragma unroll
        for (int l = 0; l < 2; l++) {
            int e = tid + (l << 7);
            int r = e >> 2, c = e & 3;
            ra[l] = *(const float4*)&A[(long)(row0 + r) * lda + k0 + (c << 2)];
            int br = col0 + r;
            if (br < Nn)
                rb[l] = *(const float4*)&Bt[(long)br * ldb + k0 + (c << 2)];
            else
                rb[l] = make_float4(0.f, 0.f, 0.f, 0.f);
        }
    };
    auto storeAB = [&](int buf) {
        #pragma unroll
        for (int l = 0; l < 2; l++) {
            int e = tid + (l << 7);
            int r = e >> 2, c = e & 3;
            int slot = ((c >> 1) << 3) + (c & 1);
            uint32_t* ap = &As[buf][r * TSTR + slot];
            ap[0] = f2tf32(ra[l].x); ap[2] = f2tf32(ra[l].y);
            ap[4] = f2tf32(ra[l].z); ap[6] = f2tf32(ra[l].w);
            uint32_t* bp = &Bs[buf][r * TSTR + slot];
            bp[0] = f2tf32(rb[l].x); bp[2] = f2tf32(rb[l].y);
            bp[4] = f2tf32(rb[l].z); bp[6] = f2tf32(rb[l].w);
        }
    };

    float acc[2][4][4];
    #pragma unroll
    for (int mi = 0; mi < 2; mi++)
        #pragma unroll
        for (int ni = 0; ni < 4; ni++)
            #pragma unroll
            for (int e = 0; e < 4; e++) acc[mi][ni][e] = 0.f;

    const int NKT = K >> 4;
    loadAB(0);
    storeAB(0);
    __syncthreads();

    const int lg = lane >> 2;
    const int lt = lane & 3;

    for (int kc = 0; kc < NKT; kc++) {
        const int cur = kc & 1;
        if (kc + 1 < NKT) loadAB(kc + 1);

        #pragma unroll
        for (int ks = 0; ks < 2; ks++) {
            const int ko = (ks << 3) + (lt << 1);
            uint32_t af[2][4], bf[4][2];
            #pragma unroll
            for (int mi = 0; mi < 2; mi++) {
                int rm = wr * 32 + mi * 16 + lg;
                uint2 lo = *(const uint2*)&As[cur][rm * TSTR + ko];
                uint2 hi = *(const uint2*)&As[cur][(rm + 8) * TSTR + ko];
                af[mi][0] = lo.x; af[mi][1] = hi.x;
                af[mi][2] = lo.y; af[mi][3] = hi.y;
            }
            #pragma unroll
            for (int ni = 0; ni < 4; ni++) {
                int cn = wc * 32 + ni * 8 + lg;
                uint2 bb = *(const uint2*)&Bs[cur][cn * TSTR + ko];
                bf[ni][0] = bb.x; bf[ni][1] = bb.y;
            }
            #pragma unroll
            for (int mi = 0; mi < 2; mi++)
                #pragma unroll
                for (int ni = 0; ni < 4; ni++)
                    mma1688(acc[mi][ni], af[mi], bf[ni]);
        }

        if (kc + 1 < NKT) storeAB(cur ^ 1);
        __syncthreads();
    }

    #pragma unroll
    for (int mi = 0; mi < 2; mi++) {
        int gr0 = row0 + wr * 32 + mi * 16 + lg;
        #pragma unroll
        for (int ni = 0; ni < 4; ni++) {
            int gc = col0 + wc * 32 + ni * 8 + 2 * lt;
            if (gc < Nn) {
                float v0 = acc[mi][ni][0], v1 = acc[mi][ni][1];
                float v2 = acc[mi][ni][2], v3 = acc[mi][ni][3];
                if (EPI == 1) {
                    v0 = tanhf(v0); v1 = tanhf(v1); v2 = tanhf(v2); v3 = tanhf(v3);
                } else if (EPI == 2) {
                    float b0 = bias[gc], b1 = bias[gc + 1];
                    v0 = -expf(v0 + b0); v1 = -expf(v1 + b1);
                    v2 = -expf(v2 + b0); v3 = -expf(v3 + b1);
                }
                *(float2*)&Cm[(long)gr0 * ldc + gc] = make_float2(v0, v1);
                *(float2*)&Cm[(long)(gr0 + 8) * ldc + gc] = make_float2(v2, v3);
            }
        }
    }
}

// ---------------- batched weight transpose -----------------------------------
struct TJob { const float* src; float* dst; int R, N, nbx, boff; };
struct TJobs { TJob j[10]; };

__global__ __launch_bounds__(256) void transpose_multi(TJobs js)
{
    __shared__ float t[32][33];
    int b = blockIdx.x;
    int ji = 0;
    #pragma unroll
    for (int q = 1; q < 10; q++)
        if (b >= js.j[q].boff) ji = q;
    TJob jb = js.j[ji];
    int rem = b - jb.boff;
    int bx = (rem % jb.nbx) * 32;
    int by = (rem / jb.nbx) * 32;
    const int x = threadIdx.x, y = threadIdx.y;
    #pragma unroll
    for (int i = 0; i < 32; i += 8) {
        int r = by + y + i, n = bx + x;
        if (r < jb.R && n < jb.N) t[y + i][x] = jb.src[(long)r * jb.N + n];
    }
    __syncthreads();
    #pragma unroll
    for (int i = 0; i < 32; i += 8) {
        int n = bx + y + i, r = by + x;
        if (n < jb.N && r < jb.R) jb.dst[(long)n * jb.R + r] = t[x][y + i];
    }
}

// ---------------- elementwise: time shift + maa_x mix ------------------------
__global__ void shift_kernel(const float* __restrict__ x,
                             const float* __restrict__ maa_x,
                             float* __restrict__ xx, float* __restrict__ xxx,
                             long total)
{
    long idx = (long)blockIdx.x * blockDim.x + threadIdx.x;
    if (idx >= total) return;
    int c = (int)(idx % C_);
    long rt = idx / C_;
    int t = (int)(rt % T_);
    float xv = x[idx];
    float xp = (t > 0) ? x[idx - C_] : 0.f;
    float d = xp - xv;
    xx[idx] = d;
    xxx[idx] = xv + d * maa_x[c];
}

// ---------------- chunked WKV6 -----------------------------------------------
__global__ __launch_bounds__(256) void wkv_chunkA(
    const float* __restrict__ r, const float* __restrict__ k,
    const float* __restrict__ v, const float* __restrict__ lw,
    const float* __restrict__ u,
    float* __restrict__ y, float* __restrict__ Dout,
    float* __restrict__ rpout, float* __restrict__ pLout)
{
    extern __shared__ float sm[];
    float* lp   = sm;
    float* bufA = lp + 65 * 64;
    float* rpT  = bufA + 64 * STRD;
    float* kpT  = rpT + 64 * STRD;
    float* kpp  = kpT + 64 * STRD;
    float* vsm  = kpp + 64 * STRD;
    float* dsm  = vsm + 64 * STRD;
    float* usm  = dsm + 64;

    const int tid = threadIdx.x;
    const int chunk = blockIdx.x;
    const int bh = chunk >> 5;
    const int c  = chunk & 31;
    const int b = bh >> 4, h = bh & 15;
    const long base = ((long)b * T_ + c * CHUNK) * C_ + h * 64;

    if (tid < 64) usm[tid] = u[h * 64 + tid];
    const int i  = tid & 63;
    const int tq = tid >> 6;

    #pragma unroll
    for (int e = 0; e < 16; e++) {
        int t = tq + 4 * e;
        bufA[t * STRD + i] = lw[base + (long)t * C_ + i];
    }
    __syncthreads();

    if (tid < 64) {
        float run = 0.f;
        for (int t = 0; t < 64; t++) {
            lp[t * 64 + tid] = run;
            run += bufA[t * STRD + tid];
        }
        lp[64 * 64 + tid] = run;
        pLout[(long)chunk * 64 + tid] = run;
    }
    __syncthreads();

    #pragma unroll
    for (int e = 0; e < 16; e++) {
        int t = tq + 4 * e;
        long gi = base + (long)t * C_ + i;
        float rr = r[gi], kk = k[gi];
        float lpti = lp[t * 64 + i];
        float lpn  = lpti + bufA[t * STRD + i];
        float lpL  = lp[64 * 64 + i];
        rpT[i * STRD + t] = rr * __expf(lpti);
        kpT[i * STRD + t] = kk * __expf(-lpn);
        kpp[t * STRD + i] = kk * __expf(lpL - lpn);
        vsm[t * STRD + i] = v[gi];
    }
    {
        int t = tid >> 2, q = tid & 3;
        long gb = base + (long)t * C_;
        float p = 0.f;
        #pragma unroll
        for (int ii = 0; ii < 16; ii++) {
            int ci = q * 16 + ii;
            p += r[gb + ci] * usm[ci] * k[gb + ci];
        }
        p += __shfl_xor_sync(0xffffffffu, p, 1);
        p += __shfl_xor_sync(0xffffffffu, p, 2);
        if (q == 0) dsm[t] = p;
    }
    __syncthreads();

    {
        float* rpg = rpout + (long)chunk * 64 * 64;
        #pragma unroll
        for (int e = 0; e < 16; e++) {
            int flat = tid + 256 * e;
            rpg[flat] = rpT[(flat >> 6) * STRD + (flat & 63)];
        }
    }

    {
        int t0 = (tid >> 4) * 4, s0 = (tid & 15) * 4;
        float acc[4][4];
        #pragma unroll
        for (int a = 0; a < 4; a++)
            #pragma unroll
            for (int bq = 0; bq < 4; bq++) acc[a][bq] = 0.f;
        for (int ii = 0; ii < 64; ii++) {
            float4 a4 = *(const float4*)&rpT[ii * STRD + t0];
            float4 b4 = *(const float4*)&kpT[ii * STRD + s0];
            float av[4] = { a4.x, a4.y, a4.z, a4.w };
            float bv[4] = { b4.x, b4.y, b4.z, b4.w };
            #pragma unroll
            for (int a = 0; a < 4; a++)
                #pragma unroll
                for (int bq = 0; bq < 4; bq++)
                    acc[a][bq] = fmaf(av[a], bv[bq], acc[a][bq]);
        }
        __syncthreads();
        #pragma unroll
        for (int a = 0; a < 4; a++)
            #pragma unroll
            for (int bq = 0; bq < 4; bq++) {
                int tt = t0 + a, ss = s0 + bq;
                float val = (tt > ss) ? acc[a][bq] : ((tt == ss) ? dsm[tt] : 0.f);
                bufA[ss * STRD + tt] = val;
            }
    }
    __syncthreads();

    {
        int t0 = (tid >> 4) * 4, j0 = (tid & 15) * 4;
        float acc[4][4];
        #pragma unroll
        for (int a = 0; a < 4; a++)
            #pragma unroll
            for (int bq = 0; bq < 4; bq++) acc[a][bq] = 0.f;
        for (int s = 0; s < 64; s++) {
            float4 a4 = *(const float4*)&bufA[s * STRD + t0];
            float4 b4 = *(const float4*)&vsm[s * STRD + j0];
            float av[4] = { a4.x, a4.y, a4.z, a4.w };
            float bv[4] = { b4.x, b4.y, b4.z, b4.w };
            #pragma unroll
            for (int a = 0; a < 4; a++)
                #pragma unroll
                for (int bq = 0; bq < 4; bq++)
                    acc[a][bq] = fmaf(av[a], bv[bq], acc[a][bq]);
        }
        #pragma unroll
        for (int a = 0; a < 4; a++) {
            float4 o = make_float4(acc[a][0], acc[a][1], acc[a][2], acc[a][3]);
            *(float4*)&y[base + (long)(t0 + a) * C_ + j0] = o;
        }
    }

    {
        int i0 = (tid >> 4) * 4, j0 = (tid & 15) * 4;
        float acc[4][4];
        #pragma unroll
        for (int a = 0; a < 4; a++)
            #pragma unroll
            for (int bq = 0; bq < 4; bq++) acc[a][bq] = 0.f;
        for (int s = 0; s < 64; s++) {
            float4 a4 = *(const float4*)&kpp[s * STRD + i0];
            float4 b4 = *(const float4*)&vsm[s * STRD + j0];
            float av[4] = { a4.x, a4.y, a4.z, a4.w };
            float bv[4] = { b4.x, b4.y, b4.z, b4.w };
            #pragma unroll
            for (int a = 0; a < 4; a++)
                #pragma unroll
                for (int bq = 0; bq < 4; bq++)
                    acc[a][bq] = fmaf(av[a], bv[bq], acc[a][bq]);
        }
        float* Dp = Dout + (long)chunk * 4096;
        #pragma unroll
        for (int a = 0; a < 4; a++) {
            float4 o = make_float4(acc[a][0], acc[a][1], acc[a][2], acc[a][3]);
            *(float4*)&Dp[(i0 + a) * 64 + j0] = o;
        }
    }
}

__global__ __launch_bounds__(256) void wkv_chunkB(
    const float* __restrict__ D, const float* __restrict__ pL,
    float* __restrict__ S)
{
    const int bh = blockIdx.x;
    const int tid = threadIdx.x;
    const int i = tid >> 2;
    const int jb = (tid & 3) * 16;
    float4 s0 = {0,0,0,0}, s1 = {0,0,0,0}, s2 = {0,0,0,0}, s3 = {0,0,0,0};
    for (int c = 0; c < G_; c++) {
        long chunk = (long)bh * G_ + c;
        long off = chunk * 4096 + i * 64 + jb;
        *(float4*)&S[off + 0]  = s0;
        *(float4*)&S[off + 4]  = s1;
        *(float4*)&S[off + 8]  = s2;
        *(float4*)&S[off + 12] = s3;
        float pl = __expf(pL[chunk * 64 + i]);
        float4 d0 = *(const float4*)&D[off + 0];
        float4 d1 = *(const float4*)&D[off + 4];
        float4 d2 = *(const float4*)&D[off + 8];
        float4 d3 = *(const float4*)&D[off + 12];
        s0 = make_float4(fmaf(pl, s0.x, d0.x), fmaf(pl, s0.y, d0.y), fmaf(pl, s0.z, d0.z), fmaf(pl, s0.w, d0.w));
        s1 = make_float4(fmaf(pl, s1.x, d1.x), fmaf(pl, s1.y, d1.y), fmaf(pl, s1.z, d1.z), fmaf(pl, s1.w, d1.w));
        s2 = make_float4(fmaf(pl, s2.x, d2.x), fmaf(pl, s2.y, d2.y), fmaf(pl, s2.z, d2.z), fmaf(pl, s2.w, d2.w));
        s3 = make_float4(fmaf(pl, s3.x, d3.x), fmaf(pl, s3.y, d3.y), fmaf(pl, s3.z, d3.z), fmaf(pl, s3.w, d3.w));
    }
}

__global__ __launch_bounds__(256) void wkv_chunkC(
    const float* __restrict__ rp, const float* __restrict__ S,
    float* __restrict__ y)
{
    __shared__ float rps[64 * 64];
    __shared__ float Ss[64 * 64];
    const int tid = threadIdx.x;
    const int chunk = blockIdx.x;
    const int bh = chunk >> 5;
    const int c  = chunk & 31;
    const int b = bh >> 4, h = bh & 15;
    const long base = ((long)b * T_ + c * CHUNK) * C_ + h * 64;

    const float* rpg = rp + (long)chunk * 4096;
    const float* Sg  = S  + (long)chunk * 4096;
    #pragma unroll
    for (int e = 0; e < 4; e++) {
        int f4 = tid + 256 * e;
        *(float4*)&rps[f4 * 4] = *(const float4*)&rpg[f4 * 4];
        *(float4*)&Ss[f4 * 4]  = *(const float4*)&Sg[f4 * 4];
    }
    __syncthreads();

    int t0 = (tid >> 4) * 4, j0 = (tid & 15) * 4;
    float acc[4][4];
    #pragma unroll
    for (int a = 0; a < 4; a++)
        #pragma unroll
        for (int bq = 0; bq < 4; bq++) acc[a][bq] = 0.f;
    for (int ii = 0; ii < 64; ii++) {
        float4 a4 = *(const float4*)&rps[ii * 64 + t0];
        float4 b4 = *(const float4*)&Ss[ii * 64 + j0];
        float av[4] = { a4.x, a4.y, a4.z, a4.w };
        float bv[4] = { b4.x, b4.y, b4.z, b4.w };
        #pragma unroll
        for (int a = 0; a < 4; a++)
            #pragma unroll
            for (int bq = 0; bq < 4; bq++)
                acc[a][bq] = fmaf(av[a], bv[bq], acc[a][bq]);
    }
    #pragma unroll
    for (int a = 0; a < 4; a++) {
        long yo = base + (long)(t0 + a) * C_ + j0;
        float4 cur = *(const float4*)&y[yo];
        cur.x += acc[a][0]; cur.y += acc[a][1];
        cur.z += acc[a][2]; cur.w += acc[a][3];
        *(float4*)&y[yo] = cur;
    }
}

// ---------------- GroupNorm over heads + gate multiply -----------------------
__global__ __launch_bounds__(512) void gn_kernel(
    const float* __restrict__ y, const float* __restrict__ ln_g,
    const float* __restrict__ ln_b, const float* __restrict__ g,
    float* __restrict__ z)
{
    const int bt = blockIdx.x;
    const int warp = threadIdx.x >> 5;
    const int lane = threadIdx.x & 31;
    const long base = (long)bt * C_ + warp * 64;

    float a0 = y[base + lane];
    float a1 = y[base + 32 + lane];
    float sum = a0 + a1;
    float sq = a0 * a0 + a1 * a1;
    #pragma unroll
    for (int off = 16; off > 0; off >>= 1) {
        sum += __shfl_xor_sync(0xffffffffu, sum, off);
        sq  += __shfl_xor_sync(0xffffffffu, sq,  off);
    }
    float mu = sum * (1.f / 64.f);
    float var = sq * (1.f / 64.f) - mu * mu;
    float inv = rsqrtf(var + 6.4e-4f);

    int c0 = warp * 64 + lane;
    float z0 = (a0 - mu) * inv * ln_g[c0] + ln_b[c0];
    float z1 = (a1 - mu) * inv * ln_g[c0 + 32] + ln_b[c0 + 32];
    z[base + lane]      = z0 * g[base + lane];
    z[base + 32 + lane] = z1 * g[base + 32 + lane];
}

// ---------------- launcher ----------------------------------------------------
extern "C" void kernel_launch(void* const* d_in, const int* in_sizes, int n_in,
                              void* d_out, int out_size)
{
    const float* x          = (const float*)d_in[0];
    const float* maa_x      = (const float*)d_in[1];
    const float* maa_w      = (const float*)d_in[2];
    const float* maa_k      = (const float*)d_in[3];
    const float* maa_v      = (const float*)d_in[4];
    const float* maa_r      = (const float*)d_in[5];
    const float* maa_g      = (const float*)d_in[6];
    const float* maa_w1     = (const float*)d_in[7];
    const float* maa_w2     = (const float*)d_in[8];
    const float* Wr         = (const float*)d_in[9];
    const float* Wk         = (const float*)d_in[10];
    const float* Wv         = (const float*)d_in[11];
    const float* Wo         = (const float*)d_in[12];
    const float* gate_w1    = (const float*)d_in[13];
    const float* gate_w2    = (const float*)d_in[14];
    const float* time_decay = (const float*)d_in[15];
    const float* decay_w1   = (const float*)d_in[16];
    const float* decay_w2   = (const float*)d_in[17];
    const float* u          = (const float*)d_in[18];
    const float* ln_g       = (const float*)d_in[19];
    const float* ln_b       = (const float*)d_in[20];
    (void)in_sizes; (void)n_in; (void)out_size;

    float *p_xx, *p_xxx, *p_xw, *p_xk, *p_xv, *p_xr, *p_xg;
    float *p_r, *p_k, *p_v, *p_w, *p_g, *p_y, *p_z, *p_lora, *p_small;
    float *p_D, *p_Sc, *p_rp, *p_pL;
    float *p_WrT, *p_WkT, *p_WvT, *p_WoT, *p_w1T, *p_w2T, *p_dw1T, *p_gw1T, *p_dw2T, *p_gw2T;
    cudaGetSymbolAddress((void**)&p_xx, g_xx);
    cudaGetSymbolAddress((void**)&p_xxx, g_xxx);
    cudaGetSymbolAddress((void**)&p_xw, g_xw);
    cudaGetSymbolAddress((void**)&p_xk, g_xk);
    cudaGetSymbolAddress((void**)&p_xv, g_xv);
    cudaGetSymbolAddress((void**)&p_xr, g_xr);
    cudaGetSymbolAddress((void**)&p_xg, g_xg);
    cudaGetSymbolAddress((void**)&p_r, g_r);
    cudaGetSymbolAddress((void**)&p_k, g_k);
    cudaGetSymbolAddress((void**)&p_v, g_v);
    cudaGetSymbolAddress((void**)&p_w, g_w);
    cudaGetSymbolAddress((void**)&p_g, g_g);
    cudaGetSymbolAddress((void**)&p_y, g_y);
    cudaGetSymbolAddress((void**)&p_z, g_z);
    cudaGetSymbolAddress((void**)&p_lora, g_lora);
    cudaGetSymbolAddress((void**)&p_small, g_small);
    cudaGetSymbolAddress((void**)&p_D, g_D);
    cudaGetSymbolAddress((void**)&p_Sc, g_Sc);
    cudaGetSymbolAddress((void**)&p_rp, g_rp);
    cudaGetSymbolAddress((void**)&p_pL, g_pL);
    cudaGetSymbolAddress((void**)&p_WrT, g_WrT);
    cudaGetSymbolAddress((void**)&p_WkT, g_WkT);
    cudaGetSymbolAddress((void**)&p_WvT, g_WvT);
    cudaGetSymbolAddress((void**)&p_WoT, g_WoT);
    cudaGetSymbolAddress((void**)&p_w1T, g_w1T);
    cudaGetSymbolAddress((void**)&p_w2T, g_w2T);
    cudaGetSymbolAddress((void**)&p_dw1T, g_dw1T);
    cudaGetSymbolAddress((void**)&p_gw1T, g_gw1T);
    cudaGetSymbolAddress((void**)&p_dw2T, g_dw2T);
    cudaGetSymbolAddress((void**)&p_gw2T, g_gw2T);

    const long total = BTC;
    const int M = B_ * T_;          // 8192
    const int gy = M / 128;         // 64
    const int gy64 = M / 64;        // 128

    const int SMEM_A = (65 * 64 + 5 * 64 * STRD + 128) * 4;
    cudaFuncSetAttribute(wkv_chunkA, cudaFuncAttributeMaxDynamicSharedMemorySize, SMEM_A);

    // build transpose job table
    TJobs tj;
    {
        const float* srcs[10] = { maa_w1, maa_w2, Wr, Wk, Wv, Wo,
                                  decay_w1, gate_w1, decay_w2, gate_w2 };
        float* dsts[10] = { p_w1T, p_w2T, p_WrT, p_WkT, p_WvT, p_WoT,
                            p_dw1T, p_gw1T, p_dw2T, p_gw2T };
        int Rs[10] = { 1024, 160, 1024, 1024, 1024, 1024, 1024, 1024, 64, 64 };
        int Ns[10] = { 160, 1024, 1024, 1024, 1024, 1024, 64, 64, 1024, 1024 };
        int off = 0;
        for (int q = 0; q < 10; q++) {
            int nbx = (Ns[q] + 31) / 32;
            int nby = (Rs[q] + 31) / 32;
            tj.j[q].src = srcs[q]; tj.j[q].dst = dsts[q];
            tj.j[q].R = Rs[q]; tj.j[q].N = Ns[q];
            tj.j[q].nbx = nbx; tj.j[q].boff = off;
            off += nbx * nby;
        }
        // total blocks = off
        // launch below uses off
        // 0. shift
        shift_kernel<<<(int)((total + 255) / 256), 256>>>(x, maa_x, p_xx, p_xxx, total);
        // 1. all weight transposes
        transpose_multi<<<off, dim3(32, 8)>>>(tj);
    }

    // 2. lora = tanh(xxx @ maa_w1)  N=160
    gemm_tc64<1><<<dim3(3, gy64), 128>>>(p_xxx, C_, p_w1T, C_, p_lora, 160, C_, 160, nullptr);
    // 3. merged 5-branch mix GEMM (profiled by ncu)
    gemm_mix<<<dim3(8, gy, 5), 256>>>(p_lora, p_w2T, x, p_xx,
        maa_w, maa_k, maa_v, maa_r, maa_g,
        p_xw, p_xk, p_xv, p_xr, p_xg);
    // 4-6. r, k, v projections
    gemm_tc<0><<<dim3(8, gy), 256>>>(p_xr, C_, p_WrT, C_, p_r, C_, C_, C_, nullptr);
    gemm_tc<0><<<dim3(8, gy), 256>>>(p_xk, C_, p_WkT, C_, p_k, C_, C_, C_, nullptr);
    gemm_tc<0><<<dim3(8, gy), 256>>>(p_xv, C_, p_WvT, C_, p_v, C_, C_, C_, nullptr);
    // 7-8. decay: lw = -exp(time_decay + tanh(xw@decay_w1)@decay_w2)
    gemm_tc64<1><<<dim3(1, gy64), 128>>>(p_xw, C_, p_dw1T, C_, p_small, 64, C_, 64, nullptr);
    gemm_tc<2><<<dim3(8, gy), 256>>>(p_small, 64, p_dw2T, 64, p_w, C_, 64, C_, time_decay);
    // 9-11. chunked WKV6
    wkv_chunkA<<<NCHUNK, 256, SMEM_A>>>(p_r, p_k, p_v, p_w, u, p_y, p_D, p_rp, p_pL);
    wkv_chunkB<<<B_ * H_, 256>>>(p_D, p_pL, p_Sc);
    wkv_chunkC<<<NCHUNK, 256>>>(p_rp, p_Sc, p_y);
    // 12-13. gate
    gemm_tc64<1><<<dim3(1, gy64), 128>>>(p_xg, C_, p_gw1T, C_, p_small, 64, C_, 64, nullptr);
    gemm_tc<0><<<dim3(8, gy), 256>>>(p_small, 64, p_gw2T, 64, p_g, C_, 64, C_, nullptr);
    // 14. GroupNorm + gate multiply
    gn_kernel<<<M, 512>>>(p_y, ln_g, ln_b, p_g, p_z);
    // 15. out = z @ Wo
    gemm_tc<0><<<dim3(8, gy), 256>>>(p_z, C_, p_WoT, C_, (float*)d_out, C_, C_, C_, nullptr);
}

// round 8
// speedup vs baseline: 1.1406x; 1.1406x over previous
#include <cuda_runtime.h>
#include <cuda_bf16.h>
#include <cstdint>
#include <math.h>

// Problem constants
#define B_  4
#define T_  2048
#define C_  1024
#define H_  16
#define N_  64
#define DMIX 32

#define CHUNK 64
#define G_ 32                     // chunks per (b,h)
#define NCHUNK (B_*H_*G_)         // 2048
#define STRD 68                   // padded row stride for chunk smem tiles

static const long BTC = (long)B_ * T_ * C_;   // 8388608

// ---------------- scratch (device globals; no runtime allocation) -------------
__device__ float g_xx [ (long)B_*T_*C_ ];
__device__ float g_xxx[ (long)B_*T_*C_ ];
__device__ float g_xw [ (long)B_*T_*C_ ];
__device__ float g_xk [ (long)B_*T_*C_ ];
__device__ float g_xv [ (long)B_*T_*C_ ];
__device__ float g_xr [ (long)B_*T_*C_ ];
__device__ float g_xg [ (long)B_*T_*C_ ];
__device__ float g_r  [ (long)B_*T_*C_ ];
__device__ float g_k  [ (long)B_*T_*C_ ];
__device__ float g_v  [ (long)B_*T_*C_ ];
__device__ float g_w  [ (long)B_*T_*C_ ];   // lw = log(decay)
__device__ float g_g  [ (long)B_*T_*C_ ];
__device__ float g_y  [ (long)B_*T_*C_ ];
__device__ float g_z  [ (long)B_*T_*C_ ];
__device__ float g_lora [ (long)B_*T_*5*DMIX ];
__device__ float g_small[ (long)B_*T_*64 ];
__device__ float g_D  [ (long)NCHUNK*64*64 ];
__device__ float g_Sc [ (long)NCHUNK*64*64 ];
__device__ float g_rp [ (long)NCHUNK*64*64 ];
__device__ float g_pL [ (long)NCHUNK*64 ];
// transposed weights [N, K] K-major
__device__ float g_WrT[ (long)C_*C_ ];
__device__ float g_WkT[ (long)C_*C_ ];
__device__ float g_WvT[ (long)C_*C_ ];
__device__ float g_WoT[ (long)C_*C_ ];
__device__ float g_w1T[ (long)160*C_ ];
__device__ float g_w2T[ (long)C_*160 ];
__device__ float g_dw1T[ (long)64*C_ ];
__device__ float g_gw1T[ (long)64*C_ ];
__device__ float g_dw2T[ (long)C_*64 ];
__device__ float g_gw2T[ (long)C_*64 ];

// ================= tf32 mma.sync GEMM ========================================
#define TSTR 20   // smem row stride (16 + 4 pad) -> conflict-free fragments

__device__ __forceinline__ uint32_t f2tf32(float f) {
    uint32_t o;
    asm("cvt.rna.tf32.f32 %0, %1;" : "=r"(o) : "f"(f));
    return o;
}
__device__ __forceinline__ void mma1688(float* d, const uint32_t* a, const uint32_t* b) {
    asm volatile(
        "mma.sync.aligned.m16n8k8.row.col.f32.tf32.tf32.f32 "
        "{%0,%1,%2,%3}, {%4,%5,%6,%7}, {%8,%9}, {%0,%1,%2,%3};"
        : "+f"(d[0]), "+f"(d[1]), "+f"(d[2]), "+f"(d[3])
        : "r"(a[0]), "r"(a[1]), "r"(a[2]), "r"(a[3]), "r"(b[0]), "r"(b[1]));
}

// ---- shared 128x128 body (straight layout, vectorizable STS) ----------------
// EPI: 0 none, 1 tanh, 2 -exp(acc + bias[col]), 3 xin + xxin*(bias[col] + acc)
template<int EPI>
__device__ __forceinline__ void gemm128_body(
    uint32_t (*As)[128 * TSTR], uint32_t (*Bs)[128 * TSTR],
    const float* __restrict__ A, int lda,
    const float* __restrict__ Bt, int ldb,
    float* __restrict__ Cm, int ldc,
    int K, int Nn, const float* __restrict__ bias,
    const float* __restrict__ xin, const float* __restrict__ xxin,
    int row0, int col0)
{
    const int tid = threadIdx.x;
    const int lane = tid & 31;
    const int wid = tid >> 5;
    const int wr = wid >> 2;
    const int wc = wid & 3;

    float4 ra[2], rb[2];

    auto loadAB = [&](int kc) {
        const int k0 = kc * 16;
        #pragma unroll
        for (int l = 0; l < 2; l++) {
            int e = tid + (l << 8);
            int r = e >> 2, c = e & 3;
            ra[l] = *(const float4*)&A[(long)(row0 + r) * lda + k0 + (c << 2)];
            int br = col0 + r;
            if (br < Nn)
                rb[l] = *(const float4*)&Bt[(long)br * ldb + k0 + (c << 2)];
            else
                rb[l] = make_float4(0.f, 0.f, 0.f, 0.f);
        }
    };
    auto storeAB = [&](int buf) {
        #pragma unroll
        for (int l = 0; l < 2; l++) {
            int e = tid + (l << 8);
            int r = e >> 2, c = e & 3;
            uint32_t* ap = &As[buf][r * TSTR + (c << 2)];
            ap[0] = f2tf32(ra[l].x); ap[1] = f2tf32(ra[l].y);
            ap[2] = f2tf32(ra[l].z); ap[3] = f2tf32(ra[l].w);
            uint32_t* bp = &Bs[buf][r * TSTR + (c << 2)];
            bp[0] = f2tf32(rb[l].x); bp[1] = f2tf32(rb[l].y);
            bp[2] = f2tf32(rb[l].z); bp[3] = f2tf32(rb[l].w);
        }
    };

    float acc[4][4][4];
    #pragma unroll
    for (int mi = 0; mi < 4; mi++)
        #pragma unroll
        for (int ni = 0; ni < 4; ni++)
            #pragma unroll
            for (int e = 0; e < 4; e++) acc[mi][ni][e] = 0.f;

    const int NKT = K >> 4;
    loadAB(0);
    storeAB(0);
    __syncthreads();

    const int lg = lane >> 2;
    const int lt = lane & 3;

    for (int kc = 0; kc < NKT; kc++) {
        const int cur = kc & 1;
        if (kc + 1 < NKT) loadAB(kc + 1);

        #pragma unroll
        for (int ks = 0; ks < 2; ks++) {
            const int k0 = (ks << 3) + lt;
            uint32_t af[4][4], bf[4][2];
            #pragma unroll
            for (int mi = 0; mi < 4; mi++) {
                int rm = wr * 64 + mi * 16 + lg;
                af[mi][0] = As[cur][rm * TSTR + k0];
                af[mi][1] = As[cur][(rm + 8) * TSTR + k0];
                af[mi][2] = As[cur][rm * TSTR + k0 + 4];
                af[mi][3] = As[cur][(rm + 8) * TSTR + k0 + 4];
            }
            #pragma unroll
            for (int ni = 0; ni < 4; ni++) {
                int cn = wc * 32 + ni * 8 + lg;
                bf[ni][0] = Bs[cur][cn * TSTR + k0];
                bf[ni][1] = Bs[cur][cn * TSTR + k0 + 4];
            }
            #pragma unroll
            for (int mi = 0; mi < 4; mi++)
                #pragma unroll
                for (int ni = 0; ni < 4; ni++)
                    mma1688(acc[mi][ni], af[mi], bf[ni]);
        }

        if (kc + 1 < NKT) storeAB(cur ^ 1);
        __syncthreads();
    }

    #pragma unroll
    for (int mi = 0; mi < 4; mi++) {
        int gr0 = row0 + wr * 64 + mi * 16 + lg;
        #pragma unroll
        for (int ni = 0; ni < 4; ni++) {
            int gc = col0 + wc * 32 + ni * 8 + 2 * lt;
            if (gc < Nn) {
                float v0 = acc[mi][ni][0], v1 = acc[mi][ni][1];
                float v2 = acc[mi][ni][2], v3 = acc[mi][ni][3];
                long o0 = (long)gr0 * ldc + gc;
                long o1 = (long)(gr0 + 8) * ldc + gc;
                if (EPI == 1) {
                    v0 = tanhf(v0); v1 = tanhf(v1); v2 = tanhf(v2); v3 = tanhf(v3);
                } else if (EPI == 2) {
                    float b0 = bias[gc], b1 = bias[gc + 1];
                    v0 = -expf(v0 + b0); v1 = -expf(v1 + b1);
                    v2 = -expf(v2 + b0); v3 = -expf(v3 + b1);
                } else if (EPI == 3) {
                    float b0 = bias[gc], b1 = bias[gc + 1];
                    float2 x0 = *(const float2*)&xin[o0];
                    float2 x1 = *(const float2*)&xin[o1];
                    float2 d0 = *(const float2*)&xxin[o0];
                    float2 d1 = *(const float2*)&xxin[o1];
                    v0 = fmaf(d0.x, b0 + v0, x0.x);
                    v1 = fmaf(d0.y, b1 + v1, x0.y);
                    v2 = fmaf(d1.x, b0 + v2, x1.x);
                    v3 = fmaf(d1.y, b1 + v3, x1.y);
                }
                *(float2*)&Cm[o0] = make_float2(v0, v1);
                *(float2*)&Cm[o1] = make_float2(v2, v3);
            }
        }
    }
}

template<int EPI>
__global__ __launch_bounds__(256, 2) void gemm_tc(
    const float* __restrict__ A, int lda,
    const float* __restrict__ Bt, int ldb,
    float* __restrict__ Cm, int ldc,
    int K, int Nn, const float* __restrict__ bias)
{
    __shared__ uint32_t As[2][128 * TSTR];
    __shared__ uint32_t Bs[2][128 * TSTR];
    gemm128_body<EPI>(As, Bs, A, lda, Bt, ldb, Cm, ldc, K, Nn, bias,
                      nullptr, nullptr, blockIdx.y * 128, blockIdx.x * 128);
}

// merged 5-branch mix GEMM: z selects branch
__global__ __launch_bounds__(256, 2) void gemm_mix(
    const float* __restrict__ lora, const float* __restrict__ w2T,
    const float* __restrict__ x, const float* __restrict__ xx,
    const float* m0, const float* m1, const float* m2, const float* m3, const float* m4,
    float* o0, float* o1, float* o2, float* o3, float* o4)
{
    __shared__ uint32_t As[2][128 * TSTR];
    __shared__ uint32_t Bs[2][128 * TSTR];
    const int z = blockIdx.z;
    const float* bias = (z == 0) ? m0 : (z == 1) ? m1 : (z == 2) ? m2 : (z == 3) ? m3 : m4;
    float* out = (z == 0) ? o0 : (z == 1) ? o1 : (z == 2) ? o2 : (z == 3) ? o3 : o4;
    gemm128_body<3>(As, Bs, lora + z * DMIX, 160, w2T + z * DMIX, 160,
                    out, C_, DMIX, C_, bias, x, xx,
                    blockIdx.y * 128, blockIdx.x * 128);
}

// ---- small tile: BM=64, BN=64, 128 threads (4 warps 2x2, warp 32x32) ---------
template<int EPI>
__global__ __launch_bounds__(128, 3) void gemm_tc64(
    const float* __restrict__ A, int lda,
    const float* __restrict__ Bt, int ldb,
    float* __restrict__ Cm, int ldc,
    int K, int Nn, const float* __restrict__ bias)
{
    __shared__ uint32_t As[2][64 * TSTR];
    __shared__ uint32_t Bs[2][64 * TSTR];

    const int tid = threadIdx.x;
    const int lane = tid & 31;
    const int wid = tid >> 5;
    const int wr = wid >> 1;
    const int wc = wid & 1;
    const int row0 = blockIdx.y * 64;
    const int col0 = blockIdx.x * 64;

    float4 ra[2], rb[2];

    auto loadAB = [&](int kc) {
        const int k0 = kc * 16;
        #pragma unroll
        for (int l = 0; l < 2; l++) {
            int e = tid + (l << 7);
            int r = e >> 2, c = e & 3;
            ra[l] = *(const float4*)&A[(long)(row0 + r) * lda + k0 + (c << 2)];
            int br = col0 + r;
            if (br < Nn)
                rb[l] = *(const float4*)&Bt[(long)br * ldb + k0 + (c << 2)];
            else
                rb[l] = make_float4(0.f, 0.f, 0.f, 0.f);
        }
    };
    auto storeAB = [&](int buf) {
        #pragma unroll
        for (int l = 0; l < 2; l++) {
            int e = tid + (l << 7);
            int r = e >> 2, c = e & 3;
            uint32_t* ap = &As[buf][r * TSTR + (c << 2)];
            ap[0] = f2tf32(ra[l].x); ap[1] = f2tf32(ra[l].y);
            ap[2] = f2tf32(ra[l].z); ap[3] = f2tf32(ra[l].w);
            uint32_t* bp = &Bs[buf][r * TSTR + (c << 2)];
            bp[0] = f2tf32(rb[l].x); bp[1] = f2tf32(rb[l].y);
            bp[2] = f2tf32(rb[l].z); bp[3] = f2tf32(rb[l].w);
        }
    };

    float acc[2][4][4];
    #pragma unroll
    for (int mi = 0; mi < 2; mi++)
        #pragma unroll
        for (int ni = 0; ni < 4; ni++)
            #pragma unroll
            for (int e = 0; e < 4; e++) acc[mi][ni][e] = 0.f;

    const int NKT = K >> 4;
    loadAB(0);
    storeAB(0);
    __syncthreads();

    const int lg = lane >> 2;
    const int lt = lane & 3;

    for (int kc = 0; kc < NKT; kc++) {
        const int cur = kc & 1;
        if (kc + 1 < NKT) loadAB(kc + 1);

        #pragma unroll
        for (int ks = 0; ks < 2; ks++) {
            const int k0 = (ks << 3) + lt;
            uint32_t af[2][4], bf[4][2];
            #pragma unroll
            for (int mi = 0; mi < 2; mi++) {
                int rm = wr * 32 + mi * 16 + lg;
                af[mi][0] = As[cur][rm * TSTR + k0];
                af[mi][1] = As[cur][(rm + 8) * TSTR + k0];
                af[mi][2] = As[cur][rm * TSTR + k0 + 4];
                af[mi][3] = As[cur][(rm + 8) * TSTR + k0 + 4];
            }
            #pragma unroll
            for (int ni = 0; ni < 4; ni++) {
                int cn = wc * 32 + ni * 8 + lg;
                bf[ni][0] = Bs[cur][cn * TSTR + k0];
                bf[ni][1] = Bs[cur][cn * TSTR + k0 + 4];
            }
            #pragma unroll
            for (int mi = 0; mi < 2; mi++)
                #pragma unroll
                for (int ni = 0; ni < 4; ni++)
                    mma1688(acc[mi][ni], af[mi], bf[ni]);
        }

        if (kc + 1 < NKT) storeAB(cur ^ 1);
        __syncthreads();
    }

    #pragma unroll
    for (int mi = 0; mi < 2; mi++) {
        int gr0 = row0 + wr * 32 + mi * 16 + lg;
        #pragma unroll
        for (int ni = 0; ni < 4; ni++) {
            int gc = col0 + wc * 32 + ni * 8 + 2 * lt;
            if (gc < Nn) {
                float v0 = acc[mi][ni][0], v1 = acc[mi][ni][1];
                float v2 = acc[mi][ni][2], v3 = acc[mi][ni][3];
                if (EPI == 1) {
                    v0 = tanhf(v0); v1 = tanhf(v1); v2 = tanhf(v2); v3 = tanhf(v3);
                } else if (EPI == 2) {
                    float b0 = bias[gc], b1 = bias[gc + 1];
                    v0 = -expf(v0 + b0); v1 = -expf(v1 + b1);
                    v2 = -expf(v2 + b0); v3 = -expf(v3 + b1);
                }
                *(float2*)&Cm[(long)gr0 * ldc + gc] = make_float2(v0, v1);
                *(float2*)&Cm[(long)(gr0 + 8) * ldc + gc] = make_float2(v2, v3);
            }
        }
    }
}

// ---------------- batched weight transpose -----------------------------------
struct TJob { const float* src; float* dst; int R, N, nbx, boff; };
struct TJobs { TJob j[10]; };

__global__ __launch_bounds__(256) void transpose_multi(TJobs js)
{
    __shared__ float t[32][33];
    int b = blockIdx.x;
    int ji = 0;
    #pragma unroll
    for (int q = 1; q < 10; q++)
        if (b >= js.j[q].boff) ji = q;
    TJob jb = js.j[ji];
    int rem = b - jb.boff;
    int bx = (rem % jb.nbx) * 32;
    int by = (rem / jb.nbx) * 32;
    const int x = threadIdx.x, y = threadIdx.y;
    #pragma unroll
    for (int i = 0; i < 32; i += 8) {
        int r = by + y + i, n = bx + x;
        if (r < jb.R && n < jb.N) t[y + i][x] = jb.src[(long)r * jb.N + n];
    }
    __syncthreads();
    #pragma unroll
    for (int i = 0; i < 32; i += 8) {
        int n = bx + y + i, r = by + x;
        if (n < jb.N && r < jb.R) jb.dst[(long)n * jb.R + r] = t[x][y + i];
    }
}

// ---------------- elementwise: time shift + maa_x mix (float4) ---------------
__global__ void shift_kernel(const float4* __restrict__ x4,
                             const float* __restrict__ maa_x,
                             float4* __restrict__ xx4, float4* __restrict__ xxx4,
                             long total4)
{
    long idx = (long)blockIdx.x * blockDim.x + threadIdx.x;
    if (idx >= total4) return;
    const int C4 = C_ / 4;
    int c4 = (int)(idx % C4);
    long rt = idx / C4;
    int t = (int)(rt % T_);
    float4 xv = x4[idx];
    float4 xp = (t > 0) ? x4[idx - C4] : make_float4(0.f, 0.f, 0.f, 0.f);
    float4 mx = *(const float4*)&maa_x[c4 * 4];
    float4 d = make_float4(xp.x - xv.x, xp.y - xv.y, xp.z - xv.z, xp.w - xv.w);
    xx4[idx] = d;
    xxx4[idx] = make_float4(fmaf(d.x, mx.x, xv.x), fmaf(d.y, mx.y, xv.y),
                            fmaf(d.z, mx.z, xv.z), fmaf(d.w, mx.w, xv.w));
}

// ---------------- chunked WKV6 -----------------------------------------------
__global__ __launch_bounds__(256) void wkv_chunkA(
    const float* __restrict__ r, const float* __restrict__ k,
    const float* __restrict__ v, const float* __restrict__ lw,
    const float* __restrict__ u,
    float* __restrict__ y, float* __restrict__ Dout,
    float* __restrict__ rpout, float* __restrict__ pLout)
{
    extern __shared__ float sm[];
    float* lp   = sm;
    float* bufA = lp + 65 * 64;
    float* rpT  = bufA + 64 * STRD;
    float* kpT  = rpT + 64 * STRD;
    float* kpp  = kpT + 64 * STRD;
    float* vsm  = kpp + 64 * STRD;
    float* dsm  = vsm + 64 * STRD;
    float* usm  = dsm + 64;

    const int tid = threadIdx.x;
    const int chunk = blockIdx.x;
    const int bh = chunk >> 5;
    const int c  = chunk & 31;
    const int b = bh >> 4, h = bh & 15;
    const long base = ((long)b * T_ + c * CHUNK) * C_ + h * 64;

    if (tid < 64) usm[tid] = u[h * 64 + tid];
    const int i  = tid & 63;
    const int tq = tid >> 6;

    #pragma unroll
    for (int e = 0; e < 16; e++) {
        int t = tq + 4 * e;
        bufA[t * STRD + i] = lw[base + (long)t * C_ + i];
    }
    __syncthreads();

    if (tid < 64) {
        float run = 0.f;
        for (int t = 0; t < 64; t++) {
            lp[t * 64 + tid] = run;
            run += bufA[t * STRD + tid];
        }
        lp[64 * 64 + tid] = run;
        pLout[(long)chunk * 64 + tid] = run;
    }
    __syncthreads();

    #pragma unroll
    for (int e = 0; e < 16; e++) {
        int t = tq + 4 * e;
        long gi = base + (long)t * C_ + i;
        float rr = r[gi], kk = k[gi];
        float lpti = lp[t * 64 + i];
        float lpn  = lpti + bufA[t * STRD + i];
        float lpL  = lp[64 * 64 + i];
        rpT[i * STRD + t] = rr * __expf(lpti);
        kpT[i * STRD + t] = kk * __expf(-lpn);
        kpp[t * STRD + i] = kk * __expf(lpL - lpn);
        vsm[t * STRD + i] = v[gi];
    }
    {
        int t = tid >> 2, q = tid & 3;
        long gb = base + (long)t * C_;
        float p = 0.f;
        #pragma unroll
        for (int ii = 0; ii < 16; ii++) {
            int ci = q * 16 + ii;
            p += r[gb + ci] * usm[ci] * k[gb + ci];
        }
        p += __shfl_xor_sync(0xffffffffu, p, 1);
        p += __shfl_xor_sync(0xffffffffu, p, 2);
        if (q == 0) dsm[t] = p;
    }
    __syncthreads();

    {
        float* rpg = rpout + (long)chunk * 64 * 64;
        #pragma unroll
        for (int e = 0; e < 16; e++) {
            int flat = tid + 256 * e;
            rpg[flat] = rpT[(flat >> 6) * STRD + (flat & 63)];
        }
    }

    {
        int t0 = (tid >> 4) * 4, s0 = (tid & 15) * 4;
        float acc[4][4];
        #pragma unroll
        for (int a = 0; a < 4; a++)
            #pragma unroll
            for (int bq = 0; bq < 4; bq++) acc[a][bq] = 0.f;
        for (int ii = 0; ii < 64; ii++) {
            float4 a4 = *(const float4*)&rpT[ii * STRD + t0];
            float4 b4 = *(const float4*)&kpT[ii * STRD + s0];
            float av[4] = { a4.x, a4.y, a4.z, a4.w };
            float bv[4] = { b4.x, b4.y, b4.z, b4.w };
            #pragma unroll
            for (int a = 0; a < 4; a++)
                #pragma unroll
                for (int bq = 0; bq < 4; bq++)
                    acc[a][bq] = fmaf(av[a], bv[bq], acc[a][bq]);
        }
        __syncthreads();
        #pragma unroll
        for (int a = 0; a < 4; a++)
            #pragma unroll
            for (int bq = 0; bq < 4; bq++) {
                int tt = t0 + a, ss = s0 + bq;
                float val = (tt > ss) ? acc[a][bq] : ((tt == ss) ? dsm[tt] : 0.f);
                bufA[ss * STRD + tt] = val;
            }
    }
    __syncthreads();

    {
        int t0 = (tid >> 4) * 4, j0 = (tid & 15) * 4;
        float acc[4][4];
        #pragma unroll
        for (int a = 0; a < 4; a++)
            #pragma unroll
            for (int bq = 0; bq < 4; bq++) acc[a][bq] = 0.f;
        for (int s = 0; s < 64; s++) {
            float4 a4 = *(const float4*)&bufA[s * STRD + t0];
            float4 b4 = *(const float4*)&vsm[s * STRD + j0];
            float av[4] = { a4.x, a4.y, a4.z, a4.w };
            float bv[4] = { b4.x, b4.y, b4.z, b4.w };
            #pragma unroll
            for (int a = 0; a < 4; a++)
                #pragma unroll
                for (int bq = 0; bq < 4; bq++)
                    acc[a][bq] = fmaf(av[a], bv[bq], acc[a][bq]);
        }
        #pragma unroll
        for (int a = 0; a < 4; a++) {
            float4 o = make_float4(acc[a][0], acc[a][1], acc[a][2], acc[a][3]);
            *(float4*)&y[base + (long)(t0 + a) * C_ + j0] = o;
        }
    }

    {
        int i0 = (tid >> 4) * 4, j0 = (tid & 15) * 4;
        float acc[4][4];
        #pragma unroll
        for (int a = 0; a < 4; a++)
            #pragma unroll
            for (int bq = 0; bq < 4; bq++) acc[a][bq] = 0.f;
        for (int s = 0; s < 64; s++) {
            float4 a4 = *(const float4*)&kpp[s * STRD + i0];
            float4 b4 = *(const float4*)&vsm[s * STRD + j0];
            float av[4] = { a4.x, a4.y, a4.z, a4.w };
            float bv[4] = { b4.x, b4.y, b4.z, b4.w };
            #pragma unroll
            for (int a = 0; a < 4; a++)
                #pragma unroll
                for (int bq = 0; bq < 4; bq++)
                    acc[a][bq] = fmaf(av[a], bv[bq], acc[a][bq]);
        }
        float* Dp = Dout + (long)chunk * 4096;
        #pragma unroll
        for (int a = 0; a < 4; a++) {
            float4 o = make_float4(acc[a][0], acc[a][1], acc[a][2], acc[a][3]);
            *(float4*)&Dp[(i0 + a) * 64 + j0] = o;
        }
    }
}

__global__ __launch_bounds__(256) void wkv_chunkB(
    const float* __restrict__ D, const float* __restrict__ pL,
    float* __restrict__ S)
{
    const int bh = blockIdx.x;
    const int tid = threadIdx.x;
    const int i = tid >> 2;
    const int jb = (tid & 3) * 16;
    float4 s0 = {0,0,0,0}, s1 = {0,0,0,0}, s2 = {0,0,0,0}, s3 = {0,0,0,0};
    for (int c = 0; c < G_; c++) {
        long chunk = (long)bh * G_ + c;
        long off = chunk * 4096 + i * 64 + jb;
        *(float4*)&S[off + 0]  = s0;
        *(float4*)&S[off + 4]  = s1;
        *(float4*)&S[off + 8]  = s2;
        *(float4*)&S[off + 12] = s3;
        float pl = __expf(pL[chunk * 64 + i]);
        float4 d0 = *(const float4*)&D[off + 0];
        float4 d1 = *(const float4*)&D[off + 4];
        float4 d2 = *(const float4*)&D[off + 8];
        float4 d3 = *(const float4*)&D[off + 12];
        s0 = make_float4(fmaf(pl, s0.x, d0.x), fmaf(pl, s0.y, d0.y), fmaf(pl, s0.z, d0.z), fmaf(pl, s0.w, d0.w));
        s1 = make_float4(fmaf(pl, s1.x, d1.x), fmaf(pl, s1.y, d1.y), fmaf(pl, s1.z, d1.z), fmaf(pl, s1.w, d1.w));
        s2 = make_float4(fmaf(pl, s2.x, d2.x), fmaf(pl, s2.y, d2.y), fmaf(pl, s2.z, d2.z), fmaf(pl, s2.w, d2.w));
        s3 = make_float4(fmaf(pl, s3.x, d3.x), fmaf(pl, s3.y, d3.y), fmaf(pl, s3.z, d3.z), fmaf(pl, s3.w, d3.w));
    }
}

__global__ __launch_bounds__(256) void wkv_chunkC(
    const float* __restrict__ rp, const float* __restrict__ S,
    float* __restrict__ y)
{
    __shared__ float rps[64 * 64];
    __shared__ float Ss[64 * 64];
    const int tid = threadIdx.x;
    const int chunk = blockIdx.x;
    const int bh = chunk >> 5;
    const int c  = chunk & 31;
    const int b = bh >> 4, h = bh & 15;
    const long base = ((long)b * T_ + c * CHUNK) * C_ + h * 64;

    const float* rpg = rp + (long)chunk * 4096;
    const float* Sg  = S  + (long)chunk * 4096;
    #pragma unroll
    for (int e = 0; e < 4; e++) {
        int f4 = tid + 256 * e;
        *(float4*)&rps[f4 * 4] = *(const float4*)&rpg[f4 * 4];
        *(float4*)&Ss[f4 * 4]  = *(const float4*)&Sg[f4 * 4];
    }
    __syncthreads();

    int t0 = (tid >> 4) * 4, j0 = (tid & 15) * 4;
    float acc[4][4];
    #pragma unroll
    for (int a = 0; a < 4; a++)
        #pragma unroll
        for (int bq = 0; bq < 4; bq++) acc[a][bq] = 0.f;
    for (int ii = 0; ii < 64; ii++) {
        float4 a4 = *(const float4*)&rps[ii * 64 + t0];
        float4 b4 = *(const float4*)&Ss[ii * 64 + j0];
        float av[4] = { a4.x, a4.y, a4.z, a4.w };
        float bv[4] = { b4.x, b4.y, b4.z, b4.w };
        #pragma unroll
        for (int a = 0; a < 4; a++)
            #pragma unroll
            for (int bq = 0; bq < 4; bq++)
                acc[a][bq] = fmaf(av[a], bv[bq], acc[a][bq]);
    }
    #pragma unroll
    for (int a = 0; a < 4; a++) {
        long yo = base + (long)(t0 + a) * C_ + j0;
        float4 cur = *(const float4*)&y[yo];
        cur.x += acc[a][0]; cur.y += acc[a][1];
        cur.z += acc[a][2]; cur.w += acc[a][3];
        *(float4*)&y[yo] = cur;
    }
}

// ---------------- GroupNorm over heads + gate multiply -----------------------
__global__ __launch_bounds__(512) void gn_kernel(
    const float* __restrict__ y, const float* __restrict__ ln_g,
    const float* __restrict__ ln_b, const float* __restrict__ g,
    float* __restrict__ z)
{
    const int bt = blockIdx.x;
    const int warp = threadIdx.x >> 5;
    const int lane = threadIdx.x & 31;
    const long base = (long)bt * C_ + warp * 64;

    float a0 = y[base + lane];
    float a1 = y[base + 32 + lane];
    float sum = a0 + a1;
    float sq = a0 * a0 + a1 * a1;
    #pragma unroll
    for (int off = 16; off > 0; off >>= 1) {
        sum += __shfl_xor_sync(0xffffffffu, sum, off);
        sq  += __shfl_xor_sync(0xffffffffu, sq,  off);
    }
    float mu = sum * (1.f / 64.f);
    float var = sq * (1.f / 64.f) - mu * mu;
    float inv = rsqrtf(var + 6.4e-4f);

    int c0 = warp * 64 + lane;
    float z0 = (a0 - mu) * inv * ln_g[c0] + ln_b[c0];
    float z1 = (a1 - mu) * inv * ln_g[c0 + 32] + ln_b[c0 + 32];
    z[base + lane]      = z0 * g[base + lane];
    z[base + 32 + lane] = z1 * g[base + 32 + lane];
}

// ---------------- launcher ----------------------------------------------------
extern "C" void kernel_launch(void* const* d_in, const int* in_sizes, int n_in,
                              void* d_out, int out_size)
{
    const float* x          = (const float*)d_in[0];
    const float* maa_x      = (const float*)d_in[1];
    const float* maa_w      = (const float*)d_in[2];
    const float* maa_k      = (const float*)d_in[3];
    const float* maa_v      = (const float*)d_in[4];
    const float* maa_r      = (const float*)d_in[5];
    const float* maa_g      = (const float*)d_in[6];
    const float* maa_w1     = (const float*)d_in[7];
    const float* maa_w2     = (const float*)d_in[8];
    const float* Wr         = (const float*)d_in[9];
    const float* Wk         = (const float*)d_in[10];
    const float* Wv         = (const float*)d_in[11];
    const float* Wo         = (const float*)d_in[12];
    const float* gate_w1    = (const float*)d_in[13];
    const float* gate_w2    = (const float*)d_in[14];
    const float* time_decay = (const float*)d_in[15];
    const float* decay_w1   = (const float*)d_in[16];
    const float* decay_w2   = (const float*)d_in[17];
    const float* u          = (const float*)d_in[18];
    const float* ln_g       = (const float*)d_in[19];
    const float* ln_b       = (const float*)d_in[20];
    (void)in_sizes; (void)n_in; (void)out_size;

    float *p_xx, *p_xxx, *p_xw, *p_xk, *p_xv, *p_xr, *p_xg;
    float *p_r, *p_k, *p_v, *p_w, *p_g, *p_y, *p_z, *p_lora, *p_small;
    float *p_D, *p_Sc, *p_rp, *p_pL;
    float *p_WrT, *p_WkT, *p_WvT, *p_WoT, *p_w1T, *p_w2T, *p_dw1T, *p_gw1T, *p_dw2T, *p_gw2T;
    cudaGetSymbolAddress((void**)&p_xx, g_xx);
    cudaGetSymbolAddress((void**)&p_xxx, g_xxx);
    cudaGetSymbolAddress((void**)&p_xw, g_xw);
    cudaGetSymbolAddress((void**)&p_xk, g_xk);
    cudaGetSymbolAddress((void**)&p_xv, g_xv);
    cudaGetSymbolAddress((void**)&p_xr, g_xr);
    cudaGetSymbolAddress((void**)&p_xg, g_xg);
    cudaGetSymbolAddress((void**)&p_r, g_r);
    cudaGetSymbolAddress((void**)&p_k, g_k);
    cudaGetSymbolAddress((void**)&p_v, g_v);
    cudaGetSymbolAddress((void**)&p_w, g_w);
    cudaGetSymbolAddress((void**)&p_g, g_g);
    cudaGetSymbolAddress((void**)&p_y, g_y);
    cudaGetSymbolAddress((void**)&p_z, g_z);
    cudaGetSymbolAddress((void**)&p_lora, g_lora);
    cudaGetSymbolAddress((void**)&p_small, g_small);
    cudaGetSymbolAddress((void**)&p_D, g_D);
    cudaGetSymbolAddress((void**)&p_Sc, g_Sc);
    cudaGetSymbolAddress((void**)&p_rp, g_rp);
    cudaGetSymbolAddress((void**)&p_pL, g_pL);
    cudaGetSymbolAddress((void**)&p_WrT, g_WrT);
    cudaGetSymbolAddress((void**)&p_WkT, g_WkT);
    cudaGetSymbolAddress((void**)&p_WvT, g_WvT);
    cudaGetSymbolAddress((void**)&p_WoT, g_WoT);
    cudaGetSymbolAddress((void**)&p_w1T, g_w1T);
    cudaGetSymbolAddress((void**)&p_w2T, g_w2T);
    cudaGetSymbolAddress((void**)&p_dw1T, g_dw1T);
    cudaGetSymbolAddress((void**)&p_gw1T, g_gw1T);
    cudaGetSymbolAddress((void**)&p_dw2T, g_dw2T);
    cudaGetSymbolAddress((void**)&p_gw2T, g_gw2T);

    const long total = BTC;
    const int M = B_ * T_;          // 8192
    const int gy = M / 128;         // 64
    const int gy64 = M / 64;        // 128

    const int SMEM_A = (65 * 64 + 5 * 64 * STRD + 128) * 4;
    cudaFuncSetAttribute(wkv_chunkA, cudaFuncAttributeMaxDynamicSharedMemorySize, SMEM_A);

    // build transpose job table
    TJobs tj;
    int toff = 0;
    {
        const float* srcs[10] = { maa_w1, maa_w2, Wr, Wk, Wv, Wo,
                                  decay_w1, gate_w1, decay_w2, gate_w2 };
        float* dsts[10] = { p_w1T, p_w2T, p_WrT, p_WkT, p_WvT, p_WoT,
                            p_dw1T, p_gw1T, p_dw2T, p_gw2T };
        int Rs[10] = { 1024, 160, 1024, 1024, 1024, 1024, 1024, 1024, 64, 64 };
        int Ns[10] = { 160, 1024, 1024, 1024, 1024, 1024, 64, 64, 1024, 1024 };
        for (int q = 0; q < 10; q++) {
            int nbx = (Ns[q] + 31) / 32;
            int nby = (Rs[q] + 31) / 32;
            tj.j[q].src = srcs[q]; tj.j[q].dst = dsts[q];
            tj.j[q].R = Rs[q]; tj.j[q].N = Ns[q];
            tj.j[q].nbx = nbx; tj.j[q].boff = toff;
            toff += nbx * nby;
        }
    }

    // 0. shift (vectorized)
    shift_kernel<<<(int)((total / 4 + 255) / 256), 256>>>(
        (const float4*)x, maa_x, (float4*)p_xx, (float4*)p_xxx, total / 4);
    // 1. all weight transposes
    transpose_multi<<<toff, dim3(32, 8)>>>(tj);
    // 2. lora = tanh(xxx @ maa_w1)  N=160
    gemm_tc64<1><<<dim3(3, gy64), 128>>>(p_xxx, C_, p_w1T, C_, p_lora, 160, C_, 160, nullptr);
    // 3. merged 5-branch mix GEMM (profiled by ncu)
    gemm_mix<<<dim3(8, gy, 5), 256>>>(p_lora, p_w2T, x, p_xx,
        maa_w, maa_k, maa_v, maa_r, maa_g,
        p_xw, p_xk, p_xv, p_xr, p_xg);
    // 4-6. r, k, v projections
    gemm_tc<0><<<dim3(8, gy), 256>>>(p_xr, C_, p_WrT, C_, p_r, C_, C_, C_, nullptr);
    gemm_tc<0><<<dim3(8, gy), 256>>>(p_xk, C_, p_WkT, C_, p_k, C_, C_, C_, nullptr);
    gemm_tc<0><<<dim3(8, gy), 256>>>(p_xv, C_, p_WvT, C_, p_v, C_, C_, C_, nullptr);
    // 7-8. decay: lw = -exp(time_decay + tanh(xw@decay_w1)@decay_w2)
    gemm_tc64<1><<<dim3(1, gy64), 128>>>(p_xw, C_, p_dw1T, C_, p_small, 64, C_, 64, nullptr);
    gemm_tc<2><<<dim3(8, gy), 256>>>(p_small, 64, p_dw2T, 64, p_w, C_, 64, C_, time_decay);
    // 9-11. chunked WKV6
    wkv_chunkA<<<NCHUNK, 256, SMEM_A>>>(p_r, p_k, p_v, p_w, u, p_y, p_D, p_rp, p_pL);
    wkv_chunkB<<<B_ * H_, 256>>>(p_D, p_pL, p_Sc);
    wkv_chunkC<<<NCHUNK, 256>>>(p_rp, p_Sc, p_y);
    // 12-13. gate
    gemm_tc64<1><<<dim3(1, gy64), 128>>>(p_xg, C_, p_gw1T, C_, p_small, 64, C_, 64, nullptr);
    gemm_tc<0><<<dim3(8, gy), 256>>>(p_small, 64, p_gw2T, 64, p_g, C_, 64, C_, nullptr);
    // 14. GroupNorm + gate multiply
    gn_kernel<<<M, 512>>>(p_y, ln_g, ln_b, p_g, p_z);
    // 15. out = z @ Wo
    gemm_tc<0><<<dim3(8, gy), 256>>>(p_z, C_, p_WoT, C_, (float*)d_out, C_, C_, C_, nullptr);
}

// round 9
// speedup vs baseline: 1.2530x; 1.0985x over previous
#include <cuda_runtime.h>
#include <cuda_bf16.h>
#include <cstdint>
#include <math.h>

// Problem constants
#define B_  4
#define T_  2048
#define C_  1024
#define H_  16
#define N_  64
#define DMIX 32

#define CHUNK 64
#define G_ 32                     // chunks per (b,h)
#define NCHUNK (B_*H_*G_)         // 2048
#define STRD 68                   // padded row stride for chunk smem tiles

static const long BTC = (long)B_ * T_ * C_;   // 8388608

// ---------------- scratch (device globals; no runtime allocation) -------------
__device__ float g_xx [ (long)B_*T_*C_ ];
__device__ float g_xxx[ (long)B_*T_*C_ ];
__device__ float g_xw [ (long)B_*T_*C_ ];
__device__ float g_xk [ (long)B_*T_*C_ ];
__device__ float g_xv [ (long)B_*T_*C_ ];
__device__ float g_xr [ (long)B_*T_*C_ ];
__device__ float g_xg [ (long)B_*T_*C_ ];
__device__ float g_r  [ (long)B_*T_*C_ ];
__device__ float g_k  [ (long)B_*T_*C_ ];
__device__ float g_v  [ (long)B_*T_*C_ ];
__device__ float g_w  [ (long)B_*T_*C_ ];   // lw = log(decay)
__device__ float g_g  [ (long)B_*T_*C_ ];
__device__ float g_y  [ (long)B_*T_*C_ ];
__device__ float g_z  [ (long)B_*T_*C_ ];
__device__ float g_lora [ (long)B_*T_*5*DMIX ];
__device__ float g_small [ (long)B_*T_*64 ];
__device__ float g_small2[ (long)B_*T_*64 ];
__device__ float g_D  [ (long)NCHUNK*64*64 ];
__device__ float g_Sc [ (long)NCHUNK*64*64 ];
__device__ float g_rp [ (long)NCHUNK*64*64 ];
__device__ float g_pL [ (long)NCHUNK*64 ];
// transposed weights [N, K] K-major
__device__ float g_WrT[ (long)C_*C_ ];
__device__ float g_WkT[ (long)C_*C_ ];
__device__ float g_WvT[ (long)C_*C_ ];
__device__ float g_WoT[ (long)C_*C_ ];
__device__ float g_w1T[ (long)160*C_ ];
__device__ float g_w2T[ (long)C_*160 ];
__device__ float g_dw1T[ (long)64*C_ ];
__device__ float g_gw1T[ (long)64*C_ ];
__device__ float g_dw2T[ (long)C_*64 ];
__device__ float g_gw2T[ (long)C_*64 ];

// ================= tf32 mma.sync GEMM ========================================
#define TSTR 20   // smem row stride (16 + 4 pad) -> conflict-free fragments

__device__ __forceinline__ uint32_t f2tf32(float f) {
    uint32_t o;
    asm("cvt.rna.tf32.f32 %0, %1;" : "=r"(o) : "f"(f));
    return o;
}
__device__ __forceinline__ void mma1688(float* d, const uint32_t* a, const uint32_t* b) {
    asm volatile(
        "mma.sync.aligned.m16n8k8.row.col.f32.tf32.tf32.f32 "
        "{%0,%1,%2,%3}, {%4,%5,%6,%7}, {%8,%9}, {%0,%1,%2,%3};"
        : "+f"(d[0]), "+f"(d[1]), "+f"(d[2]), "+f"(d[3])
        : "r"(a[0]), "r"(a[1]), "r"(a[2]), "r"(a[3]), "r"(b[0]), "r"(b[1]));
}

// ---- shared 128x128 body. EPI template: 0 none, 1 tanh, 2 -exp(acc+bias),
//      3 xin + xxin*(bias + acc), -2 = runtime repi (0/1/2 only).
template<int EPI>
__device__ __forceinline__ void gemm128_body(
    uint32_t (*As)[128 * TSTR], uint32_t (*Bs)[128 * TSTR],
    const float* __restrict__ A, int lda,
    const float* __restrict__ Bt, int ldb,
    float* __restrict__ Cm, int ldc,
    int K, int Nn, const float* __restrict__ bias,
    const float* __restrict__ xin, const float* __restrict__ xxin,
    int row0, int col0, int repi)
{
    const int tid = threadIdx.x;
    const int lane = tid & 31;
    const int wid = tid >> 5;
    const int wr = wid >> 2;
    const int wc = wid & 3;

    float4 ra[2], rb[2];

    auto loadAB = [&](int kc) {
        const int k0 = kc * 16;
        #pragma unroll
        for (int l = 0; l < 2; l++) {
            int e = tid + (l << 8);
            int r = e >> 2, c = e & 3;
            ra[l] = *(const float4*)&A[(long)(row0 + r) * lda + k0 + (c << 2)];
            int br = col0 + r;
            if (br < Nn)
                rb[l] = *(const float4*)&Bt[(long)br * ldb + k0 + (c << 2)];
            else
                rb[l] = make_float4(0.f, 0.f, 0.f, 0.f);
        }
    };
    auto storeAB = [&](int buf) {
        #pragma unroll
        for (int l = 0; l < 2; l++) {
            int e = tid + (l << 8);
            int r = e >> 2, c = e & 3;
            uint32_t* ap = &As[buf][r * TSTR + (c << 2)];
            ap[0] = f2tf32(ra[l].x); ap[1] = f2tf32(ra[l].y);
            ap[2] = f2tf32(ra[l].z); ap[3] = f2tf32(ra[l].w);
            uint32_t* bp = &Bs[buf][r * TSTR + (c << 2)];
            bp[0] = f2tf32(rb[l].x); bp[1] = f2tf32(rb[l].y);
            bp[2] = f2tf32(rb[l].z); bp[3] = f2tf32(rb[l].w);
        }
    };

    float acc[4][4][4];
    #pragma unroll
    for (int mi = 0; mi < 4; mi++)
        #pragma unroll
        for (int ni = 0; ni < 4; ni++)
            #pragma unroll
            for (int e = 0; e < 4; e++) acc[mi][ni][e] = 0.f;

    const int NKT = K >> 4;
    loadAB(0);
    storeAB(0);
    __syncthreads();

    const int lg = lane >> 2;
    const int lt = lane & 3;

    for (int kc = 0; kc < NKT; kc++) {
        const int cur = kc & 1;
        if (kc + 1 < NKT) loadAB(kc + 1);

        #pragma unroll
        for (int ks = 0; ks < 2; ks++) {
            const int k0 = (ks << 3) + lt;
            uint32_t af[4][4], bf[4][2];
            #pragma unroll
            for (int mi = 0; mi < 4; mi++) {
                int rm = wr * 64 + mi * 16 + lg;
                af[mi][0] = As[cur][rm * TSTR + k0];
                af[mi][1] = As[cur][(rm + 8) * TSTR + k0];
                af[mi][2] = As[cur][rm * TSTR + k0 + 4];
                af[mi][3] = As[cur][(rm + 8) * TSTR + k0 + 4];
            }
            #pragma unroll
            for (int ni = 0; ni < 4; ni++) {
                int cn = wc * 32 + ni * 8 + lg;
                bf[ni][0] = Bs[cur][cn * TSTR + k0];
                bf[ni][1] = Bs[cur][cn * TSTR + k0 + 4];
            }
            #pragma unroll
            for (int mi = 0; mi < 4; mi++)
                #pragma unroll
                for (int ni = 0; ni < 4; ni++)
                    mma1688(acc[mi][ni], af[mi], bf[ni]);
        }

        if (kc + 1 < NKT) storeAB(cur ^ 1);
        __syncthreads();
    }

    const int ep = (EPI == -2) ? repi : EPI;
    #pragma unroll
    for (int mi = 0; mi < 4; mi++) {
        int gr0 = row0 + wr * 64 + mi * 16 + lg;
        #pragma unroll
        for (int ni = 0; ni < 4; ni++) {
            int gc = col0 + wc * 32 + ni * 8 + 2 * lt;
            if (gc < Nn) {
                float v0 = acc[mi][ni][0], v1 = acc[mi][ni][1];
                float v2 = acc[mi][ni][2], v3 = acc[mi][ni][3];
                long o0 = (long)gr0 * ldc + gc;
                long o1 = (long)(gr0 + 8) * ldc + gc;
                if (ep == 1) {
                    v0 = tanhf(v0); v1 = tanhf(v1); v2 = tanhf(v2); v3 = tanhf(v3);
                } else if (ep == 2) {
                    float b0 = bias[gc], b1 = bias[gc + 1];
                    v0 = -expf(v0 + b0); v1 = -expf(v1 + b1);
                    v2 = -expf(v2 + b0); v3 = -expf(v3 + b1);
                } else if (ep == 3) {
                    float b0 = bias[gc], b1 = bias[gc + 1];
                    float2 x0 = *(const float2*)&xin[o0];
                    float2 x1 = *(const float2*)&xin[o1];
                    float2 d0 = *(const float2*)&xxin[o0];
                    float2 d1 = *(const float2*)&xxin[o1];
                    v0 = fmaf(d0.x, b0 + v0, x0.x);
                    v1 = fmaf(d0.y, b1 + v1, x0.y);
                    v2 = fmaf(d1.x, b0 + v2, x1.x);
                    v3 = fmaf(d1.y, b1 + v3, x1.y);
                }
                *(float2*)&Cm[o0] = make_float2(v0, v1);
                *(float2*)&Cm[o1] = make_float2(v2, v3);
            }
        }
    }
}

template<int EPI>
__global__ __launch_bounds__(256, 2) void gemm_tc(
    const float* __restrict__ A, int lda,
    const float* __restrict__ Bt, int ldb,
    float* __restrict__ Cm, int ldc,
    int K, int Nn, const float* __restrict__ bias)
{
    __shared__ uint32_t As[2][128 * TSTR];
    __shared__ uint32_t Bs[2][128 * TSTR];
    gemm128_body<EPI>(As, Bs, A, lda, Bt, ldb, Cm, ldc, K, Nn, bias,
                      nullptr, nullptr, blockIdx.y * 128, blockIdx.x * 128, 0);
}

// merged r,k,v projections: z selects
__global__ __launch_bounds__(256, 2) void gemm_rkv(
    const float* xr, const float* xk, const float* xv,
    const float* WrT, const float* WkT, const float* WvT,
    float* r, float* k, float* v)
{
    __shared__ uint32_t As[2][128 * TSTR];
    __shared__ uint32_t Bs[2][128 * TSTR];
    const int z = blockIdx.z;
    const float* A  = (z == 0) ? xr : (z == 1) ? xk : xv;
    const float* Bt = (z == 0) ? WrT : (z == 1) ? WkT : WvT;
    float* Cm       = (z == 0) ? r : (z == 1) ? k : v;
    gemm128_body<0>(As, Bs, A, C_, Bt, C_, Cm, C_, C_, C_, nullptr,
                    nullptr, nullptr, blockIdx.y * 128, blockIdx.x * 128, 0);
}

// merged decay2 (epi 2) + gate2 (epi 0)
__global__ __launch_bounds__(256, 2) void gemm_dg2(
    const float* small1, const float* small2,
    const float* dw2T, const float* gw2T,
    float* w, float* g, const float* time_decay)
{
    __shared__ uint32_t As[2][128 * TSTR];
    __shared__ uint32_t Bs[2][128 * TSTR];
    const int z = blockIdx.z;
    const float* A  = (z == 0) ? small1 : small2;
    const float* Bt = (z == 0) ? dw2T : gw2T;
    float* Cm       = (z == 0) ? w : g;
    gemm128_body<-2>(As, Bs, A, 64, Bt, 64, Cm, C_, 64, C_, time_decay,
                     nullptr, nullptr, blockIdx.y * 128, blockIdx.x * 128,
                     (z == 0) ? 2 : 0);
}

// merged 5-branch mix GEMM: z selects branch
__global__ __launch_bounds__(256, 2) void gemm_mix(
    const float* __restrict__ lora, const float* __restrict__ w2T,
    const float* __restrict__ x, const float* __restrict__ xx,
    const float* m0, const float* m1, const float* m2, const float* m3, const float* m4,
    float* o0, float* o1, float* o2, float* o3, float* o4)
{
    __shared__ uint32_t As[2][128 * TSTR];
    __shared__ uint32_t Bs[2][128 * TSTR];
    const int z = blockIdx.z;
    const float* bias = (z == 0) ? m0 : (z == 1) ? m1 : (z == 2) ? m2 : (z == 3) ? m3 : m4;
    float* out = (z == 0) ? o0 : (z == 1) ? o1 : (z == 2) ? o2 : (z == 3) ? o3 : o4;
    gemm128_body<3>(As, Bs, lora + z * DMIX, 160, w2T + z * DMIX, 160,
                    out, C_, DMIX, C_, bias, x, xx,
                    blockIdx.y * 128, blockIdx.x * 128, 0);
}

// ---- small tile: BM=64, BN=64, 128 threads (4 warps 2x2, warp 32x32) ---------
template<int EPI>
__device__ __forceinline__ void gemm64_body(
    uint32_t (*As)[64 * TSTR], uint32_t (*Bs)[64 * TSTR],
    const float* __restrict__ A, int lda,
    const float* __restrict__ Bt, int ldb,
    float* __restrict__ Cm, int ldc,
    int K, int Nn, const float* __restrict__ bias,
    int row0, int col0)
{
    const int tid = threadIdx.x;
    const int lane = tid & 31;
    const int wid = tid >> 5;
    const int wr = wid >> 1;
    const int wc = wid & 1;

    float4 ra[2], rb[2];

    auto loadAB = [&](int kc) {
        const int k0 = kc * 16;
        #pragma unroll
        for (int l = 0; l < 2; l++) {
            int e = tid + (l << 7);
            int r = e >> 2, c = e & 3;
            ra[l] = *(const float4*)&A[(long)(row0 + r) * lda + k0 + (c << 2)];
            int br = col0 + r;
            if (br < Nn)
                rb[l] = *(const float4*)&Bt[(long)br * ldb + k0 + (c << 2)];
            else
                rb[l] = make_float4(0.f, 0.f, 0.f, 0.f);
        }
    };
    auto storeAB = [&](int buf) {
        #pragma unroll
        for (int l = 0; l < 2; l++) {
            int e = tid + (l << 7);
            int r = e >> 2, c = e & 3;
            uint32_t* ap = &As[buf][r * TSTR + (c << 2)];
            ap[0] = f2tf32(ra[l].x); ap[1] = f2tf32(ra[l].y);
            ap[2] = f2tf32(ra[l].z); ap[3] = f2tf32(ra[l].w);
            uint32_t* bp = &Bs[buf][r * TSTR + (c << 2)];
            bp[0] = f2tf32(rb[l].x); bp[1] = f2tf32(rb[l].y);
            bp[2] = f2tf32(rb[l].z); bp[3] = f2tf32(rb[l].w);
        }
    };

    float acc[2][4][4];
    #pragma unroll
    for (int mi = 0; mi < 2; mi++)
        #pragma unroll
        for (int ni = 0; ni < 4; ni++)
            #pragma unroll
            for (int e = 0; e < 4; e++) acc[mi][ni][e] = 0.f;

    const int NKT = K >> 4;
    loadAB(0);
    storeAB(0);
    __syncthreads();

    const int lg = lane >> 2;
    const int lt = lane & 3;

    for (int kc = 0; kc < NKT; kc++) {
        const int cur = kc & 1;
        if (kc + 1 < NKT) loadAB(kc + 1);

        #pragma unroll
        for (int ks = 0; ks < 2; ks++) {
            const int k0 = (ks << 3) + lt;
            uint32_t af[2][4], bf[4][2];
            #pragma unroll
            for (int mi = 0; mi < 2; mi++) {
                int rm = wr * 32 + mi * 16 + lg;
                af[mi][0] = As[cur][rm * TSTR + k0];
                af[mi][1] = As[cur][(rm + 8) * TSTR + k0];
                af[mi][2] = As[cur][rm * TSTR + k0 + 4];
                af[mi][3] = As[cur][(rm + 8) * TSTR + k0 + 4];
            }
            #pragma unroll
            for (int ni = 0; ni < 4; ni++) {
                int cn = wc * 32 + ni * 8 + lg;
                bf[ni][0] = Bs[cur][cn * TSTR + k0];
                bf[ni][1] = Bs[cur][cn * TSTR + k0 + 4];
            }
            #pragma unroll
            for (int mi = 0; mi < 2; mi++)
                #pragma unroll
                for (int ni = 0; ni < 4; ni++)
                    mma1688(acc[mi][ni], af[mi], bf[ni]);
        }

        if (kc + 1 < NKT) storeAB(cur ^ 1);
        __syncthreads();
    }

    #pragma unroll
    for (int mi = 0; mi < 2; mi++) {
        int gr0 = row0 + wr * 32 + mi * 16 + lg;
        #pragma unroll
        for (int ni = 0; ni < 4; ni++) {
            int gc = col0 + wc * 32 + ni * 8 + 2 * lt;
            if (gc < Nn) {
                float v0 = acc[mi][ni][0], v1 = acc[mi][ni][1];
                float v2 = acc[mi][ni][2], v3 = acc[mi][ni][3];
                if (EPI == 1) {
                    v0 = tanhf(v0); v1 = tanhf(v1); v2 = tanhf(v2); v3 = tanhf(v3);
                }
                *(float2*)&Cm[(long)gr0 * ldc + gc] = make_float2(v0, v1);
                *(float2*)&Cm[(long)(gr0 + 8) * ldc + gc] = make_float2(v2, v3);
            }
        }
    }
}

template<int EPI>
__global__ __launch_bounds__(128, 3) void gemm_tc64(
    const float* __restrict__ A, int lda,
    const float* __restrict__ Bt, int ldb,
    float* __restrict__ Cm, int ldc,
    int K, int Nn, const float* __restrict__ bias)
{
    __shared__ uint32_t As[2][64 * TSTR];
    __shared__ uint32_t Bs[2][64 * TSTR];
    gemm64_body<EPI>(As, Bs, A, lda, Bt, ldb, Cm, ldc, K, Nn, bias,
                     blockIdx.y * 64, blockIdx.x * 64);
}

// merged decay1 + gate1 (both tanh, N=64)
__global__ __launch_bounds__(128, 3) void gemm_dg1(
    const float* xw, const float* xg,
    const float* dw1T, const float* gw1T,
    float* s1, float* s2)
{
    __shared__ uint32_t As[2][64 * TSTR];
    __shared__ uint32_t Bs[2][64 * TSTR];
    const int z = blockIdx.z;
    gemm64_body<1>(As, Bs, (z == 0) ? xw : xg, C_,
                   (z == 0) ? dw1T : gw1T, C_,
                   (z == 0) ? s1 : s2, 64, C_, 64, nullptr,
                   blockIdx.y * 64, blockIdx.x * 64);
}

// ---------------- fused pre-pass: shift + all weight transposes --------------
struct TJob { const float* src; float* dst; int R, N, nbx, boff; };
struct TJobs { TJob j[10]; };

__global__ __launch_bounds__(256) void pre_kernel(
    const float4* __restrict__ x4, const float* __restrict__ maa_x,
    float4* __restrict__ xx4, float4* __restrict__ xxx4,
    TJobs js, int nshift)
{
    const int tid = threadIdx.x;
    if ((int)blockIdx.x < nshift) {
        long idx = (long)blockIdx.x * 256 + tid;
        const int C4 = C_ / 4;
        int c4 = (int)(idx % C4);
        long rt = idx / C4;
        int t = (int)(rt % T_);
        float4 xv = x4[idx];
        float4 xp = (t > 0) ? x4[idx - C4] : make_float4(0.f, 0.f, 0.f, 0.f);
        float4 mx = *(const float4*)&maa_x[c4 * 4];
        float4 d = make_float4(xp.x - xv.x, xp.y - xv.y, xp.z - xv.z, xp.w - xv.w);
        xx4[idx] = d;
        xxx4[idx] = make_float4(fmaf(d.x, mx.x, xv.x), fmaf(d.y, mx.y, xv.y),
                                fmaf(d.z, mx.z, xv.z), fmaf(d.w, mx.w, xv.w));
        return;
    }
    __shared__ float t[32][33];
    int b = blockIdx.x - nshift;
    int ji = 0;
    #pragma unroll
    for (int q = 1; q < 10; q++)
        if (b >= js.j[q].boff) ji = q;
    TJob jb = js.j[ji];
    int rem = b - jb.boff;
    int bx = (rem % jb.nbx) * 32;
    int by = (rem / jb.nbx) * 32;
    const int xq = tid & 31, yq = tid >> 5;
    #pragma unroll
    for (int i = 0; i < 32; i += 8) {
        int r = by + yq + i, n = bx + xq;
        if (r < jb.R && n < jb.N) t[yq + i][xq] = jb.src[(long)r * jb.N + n];
    }
    __syncthreads();
    #pragma unroll
    for (int i = 0; i < 32; i += 8) {
        int n = bx + yq + i, r = by + xq;
        if (n < jb.N && r < jb.R) jb.dst[(long)n * jb.R + r] = t[xq][yq + i];
    }
}

// ---------------- chunked WKV6 -----------------------------------------------
__global__ __launch_bounds__(256) void wkv_chunkA(
    const float* __restrict__ r, const float* __restrict__ k,
    const float* __restrict__ v, const float* __restrict__ lw,
    const float* __restrict__ u,
    float* __restrict__ y, float* __restrict__ Dout,
    float* __restrict__ rpout, float* __restrict__ pLout)
{
    extern __shared__ float sm[];
    float* lp   = sm;
    float* bufA = lp + 65 * 64;
    float* rpT  = bufA + 64 * STRD;
    float* kpT  = rpT + 64 * STRD;
    float* kpp  = kpT + 64 * STRD;
    float* vsm  = kpp + 64 * STRD;
    float* dsm  = vsm + 64 * STRD;
    float* usm  = dsm + 64;

    const int tid = threadIdx.x;
    const int chunk = blockIdx.x;
    const int bh = chunk >> 5;
    const int c  = chunk & 31;
    const int b = bh >> 4, h = bh & 15;
    const long base = ((long)b * T_ + c * CHUNK) * C_ + h * 64;

    if (tid < 64) usm[tid] = u[h * 64 + tid];
    const int i  = tid & 63;
    const int tq = tid >> 6;

    #pragma unroll
    for (int e = 0; e < 16; e++) {
        int t = tq + 4 * e;
        bufA[t * STRD + i] = lw[base + (long)t * C_ + i];
    }
    __syncthreads();

    if (tid < 64) {
        float run = 0.f;
        for (int t = 0; t < 64; t++) {
            lp[t * 64 + tid] = run;
            run += bufA[t * STRD + tid];
        }
        lp[64 * 64 + tid] = run;
        pLout[(long)chunk * 64 + tid] = run;
    }
    __syncthreads();

    #pragma unroll
    for (int e = 0; e < 16; e++) {
        int t = tq + 4 * e;
        long gi = base + (long)t * C_ + i;
        float rr = r[gi], kk = k[gi];
        float lpti = lp[t * 64 + i];
        float lpn  = lpti + bufA[t * STRD + i];
        float lpL  = lp[64 * 64 + i];
        rpT[i * STRD + t] = rr * __expf(lpti);
        kpT[i * STRD + t] = kk * __expf(-lpn);
        kpp[t * STRD + i] = kk * __expf(lpL - lpn);
        vsm[t * STRD + i] = v[gi];
    }
    {
        int t = tid >> 2, q = tid & 3;
        long gb = base + (long)t * C_;
        float p = 0.f;
        #pragma unroll
        for (int ii = 0; ii < 16; ii++) {
            int ci = q * 16 + ii;
            p += r[gb + ci] * usm[ci] * k[gb + ci];
        }
        p += __shfl_xor_sync(0xffffffffu, p, 1);
        p += __shfl_xor_sync(0xffffffffu, p, 2);
        if (q == 0) dsm[t] = p;
    }
    __syncthreads();

    {
        float* rpg = rpout + (long)chunk * 64 * 64;
        #pragma unroll
        for (int e = 0; e < 16; e++) {
            int flat = tid + 256 * e;
            rpg[flat] = rpT[(flat >> 6) * STRD + (flat & 63)];
        }
    }

    {
        int t0 = (tid >> 4) * 4, s0 = (tid & 15) * 4;
        float acc[4][4];
        #pragma unroll
        for (int a = 0; a < 4; a++)
            #pragma unroll
            for (int bq = 0; bq < 4; bq++) acc[a][bq] = 0.f;
        for (int ii = 0; ii < 64; ii++) {
            float4 a4 = *(const float4*)&rpT[ii * STRD + t0];
            float4 b4 = *(const float4*)&kpT[ii * STRD + s0];
            float av[4] = { a4.x, a4.y, a4.z, a4.w };
            float bv[4] = { b4.x, b4.y, b4.z, b4.w };
            #pragma unroll
            for (int a = 0; a < 4; a++)
                #pragma unroll
                for (int bq = 0; bq < 4; bq++)
                    acc[a][bq] = fmaf(av[a], bv[bq], acc[a][bq]);
        }
        __syncthreads();
        #pragma unroll
        for (int a = 0; a < 4; a++)
            #pragma unroll
            for (int bq = 0; bq < 4; bq++) {
                int tt = t0 + a, ss = s0 + bq;
                float val = (tt > ss) ? acc[a][bq] : ((tt == ss) ? dsm[tt] : 0.f);
                bufA[ss * STRD + tt] = val;
            }
    }
    __syncthreads();

    {
        int t0 = (tid >> 4) * 4, j0 = (tid & 15) * 4;
        float acc[4][4];
        #pragma unroll
        for (int a = 0; a < 4; a++)
            #pragma unroll
            for (int bq = 0; bq < 4; bq++) acc[a][bq] = 0.f;
        for (int s = 0; s < 64; s++) {
            float4 a4 = *(const float4*)&bufA[s * STRD + t0];
            float4 b4 = *(const float4*)&vsm[s * STRD + j0];
            float av[4] = { a4.x, a4.y, a4.z, a4.w };
            float bv[4] = { b4.x, b4.y, b4.z, b4.w };
            #pragma unroll
            for (int a = 0; a < 4; a++)
                #pragma unroll
                for (int bq = 0; bq < 4; bq++)
                    acc[a][bq] = fmaf(av[a], bv[bq], acc[a][bq]);
        }
        #pragma unroll
        for (int a = 0; a < 4; a++) {
            float4 o = make_float4(acc[a][0], acc[a][1], acc[a][2], acc[a][3]);
            *(float4*)&y[base + (long)(t0 + a) * C_ + j0] = o;
        }
    }

    {
        int i0 = (tid >> 4) * 4, j0 = (tid & 15) * 4;
        float acc[4][4];
        #pragma unroll
        for (int a = 0; a < 4; a++)
            #pragma unroll
            for (int bq = 0; bq < 4; bq++) acc[a][bq] = 0.f;
        for (int s = 0; s < 64; s++) {
            float4 a4 = *(const float4*)&kpp[s * STRD + i0];
            float4 b4 = *(const float4*)&vsm[s * STRD + j0];
            float av[4] = { a4.x, a4.y, a4.z, a4.w };
            float bv[4] = { b4.x, b4.y, b4.z, b4.w };
            #pragma unroll
            for (int a = 0; a < 4; a++)
                #pragma unroll
                for (int bq = 0; bq < 4; bq++)
                    acc[a][bq] = fmaf(av[a], bv[bq], acc[a][bq]);
        }
        float* Dp = Dout + (long)chunk * 4096;
        #pragma unroll
        for (int a = 0; a < 4; a++) {
            float4 o = make_float4(acc[a][0], acc[a][1], acc[a][2], acc[a][3]);
            *(float4*)&Dp[(i0 + a) * 64 + j0] = o;
        }
    }
}

__global__ __launch_bounds__(256) void wkv_chunkB(
    const float* __restrict__ D, const float* __restrict__ pL,
    float* __restrict__ S)
{
    const int bh = blockIdx.x;
    const int tid = threadIdx.x;
    const int i = tid >> 2;
    const int jb = (tid & 3) * 16;
    float4 s0 = {0,0,0,0}, s1 = {0,0,0,0}, s2 = {0,0,0,0}, s3 = {0,0,0,0};
    for (int c = 0; c < G_; c++) {
        long chunk = (long)bh * G_ + c;
        long off = chunk * 4096 + i * 64 + jb;
        *(float4*)&S[off + 0]  = s0;
        *(float4*)&S[off + 4]  = s1;
        *(float4*)&S[off + 8]  = s2;
        *(float4*)&S[off + 12] = s3;
        float pl = __expf(pL[chunk * 64 + i]);
        float4 d0 = *(const float4*)&D[off + 0];
        float4 d1 = *(const float4*)&D[off + 4];
        float4 d2 = *(const float4*)&D[off + 8];
        float4 d3 = *(const float4*)&D[off + 12];
        s0 = make_float4(fmaf(pl, s0.x, d0.x), fmaf(pl, s0.y, d0.y), fmaf(pl, s0.z, d0.z), fmaf(pl, s0.w, d0.w));
        s1 = make_float4(fmaf(pl, s1.x, d1.x), fmaf(pl, s1.y, d1.y), fmaf(pl, s1.z, d1.z), fmaf(pl, s1.w, d1.w));
        s2 = make_float4(fmaf(pl, s2.x, d2.x), fmaf(pl, s2.y, d2.y), fmaf(pl, s2.z, d2.z), fmaf(pl, s2.w, d2.w));
        s3 = make_float4(fmaf(pl, s3.x, d3.x), fmaf(pl, s3.y, d3.y), fmaf(pl, s3.z, d3.z), fmaf(pl, s3.w, d3.w));
    }
}

__global__ __launch_bounds__(256) void wkv_chunkC(
    const float* __restrict__ rp, const float* __restrict__ S,
    float* __restrict__ y)
{
    __shared__ float rps[64 * 64];
    __shared__ float Ss[64 * 64];
    const int tid = threadIdx.x;
    const int chunk = blockIdx.x;
    const int bh = chunk >> 5;
    const int c  = chunk & 31;
    const int b = bh >> 4, h = bh & 15;
    const long base = ((long)b * T_ + c * CHUNK) * C_ + h * 64;

    const float* rpg = rp + (long)chunk * 4096;
    const float* Sg  = S  + (long)chunk * 4096;
    #pragma unroll
    for (int e = 0; e < 4; e++) {
        int f4 = tid + 256 * e;
        *(float4*)&rps[f4 * 4] = *(const float4*)&rpg[f4 * 4];
        *(float4*)&Ss[f4 * 4]  = *(const float4*)&Sg[f4 * 4];
    }
    __syncthreads();

    int t0 = (tid >> 4) * 4, j0 = (tid & 15) * 4;
    float acc[4][4];
    #pragma unroll
    for (int a = 0; a < 4; a++)
        #pragma unroll
        for (int bq = 0; bq < 4; bq++) acc[a][bq] = 0.f;
    for (int ii = 0; ii < 64; ii++) {
        float4 a4 = *(const float4*)&rps[ii * 64 + t0];
        float4 b4 = *(const float4*)&Ss[ii * 64 + j0];
        float av[4] = { a4.x, a4.y, a4.z, a4.w };
        float bv[4] = { b4.x, b4.y, b4.z, b4.w };
        #pragma unroll
        for (int a = 0; a < 4; a++)
            #pragma unroll
            for (int bq = 0; bq < 4; bq++)
                acc[a][bq] = fmaf(av[a], bv[bq], acc[a][bq]);
    }
    #pragma unroll
    for (int a = 0; a < 4; a++) {
        long yo = base + (long)(t0 + a) * C_ + j0;
        float4 cur = *(const float4*)&y[yo];
        cur.x += acc[a][0]; cur.y += acc[a][1];
        cur.z += acc[a][2]; cur.w += acc[a][3];
        *(float4*)&y[yo] = cur;
    }
}

// ---------------- GroupNorm over heads + gate multiply -----------------------
__global__ __launch_bounds__(512) void gn_kernel(
    const float* __restrict__ y, const float* __restrict__ ln_g,
    const float* __restrict__ ln_b, const float* __restrict__ g,
    float* __restrict__ z)
{
    const int bt = blockIdx.x;
    const int warp = threadIdx.x >> 5;
    const int lane = threadIdx.x & 31;
    const long base = (long)bt * C_ + warp * 64;

    float a0 = y[base + lane];
    float a1 = y[base + 32 + lane];
    float sum = a0 + a1;
    float sq = a0 * a0 + a1 * a1;
    #pragma unroll
    for (int off = 16; off > 0; off >>= 1) {
        sum += __shfl_xor_sync(0xffffffffu, sum, off);
        sq  += __shfl_xor_sync(0xffffffffu, sq,  off);
    }
    float mu = sum * (1.f / 64.f);
    float var = sq * (1.f / 64.f) - mu * mu;
    float inv = rsqrtf(var + 6.4e-4f);

    int c0 = warp * 64 + lane;
    float z0 = (a0 - mu) * inv * ln_g[c0] + ln_b[c0];
    float z1 = (a1 - mu) * inv * ln_g[c0 + 32] + ln_b[c0 + 32];
    z[base + lane]      = z0 * g[base + lane];
    z[base + 32 + lane] = z1 * g[base + 32 + lane];
}

// ---------------- launcher ----------------------------------------------------
extern "C" void kernel_launch(void* const* d_in, const int* in_sizes, int n_in,
                              void* d_out, int out_size)
{
    const float* x          = (const float*)d_in[0];
    const float* maa_x      = (const float*)d_in[1];
    const float* maa_w      = (const float*)d_in[2];
    const float* maa_k      = (const float*)d_in[3];
    const float* maa_v      = (const float*)d_in[4];
    const float* maa_r      = (const float*)d_in[5];
    const float* maa_g      = (const float*)d_in[6];
    const float* maa_w1     = (const float*)d_in[7];
    const float* maa_w2     = (const float*)d_in[8];
    const float* Wr         = (const float*)d_in[9];
    const float* Wk         = (const float*)d_in[10];
    const float* Wv         = (const float*)d_in[11];
    const float* Wo         = (const float*)d_in[12];
    const float* gate_w1    = (const float*)d_in[13];
    const float* gate_w2    = (const float*)d_in[14];
    const float* time_decay = (const float*)d_in[15];
    const float* decay_w1   = (const float*)d_in[16];
    const float* decay_w2   = (const float*)d_in[17];
    const float* u          = (const float*)d_in[18];
    const float* ln_g       = (const float*)d_in[19];
    const float* ln_b       = (const float*)d_in[20];
    (void)in_sizes; (void)n_in; (void)out_size;

    float *p_xx, *p_xxx, *p_xw, *p_xk, *p_xv, *p_xr, *p_xg;
    float *p_r, *p_k, *p_v, *p_w, *p_g, *p_y, *p_z, *p_lora, *p_s1, *p_s2;
    float *p_D, *p_Sc, *p_rp, *p_pL;
    float *p_WrT, *p_WkT, *p_WvT, *p_WoT, *p_w1T, *p_w2T, *p_dw1T, *p_gw1T, *p_dw2T, *p_gw2T;
    cudaGetSymbolAddress((void**)&p_xx, g_xx);
    cudaGetSymbolAddress((void**)&p_xxx, g_xxx);
    cudaGetSymbolAddress((void**)&p_xw, g_xw);
    cudaGetSymbolAddress((void**)&p_xk, g_xk);
    cudaGetSymbolAddress((void**)&p_xv, g_xv);
    cudaGetSymbolAddress((void**)&p_xr, g_xr);
    cudaGetSymbolAddress((void**)&p_xg, g_xg);
    cudaGetSymbolAddress((void**)&p_r, g_r);
    cudaGetSymbolAddress((void**)&p_k, g_k);
    cudaGetSymbolAddress((void**)&p_v, g_v);
    cudaGetSymbolAddress((void**)&p_w, g_w);
    cudaGetSymbolAddress((void**)&p_g, g_g);
    cudaGetSymbolAddress((void**)&p_y, g_y);
    cudaGetSymbolAddress((void**)&p_z, g_z);
    cudaGetSymbolAddress((void**)&p_lora, g_lora);
    cudaGetSymbolAddress((void**)&p_s1, g_small);
    cudaGetSymbolAddress((void**)&p_s2, g_small2);
    cudaGetSymbolAddress((void**)&p_D, g_D);
    cudaGetSymbolAddress((void**)&p_Sc, g_Sc);
    cudaGetSymbolAddress((void**)&p_rp, g_rp);
    cudaGetSymbolAddress((void**)&p_pL, g_pL);
    cudaGetSymbolAddress((void**)&p_WrT, g_WrT);
    cudaGetSymbolAddress((void**)&p_WkT, g_WkT);
    cudaGetSymbolAddress((void**)&p_WvT, g_WvT);
    cudaGetSymbolAddress((void**)&p_WoT, g_WoT);
    cudaGetSymbolAddress((void**)&p_w1T, g_w1T);
    cudaGetSymbolAddress((void**)&p_w2T, g_w2T);
    cudaGetSymbolAddress((void**)&p_dw1T, g_dw1T);
    cudaGetSymbolAddress((void**)&p_gw1T, g_gw1T);
    cudaGetSymbolAddress((void**)&p_dw2T, g_dw2T);
    cudaGetSymbolAddress((void**)&p_gw2T, g_gw2T);

    const long total = BTC;
    const int M = B_ * T_;          // 8192
    const int gy = M / 128;         // 64
    const int gy64 = M / 64;        // 128

    const int SMEM_A = (65 * 64 + 5 * 64 * STRD + 128) * 4;
    cudaFuncSetAttribute(wkv_chunkA, cudaFuncAttributeMaxDynamicSharedMemorySize, SMEM_A);

    // transpose job table
    TJobs tj;
    int toff = 0;
    {
        const float* srcs[10] = { maa_w1, maa_w2, Wr, Wk, Wv, Wo,
                                  decay_w1, gate_w1, decay_w2, gate_w2 };
        float* dsts[10] = { p_w1T, p_w2T, p_WrT, p_WkT, p_WvT, p_WoT,
                            p_dw1T, p_gw1T, p_dw2T, p_gw2T };
        int Rs[10] = { 1024, 160, 1024, 1024, 1024, 1024, 1024, 1024, 64, 64 };
        int Ns[10] = { 160, 1024, 1024, 1024, 1024, 1024, 64, 64, 1024, 1024 };
        for (int q = 0; q < 10; q++) {
            int nbx = (Ns[q] + 31) / 32;
            int nby = (Rs[q] + 31) / 32;
            tj.j[q].src = srcs[q]; tj.j[q].dst = dsts[q];
            tj.j[q].R = Rs[q]; tj.j[q].N = Ns[q];
            tj.j[q].nbx = nbx; tj.j[q].boff = toff;
            toff += nbx * nby;
        }
    }
    const int nshift = (int)(total / 4 / 256);   // 8192

    // 0. fused shift + transposes
    pre_kernel<<<nshift + toff, 256>>>((const float4*)x, maa_x,
        (float4*)p_xx, (float4*)p_xxx, tj, nshift);
    // 1. lora = tanh(xxx @ maa_w1)  N=160
    gemm_tc64<1><<<dim3(3, gy64), 128>>>(p_xxx, C_, p_w1T, C_, p_lora, 160, C_, 160, nullptr);
    // 2. merged 5-branch mix GEMM
    gemm_mix<<<dim3(8, gy, 5), 256>>>(p_lora, p_w2T, x, p_xx,
        maa_w, maa_k, maa_v, maa_r, maa_g,
        p_xw, p_xk, p_xv, p_xr, p_xg);
    // 3. merged r,k,v projections  <-- profiled by ncu (-s 5 = 6th launch)
    gemm_rkv<<<dim3(8, gy, 3), 256>>>(p_xr, p_xk, p_xv, p_WrT, p_WkT, p_WvT,
                                      p_r, p_k, p_v);
    // 4. merged decay1 + gate1
    gemm_dg1<<<dim3(1, gy64, 2), 128>>>(p_xw, p_xg, p_dw1T, p_gw1T, p_s1, p_s2);
    // 5. merged decay2 + gate2
    gemm_dg2<<<dim3(8, gy, 2), 256>>>(p_s1, p_s2, p_dw2T, p_gw2T, p_w, p_g, time_decay);
    // 6-8. chunked WKV6
    wkv_chunkA<<<NCHUNK, 256, SMEM_A>>>(p_r, p_k, p_v, p_w, u, p_y, p_D, p_rp, p_pL);
    wkv_chunkB<<<B_ * H_, 256>>>(p_D, p_pL, p_Sc);
    wkv_chunkC<<<NCHUNK, 256>>>(p_rp, p_Sc, p_y);
    // 9. GroupNorm + gate multiply
    gn_kernel<<<M, 512>>>(p_y, ln_g, ln_b, p_g, p_z);
    // 10. out = z @ Wo
    gemm_tc<0><<<dim3(8, gy), 256>>>(p_z, C_, p_WoT, C_, (float*)d_out, C_, C_, C_, nullptr);
}

// round 10
// speedup vs baseline: 1.3196x; 1.0532x over previous
#include <cuda_runtime.h>
#include <cuda_bf16.h>
#include <cstdint>
#include <math.h>

// Problem constants
#define B_  4
#define T_  2048
#define C_  1024
#define H_  16
#define N_  64
#define DMIX 32

#define CHUNK 64
#define G_ 32                     // chunks per (b,h)
#define NCHUNK (B_*H_*G_)         // 2048
#define STRD 68                   // padded row stride for chunk smem tiles

static const long BTC = (long)B_ * T_ * C_;   // 8388608

// ---------------- scratch (device globals; no runtime allocation) -------------
__device__ float g_xx [ (long)B_*T_*C_ ];
__device__ float g_xxx[ (long)B_*T_*C_ ];
__device__ float g_xw [ (long)B_*T_*C_ ];
__device__ float g_xk [ (long)B_*T_*C_ ];
__device__ float g_xv [ (long)B_*T_*C_ ];
__device__ float g_xr [ (long)B_*T_*C_ ];
__device__ float g_xg [ (long)B_*T_*C_ ];
__device__ float g_r  [ (long)B_*T_*C_ ];
__device__ float g_k  [ (long)B_*T_*C_ ];
__device__ float g_v  [ (long)B_*T_*C_ ];
__device__ float g_w  [ (long)B_*T_*C_ ];   // lw = log(decay)
__device__ float g_g  [ (long)B_*T_*C_ ];
__device__ float g_y  [ (long)B_*T_*C_ ];
__device__ float g_z  [ (long)B_*T_*C_ ];
__device__ float g_lora [ (long)B_*T_*5*DMIX ];
__device__ float g_small [ (long)B_*T_*64 ];
__device__ float g_small2[ (long)B_*T_*64 ];
__device__ float g_D  [ (long)NCHUNK*64*64 ];
__device__ float g_Sc [ (long)NCHUNK*64*64 ];
__device__ float g_rp [ (long)NCHUNK*64*64 ];
__device__ float g_pL [ (long)NCHUNK*64 ];
// transposed weights [N, K] K-major
__device__ float g_WrT[ (long)C_*C_ ];
__device__ float g_WkT[ (long)C_*C_ ];
__device__ float g_WvT[ (long)C_*C_ ];
__device__ float g_WoT[ (long)C_*C_ ];
__device__ float g_w1T[ (long)160*C_ ];
__device__ float g_w2T[ (long)C_*160 ];
__device__ float g_dw1T[ (long)64*C_ ];
__device__ float g_gw1T[ (long)64*C_ ];
__device__ float g_dw2T[ (long)C_*64 ];
__device__ float g_gw2T[ (long)C_*64 ];

// ================= tf32 mma.sync GEMM ========================================
#define TSTR 20   // smem row stride (16 + 4 pad) -> conflict-free fragments

__device__ __forceinline__ uint32_t f2tf32(float f) {
    uint32_t o;
    asm("cvt.rna.tf32.f32 %0, %1;" : "=r"(o) : "f"(f));
    return o;
}
__device__ __forceinline__ void mma1688(float* d, const uint32_t* a, const uint32_t* b) {
    asm volatile(
        "mma.sync.aligned.m16n8k8.row.col.f32.tf32.tf32.f32 "
        "{%0,%1,%2,%3}, {%4,%5,%6,%7}, {%8,%9}, {%0,%1,%2,%3};"
        : "+f"(d[0]), "+f"(d[1]), "+f"(d[2]), "+f"(d[3])
        : "r"(a[0]), "r"(a[1]), "r"(a[2]), "r"(a[3]), "r"(b[0]), "r"(b[1]));
}

// ---- shared 128x128 body: 128 threads, 4 warps (2x2), warp tile 64x64 --------
// EPI: 0 none, 1 tanh, 2 -exp(acc+bias), 3 xin + xxin*(bias + acc),
//      -2 = runtime repi (0/1/2 only).
template<int EPI>
__device__ __forceinline__ void gemm128_body(
    uint32_t (*As)[128 * TSTR], uint32_t (*Bs)[128 * TSTR],
    const float* __restrict__ A, int lda,
    const float* __restrict__ Bt, int ldb,
    float* __restrict__ Cm, int ldc,
    int K, int Nn, const float* __restrict__ bias,
    const float* __restrict__ xin, const float* __restrict__ xxin,
    int row0, int col0, int repi)
{
    const int tid = threadIdx.x;       // 0..127
    const int lane = tid & 31;
    const int wid = tid >> 5;          // 0..3
    const int wr = wid >> 1;           // 0..1
    const int wc = wid & 1;            // 0..1

    float4 ra[4], rb[4];

    auto loadAB = [&](int kc) {
        const int k0 = kc * 16;
        #pragma unroll
        for (int l = 0; l < 4; l++) {
            int e = tid + (l << 7);
            int r = e >> 2, c = e & 3;
            ra[l] = *(const float4*)&A[(long)(row0 + r) * lda + k0 + (c << 2)];
            int br = col0 + r;
            if (br < Nn)
                rb[l] = *(const float4*)&Bt[(long)br * ldb + k0 + (c << 2)];
            else
                rb[l] = make_float4(0.f, 0.f, 0.f, 0.f);
        }
    };
    auto storeAB = [&](int buf) {
        #pragma unroll
        for (int l = 0; l < 4; l++) {
            int e = tid + (l << 7);
            int r = e >> 2, c = e & 3;
            uint32_t* ap = &As[buf][r * TSTR + (c << 2)];
            ap[0] = f2tf32(ra[l].x); ap[1] = f2tf32(ra[l].y);
            ap[2] = f2tf32(ra[l].z); ap[3] = f2tf32(ra[l].w);
            uint32_t* bp = &Bs[buf][r * TSTR + (c << 2)];
            bp[0] = f2tf32(rb[l].x); bp[1] = f2tf32(rb[l].y);
            bp[2] = f2tf32(rb[l].z); bp[3] = f2tf32(rb[l].w);
        }
    };

    float acc[4][8][4];
    #pragma unroll
    for (int mi = 0; mi < 4; mi++)
        #pragma unroll
        for (int ni = 0; ni < 8; ni++)
            #pragma unroll
            for (int e = 0; e < 4; e++) acc[mi][ni][e] = 0.f;

    const int NKT = K >> 4;
    loadAB(0);
    storeAB(0);
    __syncthreads();

    const int lg = lane >> 2;
    const int lt = lane & 3;

    for (int kc = 0; kc < NKT; kc++) {
        const int cur = kc & 1;
        if (kc + 1 < NKT) loadAB(kc + 1);

        #pragma unroll
        for (int ks = 0; ks < 2; ks++) {
            const int k0 = (ks << 3) + lt;
            uint32_t af[4][4], bf[8][2];
            #pragma unroll
            for (int mi = 0; mi < 4; mi++) {
                int rm = wr * 64 + mi * 16 + lg;
                af[mi][0] = As[cur][rm * TSTR + k0];
                af[mi][1] = As[cur][(rm + 8) * TSTR + k0];
                af[mi][2] = As[cur][rm * TSTR + k0 + 4];
                af[mi][3] = As[cur][(rm + 8) * TSTR + k0 + 4];
            }
            #pragma unroll
            for (int ni = 0; ni < 8; ni++) {
                int cn = wc * 64 + ni * 8 + lg;
                bf[ni][0] = Bs[cur][cn * TSTR + k0];
                bf[ni][1] = Bs[cur][cn * TSTR + k0 + 4];
            }
            #pragma unroll
            for (int mi = 0; mi < 4; mi++)
                #pragma unroll
                for (int ni = 0; ni < 8; ni++)
                    mma1688(acc[mi][ni], af[mi], bf[ni]);
        }

        if (kc + 1 < NKT) storeAB(cur ^ 1);
        __syncthreads();
    }

    const int ep = (EPI == -2) ? repi : EPI;
    #pragma unroll
    for (int mi = 0; mi < 4; mi++) {
        int gr0 = row0 + wr * 64 + mi * 16 + lg;
        #pragma unroll
        for (int ni = 0; ni < 8; ni++) {
            int gc = col0 + wc * 64 + ni * 8 + 2 * lt;
            if (gc < Nn) {
                float v0 = acc[mi][ni][0], v1 = acc[mi][ni][1];
                float v2 = acc[mi][ni][2], v3 = acc[mi][ni][3];
                long o0 = (long)gr0 * ldc + gc;
                long o1 = (long)(gr0 + 8) * ldc + gc;
                if (ep == 1) {
                    v0 = tanhf(v0); v1 = tanhf(v1); v2 = tanhf(v2); v3 = tanhf(v3);
                } else if (ep == 2) {
                    float b0 = bias[gc], b1 = bias[gc + 1];
                    v0 = -expf(v0 + b0); v1 = -expf(v1 + b1);
                    v2 = -expf(v2 + b0); v3 = -expf(v3 + b1);
                } else if (ep == 3) {
                    float b0 = bias[gc], b1 = bias[gc + 1];
                    float2 x0 = *(const float2*)&xin[o0];
                    float2 x1 = *(const float2*)&xin[o1];
                    float2 d0 = *(const float2*)&xxin[o0];
                    float2 d1 = *(const float2*)&xxin[o1];
                    v0 = fmaf(d0.x, b0 + v0, x0.x);
                    v1 = fmaf(d0.y, b1 + v1, x0.y);
                    v2 = fmaf(d1.x, b0 + v2, x1.x);
                    v3 = fmaf(d1.y, b1 + v3, x1.y);
                }
                *(float2*)&Cm[o0] = make_float2(v0, v1);
                *(float2*)&Cm[o1] = make_float2(v2, v3);
            }
        }
    }
}

template<int EPI>
__global__ __launch_bounds__(128, 2) void gemm_tc(
    const float* __restrict__ A, int lda,
    const float* __restrict__ Bt, int ldb,
    float* __restrict__ Cm, int ldc,
    int K, int Nn, const float* __restrict__ bias)
{
    __shared__ uint32_t As[2][128 * TSTR];
    __shared__ uint32_t Bs[2][128 * TSTR];
    gemm128_body<EPI>(As, Bs, A, lda, Bt, ldb, Cm, ldc, K, Nn, bias,
                      nullptr, nullptr, blockIdx.y * 128, blockIdx.x * 128, 0);
}

// merged r,k,v projections: z selects
__global__ __launch_bounds__(128, 2) void gemm_rkv(
    const float* xr, const float* xk, const float* xv,
    const float* WrT, const float* WkT, const float* WvT,
    float* r, float* k, float* v)
{
    __shared__ uint32_t As[2][128 * TSTR];
    __shared__ uint32_t Bs[2][128 * TSTR];
    const int z = blockIdx.z;
    const float* A  = (z == 0) ? xr : (z == 1) ? xk : xv;
    const float* Bt = (z == 0) ? WrT : (z == 1) ? WkT : WvT;
    float* Cm       = (z == 0) ? r : (z == 1) ? k : v;
    gemm128_body<0>(As, Bs, A, C_, Bt, C_, Cm, C_, C_, C_, nullptr,
                    nullptr, nullptr, blockIdx.y * 128, blockIdx.x * 128, 0);
}

// merged decay2 (epi 2) + gate2 (epi 0)
__global__ __launch_bounds__(128, 2) void gemm_dg2(
    const float* small1, const float* small2,
    const float* dw2T, const float* gw2T,
    float* w, float* g, const float* time_decay)
{
    __shared__ uint32_t As[2][128 * TSTR];
    __shared__ uint32_t Bs[2][128 * TSTR];
    const int z = blockIdx.z;
    const float* A  = (z == 0) ? small1 : small2;
    const float* Bt = (z == 0) ? dw2T : gw2T;
    float* Cm       = (z == 0) ? w : g;
    gemm128_body<-2>(As, Bs, A, 64, Bt, 64, Cm, C_, 64, C_, time_decay,
                     nullptr, nullptr, blockIdx.y * 128, blockIdx.x * 128,
                     (z == 0) ? 2 : 0);
}

// merged 5-branch mix GEMM: z selects branch
__global__ __launch_bounds__(128, 2) void gemm_mix(
    const float* __restrict__ lora, const float* __restrict__ w2T,
    const float* __restrict__ x, const float* __restrict__ xx,
    const float* m0, const float* m1, const float* m2, const float* m3, const float* m4,
    float* o0, float* o1, float* o2, float* o3, float* o4)
{
    __shared__ uint32_t As[2][128 * TSTR];
    __shared__ uint32_t Bs[2][128 * TSTR];
    const int z = blockIdx.z;
    const float* bias = (z == 0) ? m0 : (z == 1) ? m1 : (z == 2) ? m2 : (z == 3) ? m3 : m4;
    float* out = (z == 0) ? o0 : (z == 1) ? o1 : (z == 2) ? o2 : (z == 3) ? o3 : o4;
    gemm128_body<3>(As, Bs, lora + z * DMIX, 160, w2T + z * DMIX, 160,
                    out, C_, DMIX, C_, bias, x, xx,
                    blockIdx.y * 128, blockIdx.x * 128, 0);
}

// ---- small tile: BM=64, BN=64, 128 threads (4 warps 2x2, warp 32x32) ---------
template<int EPI>
__device__ __forceinline__ void gemm64_body(
    uint32_t (*As)[64 * TSTR], uint32_t (*Bs)[64 * TSTR],
    const float* __restrict__ A, int lda,
    const float* __restrict__ Bt, int ldb,
    float* __restrict__ Cm, int ldc,
    int K, int Nn, const float* __restrict__ bias,
    int row0, int col0)
{
    const int tid = threadIdx.x;
    const int lane = tid & 31;
    const int wid = tid >> 5;
    const int wr = wid >> 1;
    const int wc = wid & 1;

    float4 ra[2], rb[2];

    auto loadAB = [&](int kc) {
        const int k0 = kc * 16;
        #pragma unroll
        for (int l = 0; l < 2; l++) {
            int e = tid + (l << 7);
            int r = e >> 2, c = e & 3;
            ra[l] = *(const float4*)&A[(long)(row0 + r) * lda + k0 + (c << 2)];
            int br = col0 + r;
            if (br < Nn)
                rb[l] = *(const float4*)&Bt[(long)br * ldb + k0 + (c << 2)];
            else
                rb[l] = make_float4(0.f, 0.f, 0.f, 0.f);
        }
    };
    auto storeAB = [&](int buf) {
        #pragma unroll
        for (int l = 0; l < 2; l++) {
            int e = tid + (l << 7);
            int r = e >> 2, c = e & 3;
            uint32_t* ap = &As[buf][r * TSTR + (c << 2)];
            ap[0] = f2tf32(ra[l].x); ap[1] = f2tf32(ra[l].y);
            ap[2] = f2tf32(ra[l].z); ap[3] = f2tf32(ra[l].w);
            uint32_t* bp = &Bs[buf][r * TSTR + (c << 2)];
            bp[0] = f2tf32(rb[l].x); bp[1] = f2tf32(rb[l].y);
            bp[2] = f2tf32(rb[l].z); bp[3] = f2tf32(rb[l].w);
        }
    };

    float acc[2][4][4];
    #pragma unroll
    for (int mi = 0; mi < 2; mi++)
        #pragma unroll
        for (int ni = 0; ni < 4; ni++)
            #pragma unroll
            for (int e = 0; e < 4; e++) acc[mi][ni][e] = 0.f;

    const int NKT = K >> 4;
    loadAB(0);
    storeAB(0);
    __syncthreads();

    const int lg = lane >> 2;
    const int lt = lane & 3;

    for (int kc = 0; kc < NKT; kc++) {
        const int cur = kc & 1;
        if (kc + 1 < NKT) loadAB(kc + 1);

        #pragma unroll
        for (int ks = 0; ks < 2; ks++) {
            const int k0 = (ks << 3) + lt;
            uint32_t af[2][4], bf[4][2];
            #pragma unroll
            for (int mi = 0; mi < 2; mi++) {
                int rm = wr * 32 + mi * 16 + lg;
                af[mi][0] = As[cur][rm * TSTR + k0];
                af[mi][1] = As[cur][(rm + 8) * TSTR + k0];
                af[mi][2] = As[cur][rm * TSTR + k0 + 4];
                af[mi][3] = As[cur][(rm + 8) * TSTR + k0 + 4];
            }
            #pragma unroll
            for (int ni = 0; ni < 4; ni++) {
                int cn = wc * 32 + ni * 8 + lg;
                bf[ni][0] = Bs[cur][cn * TSTR + k0];
                bf[ni][1] = Bs[cur][cn * TSTR + k0 + 4];
            }
            #pragma unroll
            for (int mi = 0; mi < 2; mi++)
                #pragma unroll
                for (int ni = 0; ni < 4; ni++)
                    mma1688(acc[mi][ni], af[mi], bf[ni]);
        }

        if (kc + 1 < NKT) storeAB(cur ^ 1);
        __syncthreads();
    }

    #pragma unroll
    for (int mi = 0; mi < 2; mi++) {
        int gr0 = row0 + wr * 32 + mi * 16 + lg;
        #pragma unroll
        for (int ni = 0; ni < 4; ni++) {
            int gc = col0 + wc * 32 + ni * 8 + 2 * lt;
            if (gc < Nn) {
                float v0 = acc[mi][ni][0], v1 = acc[mi][ni][1];
                float v2 = acc[mi][ni][2], v3 = acc[mi][ni][3];
                if (EPI == 1) {
                    v0 = tanhf(v0); v1 = tanhf(v1); v2 = tanhf(v2); v3 = tanhf(v3);
                }
                *(float2*)&Cm[(long)gr0 * ldc + gc] = make_float2(v0, v1);
                *(float2*)&Cm[(long)(gr0 + 8) * ldc + gc] = make_float2(v2, v3);
            }
        }
    }
}

template<int EPI>
__global__ __launch_bounds__(128, 3) void gemm_tc64(
    const float* __restrict__ A, int lda,
    const float* __restrict__ Bt, int ldb,
    float* __restrict__ Cm, int ldc,
    int K, int Nn, const float* __restrict__ bias)
{
    __shared__ uint32_t As[2][64 * TSTR];
    __shared__ uint32_t Bs[2][64 * TSTR];
    gemm64_body<EPI>(As, Bs, A, lda, Bt, ldb, Cm, ldc, K, Nn, bias,
                     blockIdx.y * 64, blockIdx.x * 64);
}

// merged decay1 + gate1 (both tanh, N=64)
__global__ __launch_bounds__(128, 3) void gemm_dg1(
    const float* xw, const float* xg,
    const float* dw1T, const float* gw1T,
    float* s1, float* s2)
{
    __shared__ uint32_t As[2][64 * TSTR];
    __shared__ uint32_t Bs[2][64 * TSTR];
    const int z = blockIdx.z;
    gemm64_body<1>(As, Bs, (z == 0) ? xw : xg, C_,
                   (z == 0) ? dw1T : gw1T, C_,
                   (z == 0) ? s1 : s2, 64, C_, 64, nullptr,
                   blockIdx.y * 64, blockIdx.x * 64);
}

// ---------------- fused pre-pass: shift + all weight transposes --------------
struct TJob { const float* src; float* dst; int R, N, nbx, boff; };
struct TJobs { TJob j[10]; };

__global__ __launch_bounds__(256) void pre_kernel(
    const float4* __restrict__ x4, const float* __restrict__ maa_x,
    float4* __restrict__ xx4, float4* __restrict__ xxx4,
    TJobs js, int nshift)
{
    const int tid = threadIdx.x;
    if ((int)blockIdx.x < nshift) {
        long idx = (long)blockIdx.x * 256 + tid;
        const int C4 = C_ / 4;
        int c4 = (int)(idx % C4);
        long rt = idx / C4;
        int t = (int)(rt % T_);
        float4 xv = x4[idx];
        float4 xp = (t > 0) ? x4[idx - C4] : make_float4(0.f, 0.f, 0.f, 0.f);
        float4 mx = *(const float4*)&maa_x[c4 * 4];
        float4 d = make_float4(xp.x - xv.x, xp.y - xv.y, xp.z - xv.z, xp.w - xv.w);
        xx4[idx] = d;
        xxx4[idx] = make_float4(fmaf(d.x, mx.x, xv.x), fmaf(d.y, mx.y, xv.y),
                                fmaf(d.z, mx.z, xv.z), fmaf(d.w, mx.w, xv.w));
        return;
    }
    __shared__ float t[32][33];
    int b = blockIdx.x - nshift;
    int ji = 0;
    #pragma unroll
    for (int q = 1; q < 10; q++)
        if (b >= js.j[q].boff) ji = q;
    TJob jb = js.j[ji];
    int rem = b - jb.boff;
    int bx = (rem % jb.nbx) * 32;
    int by = (rem / jb.nbx) * 32;
    const int xq = tid & 31, yq = tid >> 5;
    #pragma unroll
    for (int i = 0; i < 32; i += 8) {
        int r = by + yq + i, n = bx + xq;
        if (r < jb.R && n < jb.N) t[yq + i][xq] = jb.src[(long)r * jb.N + n];
    }
    __syncthreads();
    #pragma unroll
    for (int i = 0; i < 32; i += 8) {
        int n = bx + yq + i, r = by + xq;
        if (n < jb.N && r < jb.R) jb.dst[(long)n * jb.R + r] = t[xq][yq + i];
    }
}

// ---------------- chunked WKV6 -----------------------------------------------
__global__ __launch_bounds__(256) void wkv_chunkA(
    const float* __restrict__ r, const float* __restrict__ k,
    const float* __restrict__ v, const float* __restrict__ lw,
    const float* __restrict__ u,
    float* __restrict__ y, float* __restrict__ Dout,
    float* __restrict__ rpout, float* __restrict__ pLout)
{
    extern __shared__ float sm[];
    float* lp   = sm;
    float* bufA = lp + 65 * 64;
    float* rpT  = bufA + 64 * STRD;
    float* kpT  = rpT + 64 * STRD;
    float* kpp  = kpT + 64 * STRD;
    float* vsm  = kpp + 64 * STRD;
    float* dsm  = vsm + 64 * STRD;
    float* usm  = dsm + 64;

    const int tid = threadIdx.x;
    const int chunk = blockIdx.x;
    const int bh = chunk >> 5;
    const int c  = chunk & 31;
    const int b = bh >> 4, h = bh & 15;
    const long base = ((long)b * T_ + c * CHUNK) * C_ + h * 64;

    if (tid < 64) usm[tid] = u[h * 64 + tid];
    const int i  = tid & 63;
    const int tq = tid >> 6;

    #pragma unroll
    for (int e = 0; e < 16; e++) {
        int t = tq + 4 * e;
        bufA[t * STRD + i] = lw[base + (long)t * C_ + i];
    }
    __syncthreads();

    if (tid < 64) {
        float run = 0.f;
        for (int t = 0; t < 64; t++) {
            lp[t * 64 + tid] = run;
            run += bufA[t * STRD + tid];
        }
        lp[64 * 64 + tid] = run;
        pLout[(long)chunk * 64 + tid] = run;
    }
    __syncthreads();

    #pragma unroll
    for (int e = 0; e < 16; e++) {
        int t = tq + 4 * e;
        long gi = base + (long)t * C_ + i;
        float rr = r[gi], kk = k[gi];
        float lpti = lp[t * 64 + i];
        float lpn  = lpti + bufA[t * STRD + i];
        float lpL  = lp[64 * 64 + i];
        rpT[i * STRD + t] = rr * __expf(lpti);
        kpT[i * STRD + t] = kk * __expf(-lpn);
        kpp[t * STRD + i] = kk * __expf(lpL - lpn);
        vsm[t * STRD + i] = v[gi];
    }
    {
        int t = tid >> 2, q = tid & 3;
        long gb = base + (long)t * C_;
        float p = 0.f;
        #pragma unroll
        for (int ii = 0; ii < 16; ii++) {
            int ci = q * 16 + ii;
            p += r[gb + ci] * usm[ci] * k[gb + ci];
        }
        p += __shfl_xor_sync(0xffffffffu, p, 1);
        p += __shfl_xor_sync(0xffffffffu, p, 2);
        if (q == 0) dsm[t] = p;
    }
    __syncthreads();

    {
        float* rpg = rpout + (long)chunk * 64 * 64;
        #pragma unroll
        for (int e = 0; e < 16; e++) {
            int flat = tid + 256 * e;
            rpg[flat] = rpT[(flat >> 6) * STRD + (flat & 63)];
        }
    }

    {
        int t0 = (tid >> 4) * 4, s0 = (tid & 15) * 4;
        float acc[4][4];
        #pragma unroll
        for (int a = 0; a < 4; a++)
            #pragma unroll
            for (int bq = 0; bq < 4; bq++) acc[a][bq] = 0.f;
        for (int ii = 0; ii < 64; ii++) {
            float4 a4 = *(const float4*)&rpT[ii * STRD + t0];
            float4 b4 = *(const float4*)&kpT[ii * STRD + s0];
            float av[4] = { a4.x, a4.y, a4.z, a4.w };
            float bv[4] = { b4.x, b4.y, b4.z, b4.w };
            #pragma unroll
            for (int a = 0; a < 4; a++)
                #pragma unroll
                for (int bq = 0; bq < 4; bq++)
                    acc[a][bq] = fmaf(av[a], bv[bq], acc[a][bq]);
        }
        __syncthreads();
        #pragma unroll
        for (int a = 0; a < 4; a++)
            #pragma unroll
            for (int bq = 0; bq < 4; bq++) {
                int tt = t0 + a, ss = s0 + bq;
                float val = (tt > ss) ? acc[a][bq] : ((tt == ss) ? dsm[tt] : 0.f);
                bufA[ss * STRD + tt] = val;
            }
    }
    __syncthreads();

    {
        int t0 = (tid >> 4) * 4, j0 = (tid & 15) * 4;
        float acc[4][4];
        #pragma unroll
        for (int a = 0; a < 4; a++)
            #pragma unroll
            for (int bq = 0; bq < 4; bq++) acc[a][bq] = 0.f;
        for (int s = 0; s < 64; s++) {
            float4 a4 = *(const float4*)&bufA[s * STRD + t0];
            float4 b4 = *(const float4*)&vsm[s * STRD + j0];
            float av[4] = { a4.x, a4.y, a4.z, a4.w };
            float bv[4] = { b4.x, b4.y, b4.z, b4.w };
            #pragma unroll
            for (int a = 0; a < 4; a++)
                #pragma unroll
                for (int bq = 0; bq < 4; bq++)
                    acc[a][bq] = fmaf(av[a], bv[bq], acc[a][bq]);
        }
        #pragma unroll
        for (int a = 0; a < 4; a++) {
            float4 o = make_float4(acc[a][0], acc[a][1], acc[a][2], acc[a][3]);
            *(float4*)&y[base + (long)(t0 + a) * C_ + j0] = o;
        }
    }

    {
        int i0 = (tid >> 4) * 4, j0 = (tid & 15) * 4;
        float acc[4][4];
        #pragma unroll
        for (int a = 0; a < 4; a++)
            #pragma unroll
            for (int bq = 0; bq < 4; bq++) acc[a][bq] = 0.f;
        for (int s = 0; s < 64; s++) {
            float4 a4 = *(const float4*)&kpp[s * STRD + i0];
            float4 b4 = *(const float4*)&vsm[s * STRD + j0];
            float av[4] = { a4.x, a4.y, a4.z, a4.w };
            float bv[4] = { b4.x, b4.y, b4.z, b4.w };
            #pragma unroll
            for (int a = 0; a < 4; a++)
                #pragma unroll
                for (int bq = 0; bq < 4; bq++)
                    acc[a][bq] = fmaf(av[a], bv[bq], acc[a][bq]);
        }
        float* Dp = Dout + (long)chunk * 4096;
        #pragma unroll
        for (int a = 0; a < 4; a++) {
            float4 o = make_float4(acc[a][0], acc[a][1], acc[a][2], acc[a][3]);
            *(float4*)&Dp[(i0 + a) * 64 + j0] = o;
        }
    }
}

__global__ __launch_bounds__(256) void wkv_chunkB(
    const float* __restrict__ D, const float* __restrict__ pL,
    float* __restrict__ S)
{
    const int bh = blockIdx.x;
    const int tid = threadIdx.x;
    const int i = tid >> 2;
    const int jb = (tid & 3) * 16;
    float4 s0 = {0,0,0,0}, s1 = {0,0,0,0}, s2 = {0,0,0,0}, s3 = {0,0,0,0};
    for (int c = 0; c < G_; c++) {
        long chunk = (long)bh * G_ + c;
        long off = chunk * 4096 + i * 64 + jb;
        *(float4*)&S[off + 0]  = s0;
        *(float4*)&S[off + 4]  = s1;
        *(float4*)&S[off + 8]  = s2;
        *(float4*)&S[off + 12] = s3;
        float pl = __expf(pL[chunk * 64 + i]);
        float4 d0 = *(const float4*)&D[off + 0];
        float4 d1 = *(const float4*)&D[off + 4];
        float4 d2 = *(const float4*)&D[off + 8];
        float4 d3 = *(const float4*)&D[off + 12];
        s0 = make_float4(fmaf(pl, s0.x, d0.x), fmaf(pl, s0.y, d0.y), fmaf(pl, s0.z, d0.z), fmaf(pl, s0.w, d0.w));
        s1 = make_float4(fmaf(pl, s1.x, d1.x), fmaf(pl, s1.y, d1.y), fmaf(pl, s1.z, d1.z), fmaf(pl, s1.w, d1.w));
        s2 = make_float4(fmaf(pl, s2.x, d2.x), fmaf(pl, s2.y, d2.y), fmaf(pl, s2.z, d2.z), fmaf(pl, s2.w, d2.w));
        s3 = make_float4(fmaf(pl, s3.x, d3.x), fmaf(pl, s3.y, d3.y), fmaf(pl, s3.z, d3.z), fmaf(pl, s3.w, d3.w));
    }
}

__global__ __launch_bounds__(256) void wkv_chunkC(
    const float* __restrict__ rp, const float* __restrict__ S,
    float* __restrict__ y)
{
    __shared__ float rps[64 * 64];
    __shared__ float Ss[64 * 64];
    const int tid = threadIdx.x;
    const int chunk = blockIdx.x;
    const int bh = chunk >> 5;
    const int c  = chunk & 31;
    const int b = bh >> 4, h = bh & 15;
    const long base = ((long)b * T_ + c * CHUNK) * C_ + h * 64;

    const float* rpg = rp + (long)chunk * 4096;
    const float* Sg  = S  + (long)chunk * 4096;
    #pragma unroll
    for (int e = 0; e < 4; e++) {
        int f4 = tid + 256 * e;
        *(float4*)&rps[f4 * 4] = *(const float4*)&rpg[f4 * 4];
        *(float4*)&Ss[f4 * 4]  = *(const float4*)&Sg[f4 * 4];
    }
    __syncthreads();

    int t0 = (tid >> 4) * 4, j0 = (tid & 15) * 4;
    float acc[4][4];
    #pragma unroll
    for (int a = 0; a < 4; a++)
        #pragma unroll
        for (int bq = 0; bq < 4; bq++) acc[a][bq] = 0.f;
    for (int ii = 0; ii < 64; ii++) {
        float4 a4 = *(const float4*)&rps[ii * 64 + t0];
        float4 b4 = *(const float4*)&Ss[ii * 64 + j0];
        float av[4] = { a4.x, a4.y, a4.z, a4.w };
        float bv[4] = { b4.x, b4.y, b4.z, b4.w };
        #pragma unroll
        for (int a = 0; a < 4; a++)
            #pragma unroll
            for (int bq = 0; bq < 4; bq++)
                acc[a][bq] = fmaf(av[a], bv[bq], acc[a][bq]);
    }
    #pragma unroll
    for (int a = 0; a < 4; a++) {
        long yo = base + (long)(t0 + a) * C_ + j0;
        float4 cur = *(const float4*)&y[yo];
        cur.x += acc[a][0]; cur.y += acc[a][1];
        cur.z += acc[a][2]; cur.w += acc[a][3];
        *(float4*)&y[yo] = cur;
    }
}

// ---------------- GroupNorm over heads + gate multiply -----------------------
__global__ __launch_bounds__(512) void gn_kernel(
    const float* __restrict__ y, const float* __restrict__ ln_g,
    const float* __restrict__ ln_b, const float* __restrict__ g,
    float* __restrict__ z)
{
    const int bt = blockIdx.x;
    const int warp = threadIdx.x >> 5;
    const int lane = threadIdx.x & 31;
    const long base = (long)bt * C_ + warp * 64;

    float a0 = y[base + lane];
    float a1 = y[base + 32 + lane];
    float sum = a0 + a1;
    float sq = a0 * a0 + a1 * a1;
    #pragma unroll
    for (int off = 16; off > 0; off >>= 1) {
        sum += __shfl_xor_sync(0xffffffffu, sum, off);
        sq  += __shfl_xor_sync(0xffffffffu, sq,  off);
    }
    float mu = sum * (1.f / 64.f);
    float var = sq * (1.f / 64.f) - mu * mu;
    float inv = rsqrtf(var + 6.4e-4f);

    int c0 = warp * 64 + lane;
    float z0 = (a0 - mu) * inv * ln_g[c0] + ln_b[c0];
    float z1 = (a1 - mu) * inv * ln_g[c0 + 32] + ln_b[c0 + 32];
    z[base + lane]      = z0 * g[base + lane];
    z[base + 32 + lane] = z1 * g[base + 32 + lane];
}

// ---------------- launcher ----------------------------------------------------
extern "C" void kernel_launch(void* const* d_in, const int* in_sizes, int n_in,
                              void* d_out, int out_size)
{
    const float* x          = (const float*)d_in[0];
    const float* maa_x      = (const float*)d_in[1];
    const float* maa_w      = (const float*)d_in[2];
    const float* maa_k      = (const float*)d_in[3];
    const float* maa_v      = (const float*)d_in[4];
    const float* maa_r      = (const float*)d_in[5];
    const float* maa_g      = (const float*)d_in[6];
    const float* maa_w1     = (const float*)d_in[7];
    const float* maa_w2     = (const float*)d_in[8];
    const float* Wr         = (const float*)d_in[9];
    const float* Wk         = (const float*)d_in[10];
    const float* Wv         = (const float*)d_in[11];
    const float* Wo         = (const float*)d_in[12];
    const float* gate_w1    = (const float*)d_in[13];
    const float* gate_w2    = (const float*)d_in[14];
    const float* time_decay = (const float*)d_in[15];
    const float* decay_w1   = (const float*)d_in[16];
    const float* decay_w2   = (const float*)d_in[17];
    const float* u          = (const float*)d_in[18];
    const float* ln_g       = (const float*)d_in[19];
    const float* ln_b       = (const float*)d_in[20];
    (void)in_sizes; (void)n_in; (void)out_size;

    float *p_xx, *p_xxx, *p_xw, *p_xk, *p_xv, *p_xr, *p_xg;
    float *p_r, *p_k, *p_v, *p_w, *p_g, *p_y, *p_z, *p_lora, *p_s1, *p_s2;
    float *p_D, *p_Sc, *p_rp, *p_pL;
    float *p_WrT, *p_WkT, *p_WvT, *p_WoT, *p_w1T, *p_w2T, *p_dw1T, *p_gw1T, *p_dw2T, *p_gw2T;
    cudaGetSymbolAddress((void**)&p_xx, g_xx);
    cudaGetSymbolAddress((void**)&p_xxx, g_xxx);
    cudaGetSymbolAddress((void**)&p_xw, g_xw);
    cudaGetSymbolAddress((void**)&p_xk, g_xk);
    cudaGetSymbolAddress((void**)&p_xv, g_xv);
    cudaGetSymbolAddress((void**)&p_xr, g_xr);
    cudaGetSymbolAddress((void**)&p_xg, g_xg);
    cudaGetSymbolAddress((void**)&p_r, g_r);
    cudaGetSymbolAddress((void**)&p_k, g_k);
    cudaGetSymbolAddress((void**)&p_v, g_v);
    cudaGetSymbolAddress((void**)&p_w, g_w);
    cudaGetSymbolAddress((void**)&p_g, g_g);
    cudaGetSymbolAddress((void**)&p_y, g_y);
    cudaGetSymbolAddress((void**)&p_z, g_z);
    cudaGetSymbolAddress((void**)&p_lora, g_lora);
    cudaGetSymbolAddress((void**)&p_s1, g_small);
    cudaGetSymbolAddress((void**)&p_s2, g_small2);
    cudaGetSymbolAddress((void**)&p_D, g_D);
    cudaGetSymbolAddress((void**)&p_Sc, g_Sc);
    cudaGetSymbolAddress((void**)&p_rp, g_rp);
    cudaGetSymbolAddress((void**)&p_pL, g_pL);
    cudaGetSymbolAddress((void**)&p_WrT, g_WrT);
    cudaGetSymbolAddress((void**)&p_WkT, g_WkT);
    cudaGetSymbolAddress((void**)&p_WvT, g_WvT);
    cudaGetSymbolAddress((void**)&p_WoT, g_WoT);
    cudaGetSymbolAddress((void**)&p_w1T, g_w1T);
    cudaGetSymbolAddress((void**)&p_w2T, g_w2T);
    cudaGetSymbolAddress((void**)&p_dw1T, g_dw1T);
    cudaGetSymbolAddress((void**)&p_gw1T, g_gw1T);
    cudaGetSymbolAddress((void**)&p_dw2T, g_dw2T);
    cudaGetSymbolAddress((void**)&p_gw2T, g_gw2T);

    const long total = BTC;
    const int M = B_ * T_;          // 8192
    const int gy = M / 128;         // 64
    const int gy64 = M / 64;        // 128

    const int SMEM_A = (65 * 64 + 5 * 64 * STRD + 128) * 4;
    cudaFuncSetAttribute(wkv_chunkA, cudaFuncAttributeMaxDynamicSharedMemorySize, SMEM_A);

    // transpose job table
    TJobs tj;
    int toff = 0;
    {
        const float* srcs[10] = { maa_w1, maa_w2, Wr, Wk, Wv, Wo,
                                  decay_w1, gate_w1, decay_w2, gate_w2 };
        float* dsts[10] = { p_w1T, p_w2T, p_WrT, p_WkT, p_WvT, p_WoT,
                            p_dw1T, p_gw1T, p_dw2T, p_gw2T };
        int Rs[10] = { 1024, 160, 1024, 1024, 1024, 1024, 1024, 1024, 64, 64 };
        int Ns[10] = { 160, 1024, 1024, 1024, 1024, 1024, 64, 64, 1024, 1024 };
        for (int q = 0; q < 10; q++) {
            int nbx = (Ns[q] + 31) / 32;
            int nby = (Rs[q] + 31) / 32;
            tj.j[q].src = srcs[q]; tj.j[q].dst = dsts[q];
            tj.j[q].R = Rs[q]; tj.j[q].N = Ns[q];
            tj.j[q].nbx = nbx; tj.j[q].boff = toff;
            toff += nbx * nby;
        }
    }
    const int nshift = (int)(total / 4 / 256);   // 8192

    // 0. fused shift + transposes
    pre_kernel<<<nshift + toff, 256>>>((const float4*)x, maa_x,
        (float4*)p_xx, (float4*)p_xxx, tj, nshift);
    // 1. lora = tanh(xxx @ maa_w1)  N=160
    gemm_tc64<1><<<dim3(3, gy64), 128>>>(p_xxx, C_, p_w1T, C_, p_lora, 160, C_, 160, nullptr);
    // 2. merged 5-branch mix GEMM
    gemm_mix<<<dim3(8, gy, 5), 128>>>(p_lora, p_w2T, x, p_xx,
        maa_w, maa_k, maa_v, maa_r, maa_g,
        p_xw, p_xk, p_xv, p_xr, p_xg);
    // 3. merged r,k,v projections  <-- profiled by ncu
    gemm_rkv<<<dim3(8, gy, 3), 128>>>(p_xr, p_xk, p_xv, p_WrT, p_WkT, p_WvT,
                                      p_r, p_k, p_v);
    // 4. merged decay1 + gate1
    gemm_dg1<<<dim3(1, gy64, 2), 128>>>(p_xw, p_xg, p_dw1T, p_gw1T, p_s1, p_s2);
    // 5. merged decay2 + gate2
    gemm_dg2<<<dim3(8, gy, 2), 128>>>(p_s1, p_s2, p_dw2T, p_gw2T, p_w, p_g, time_decay);
    // 6-8. chunked WKV6
    wkv_chunkA<<<NCHUNK, 256, SMEM_A>>>(p_r, p_k, p_v, p_w, u, p_y, p_D, p_rp, p_pL);
    wkv_chunkB<<<B_ * H_, 256>>>(p_D, p_pL, p_Sc);
    wkv_chunkC<<<NCHUNK, 256>>>(p_rp, p_Sc, p_y);
    // 9. GroupNorm + gate multiply
    gn_kernel<<<M, 512>>>(p_y, ln_g, ln_b, p_g, p_z);
    // 10. out = z @ Wo
    gemm_tc<0><<<dim3(8, gy), 128>>>(p_z, C_, p_WoT, C_, (float*)d_out, C_, C_, C_, nullptr);
}

// round 11
// speedup vs baseline: 1.4092x; 1.0679x over previous
#include <cuda_runtime.h>
#include <cuda_bf16.h>
#include <cstdint>
#include <math.h>

// Problem constants
#define B_  4
#define T_  2048
#define C_  1024
#define H_  16
#define N_  64
#define DMIX 32

#define CHUNK 64
#define G_ 32
#define NCHUNK (B_*H_*G_)         // 2048
#define STRD 68

static const long BTC = (long)B_ * T_ * C_;   // 8388608

// ---------------- scratch (device globals; no runtime allocation) -------------
__device__ float g_xx [ (long)B_*T_*C_ ];
__device__ float g_xxx[ (long)B_*T_*C_ ];
__device__ float g_xw [ (long)B_*T_*C_ ];
__device__ float g_xk [ (long)B_*T_*C_ ];
__device__ float g_xv [ (long)B_*T_*C_ ];
__device__ float g_xr [ (long)B_*T_*C_ ];
__device__ float g_xg [ (long)B_*T_*C_ ];
__device__ float g_r  [ (long)B_*T_*C_ ];
__device__ float g_k  [ (long)B_*T_*C_ ];
__device__ float g_v  [ (long)B_*T_*C_ ];
__device__ float g_w  [ (long)B_*T_*C_ ];
__device__ float g_g  [ (long)B_*T_*C_ ];
__device__ float g_y  [ (long)B_*T_*C_ ];
__device__ float g_z  [ (long)B_*T_*C_ ];
__device__ float g_lora [ (long)B_*T_*5*DMIX ];
__device__ float g_small [ (long)B_*T_*64 ];
__device__ float g_small2[ (long)B_*T_*64 ];
__device__ float g_D  [ (long)NCHUNK*64*64 ];
__device__ float g_Sc [ (long)NCHUNK*64*64 ];
__device__ float g_rp [ (long)NCHUNK*64*64 ];
__device__ float g_pL [ (long)NCHUNK*64 ];
__device__ float g_WrT[ (long)C_*C_ ];
__device__ float g_WkT[ (long)C_*C_ ];
__device__ float g_WvT[ (long)C_*C_ ];
__device__ float g_WoT[ (long)C_*C_ ];
__device__ float g_w1T[ (long)160*C_ ];
__device__ float g_w2T[ (long)C_*160 ];
__device__ float g_dw1T[ (long)64*C_ ];
__device__ float g_gw1T[ (long)64*C_ ];
__device__ float g_dw2T[ (long)C_*64 ];
__device__ float g_gw2T[ (long)C_*64 ];

// ================= helpers ====================================================
#define TSTR 20
#define STAGES 3

__device__ __forceinline__ uint32_t f2tf32(float f) {
    uint32_t o;
    asm("cvt.rna.tf32.f32 %0, %1;" : "=r"(o) : "f"(f));
    return o;
}
__device__ __forceinline__ float rndt(float f) {   // tf32-round, keep as float
    return __uint_as_float(f2tf32(f));
}
__device__ __forceinline__ uint32_t smem_u32(const void* p) {
    uint32_t a;
    asm("{ .reg .u64 t; cvta.to.shared.u64 t, %1; cvt.u32.u64 %0, t; }"
        : "=r"(a) : "l"(p));
    return a;
}
#define CP_A16(dst, src) \
    asm volatile("cp.async.cg.shared.global [%0], [%1], 16;" :: "r"(dst), "l"(src))
#define CP_COMMIT() asm volatile("cp.async.commit_group;" ::: "memory")
#define CP_WAIT(n)  asm volatile("cp.async.wait_group %0;" :: "n"(n) : "memory")

__device__ __forceinline__ void mma1688(float* d, const uint32_t* a, const uint32_t* b) {
    asm volatile(
        "mma.sync.aligned.m16n8k8.row.col.f32.tf32.tf32.f32 "
        "{%0,%1,%2,%3}, {%4,%5,%6,%7}, {%8,%9}, {%0,%1,%2,%3};"
        : "+f"(d[0]), "+f"(d[1]), "+f"(d[2]), "+f"(d[3])
        : "r"(a[0]), "r"(a[1]), "r"(a[2]), "r"(a[3]), "r"(b[0]), "r"(b[1]));
}

// ---- 128x128 body: 128 threads, 4 warps (2x2), warp tile 64x64, cp.async -----
// Inputs MUST be pre-rounded to tf32. EPI: 0 none, 1 tanh, 2 -exp(acc+bias),
// 3 xin+xxin*(bias+acc), -2 runtime repi. RND: tf32-round outputs.
template<int EPI, bool RND>
__device__ __forceinline__ void gemm128_body(
    uint32_t* dynsm,
    const float* __restrict__ A, int lda,
    const float* __restrict__ Bt, int ldb,
    float* __restrict__ Cm, int ldc,
    int K, int Nn, const float* __restrict__ bias,
    const float* __restrict__ xin, const float* __restrict__ xxin,
    int row0, int col0, int repi)
{
    const int tid = threadIdx.x;
    const int lane = tid & 31;
    const int wid = tid >> 5;
    const int wr = wid >> 1;
    const int wc = wid & 1;

    uint32_t* As = dynsm;
    uint32_t* Bs = dynsm + STAGES * 128 * TSTR;
    const uint32_t as0 = smem_u32(As);
    const uint32_t bs0 = smem_u32(Bs);

    auto issueStage = [&](int kc, int buf) {
        const int k0 = kc * 16;
        const uint32_t ao = as0 + buf * (128 * TSTR * 4);
        const uint32_t bo = bs0 + buf * (128 * TSTR * 4);
        #pragma unroll
        for (int l = 0; l < 4; l++) {
            int e = tid + (l << 7);
            int r = e >> 2, c = e & 3;
            uint32_t so = (uint32_t)(r * TSTR + (c << 2)) * 4u;
            CP_A16(ao + so, &A[(long)(row0 + r) * lda + k0 + (c << 2)]);
            CP_A16(bo + so, &Bt[(long)(col0 + r) * ldb + k0 + (c << 2)]);
        }
        CP_COMMIT();
    };

    float acc[4][8][4];
    #pragma unroll
    for (int mi = 0; mi < 4; mi++)
        #pragma unroll
        for (int ni = 0; ni < 8; ni++)
            #pragma unroll
            for (int e = 0; e < 4; e++) acc[mi][ni][e] = 0.f;

    const int NKT = K >> 4;
    issueStage(0, 0);
    if (NKT > 1) issueStage(1, 1);

    const int lg = lane >> 2;
    const int lt = lane & 3;

    for (int kc = 0; kc < NKT; kc++) {
        const int buf = kc % 3;
        if (kc + 2 < NKT) { CP_WAIT(1); } else { CP_WAIT(0); }
        __syncthreads();

        const uint32_t* Ab = As + buf * 128 * TSTR;
        const uint32_t* Bb = Bs + buf * 128 * TSTR;
        #pragma unroll
        for (int ks = 0; ks < 2; ks++) {
            const int k0 = (ks << 3) + lt;
            uint32_t af[4][4], bf[8][2];
            #pragma unroll
            for (int mi = 0; mi < 4; mi++) {
                int rm = wr * 64 + mi * 16 + lg;
                af[mi][0] = Ab[rm * TSTR + k0];
                af[mi][1] = Ab[(rm + 8) * TSTR + k0];
                af[mi][2] = Ab[rm * TSTR + k0 + 4];
                af[mi][3] = Ab[(rm + 8) * TSTR + k0 + 4];
            }
            #pragma unroll
            for (int ni = 0; ni < 8; ni++) {
                int cn = wc * 64 + ni * 8 + lg;
                bf[ni][0] = Bb[cn * TSTR + k0];
                bf[ni][1] = Bb[cn * TSTR + k0 + 4];
            }
            #pragma unroll
            for (int mi = 0; mi < 4; mi++)
                #pragma unroll
                for (int ni = 0; ni < 8; ni++)
                    mma1688(acc[mi][ni], af[mi], bf[ni]);
        }

        if (kc + 2 < NKT) issueStage(kc + 2, (kc + 2) % 3);
    }

    const int ep = (EPI == -2) ? repi : EPI;
    #pragma unroll
    for (int mi = 0; mi < 4; mi++) {
        int gr0 = row0 + wr * 64 + mi * 16 + lg;
        #pragma unroll
        for (int ni = 0; ni < 8; ni++) {
            int gc = col0 + wc * 64 + ni * 8 + 2 * lt;
            if (gc < Nn) {
                float v0 = acc[mi][ni][0], v1 = acc[mi][ni][1];
                float v2 = acc[mi][ni][2], v3 = acc[mi][ni][3];
                long o0 = (long)gr0 * ldc + gc;
                long o1 = (long)(gr0 + 8) * ldc + gc;
                if (ep == 1) {
                    v0 = tanhf(v0); v1 = tanhf(v1); v2 = tanhf(v2); v3 = tanhf(v3);
                } else if (ep == 2) {
                    float b0 = bias[gc], b1 = bias[gc + 1];
                    v0 = -expf(v0 + b0); v1 = -expf(v1 + b1);
                    v2 = -expf(v2 + b0); v3 = -expf(v3 + b1);
                } else if (ep == 3) {
                    float b0 = bias[gc], b1 = bias[gc + 1];
                    float2 x0 = *(const float2*)&xin[o0];
                    float2 x1 = *(const float2*)&xin[o1];
                    float2 d0 = *(const float2*)&xxin[o0];
                    float2 d1 = *(const float2*)&xxin[o1];
                    v0 = fmaf(d0.x, b0 + v0, x0.x);
                    v1 = fmaf(d0.y, b1 + v1, x0.y);
                    v2 = fmaf(d1.x, b0 + v2, x1.x);
                    v3 = fmaf(d1.y, b1 + v3, x1.y);
                }
                if (RND) {
                    v0 = rndt(v0); v1 = rndt(v1); v2 = rndt(v2); v3 = rndt(v3);
                }
                *(float2*)&Cm[o0] = make_float2(v0, v1);
                *(float2*)&Cm[o1] = make_float2(v2, v3);
            }
        }
    }
}

#define SMEM_G (STAGES * 128 * TSTR * 4 * 2)   // 61440 bytes

template<int EPI, bool RND>
__global__ __launch_bounds__(128, 2) void gemm_tc(
    const float* __restrict__ A, int lda,
    const float* __restrict__ Bt, int ldb,
    float* __restrict__ Cm, int ldc,
    int K, int Nn, const float* __restrict__ bias)
{
    extern __shared__ uint32_t dynsm[];
    gemm128_body<EPI, RND>(dynsm, A, lda, Bt, ldb, Cm, ldc, K, Nn, bias,
                           nullptr, nullptr, blockIdx.y * 128, blockIdx.x * 128, 0);
}

__global__ __launch_bounds__(128, 2) void gemm_rkv(
    const float* xr, const float* xk, const float* xv,
    const float* WrT, const float* WkT, const float* WvT,
    float* r, float* k, float* v)
{
    extern __shared__ uint32_t dynsm[];
    const int z = blockIdx.z;
    const float* A  = (z == 0) ? xr : (z == 1) ? xk : xv;
    const float* Bt = (z == 0) ? WrT : (z == 1) ? WkT : WvT;
    float* Cm       = (z == 0) ? r : (z == 1) ? k : v;
    gemm128_body<0, false>(dynsm, A, C_, Bt, C_, Cm, C_, C_, C_, nullptr,
                           nullptr, nullptr, blockIdx.y * 128, blockIdx.x * 128, 0);
}

__global__ __launch_bounds__(128, 2) void gemm_dg2(
    const float* small1, const float* small2,
    const float* dw2T, const float* gw2T,
    float* w, float* g, const float* time_decay)
{
    extern __shared__ uint32_t dynsm[];
    const int z = blockIdx.z;
    gemm128_body<-2, false>(dynsm, (z == 0) ? small1 : small2, 64,
                            (z == 0) ? dw2T : gw2T, 64,
                            (z == 0) ? w : g, C_, 64, C_, time_decay,
                            nullptr, nullptr, blockIdx.y * 128, blockIdx.x * 128,
                            (z == 0) ? 2 : 0);
}

__global__ __launch_bounds__(128, 2) void gemm_mix(
    const float* __restrict__ lora, const float* __restrict__ w2T,
    const float* __restrict__ x, const float* __restrict__ xx,
    const float* m0, const float* m1, const float* m2, const float* m3, const float* m4,
    float* o0, float* o1, float* o2, float* o3, float* o4)
{
    extern __shared__ uint32_t dynsm[];
    const int z = blockIdx.z;
    const float* bias = (z == 0) ? m0 : (z == 1) ? m1 : (z == 2) ? m2 : (z == 3) ? m3 : m4;
    float* out = (z == 0) ? o0 : (z == 1) ? o1 : (z == 2) ? o2 : (z == 3) ? o3 : o4;
    gemm128_body<3, true>(dynsm, lora + z * DMIX, 160, w2T + z * DMIX, 160,
                          out, C_, DMIX, C_, bias, x, xx,
                          blockIdx.y * 128, blockIdx.x * 128, 0);
}

// ---- small tile: BM=64, BN=64, 128 threads (classic path, cvt idempotent) ----
template<int EPI, bool RND>
__device__ __forceinline__ void gemm64_body(
    uint32_t (*As)[64 * TSTR], uint32_t (*Bs)[64 * TSTR],
    const float* __restrict__ A, int lda,
    const float* __restrict__ Bt, int ldb,
    float* __restrict__ Cm, int ldc,
    int K, int Nn, const float* __restrict__ bias,
    int row0, int col0)
{
    const int tid = threadIdx.x;
    const int lane = tid & 31;
    const int wid = tid >> 5;
    const int wr = wid >> 1;
    const int wc = wid & 1;

    float4 ra[2], rb[2];

    auto loadAB = [&](int kc) {
        const int k0 = kc * 16;
        #pragma unroll
        for (int l = 0; l < 2; l++) {
            int e = tid + (l << 7);
            int r = e >> 2, c = e & 3;
            ra[l] = *(const float4*)&A[(long)(row0 + r) * lda + k0 + (c << 2)];
            int br = col0 + r;
            if (br < Nn)
                rb[l] = *(const float4*)&Bt[(long)br * ldb + k0 + (c << 2)];
            else
                rb[l] = make_float4(0.f, 0.f, 0.f, 0.f);
        }
    };
    auto storeAB = [&](int buf) {
        #pragma unroll
        for (int l = 0; l < 2; l++) {
            int e = tid + (l << 7);
            int r = e >> 2, c = e & 3;
            uint32_t* ap = &As[buf][r * TSTR + (c << 2)];
            ap[0] = f2tf32(ra[l].x); ap[1] = f2tf32(ra[l].y);
            ap[2] = f2tf32(ra[l].z); ap[3] = f2tf32(ra[l].w);
            uint32_t* bp = &Bs[buf][r * TSTR + (c << 2)];
            bp[0] = f2tf32(rb[l].x); bp[1] = f2tf32(rb[l].y);
            bp[2] = f2tf32(rb[l].z); bp[3] = f2tf32(rb[l].w);
        }
    };

    float acc[2][4][4];
    #pragma unroll
    for (int mi = 0; mi < 2; mi++)
        #pragma unroll
        for (int ni = 0; ni < 4; ni++)
            #pragma unroll
            for (int e = 0; e < 4; e++) acc[mi][ni][e] = 0.f;

    const int NKT = K >> 4;
    loadAB(0);
    storeAB(0);
    __syncthreads();

    const int lg = lane >> 2;
    const int lt = lane & 3;

    for (int kc = 0; kc < NKT; kc++) {
        const int cur = kc & 1;
        if (kc + 1 < NKT) loadAB(kc + 1);

        #pragma unroll
        for (int ks = 0; ks < 2; ks++) {
            const int k0 = (ks << 3) + lt;
            uint32_t af[2][4], bf[4][2];
            #pragma unroll
            for (int mi = 0; mi < 2; mi++) {
                int rm = wr * 32 + mi * 16 + lg;
                af[mi][0] = As[cur][rm * TSTR + k0];
                af[mi][1] = As[cur][(rm + 8) * TSTR + k0];
                af[mi][2] = As[cur][rm * TSTR + k0 + 4];
                af[mi][3] = As[cur][(rm + 8) * TSTR + k0 + 4];
            }
            #pragma unroll
            for (int ni = 0; ni < 4; ni++) {
                int cn = wc * 32 + ni * 8 + lg;
                bf[ni][0] = Bs[cur][cn * TSTR + k0];
                bf[ni][1] = Bs[cur][cn * TSTR + k0 + 4];
            }
            #pragma unroll
            for (int mi = 0; mi < 2; mi++)
                #pragma unroll
                for (int ni = 0; ni < 4; ni++)
                    mma1688(acc[mi][ni], af[mi], bf[ni]);
        }

        if (kc + 1 < NKT) storeAB(cur ^ 1);
        __syncthreads();
    }

    #pragma unroll
    for (int mi = 0; mi < 2; mi++) {
        int gr0 = row0 + wr * 32 + mi * 16 + lg;
        #pragma unroll
        for (int ni = 0; ni < 4; ni++) {
            int gc = col0 + wc * 32 + ni * 8 + 2 * lt;
            if (gc < Nn) {
                float v0 = acc[mi][ni][0], v1 = acc[mi][ni][1];
                float v2 = acc[mi][ni][2], v3 = acc[mi][ni][3];
                if (EPI == 1) {
                    v0 = tanhf(v0); v1 = tanhf(v1); v2 = tanhf(v2); v3 = tanhf(v3);
                }
                if (RND) {
                    v0 = rndt(v0); v1 = rndt(v1); v2 = rndt(v2); v3 = rndt(v3);
                }
                *(float2*)&Cm[(long)gr0 * ldc + gc] = make_float2(v0, v1);
                *(float2*)&Cm[(long)(gr0 + 8) * ldc + gc] = make_float2(v2, v3);
            }
        }
    }
}

template<int EPI, bool RND>
__global__ __launch_bounds__(128, 3) void gemm_tc64(
    const float* __restrict__ A, int lda,
    const float* __restrict__ Bt, int ldb,
    float* __restrict__ Cm, int ldc,
    int K, int Nn, const float* __restrict__ bias)
{
    __shared__ uint32_t As[2][64 * TSTR];
    __shared__ uint32_t Bs[2][64 * TSTR];
    gemm64_body<EPI, RND>(As, Bs, A, lda, Bt, ldb, Cm, ldc, K, Nn, bias,
                          blockIdx.y * 64, blockIdx.x * 64);
}

__global__ __launch_bounds__(128, 3) void gemm_dg1(
    const float* xw, const float* xg,
    const float* dw1T, const float* gw1T,
    float* s1, float* s2)
{
    __shared__ uint32_t As[2][64 * TSTR];
    __shared__ uint32_t Bs[2][64 * TSTR];
    const int z = blockIdx.z;
    gemm64_body<1, true>(As, Bs, (z == 0) ? xw : xg, C_,
                         (z == 0) ? dw1T : gw1T, C_,
                         (z == 0) ? s1 : s2, 64, C_, 64, nullptr,
                         blockIdx.y * 64, blockIdx.x * 64);
}

// ---------------- fused pre-pass: shift + all weight transposes --------------
// Transposed weights and xxx are tf32-pre-rounded (GEMM operands).
struct TJob { const float* src; float* dst; int R, N, nbx, boff; };
struct TJobs { TJob j[10]; };

__global__ __launch_bounds__(256) void pre_kernel(
    const float4* __restrict__ x4, const float* __restrict__ maa_x,
    float4* __restrict__ xx4, float4* __restrict__ xxx4,
    TJobs js, int nshift)
{
    const int tid = threadIdx.x;
    if ((int)blockIdx.x < nshift) {
        long idx = (long)blockIdx.x * 256 + tid;
        const int C4 = C_ / 4;
        int c4 = (int)(idx % C4);
        long rt = idx / C4;
        int t = (int)(rt % T_);
        float4 xv = x4[idx];
        float4 xp = (t > 0) ? x4[idx - C4] : make_float4(0.f, 0.f, 0.f, 0.f);
        float4 mx = *(const float4*)&maa_x[c4 * 4];
        float4 d = make_float4(xp.x - xv.x, xp.y - xv.y, xp.z - xv.z, xp.w - xv.w);
        xx4[idx] = d;
        xxx4[idx] = make_float4(rndt(fmaf(d.x, mx.x, xv.x)), rndt(fmaf(d.y, mx.y, xv.y)),
                                rndt(fmaf(d.z, mx.z, xv.z)), rndt(fmaf(d.w, mx.w, xv.w)));
        return;
    }
    __shared__ float t[32][33];
    int b = blockIdx.x - nshift;
    int ji = 0;
    #pragma unroll
    for (int q = 1; q < 10; q++)
        if (b >= js.j[q].boff) ji = q;
    TJob jb = js.j[ji];
    int rem = b - jb.boff;
    int bx = (rem % jb.nbx) * 32;
    int by = (rem / jb.nbx) * 32;
    const int xq = tid & 31, yq = tid >> 5;
    #pragma unroll
    for (int i = 0; i < 32; i += 8) {
        int r = by + yq + i, n = bx + xq;
        if (r < jb.R && n < jb.N) t[yq + i][xq] = jb.src[(long)r * jb.N + n];
    }
    __syncthreads();
    #pragma unroll
    for (int i = 0; i < 32; i += 8) {
        int n = bx + yq + i, r = by + xq;
        if (n < jb.N && r < jb.R) jb.dst[(long)n * jb.R + r] = rndt(t[xq][yq + i]);
    }
}

// ---------------- chunked WKV6 -----------------------------------------------
__global__ __launch_bounds__(256) void wkv_chunkA(
    const float* __restrict__ r, const float* __restrict__ k,
    const float* __restrict__ v, const float* __restrict__ lw,
    const float* __restrict__ u,
    float* __restrict__ y, float* __restrict__ Dout,
    float* __restrict__ rpout, float* __restrict__ pLout)
{
    extern __shared__ float sm[];
    float* lp   = sm;
    float* bufA = lp + 65 * 64;
    float* rpT  = bufA + 64 * STRD;
    float* kpT  = rpT + 64 * STRD;
    float* kpp  = kpT + 64 * STRD;
    float* vsm  = kpp + 64 * STRD;
    float* dsm  = vsm + 64 * STRD;
    float* usm  = dsm + 64;

    const int tid = threadIdx.x;
    const int chunk = blockIdx.x;
    const int bh = chunk >> 5;
    const int c  = chunk & 31;
    const int b = bh >> 4, h = bh & 15;
    const long base = ((long)b * T_ + c * CHUNK) * C_ + h * 64;

    if (tid < 64) usm[tid] = u[h * 64 + tid];
    const int i  = tid & 63;
    const int tq = tid >> 6;

    #pragma unroll
    for (int e = 0; e < 16; e++) {
        int t = tq + 4 * e;
        bufA[t * STRD + i] = lw[base + (long)t * C_ + i];
    }
    __syncthreads();

    if (tid < 64) {
        float run = 0.f;
        for (int t = 0; t < 64; t++) {
            lp[t * 64 + tid] = run;
            run += bufA[t * STRD + tid];
        }
        lp[64 * 64 + tid] = run;
        pLout[(long)chunk * 64 + tid] = run;
    }
    __syncthreads();

    #pragma unroll
    for (int e = 0; e < 16; e++) {
        int t = tq + 4 * e;
        long gi = base + (long)t * C_ + i;
        float rr = r[gi], kk = k[gi];
        float lpti = lp[t * 64 + i];
        float lpn  = lpti + bufA[t * STRD + i];
        float lpL  = lp[64 * 64 + i];
        rpT[i * STRD + t] = rr * __expf(lpti);
        kpT[i * STRD + t] = kk * __expf(-lpn);
        kpp[t * STRD + i] = kk * __expf(lpL - lpn);
        vsm[t * STRD + i] = v[gi];
    }
    {
        int t = tid >> 2, q = tid & 3;
        long gb = base + (long)t * C_;
        float p = 0.f;
        #pragma unroll
        for (int ii = 0; ii < 16; ii++) {
            int ci = q * 16 + ii;
            p += r[gb + ci] * usm[ci] * k[gb + ci];
        }
        p += __shfl_xor_sync(0xffffffffu, p, 1);
        p += __shfl_xor_sync(0xffffffffu, p, 2);
        if (q == 0) dsm[t] = p;
    }
    __syncthreads();

    {
        float* rpg = rpout + (long)chunk * 64 * 64;
        #pragma unroll
        for (int e = 0; e < 16; e++) {
            int flat = tid + 256 * e;
            rpg[flat] = rpT[(flat >> 6) * STRD + (flat & 63)];
        }
    }

    {
        int t0 = (tid >> 4) * 4, s0 = (tid & 15) * 4;
        float acc[4][4];
        #pragma unroll
        for (int a = 0; a < 4; a++)
            #pragma unroll
            for (int bq = 0; bq < 4; bq++) acc[a][bq] = 0.f;
        for (int ii = 0; ii < 64; ii++) {
            float4 a4 = *(const float4*)&rpT[ii * STRD + t0];
            float4 b4 = *(const float4*)&kpT[ii * STRD + s0];
            float av[4] = { a4.x, a4.y, a4.z, a4.w };
            float bv[4] = { b4.x, b4.y, b4.z, b4.w };
            #pragma unroll
            for (int a = 0; a < 4; a++)
                #pragma unroll
                for (int bq = 0; bq < 4; bq++)
                    acc[a][bq] = fmaf(av[a], bv[bq], acc[a][bq]);
        }
        __syncthreads();
        #pragma unroll
        for (int a = 0; a < 4; a++)
            #pragma unroll
            for (int bq = 0; bq < 4; bq++) {
                int tt = t0 + a, ss = s0 + bq;
                float val = (tt > ss) ? acc[a][bq] : ((tt == ss) ? dsm[tt] : 0.f);
                bufA[ss * STRD + tt] = val;
            }
    }
    __syncthreads();

    {
        int t0 = (tid >> 4) * 4, j0 = (tid & 15) * 4;
        float acc[4][4];
        #pragma unroll
        for (int a = 0; a < 4; a++)
            #pragma unroll
            for (int bq = 0; bq < 4; bq++) acc[a][bq] = 0.f;
        for (int s = 0; s < 64; s++) {
            float4 a4 = *(const float4*)&bufA[s * STRD + t0];
            float4 b4 = *(const float4*)&vsm[s * STRD + j0];
            float av[4] = { a4.x, a4.y, a4.z, a4.w };
            float bv[4] = { b4.x, b4.y, b4.z, b4.w };
            #pragma unroll
            for (int a = 0; a < 4; a++)
                #pragma unroll
                for (int bq = 0; bq < 4; bq++)
                    acc[a][bq] = fmaf(av[a], bv[bq], acc[a][bq]);
        }
        #pragma unroll
        for (int a = 0; a < 4; a++) {
            float4 o = make_float4(acc[a][0], acc[a][1], acc[a][2], acc[a][3]);
            *(float4*)&y[base + (long)(t0 + a) * C_ + j0] = o;
        }
    }

    {
        int i0 = (tid >> 4) * 4, j0 = (tid & 15) * 4;
        float acc[4][4];
        #pragma unroll
        for (int a = 0; a < 4; a++)
            #pragma unroll
            for (int bq = 0; bq < 4; bq++) acc[a][bq] = 0.f;
        for (int s = 0; s < 64; s++) {
            float4 a4 = *(const float4*)&kpp[s * STRD + i0];
            float4 b4 = *(const float4*)&vsm[s * STRD + j0];
            float av[4] = { a4.x, a4.y, a4.z, a4.w };
            float bv[4] = { b4.x, b4.y, b4.z, b4.w };
            #pragma unroll
            for (int a = 0; a < 4; a++)
                #pragma unroll
                for (int bq = 0; bq < 4; bq++)
                    acc[a][bq] = fmaf(av[a], bv[bq], acc[a][bq]);
        }
        float* Dp = Dout + (long)chunk * 4096;
        #pragma unroll
        for (int a = 0; a < 4; a++) {
            float4 o = make_float4(acc[a][0], acc[a][1], acc[a][2], acc[a][3]);
            *(float4*)&Dp[(i0 + a) * 64 + j0] = o;
        }
    }
}

__global__ __launch_bounds__(256) void wkv_chunkB(
    const float* __restrict__ D, const float* __restrict__ pL,
    float* __restrict__ S)
{
    const int bh = blockIdx.x;
    const int tid = threadIdx.x;
    const int i = tid >> 2;
    const int jb = (tid & 3) * 16;
    float4 s0 = {0,0,0,0}, s1 = {0,0,0,0}, s2 = {0,0,0,0}, s3 = {0,0,0,0};
    for (int c = 0; c < G_; c++) {
        long chunk = (long)bh * G_ + c;
        long off = chunk * 4096 + i * 64 + jb;
        *(float4*)&S[off + 0]  = s0;
        *(float4*)&S[off + 4]  = s1;
        *(float4*)&S[off + 8]  = s2;
        *(float4*)&S[off + 12] = s3;
        float pl = __expf(pL[chunk * 64 + i]);
        float4 d0 = *(const float4*)&D[off + 0];
        float4 d1 = *(const float4*)&D[off + 4];
        float4 d2 = *(const float4*)&D[off + 8];
        float4 d3 = *(const float4*)&D[off + 12];
        s0 = make_float4(fmaf(pl, s0.x, d0.x), fmaf(pl, s0.y, d0.y), fmaf(pl, s0.z, d0.z), fmaf(pl, s0.w, d0.w));
        s1 = make_float4(fmaf(pl, s1.x, d1.x), fmaf(pl, s1.y, d1.y), fmaf(pl, s1.z, d1.z), fmaf(pl, s1.w, d1.w));
        s2 = make_float4(fmaf(pl, s2.x, d2.x), fmaf(pl, s2.y, d2.y), fmaf(pl, s2.z, d2.z), fmaf(pl, s2.w, d2.w));
        s3 = make_float4(fmaf(pl, s3.x, d3.x), fmaf(pl, s3.y, d3.y), fmaf(pl, s3.z, d3.z), fmaf(pl, s3.w, d3.w));
    }
}

__global__ __launch_bounds__(256) void wkv_chunkC(
    const float* __restrict__ rp, const float* __restrict__ S,
    float* __restrict__ y)
{
    __shared__ float rps[64 * 64];
    __shared__ float Ss[64 * 64];
    const int tid = threadIdx.x;
    const int chunk = blockIdx.x;
    const int bh = chunk >> 5;
    const int c  = chunk & 31;
    const int b = bh >> 4, h = bh & 15;
    const long base = ((long)b * T_ + c * CHUNK) * C_ + h * 64;

    const float* rpg = rp + (long)chunk * 4096;
    const float* Sg  = S  + (long)chunk * 4096;
    #pragma unroll
    for (int e = 0; e < 4; e++) {
        int f4 = tid + 256 * e;
        *(float4*)&rps[f4 * 4] = *(const float4*)&rpg[f4 * 4];
        *(float4*)&Ss[f4 * 4]  = *(const float4*)&Sg[f4 * 4];
    }
    __syncthreads();

    int t0 = (tid >> 4) * 4, j0 = (tid & 15) * 4;
    float acc[4][4];
    #pragma unroll
    for (int a = 0; a < 4; a++)
        #pragma unroll
        for (int bq = 0; bq < 4; bq++) acc[a][bq] = 0.f;
    for (int ii = 0; ii < 64; ii++) {
        float4 a4 = *(const float4*)&rps[ii * 64 + t0];
        float4 b4 = *(const float4*)&Ss[ii * 64 + j0];
        float av[4] = { a4.x, a4.y, a4.z, a4.w };
        float bv[4] = { b4.x, b4.y, b4.z, b4.w };
        #pragma unroll
        for (int a = 0; a < 4; a++)
            #pragma unroll
            for (int bq = 0; bq < 4; bq++)
                acc[a][bq] = fmaf(av[a], bv[bq], acc[a][bq]);
    }
    #pragma unroll
    for (int a = 0; a < 4; a++) {
        long yo = base + (long)(t0 + a) * C_ + j0;
        float4 cur = *(const float4*)&y[yo];
        cur.x += acc[a][0]; cur.y += acc[a][1];
        cur.z += acc[a][2]; cur.w += acc[a][3];
        *(float4*)&y[yo] = cur;
    }
}

// ---------------- GroupNorm over heads + gate multiply (z tf32-rounded) ------
__global__ __launch_bounds__(512) void gn_kernel(
    const float* __restrict__ y, const float* __restrict__ ln_g,
    const float* __restrict__ ln_b, const float* __restrict__ g,
    float* __restrict__ z)
{
    const int bt = blockIdx.x;
    const int warp = threadIdx.x >> 5;
    const int lane = threadIdx.x & 31;
    const long base = (long)bt * C_ + warp * 64;

    float a0 = y[base + lane];
    float a1 = y[base + 32 + lane];
    float sum = a0 + a1;
    float sq = a0 * a0 + a1 * a1;
    #pragma unroll
    for (int off = 16; off > 0; off >>= 1) {
        sum += __shfl_xor_sync(0xffffffffu, sum, off);
        sq  += __shfl_xor_sync(0xffffffffu, sq,  off);
    }
    float mu = sum * (1.f / 64.f);
    float var = sq * (1.f / 64.f) - mu * mu;
    float inv = rsqrtf(var + 6.4e-4f);

    int c0 = warp * 64 + lane;
    float z0 = (a0 - mu) * inv * ln_g[c0] + ln_b[c0];
    float z1 = (a1 - mu) * inv * ln_g[c0 + 32] + ln_b[c0 + 32];
    z[base + lane]      = rndt(z0 * g[base + lane]);
    z[base + 32 + lane] = rndt(z1 * g[base + 32 + lane]);
}

// ---------------- launcher ----------------------------------------------------
extern "C" void kernel_launch(void* const* d_in, const int* in_sizes, int n_in,
                              void* d_out, int out_size)
{
    const float* x          = (const float*)d_in[0];
    const float* maa_x      = (const float*)d_in[1];
    const float* maa_w      = (const float*)d_in[2];
    const float* maa_k      = (const float*)d_in[3];
    const float* maa_v      = (const float*)d_in[4];
    const float* maa_r      = (const float*)d_in[5];
    const float* maa_g      = (const float*)d_in[6];
    const float* maa_w1     = (const float*)d_in[7];
    const float* maa_w2     = (const float*)d_in[8];
    const float* Wr         = (const float*)d_in[9];
    const float* Wk         = (const float*)d_in[10];
    const float* Wv         = (const float*)d_in[11];
    const float* Wo         = (const float*)d_in[12];
    const float* gate_w1    = (const float*)d_in[13];
    const float* gate_w2    = (const float*)d_in[14];
    const float* time_decay = (const float*)d_in[15];
    const float* decay_w1   = (const float*)d_in[16];
    const float* decay_w2   = (const float*)d_in[17];
    const float* u          = (const float*)d_in[18];
    const float* ln_g       = (const float*)d_in[19];
    const float* ln_b       = (const float*)d_in[20];
    (void)in_sizes; (void)n_in; (void)out_size;

    float *p_xx, *p_xxx, *p_xw, *p_xk, *p_xv, *p_xr, *p_xg;
    float *p_r, *p_k, *p_v, *p_w, *p_g, *p_y, *p_z, *p_lora, *p_s1, *p_s2;
    float *p_D, *p_Sc, *p_rp, *p_pL;
    float *p_WrT, *p_WkT, *p_WvT, *p_WoT, *p_w1T, *p_w2T, *p_dw1T, *p_gw1T, *p_dw2T, *p_gw2T;
    cudaGetSymbolAddress((void**)&p_xx, g_xx);
    cudaGetSymbolAddress((void**)&p_xxx, g_xxx);
    cudaGetSymbolAddress((void**)&p_xw, g_xw);
    cudaGetSymbolAddress((void**)&p_xk, g_xk);
    cudaGetSymbolAddress((void**)&p_xv, g_xv);
    cudaGetSymbolAddress((void**)&p_xr, g_xr);
    cudaGetSymbolAddress((void**)&p_xg, g_xg);
    cudaGetSymbolAddress((void**)&p_r, g_r);
    cudaGetSymbolAddress((void**)&p_k, g_k);
    cudaGetSymbolAddress((void**)&p_v, g_v);
    cudaGetSymbolAddress((void**)&p_w, g_w);
    cudaGetSymbolAddress((void**)&p_g, g_g);
    cudaGetSymbolAddress((void**)&p_y, g_y);
    cudaGetSymbolAddress((void**)&p_z, g_z);
    cudaGetSymbolAddress((void**)&p_lora, g_lora);
    cudaGetSymbolAddress((void**)&p_s1, g_small);
    cudaGetSymbolAddress((void**)&p_s2, g_small2);
    cudaGetSymbolAddress((void**)&p_D, g_D);
    cudaGetSymbolAddress((void**)&p_Sc, g_Sc);
    cudaGetSymbolAddress((void**)&p_rp, g_rp);
    cudaGetSymbolAddress((void**)&p_pL, g_pL);
    cudaGetSymbolAddress((void**)&p_WrT, g_WrT);
    cudaGetSymbolAddress((void**)&p_WkT, g_WkT);
    cudaGetSymbolAddress((void**)&p_WvT, g_WvT);
    cudaGetSymbolAddress((void**)&p_WoT, g_WoT);
    cudaGetSymbolAddress((void**)&p_w1T, g_w1T);
    cudaGetSymbolAddress((void**)&p_w2T, g_w2T);
    cudaGetSymbolAddress((void**)&p_dw1T, g_dw1T);
    cudaGetSymbolAddress((void**)&p_gw1T, g_gw1T);
    cudaGetSymbolAddress((void**)&p_dw2T, g_dw2T);
    cudaGetSymbolAddress((void**)&p_gw2T, g_gw2T);

    const long total = BTC;
    const int M = B_ * T_;          // 8192
    const int gy = M / 128;         // 64
    const int gy64 = M / 64;        // 128

    const int SMEM_A = (65 * 64 + 5 * 64 * STRD + 128) * 4;
    cudaFuncSetAttribute(wkv_chunkA, cudaFuncAttributeMaxDynamicSharedMemorySize, SMEM_A);
    cudaFuncSetAttribute(gemm_rkv, cudaFuncAttributeMaxDynamicSharedMemorySize, SMEM_G);
    cudaFuncSetAttribute(gemm_mix, cudaFuncAttributeMaxDynamicSharedMemorySize, SMEM_G);
    cudaFuncSetAttribute(gemm_dg2, cudaFuncAttributeMaxDynamicSharedMemorySize, SMEM_G);
    cudaFuncSetAttribute((const void*)gemm_tc<0, false>,
                         cudaFuncAttributeMaxDynamicSharedMemorySize, SMEM_G);

    // transpose job table
    TJobs tj;
    int toff = 0;
    {
        const float* srcs[10] = { maa_w1, maa_w2, Wr, Wk, Wv, Wo,
                                  decay_w1, gate_w1, decay_w2, gate_w2 };
        float* dsts[10] = { p_w1T, p_w2T, p_WrT, p_WkT, p_WvT, p_WoT,
                            p_dw1T, p_gw1T, p_dw2T, p_gw2T };
        int Rs[10] = { 1024, 160, 1024, 1024, 1024, 1024, 1024, 1024, 64, 64 };
        int Ns[10] = { 160, 1024, 1024, 1024, 1024, 1024, 64, 64, 1024, 1024 };
        for (int q = 0; q < 10; q++) {
            int nbx = (Ns[q] + 31) / 32;
            int nby = (Rs[q] + 31) / 32;
            tj.j[q].src = srcs[q]; tj.j[q].dst = dsts[q];
            tj.j[q].R = Rs[q]; tj.j[q].N = Ns[q];
            tj.j[q].nbx = nbx; tj.j[q].boff = toff;
            toff += nbx * nby;
        }
    }
    const int nshift = (int)(total / 4 / 256);   // 8192

    // 0. fused shift + transposes (xxx + weights tf32-rounded)
    pre_kernel<<<nshift + toff, 256>>>((const float4*)x, maa_x,
        (float4*)p_xx, (float4*)p_xxx, tj, nshift);
    // 1. lora = tanh(xxx @ maa_w1), rounded
    gemm_tc64<1, true><<<dim3(3, gy64), 128>>>(p_xxx, C_, p_w1T, C_, p_lora, 160, C_, 160, nullptr);
    // 2. merged 5-branch mix GEMM (outputs rounded)
    gemm_mix<<<dim3(8, gy, 5), 128, SMEM_G>>>(p_lora, p_w2T, x, p_xx,
        maa_w, maa_k, maa_v, maa_r, maa_g,
        p_xw, p_xk, p_xv, p_xr, p_xg);
    // 3. merged r,k,v projections  <-- profiled by ncu
    gemm_rkv<<<dim3(8, gy, 3), 128, SMEM_G>>>(p_xr, p_xk, p_xv, p_WrT, p_WkT, p_WvT,
                                              p_r, p_k, p_v);
    // 4. merged decay1 + gate1 (outputs rounded)
    gemm_dg1<<<dim3(1, gy64, 2), 128>>>(p_xw, p_xg, p_dw1T, p_gw1T, p_s1, p_s2);
    // 5. merged decay2 + gate2
    gemm_dg2<<<dim3(8, gy, 2), 128, SMEM_G>>>(p_s1, p_s2, p_dw2T, p_gw2T, p_w, p_g, time_decay);
    // 6-8. chunked WKV6
    wkv_chunkA<<<NCHUNK, 256, SMEM_A>>>(p_r, p_k, p_v, p_w, u, p_y, p_D, p_rp, p_pL);
    wkv_chunkB<<<B_ * H_, 256>>>(p_D, p_pL, p_Sc);
    wkv_chunkC<<<NCHUNK, 256>>>(p_rp, p_Sc, p_y);
    // 9. GroupNorm + gate multiply (z rounded)
    gn_kernel<<<M, 512>>>(p_y, ln_g, ln_b, p_g, p_z);
    // 10. out = z @ Wo
    gemm_tc<0, false><<<dim3(8, gy), 128, SMEM_G>>>(p_z, C_, p_WoT, C_, (float*)d_out, C_, C_, C_, nullptr);
}

// round 12
// speedup vs baseline: 1.4436x; 1.0244x over previous
#include <cuda_runtime.h>
#include <cuda_bf16.h>
#include <cstdint>
#include <math.h>

// Problem constants
#define B_  4
#define T_  2048
#define C_  1024
#define H_  16
#define N_  64
#define DMIX 32

#define CHUNK 64
#define G_ 32
#define NCHUNK (B_*H_*G_)         // 2048
#define STRD 68

static const long BTC = (long)B_ * T_ * C_;   // 8388608

// ---------------- scratch (device globals; no runtime allocation) -------------
__device__ float g_xx [ (long)B_*T_*C_ ];
__device__ float g_xxx[ (long)B_*T_*C_ ];
__device__ float g_xw [ (long)B_*T_*C_ ];
__device__ float g_xk [ (long)B_*T_*C_ ];
__device__ float g_xv [ (long)B_*T_*C_ ];
__device__ float g_xr [ (long)B_*T_*C_ ];
__device__ float g_xg [ (long)B_*T_*C_ ];
__device__ float g_r  [ (long)B_*T_*C_ ];
__device__ float g_k  [ (long)B_*T_*C_ ];
__device__ float g_v  [ (long)B_*T_*C_ ];
__device__ float g_w  [ (long)B_*T_*C_ ];
__device__ float g_g  [ (long)B_*T_*C_ ];
__device__ float g_y  [ (long)B_*T_*C_ ];
__device__ float g_z  [ (long)B_*T_*C_ ];
__device__ float g_lora [ (long)B_*T_*5*DMIX ];
__device__ float g_small [ (long)B_*T_*64 ];
__device__ float g_small2[ (long)B_*T_*64 ];
__device__ float g_D  [ (long)NCHUNK*64*64 ];
__device__ float g_Sc [ (long)NCHUNK*64*64 ];
__device__ float g_rp [ (long)NCHUNK*64*64 ];
__device__ float g_pL [ (long)NCHUNK*64 ];
__device__ float g_WrT[ (long)C_*C_ ];
__device__ float g_WkT[ (long)C_*C_ ];
__device__ float g_WvT[ (long)C_*C_ ];
__device__ float g_WoT[ (long)C_*C_ ];
__device__ float g_w1T[ (long)160*C_ ];
__device__ float g_w2T[ (long)C_*160 ];
__device__ float g_dw1T[ (long)64*C_ ];
__device__ float g_gw1T[ (long)64*C_ ];
__device__ float g_dw2T[ (long)C_*64 ];
__device__ float g_gw2T[ (long)C_*64 ];

// ================= helpers ====================================================
#define TSTR 20
#define STAGES 4

__device__ __forceinline__ uint32_t f2tf32(float f) {
    uint32_t o;
    asm("cvt.rna.tf32.f32 %0, %1;" : "=r"(o) : "f"(f));
    return o;
}
__device__ __forceinline__ float rndt(float f) {
    return __uint_as_float(f2tf32(f));
}
__device__ __forceinline__ uint32_t smem_u32(const void* p) {
    uint32_t a;
    asm("{ .reg .u64 t; cvta.to.shared.u64 t, %1; cvt.u32.u64 %0, t; }"
        : "=r"(a) : "l"(p));
    return a;
}
#define CP_A16(dst, src) \
    asm volatile("cp.async.cg.shared.global [%0], [%1], 16;" :: "r"(dst), "l"(src))
#define CP_COMMIT() asm volatile("cp.async.commit_group;" ::: "memory")
#define CP_WAIT(n)  asm volatile("cp.async.wait_group %0;" :: "n"(n) : "memory")

__device__ __forceinline__ void mma1688(float* d, const uint32_t* a, const uint32_t* b) {
    asm volatile(
        "mma.sync.aligned.m16n8k8.row.col.f32.tf32.tf32.f32 "
        "{%0,%1,%2,%3}, {%4,%5,%6,%7}, {%8,%9}, {%0,%1,%2,%3};"
        : "+f"(d[0]), "+f"(d[1]), "+f"(d[2]), "+f"(d[3])
        : "r"(a[0]), "r"(a[1]), "r"(a[2]), "r"(a[3]), "r"(b[0]), "r"(b[1]));
}

// ---- 128x128 body: 128 threads, 4 warps (2x2), warp tile 64x64, cp.async -----
// Inputs MUST be pre-rounded tf32. EPI: 0 none, 1 tanh, 2 -exp(acc+bias),
// 3 xin+xxin*(bias+acc), -2 runtime repi (0/1/2). rrnd: runtime output rounding.
template<int EPI, bool RND>
__device__ __forceinline__ void gemm128_body(
    uint32_t* dynsm,
    const float* __restrict__ A, int lda,
    const float* __restrict__ Bt, int ldb,
    float* __restrict__ Cm, int ldc,
    int K, int Nn, const float* __restrict__ bias,
    const float* __restrict__ xin, const float* __restrict__ xxin,
    int row0, int col0, int repi, bool rrnd)
{
    const int tid = threadIdx.x;
    const int lane = tid & 31;
    const int wid = tid >> 5;
    const int wr = wid >> 1;
    const int wc = wid & 1;

    uint32_t* As = dynsm;
    uint32_t* Bs = dynsm + STAGES * 128 * TSTR;
    const uint32_t as0 = smem_u32(As);
    const uint32_t bs0 = smem_u32(Bs);

    auto issueStage = [&](int kc, int buf) {
        const int k0 = kc * 16;
        const uint32_t ao = as0 + buf * (128 * TSTR * 4);
        const uint32_t bo = bs0 + buf * (128 * TSTR * 4);
        #pragma unroll
        for (int l = 0; l < 4; l++) {
            int e = tid + (l << 7);
            int r = e >> 2, c = e & 3;
            uint32_t so = (uint32_t)(r * TSTR + (c << 2)) * 4u;
            CP_A16(ao + so, &A[(long)(row0 + r) * lda + k0 + (c << 2)]);
            CP_A16(bo + so, &Bt[(long)(col0 + r) * ldb + k0 + (c << 2)]);
        }
        CP_COMMIT();
    };

    float acc[4][8][4];
    #pragma unroll
    for (int mi = 0; mi < 4; mi++)
        #pragma unroll
        for (int ni = 0; ni < 8; ni++)
            #pragma unroll
            for (int e = 0; e < 4; e++) acc[mi][ni][e] = 0.f;

    const int NKT = K >> 4;
    issueStage(0, 0);
    if (NKT > 1) issueStage(1, 1);
    if (NKT > 2) issueStage(2, 2);

    const int lg = lane >> 2;
    const int lt = lane & 3;

    for (int kc = 0; kc < NKT; kc++) {
        const int buf = kc & 3;
        if (kc + 3 < NKT)      { CP_WAIT(2); }
        else if (kc + 2 < NKT) { CP_WAIT(1); }
        else                   { CP_WAIT(0); }
        __syncthreads();

        const uint32_t* Ab = As + buf * 128 * TSTR;
        const uint32_t* Bb = Bs + buf * 128 * TSTR;
        #pragma unroll
        for (int ks = 0; ks < 2; ks++) {
            const int k0 = (ks << 3) + lt;
            uint32_t af[4][4], bf[8][2];
            #pragma unroll
            for (int mi = 0; mi < 4; mi++) {
                int rm = wr * 64 + mi * 16 + lg;
                af[mi][0] = Ab[rm * TSTR + k0];
                af[mi][1] = Ab[(rm + 8) * TSTR + k0];
                af[mi][2] = Ab[rm * TSTR + k0 + 4];
                af[mi][3] = Ab[(rm + 8) * TSTR + k0 + 4];
            }
            #pragma unroll
            for (int ni = 0; ni < 8; ni++) {
                int cn = wc * 64 + ni * 8 + lg;
                bf[ni][0] = Bb[cn * TSTR + k0];
                bf[ni][1] = Bb[cn * TSTR + k0 + 4];
            }
            #pragma unroll
            for (int mi = 0; mi < 4; mi++)
                #pragma unroll
                for (int ni = 0; ni < 8; ni++)
                    mma1688(acc[mi][ni], af[mi], bf[ni]);
        }

        if (kc + 3 < NKT) issueStage(kc + 3, (kc + 3) & 3);
    }

    const int ep = (EPI == -2) ? repi : EPI;
    #pragma unroll
    for (int mi = 0; mi < 4; mi++) {
        int gr0 = row0 + wr * 64 + mi * 16 + lg;
        #pragma unroll
        for (int ni = 0; ni < 8; ni++) {
            int gc = col0 + wc * 64 + ni * 8 + 2 * lt;
            if (gc < Nn) {
                float v0 = acc[mi][ni][0], v1 = acc[mi][ni][1];
                float v2 = acc[mi][ni][2], v3 = acc[mi][ni][3];
                long o0 = (long)gr0 * ldc + gc;
                long o1 = (long)(gr0 + 8) * ldc + gc;
                if (ep == 1) {
                    v0 = tanhf(v0); v1 = tanhf(v1); v2 = tanhf(v2); v3 = tanhf(v3);
                } else if (ep == 2) {
                    float b0 = bias[gc], b1 = bias[gc + 1];
                    v0 = -expf(v0 + b0); v1 = -expf(v1 + b1);
                    v2 = -expf(v2 + b0); v3 = -expf(v3 + b1);
                } else if (ep == 3) {
                    float b0 = bias[gc], b1 = bias[gc + 1];
                    float2 x0 = *(const float2*)&xin[o0];
                    float2 x1 = *(const float2*)&xin[o1];
                    float2 d0 = *(const float2*)&xxin[o0];
                    float2 d1 = *(const float2*)&xxin[o1];
                    v0 = fmaf(d0.x, b0 + v0, x0.x);
                    v1 = fmaf(d0.y, b1 + v1, x0.y);
                    v2 = fmaf(d1.x, b0 + v2, x1.x);
                    v3 = fmaf(d1.y, b1 + v3, x1.y);
                }
                if (RND || rrnd) {
                    v0 = rndt(v0); v1 = rndt(v1); v2 = rndt(v2); v3 = rndt(v3);
                }
                *(float2*)&Cm[o0] = make_float2(v0, v1);
                *(float2*)&Cm[o1] = make_float2(v2, v3);
            }
        }
    }
}

#define SMEM_G (STAGES * 128 * TSTR * 4 * 2)   // 81920 bytes

template<int EPI, bool RND>
__global__ __launch_bounds__(128, 2) void gemm_tc(
    const float* __restrict__ A, int lda,
    const float* __restrict__ Bt, int ldb,
    float* __restrict__ Cm, int ldc,
    int K, int Nn, const float* __restrict__ bias)
{
    extern __shared__ uint32_t dynsm[];
    gemm128_body<EPI, RND>(dynsm, A, lda, Bt, ldb, Cm, ldc, K, Nn, bias,
                           nullptr, nullptr, blockIdx.y * 128, blockIdx.x * 128,
                           0, false);
}

// merged r,k,v projections + decay1 + gate1: z selects (z=3,4 are N=64 LoRA)
__global__ __launch_bounds__(128, 2) void gemm_rkv(
    const float* xr, const float* xk, const float* xv,
    const float* xw, const float* xg,
    const float* WrT, const float* WkT, const float* WvT,
    const float* dw1T, const float* gw1T,
    float* r, float* k, float* v, float* s1, float* s2)
{
    extern __shared__ uint32_t dynsm[];
    const int z = blockIdx.z;
    const int col0 = blockIdx.x * 128;
    const float* A;
    const float* Bt;
    float* Cm;
    int Nn, ldc, repi;
    bool rr;
    if (z < 3) {
        A  = (z == 0) ? xr : (z == 1) ? xk : xv;
        Bt = (z == 0) ? WrT : (z == 1) ? WkT : WvT;
        Cm = (z == 0) ? r : (z == 1) ? k : v;
        Nn = C_; ldc = C_; repi = 0; rr = false;
    } else {
        A  = (z == 3) ? xw : xg;
        Bt = (z == 3) ? dw1T : gw1T;
        Cm = (z == 3) ? s1 : s2;
        Nn = 64; ldc = 64; repi = 1; rr = true;
        if (col0 >= 64) return;
    }
    gemm128_body<-2, false>(dynsm, A, C_, Bt, C_, Cm, ldc, C_, Nn, nullptr,
                            nullptr, nullptr, blockIdx.y * 128, col0, repi, rr);
}

__global__ __launch_bounds__(128, 2) void gemm_dg2(
    const float* small1, const float* small2,
    const float* dw2T, const float* gw2T,
    float* w, float* g, const float* time_decay)
{
    extern __shared__ uint32_t dynsm[];
    const int z = blockIdx.z;
    gemm128_body<-2, false>(dynsm, (z == 0) ? small1 : small2, 64,
                            (z == 0) ? dw2T : gw2T, 64,
                            (z == 0) ? w : g, C_, 64, C_, time_decay,
                            nullptr, nullptr, blockIdx.y * 128, blockIdx.x * 128,
                            (z == 0) ? 2 : 0, false);
}

__global__ __launch_bounds__(128, 2) void gemm_mix(
    const float* __restrict__ lora, const float* __restrict__ w2T,
    const float* __restrict__ x, const float* __restrict__ xx,
    const float* m0, const float* m1, const float* m2, const float* m3, const float* m4,
    float* o0, float* o1, float* o2, float* o3, float* o4)
{
    extern __shared__ uint32_t dynsm[];
    const int z = blockIdx.z;
    const float* bias = (z == 0) ? m0 : (z == 1) ? m1 : (z == 2) ? m2 : (z == 3) ? m3 : m4;
    float* out = (z == 0) ? o0 : (z == 1) ? o1 : (z == 2) ? o2 : (z == 3) ? o3 : o4;
    gemm128_body<3, true>(dynsm, lora + z * DMIX, 160, w2T + z * DMIX, 160,
                          out, C_, DMIX, C_, bias, x, xx,
                          blockIdx.y * 128, blockIdx.x * 128, 0, false);
}

// ---- small tile: BM=64, BN=64, 128 threads (classic path) --------------------
template<int EPI, bool RND>
__device__ __forceinline__ void gemm64_body(
    uint32_t (*As)[64 * TSTR], uint32_t (*Bs)[64 * TSTR],
    const float* __restrict__ A, int lda,
    const float* __restrict__ Bt, int ldb,
    float* __restrict__ Cm, int ldc,
    int K, int Nn, const float* __restrict__ bias,
    int row0, int col0)
{
    const int tid = threadIdx.x;
    const int lane = tid & 31;
    const int wid = tid >> 5;
    const int wr = wid >> 1;
    const int wc = wid & 1;

    float4 ra[2], rb[2];

    auto loadAB = [&](int kc) {
        const int k0 = kc * 16;
        #pragma unroll
        for (int l = 0; l < 2; l++) {
            int e = tid + (l << 7);
            int r = e >> 2, c = e & 3;
            ra[l] = *(const float4*)&A[(long)(row0 + r) * lda + k0 + (c << 2)];
            int br = col0 + r;
            if (br < Nn)
                rb[l] = *(const float4*)&Bt[(long)br * ldb + k0 + (c << 2)];
            else
                rb[l] = make_float4(0.f, 0.f, 0.f, 0.f);
        }
    };
    auto storeAB = [&](int buf) {
        #pragma unroll
        for (int l = 0; l < 2; l++) {
            int e = tid + (l << 7);
            int r = e >> 2, c = e & 3;
            uint32_t* ap = &As[buf][r * TSTR + (c << 2)];
            ap[0] = f2tf32(ra[l].x); ap[1] = f2tf32(ra[l].y);
            ap[2] = f2tf32(ra[l].z); ap[3] = f2tf32(ra[l].w);
            uint32_t* bp = &Bs[buf][r * TSTR + (c << 2)];
            bp[0] = f2tf32(rb[l].x); bp[1] = f2tf32(rb[l].y);
            bp[2] = f2tf32(rb[l].z); bp[3] = f2tf32(rb[l].w);
        }
    };

    float acc[2][4][4];
    #pragma unroll
    for (int mi = 0; mi < 2; mi++)
        #pragma unroll
        for (int ni = 0; ni < 4; ni++)
            #pragma unroll
            for (int e = 0; e < 4; e++) acc[mi][ni][e] = 0.f;

    const int NKT = K >> 4;
    loadAB(0);
    storeAB(0);
    __syncthreads();

    const int lg = lane >> 2;
    const int lt = lane & 3;

    for (int kc = 0; kc < NKT; kc++) {
        const int cur = kc & 1;
        if (kc + 1 < NKT) loadAB(kc + 1);

        #pragma unroll
        for (int ks = 0; ks < 2; ks++) {
            const int k0 = (ks << 3) + lt;
            uint32_t af[2][4], bf[4][2];
            #pragma unroll
            for (int mi = 0; mi < 2; mi++) {
                int rm = wr * 32 + mi * 16 + lg;
                af[mi][0] = As[cur][rm * TSTR + k0];
                af[mi][1] = As[cur][(rm + 8) * TSTR + k0];
                af[mi][2] = As[cur][rm * TSTR + k0 + 4];
                af[mi][3] = As[cur][(rm + 8) * TSTR + k0 + 4];
            }
            #pragma unroll
            for (int ni = 0; ni < 4; ni++) {
                int cn = wc * 32 + ni * 8 + lg;
                bf[ni][0] = Bs[cur][cn * TSTR + k0];
                bf[ni][1] = Bs[cur][cn * TSTR + k0 + 4];
            }
            #pragma unroll
            for (int mi = 0; mi < 2; mi++)
                #pragma unroll
                for (int ni = 0; ni < 4; ni++)
                    mma1688(acc[mi][ni], af[mi], bf[ni]);
        }

        if (kc + 1 < NKT) storeAB(cur ^ 1);
        __syncthreads();
    }

    #pragma unroll
    for (int mi = 0; mi < 2; mi++) {
        int gr0 = row0 + wr * 32 + mi * 16 + lg;
        #pragma unroll
        for (int ni = 0; ni < 4; ni++) {
            int gc = col0 + wc * 32 + ni * 8 + 2 * lt;
            if (gc < Nn) {
                float v0 = acc[mi][ni][0], v1 = acc[mi][ni][1];
                float v2 = acc[mi][ni][2], v3 = acc[mi][ni][3];
                if (EPI == 1) {
                    v0 = tanhf(v0); v1 = tanhf(v1); v2 = tanhf(v2); v3 = tanhf(v3);
                }
                if (RND) {
                    v0 = rndt(v0); v1 = rndt(v1); v2 = rndt(v2); v3 = rndt(v3);
                }
                *(float2*)&Cm[(long)gr0 * ldc + gc] = make_float2(v0, v1);
                *(float2*)&Cm[(long)(gr0 + 8) * ldc + gc] = make_float2(v2, v3);
            }
        }
    }
}

template<int EPI, bool RND>
__global__ __launch_bounds__(128, 3) void gemm_tc64(
    const float* __restrict__ A, int lda,
    const float* __restrict__ Bt, int ldb,
    float* __restrict__ Cm, int ldc,
    int K, int Nn, const float* __restrict__ bias)
{
    __shared__ uint32_t As[2][64 * TSTR];
    __shared__ uint32_t Bs[2][64 * TSTR];
    gemm64_body<EPI, RND>(As, Bs, A, lda, Bt, ldb, Cm, ldc, K, Nn, bias,
                          blockIdx.y * 64, blockIdx.x * 64);
}

// ---------------- fused pre-pass: shift + all weight transposes --------------
struct TJob { const float* src; float* dst; int R, N, nbx, boff; };
struct TJobs { TJob j[10]; };

__global__ __launch_bounds__(256) void pre_kernel(
    const float4* __restrict__ x4, const float* __restrict__ maa_x,
    float4* __restrict__ xx4, float4* __restrict__ xxx4,
    TJobs js, int nshift)
{
    const int tid = threadIdx.x;
    if ((int)blockIdx.x < nshift) {
        long idx = (long)blockIdx.x * 256 + tid;
        const int C4 = C_ / 4;
        int c4 = (int)(idx % C4);
        long rt = idx / C4;
        int t = (int)(rt % T_);
        float4 xv = x4[idx];
        float4 xp = (t > 0) ? x4[idx - C4] : make_float4(0.f, 0.f, 0.f, 0.f);
        float4 mx = *(const float4*)&maa_x[c4 * 4];
        float4 d = make_float4(xp.x - xv.x, xp.y - xv.y, xp.z - xv.z, xp.w - xv.w);
        xx4[idx] = d;
        xxx4[idx] = make_float4(rndt(fmaf(d.x, mx.x, xv.x)), rndt(fmaf(d.y, mx.y, xv.y)),
                                rndt(fmaf(d.z, mx.z, xv.z)), rndt(fmaf(d.w, mx.w, xv.w)));
        return;
    }
    __shared__ float t[32][33];
    int b = blockIdx.x - nshift;
    int ji = 0;
    #pragma unroll
    for (int q = 1; q < 10; q++)
        if (b >= js.j[q].boff) ji = q;
    TJob jb = js.j[ji];
    int rem = b - jb.boff;
    int bx = (rem % jb.nbx) * 32;
    int by = (rem / jb.nbx) * 32;
    const int xq = tid & 31, yq = tid >> 5;
    #pragma unroll
    for (int i = 0; i < 32; i += 8) {
        int r = by + yq + i, n = bx + xq;
        if (r < jb.R && n < jb.N) t[yq + i][xq] = jb.src[(long)r * jb.N + n];
    }
    __syncthreads();
    #pragma unroll
    for (int i = 0; i < 32; i += 8) {
        int n = bx + yq + i, r = by + xq;
        if (n < jb.N && r < jb.R) jb.dst[(long)n * jb.R + r] = rndt(t[xq][yq + i]);
    }
}

// ---------------- chunked WKV6 -----------------------------------------------
__global__ __launch_bounds__(256) void wkv_chunkA(
    const float* __restrict__ r, const float* __restrict__ k,
    const float* __restrict__ v, const float* __restrict__ lw,
    const float* __restrict__ u,
    float* __restrict__ y, float* __restrict__ Dout,
    float* __restrict__ rpout, float* __restrict__ pLout)
{
    extern __shared__ float sm[];
    float* lp   = sm;
    float* bufA = lp + 65 * 64;
    float* rpT  = bufA + 64 * STRD;
    float* kpT  = rpT + 64 * STRD;
    float* kpp  = kpT + 64 * STRD;
    float* vsm  = kpp + 64 * STRD;
    float* dsm  = vsm + 64 * STRD;
    float* usm  = dsm + 64;

    const int tid = threadIdx.x;
    const int chunk = blockIdx.x;
    const int bh = chunk >> 5;
    const int c  = chunk & 31;
    const int b = bh >> 4, h = bh & 15;
    const long base = ((long)b * T_ + c * CHUNK) * C_ + h * 64;

    if (tid < 64) usm[tid] = u[h * 64 + tid];
    const int i  = tid & 63;
    const int tq = tid >> 6;

    #pragma unroll
    for (int e = 0; e < 16; e++) {
        int t = tq + 4 * e;
        bufA[t * STRD + i] = lw[base + (long)t * C_ + i];
    }
    __syncthreads();

    if (tid < 64) {
        float run = 0.f;
        for (int t = 0; t < 64; t++) {
            lp[t * 64 + tid] = run;
            run += bufA[t * STRD + tid];
        }
        lp[64 * 64 + tid] = run;
        pLout[(long)chunk * 64 + tid] = run;
    }
    __syncthreads();

    #pragma unroll
    for (int e = 0; e < 16; e++) {
        int t = tq + 4 * e;
        long gi = base + (long)t * C_ + i;
        float rr = r[gi], kk = k[gi];
        float lpti = lp[t * 64 + i];
        float lpn  = lpti + bufA[t * STRD + i];
        float lpL  = lp[64 * 64 + i];
        rpT[i * STRD + t] = rr * __expf(lpti);
        kpT[i * STRD + t] = kk * __expf(-lpn);
        kpp[t * STRD + i] = kk * __expf(lpL - lpn);
        vsm[t * STRD + i] = v[gi];
    }
    {
        int t = tid >> 2, q = tid & 3;
        long gb = base + (long)t * C_;
        float p = 0.f;
        #pragma unroll
        for (int ii = 0; ii < 16; ii++) {
            int ci = q * 16 + ii;
            p += r[gb + ci] * usm[ci] * k[gb + ci];
        }
        p += __shfl_xor_sync(0xffffffffu, p, 1);
        p += __shfl_xor_sync(0xffffffffu, p, 2);
        if (q == 0) dsm[t] = p;
    }
    __syncthreads();

    {
        float* rpg = rpout + (long)chunk * 64 * 64;
        #pragma unroll
        for (int e = 0; e < 16; e++) {
            int flat = tid + 256 * e;
            rpg[flat] = rpT[(flat >> 6) * STRD + (flat & 63)];
        }
    }

    {
        int t0 = (tid >> 4) * 4, s0 = (tid & 15) * 4;
        float acc[4][4];
        #pragma unroll
        for (int a = 0; a < 4; a++)
            #pragma unroll
            for (int bq = 0; bq < 4; bq++) acc[a][bq] = 0.f;
        for (int ii = 0; ii < 64; ii++) {
            float4 a4 = *(const float4*)&rpT[ii * STRD + t0];
            float4 b4 = *(const float4*)&kpT[ii * STRD + s0];
            float av[4] = { a4.x, a4.y, a4.z, a4.w };
            float bv[4] = { b4.x, b4.y, b4.z, b4.w };
            #pragma unroll
            for (int a = 0; a < 4; a++)
                #pragma unroll
                for (int bq = 0; bq < 4; bq++)
                    acc[a][bq] = fmaf(av[a], bv[bq], acc[a][bq]);
        }
        __syncthreads();
        #pragma unroll
        for (int a = 0; a < 4; a++)
            #pragma unroll
            for (int bq = 0; bq < 4; bq++) {
                int tt = t0 + a, ss = s0 + bq;
                float val = (tt > ss) ? acc[a][bq] : ((tt == ss) ? dsm[tt] : 0.f);
                bufA[ss * STRD + tt] = val;
            }
    }
    __syncthreads();

    {
        int t0 = (tid >> 4) * 4, j0 = (tid & 15) * 4;
        float acc[4][4];
        #pragma unroll
        for (int a = 0; a < 4; a++)
            #pragma unroll
            for (int bq = 0; bq < 4; bq++) acc[a][bq] = 0.f;
        for (int s = 0; s < 64; s++) {
            float4 a4 = *(const float4*)&bufA[s * STRD + t0];
            float4 b4 = *(const float4*)&vsm[s * STRD + j0];
            float av[4] = { a4.x, a4.y, a4.z, a4.w };
            float bv[4] = { b4.x, b4.y, b4.z, b4.w };
            #pragma unroll
            for (int a = 0; a < 4; a++)
                #pragma unroll
                for (int bq = 0; bq < 4; bq++)
                    acc[a][bq] = fmaf(av[a], bv[bq], acc[a][bq]);
        }
        #pragma unroll
        for (int a = 0; a < 4; a++) {
            float4 o = make_float4(acc[a][0], acc[a][1], acc[a][2], acc[a][3]);
            *(float4*)&y[base + (long)(t0 + a) * C_ + j0] = o;
        }
    }

    {
        int i0 = (tid >> 4) * 4, j0 = (tid & 15) * 4;
        float acc[4][4];
        #pragma unroll
        for (int a = 0; a < 4; a++)
            #pragma unroll
            for (int bq = 0; bq < 4; bq++) acc[a][bq] = 0.f;
        for (int s = 0; s < 64; s++) {
            float4 a4 = *(const float4*)&kpp[s * STRD + i0];
            float4 b4 = *(const float4*)&vsm[s * STRD + j0];
            float av[4] = { a4.x, a4.y, a4.z, a4.w };
            float bv[4] = { b4.x, b4.y, b4.z, b4.w };
            #pragma unroll
            for (int a = 0; a < 4; a++)
                #pragma unroll
                for (int bq = 0; bq < 4; bq++)
                    acc[a][bq] = fmaf(av[a], bv[bq], acc[a][bq]);
        }
        float* Dp = Dout + (long)chunk * 4096;
        #pragma unroll
        for (int a = 0; a < 4; a++) {
            float4 o = make_float4(acc[a][0], acc[a][1], acc[a][2], acc[a][3]);
            *(float4*)&Dp[(i0 + a) * 64 + j0] = o;
        }
    }
}

__global__ __launch_bounds__(256) void wkv_chunkB(
    const float* __restrict__ D, const float* __restrict__ pL,
    float* __restrict__ S)
{
    const int bh = blockIdx.x;
    const int tid = threadIdx.x;
    const int i = tid >> 2;
    const int jb = (tid & 3) * 16;
    float4 s0 = {0,0,0,0}, s1 = {0,0,0,0}, s2 = {0,0,0,0}, s3 = {0,0,0,0};
    for (int c = 0; c < G_; c++) {
        long chunk = (long)bh * G_ + c;
        long off = chunk * 4096 + i * 64 + jb;
        *(float4*)&S[off + 0]  = s0;
        *(float4*)&S[off + 4]  = s1;
        *(float4*)&S[off + 8]  = s2;
        *(float4*)&S[off + 12] = s3;
        float pl = __expf(pL[chunk * 64 + i]);
        float4 d0 = *(const float4*)&D[off + 0];
        float4 d1 = *(const float4*)&D[off + 4];
        float4 d2 = *(const float4*)&D[off + 8];
        float4 d3 = *(const float4*)&D[off + 12];
        s0 = make_float4(fmaf(pl, s0.x, d0.x), fmaf(pl, s0.y, d0.y), fmaf(pl, s0.z, d0.z), fmaf(pl, s0.w, d0.w));
        s1 = make_float4(fmaf(pl, s1.x, d1.x), fmaf(pl, s1.y, d1.y), fmaf(pl, s1.z, d1.z), fmaf(pl, s1.w, d1.w));
        s2 = make_float4(fmaf(pl, s2.x, d2.x), fmaf(pl, s2.y, d2.y), fmaf(pl, s2.z, d2.z), fmaf(pl, s2.w, d2.w));
        s3 = make_float4(fmaf(pl, s3.x, d3.x), fmaf(pl, s3.y, d3.y), fmaf(pl, s3.z, d3.z), fmaf(pl, s3.w, d3.w));
    }
}

__global__ __launch_bounds__(256) void wkv_chunkC(
    const float* __restrict__ rp, const float* __restrict__ S,
    float* __restrict__ y)
{
    __shared__ float rps[64 * 64];
    __shared__ float Ss[64 * 64];
    const int tid = threadIdx.x;
    const int chunk = blockIdx.x;
    const int bh = chunk >> 5;
    const int c  = chunk & 31;
    const int b = bh >> 4, h = bh & 15;
    const long base = ((long)b * T_ + c * CHUNK) * C_ + h * 64;

    const float* rpg = rp + (long)chunk * 4096;
    const float* Sg  = S  + (long)chunk * 4096;
    #pragma unroll
    for (int e = 0; e < 4; e++) {
        int f4 = tid + 256 * e;
        *(float4*)&rps[f4 * 4] = *(const float4*)&rpg[f4 * 4];
        *(float4*)&Ss[f4 * 4]  = *(const float4*)&Sg[f4 * 4];
    }
    __syncthreads();

    int t0 = (tid >> 4) * 4, j0 = (tid & 15) * 4;
    float acc[4][4];
    #pragma unroll
    for (int a = 0; a < 4; a++)
        #pragma unroll
        for (int bq = 0; bq < 4; bq++) acc[a][bq] = 0.f;
    for (int ii = 0; ii < 64; ii++) {
        float4 a4 = *(const float4*)&rps[ii * 64 + t0];
        float4 b4 = *(const float4*)&Ss[ii * 64 + j0];
        float av[4] = { a4.x, a4.y, a4.z, a4.w };
        float bv[4] = { b4.x, b4.y, b4.z, b4.w };
        #pragma unroll
        for (int a = 0; a < 4; a++)
            #pragma unroll
            for (int bq = 0; bq < 4; bq++)
                acc[a][bq] = fmaf(av[a], bv[bq], acc[a][bq]);
    }
    #pragma unroll
    for (int a = 0; a < 4; a++) {
        long yo = base + (long)(t0 + a) * C_ + j0;
        float4 cur = *(const float4*)&y[yo];
        cur.x += acc[a][0]; cur.y += acc[a][1];
        cur.z += acc[a][2]; cur.w += acc[a][3];
        *(float4*)&y[yo] = cur;
    }
}

// ---------------- GroupNorm over heads + gate multiply (z tf32-rounded) ------
__global__ __launch_bounds__(512) void gn_kernel(
    const float* __restrict__ y, const float* __restrict__ ln_g,
    const float* __restrict__ ln_b, const float* __restrict__ g,
    float* __restrict__ z)
{
    const int bt = blockIdx.x;
    const int warp = threadIdx.x >> 5;
    const int lane = threadIdx.x & 31;
    const long base = (long)bt * C_ + warp * 64;

    float a0 = y[base + lane];
    float a1 = y[base + 32 + lane];
    float sum = a0 + a1;
    float sq = a0 * a0 + a1 * a1;
    #pragma unroll
    for (int off = 16; off > 0; off >>= 1) {
        sum += __shfl_xor_sync(0xffffffffu, sum, off);
        sq  += __shfl_xor_sync(0xffffffffu, sq,  off);
    }
    float mu = sum * (1.f / 64.f);
    float var = sq * (1.f / 64.f) - mu * mu;
    float inv = rsqrtf(var + 6.4e-4f);

    int c0 = warp * 64 + lane;
    float z0 = (a0 - mu) * inv * ln_g[c0] + ln_b[c0];
    float z1 = (a1 - mu) * inv * ln_g[c0 + 32] + ln_b[c0 + 32];
    z[base + lane]      = rndt(z0 * g[base + lane]);
    z[base + 32 + lane] = rndt(z1 * g[base + 32 + lane]);
}

// ---------------- launcher ----------------------------------------------------
extern "C" void kernel_launch(void* const* d_in, const int* in_sizes, int n_in,
                              void* d_out, int out_size)
{
    const float* x          = (const float*)d_in[0];
    const float* maa_x      = (const float*)d_in[1];
    const float* maa_w      = (const float*)d_in[2];
    const float* maa_k      = (const float*)d_in[3];
    const float* maa_v      = (const float*)d_in[4];
    const float* maa_r      = (const float*)d_in[5];
    const float* maa_g      = (const float*)d_in[6];
    const float* maa_w1     = (const float*)d_in[7];
    const float* maa_w2     = (const float*)d_in[8];
    const float* Wr         = (const float*)d_in[9];
    const float* Wk         = (const float*)d_in[10];
    const float* Wv         = (const float*)d_in[11];
    const float* Wo         = (const float*)d_in[12];
    const float* gate_w1    = (const float*)d_in[13];
    const float* gate_w2    = (const float*)d_in[14];
    const float* time_decay = (const float*)d_in[15];
    const float* decay_w1   = (const float*)d_in[16];
    const float* decay_w2   = (const float*)d_in[17];
    const float* u          = (const float*)d_in[18];
    const float* ln_g       = (const float*)d_in[19];
    const float* ln_b       = (const float*)d_in[20];
    (void)in_sizes; (void)n_in; (void)out_size;

    float *p_xx, *p_xxx, *p_xw, *p_xk, *p_xv, *p_xr, *p_xg;
    float *p_r, *p_k, *p_v, *p_w, *p_g, *p_y, *p_z, *p_lora, *p_s1, *p_s2;
    float *p_D, *p_Sc, *p_rp, *p_pL;
    float *p_WrT, *p_WkT, *p_WvT, *p_WoT, *p_w1T, *p_w2T, *p_dw1T, *p_gw1T, *p_dw2T, *p_gw2T;
    cudaGetSymbolAddress((void**)&p_xx, g_xx);
    cudaGetSymbolAddress((void**)&p_xxx, g_xxx);
    cudaGetSymbolAddress((void**)&p_xw, g_xw);
    cudaGetSymbolAddress((void**)&p_xk, g_xk);
    cudaGetSymbolAddress((void**)&p_xv, g_xv);
    cudaGetSymbolAddress((void**)&p_xr, g_xr);
    cudaGetSymbolAddress((void**)&p_xg, g_xg);
    cudaGetSymbolAddress((void**)&p_r, g_r);
    cudaGetSymbolAddress((void**)&p_k, g_k);
    cudaGetSymbolAddress((void**)&p_v, g_v);
    cudaGetSymbolAddress((void**)&p_w, g_w);
    cudaGetSymbolAddress((void**)&p_g, g_g);
    cudaGetSymbolAddress((void**)&p_y, g_y);
    cudaGetSymbolAddress((void**)&p_z, g_z);
    cudaGetSymbolAddress((void**)&p_lora, g_lora);
    cudaGetSymbolAddress((void**)&p_s1, g_small);
    cudaGetSymbolAddress((void**)&p_s2, g_small2);
    cudaGetSymbolAddress((void**)&p_D, g_D);
    cudaGetSymbolAddress((void**)&p_Sc, g_Sc);
    cudaGetSymbolAddress((void**)&p_rp, g_rp);
    cudaGetSymbolAddress((void**)&p_pL, g_pL);
    cudaGetSymbolAddress((void**)&p_WrT, g_WrT);
    cudaGetSymbolAddress((void**)&p_WkT, g_WkT);
    cudaGetSymbolAddress((void**)&p_WvT, g_WvT);
    cudaGetSymbolAddress((void**)&p_WoT, g_WoT);
    cudaGetSymbolAddress((void**)&p_w1T, g_w1T);
    cudaGetSymbolAddress((void**)&p_w2T, g_w2T);
    cudaGetSymbolAddress((void**)&p_dw1T, g_dw1T);
    cudaGetSymbolAddress((void**)&p_gw1T, g_gw1T);
    cudaGetSymbolAddress((void**)&p_dw2T, g_dw2T);
    cudaGetSymbolAddress((void**)&p_gw2T, g_gw2T);

    const long total = BTC;
    const int M = B_ * T_;          // 8192
    const int gy = M / 128;         // 64
    const int gy64 = M / 64;        // 128

    const int SMEM_A = (65 * 64 + 5 * 64 * STRD + 128) * 4;
    cudaFuncSetAttribute(wkv_chunkA, cudaFuncAttributeMaxDynamicSharedMemorySize, SMEM_A);
    cudaFuncSetAttribute(gemm_rkv, cudaFuncAttributeMaxDynamicSharedMemorySize, SMEM_G);
    cudaFuncSetAttribute(gemm_mix, cudaFuncAttributeMaxDynamicSharedMemorySize, SMEM_G);
    cudaFuncSetAttribute(gemm_dg2, cudaFuncAttributeMaxDynamicSharedMemorySize, SMEM_G);
    cudaFuncSetAttribute((const void*)gemm_tc<0, false>,
                         cudaFuncAttributeMaxDynamicSharedMemorySize, SMEM_G);

    // transpose job table
    TJobs tj;
    int toff = 0;
    {
        const float* srcs[10] = { maa_w1, maa_w2, Wr, Wk, Wv, Wo,
                                  decay_w1, gate_w1, decay_w2, gate_w2 };
        float* dsts[10] = { p_w1T, p_w2T, p_WrT, p_WkT, p_WvT, p_WoT,
                            p_dw1T, p_gw1T, p_dw2T, p_gw2T };
        int Rs[10] = { 1024, 160, 1024, 1024, 1024, 1024, 1024, 1024, 64, 64 };
        int Ns[10] = { 160, 1024, 1024, 1024, 1024, 1024, 64, 64, 1024, 1024 };
        for (int q = 0; q < 10; q++) {
            int nbx = (Ns[q] + 31) / 32;
            int nby = (Rs[q] + 31) / 32;
            tj.j[q].src = srcs[q]; tj.j[q].dst = dsts[q];
            tj.j[q].R = Rs[q]; tj.j[q].N = Ns[q];
            tj.j[q].nbx = nbx; tj.j[q].boff = toff;
            toff += nbx * nby;
        }
    }
    const int nshift = (int)(total / 4 / 256);   // 8192

    // 0. fused shift + transposes (xxx + weights tf32-rounded)
    pre_kernel<<<nshift + toff, 256>>>((const float4*)x, maa_x,
        (float4*)p_xx, (float4*)p_xxx, tj, nshift);
    // 1. lora = tanh(xxx @ maa_w1), rounded
    gemm_tc64<1, true><<<dim3(3, gy64), 128>>>(p_xxx, C_, p_w1T, C_, p_lora, 160, C_, 160, nullptr);
    // 2. merged 5-branch mix GEMM (outputs rounded)
    gemm_mix<<<dim3(8, gy, 5), 128, SMEM_G>>>(p_lora, p_w2T, x, p_xx,
        maa_w, maa_k, maa_v, maa_r, maa_g,
        p_xw, p_xk, p_xv, p_xr, p_xg);
    // 3. merged r,k,v + decay1 + gate1 projections  <-- profiled by ncu
    gemm_rkv<<<dim3(8, gy, 5), 128, SMEM_G>>>(p_xr, p_xk, p_xv, p_xw, p_xg,
                                              p_WrT, p_WkT, p_WvT, p_dw1T, p_gw1T,
                                              p_r, p_k, p_v, p_s1, p_s2);
    // 4. merged decay2 + gate2
    gemm_dg2<<<dim3(8, gy, 2), 128, SMEM_G>>>(p_s1, p_s2, p_dw2T, p_gw2T, p_w, p_g, time_decay);
    // 5-7. chunked WKV6
    wkv_chunkA<<<NCHUNK, 256, SMEM_A>>>(p_r, p_k, p_v, p_w, u, p_y, p_D, p_rp, p_pL);
    wkv_chunkB<<<B_ * H_, 256>>>(p_D, p_pL, p_Sc);
    wkv_chunkC<<<NCHUNK, 256>>>(p_rp, p_Sc, p_y);
    // 8. GroupNorm + gate multiply (z rounded)
    gn_kernel<<<M, 512>>>(p_y, ln_g, ln_b, p_g, p_z);
    // 9. out = z @ Wo
    gemm_tc<0, false><<<dim3(8, gy), 128, SMEM_G>>>(p_z, C_, p_WoT, C_, (float*)d_out, C_, C_, C_, nullptr);
}

// round 13
// speedup vs baseline: 1.4439x; 1.0002x over previous
#include <cuda_runtime.h>
#include <cuda_bf16.h>
#include <cstdint>
#include <math.h>

// Problem constants
#define B_  4
#define T_  2048
#define C_  1024
#define H_  16
#define N_  64
#define DMIX 32

#define CHUNK 64
#define G_ 32
#define NCHUNK (B_*H_*G_)         // 2048
#define STRD 68

static const long BTC = (long)B_ * T_ * C_;   // 8388608

// ---------------- scratch (device globals; no runtime allocation) -------------
__device__ float g_xx [ (long)B_*T_*C_ ];
__device__ float g_xxx[ (long)B_*T_*C_ ];
__device__ float g_xw [ (long)B_*T_*C_ ];
__device__ float g_xk [ (long)B_*T_*C_ ];
__device__ float g_xv [ (long)B_*T_*C_ ];
__device__ float g_xr [ (long)B_*T_*C_ ];
__device__ float g_xg [ (long)B_*T_*C_ ];
__device__ float g_r  [ (long)B_*T_*C_ ];
__device__ float g_k  [ (long)B_*T_*C_ ];
__device__ float g_v  [ (long)B_*T_*C_ ];
__device__ float g_w  [ (long)B_*T_*C_ ];
__device__ float g_g  [ (long)B_*T_*C_ ];
__device__ float g_y  [ (long)B_*T_*C_ ];
__device__ float g_z  [ (long)B_*T_*C_ ];
__device__ float g_lora [ (long)B_*T_*5*DMIX ];
__device__ float g_small [ (long)B_*T_*64 ];
__device__ float g_small2[ (long)B_*T_*64 ];
__device__ float g_D  [ (long)NCHUNK*64*64 ];
__device__ float g_Sc [ (long)NCHUNK*64*64 ];
__device__ float g_rp [ (long)NCHUNK*64*64 ];
__device__ float g_pL [ (long)NCHUNK*64 ];
__device__ float g_WrT[ (long)C_*C_ ];
__device__ float g_WkT[ (long)C_*C_ ];
__device__ float g_WvT[ (long)C_*C_ ];
__device__ float g_WoT[ (long)C_*C_ ];
__device__ float g_w1T[ (long)160*C_ ];
__device__ float g_w2T[ (long)C_*160 ];
__device__ float g_dw1T[ (long)64*C_ ];
__device__ float g_gw1T[ (long)64*C_ ];
__device__ float g_dw2T[ (long)C_*64 ];
__device__ float g_gw2T[ (long)C_*64 ];

// ================= helpers ====================================================
#define TSTR 20
#define STAGES 4

__device__ __forceinline__ uint32_t f2tf32(float f) {
    uint32_t o;
    asm("cvt.rna.tf32.f32 %0, %1;" : "=r"(o) : "f"(f));
    return o;
}
__device__ __forceinline__ float rndt(float f) {
    return __uint_as_float(f2tf32(f));
}
__device__ __forceinline__ uint32_t smem_u32(const void* p) {
    uint32_t a;
    asm("{ .reg .u64 t; cvta.to.shared.u64 t, %1; cvt.u32.u64 %0, t; }"
        : "=r"(a) : "l"(p));
    return a;
}
#define CP_A16(dst, src) \
    asm volatile("cp.async.cg.shared.global [%0], [%1], 16;" :: "r"(dst), "l"(src))
#define CP_COMMIT() asm volatile("cp.async.commit_group;" ::: "memory")
#define CP_WAIT(n)  asm volatile("cp.async.wait_group %0;" :: "n"(n) : "memory")

__device__ __forceinline__ void mma1688(float* d, const uint32_t* a, const uint32_t* b) {
    asm volatile(
        "mma.sync.aligned.m16n8k8.row.col.f32.tf32.tf32.f32 "
        "{%0,%1,%2,%3}, {%4,%5,%6,%7}, {%8,%9}, {%0,%1,%2,%3};"
        : "+f"(d[0]), "+f"(d[1]), "+f"(d[2]), "+f"(d[3])
        : "r"(a[0]), "r"(a[1]), "r"(a[2]), "r"(a[3]), "r"(b[0]), "r"(b[1]));
}

// ---- 128x128 body: 128 threads, 4 warps (2x2), warp tile 64x64, cp.async -----
// Inputs MUST be pre-rounded tf32. EPI: 0 none, 1 tanh, 2 -exp(acc+bias),
// 3 xin+xxin*(bias+acc), -2 runtime repi (0/1/2). rrnd: runtime output rounding.
template<int EPI, bool RND>
__device__ __forceinline__ void gemm128_body(
    uint32_t* dynsm,
    const float* __restrict__ A, int lda,
    const float* __restrict__ Bt, int ldb,
    float* __restrict__ Cm, int ldc,
    int K, int Nn, const float* __restrict__ bias,
    const float* __restrict__ xin, const float* __restrict__ xxin,
    int row0, int col0, int repi, bool rrnd)
{
    const int tid = threadIdx.x;
    const int lane = tid & 31;
    const int wid = tid >> 5;
    const int wr = wid >> 1;
    const int wc = wid & 1;

    uint32_t* As = dynsm;
    uint32_t* Bs = dynsm + STAGES * 128 * TSTR;
    const uint32_t as0 = smem_u32(As);
    const uint32_t bs0 = smem_u32(Bs);

    auto issueStage = [&](int kc, int buf) {
        const int k0 = kc * 16;
        const uint32_t ao = as0 + buf * (128 * TSTR * 4);
        const uint32_t bo = bs0 + buf * (128 * TSTR * 4);
        #pragma unroll
        for (int l = 0; l < 4; l++) {
            int e = tid + (l << 7);
            int r = e >> 2, c = e & 3;
            uint32_t so = (uint32_t)(r * TSTR + (c << 2)) * 4u;
            CP_A16(ao + so, &A[(long)(row0 + r) * lda + k0 + (c << 2)]);
            CP_A16(bo + so, &Bt[(long)(col0 + r) * ldb + k0 + (c << 2)]);
        }
        CP_COMMIT();
    };

    float acc[4][8][4];
    #pragma unroll
    for (int mi = 0; mi < 4; mi++)
        #pragma unroll
        for (int ni = 0; ni < 8; ni++)
            #pragma unroll
            for (int e = 0; e < 4; e++) acc[mi][ni][e] = 0.f;

    const int NKT = K >> 4;
    issueStage(0, 0);
    if (NKT > 1) issueStage(1, 1);
    if (NKT > 2) issueStage(2, 2);

    const int lg = lane >> 2;
    const int lt = lane & 3;

    uint32_t af[2][4][4], bf[2][8][2];

    auto loadFrag = [&](const uint32_t* Ab, const uint32_t* Bb, int ks, int fb) {
        const int k0 = (ks << 3) + lt;
        #pragma unroll
        for (int mi = 0; mi < 4; mi++) {
            int rm = wr * 64 + mi * 16 + lg;
            af[fb][mi][0] = Ab[rm * TSTR + k0];
            af[fb][mi][1] = Ab[(rm + 8) * TSTR + k0];
            af[fb][mi][2] = Ab[rm * TSTR + k0 + 4];
            af[fb][mi][3] = Ab[(rm + 8) * TSTR + k0 + 4];
        }
        #pragma unroll
        for (int ni = 0; ni < 8; ni++) {
            int cn = wc * 64 + ni * 8 + lg;
            bf[fb][ni][0] = Bb[cn * TSTR + k0];
            bf[fb][ni][1] = Bb[cn * TSTR + k0 + 4];
        }
    };

    for (int kc = 0; kc < NKT; kc++) {
        const int buf = kc & 3;
        if (kc + 3 < NKT)      { CP_WAIT(2); }
        else if (kc + 2 < NKT) { CP_WAIT(1); }
        else                   { CP_WAIT(0); }
        __syncthreads();

        const uint32_t* Ab = As + buf * 128 * TSTR;
        const uint32_t* Bb = Bs + buf * 128 * TSTR;

        loadFrag(Ab, Bb, 0, 0);
        // prefetch ks=1 fragments, then run ks=0 MMAs (loads overlap MMA burst)
        loadFrag(Ab, Bb, 1, 1);
        #pragma unroll
        for (int mi = 0; mi < 4; mi++)
            #pragma unroll
            for (int ni = 0; ni < 8; ni++)
                mma1688(acc[mi][ni], af[0][mi], bf[0][ni]);
        #pragma unroll
        for (int mi = 0; mi < 4; mi++)
            #pragma unroll
            for (int ni = 0; ni < 8; ni++)
                mma1688(acc[mi][ni], af[1][mi], bf[1][ni]);

        if (kc + 3 < NKT) issueStage(kc + 3, (kc + 3) & 3);
    }

    const int ep = (EPI == -2) ? repi : EPI;
    #pragma unroll
    for (int mi = 0; mi < 4; mi++) {
        int gr0 = row0 + wr * 64 + mi * 16 + lg;
        #pragma unroll
        for (int ni = 0; ni < 8; ni++) {
            int gc = col0 + wc * 64 + ni * 8 + 2 * lt;
            if (gc < Nn) {
                float v0 = acc[mi][ni][0], v1 = acc[mi][ni][1];
                float v2 = acc[mi][ni][2], v3 = acc[mi][ni][3];
                long o0 = (long)gr0 * ldc + gc;
                long o1 = (long)(gr0 + 8) * ldc + gc;
                if (ep == 1) {
                    v0 = tanhf(v0); v1 = tanhf(v1); v2 = tanhf(v2); v3 = tanhf(v3);
                } else if (ep == 2) {
                    float b0 = bias[gc], b1 = bias[gc + 1];
                    v0 = -expf(v0 + b0); v1 = -expf(v1 + b1);
                    v2 = -expf(v2 + b0); v3 = -expf(v3 + b1);
                } else if (ep == 3) {
                    float b0 = bias[gc], b1 = bias[gc + 1];
                    float2 x0 = *(const float2*)&xin[o0];
                    float2 x1 = *(const float2*)&xin[o1];
                    float2 d0 = *(const float2*)&xxin[o0];
                    float2 d1 = *(const float2*)&xxin[o1];
                    v0 = fmaf(d0.x, b0 + v0, x0.x);
                    v1 = fmaf(d0.y, b1 + v1, x0.y);
                    v2 = fmaf(d1.x, b0 + v2, x1.x);
                    v3 = fmaf(d1.y, b1 + v3, x1.y);
                }
                if (RND || rrnd) {
                    v0 = rndt(v0); v1 = rndt(v1); v2 = rndt(v2); v3 = rndt(v3);
                }
                *(float2*)&Cm[o0] = make_float2(v0, v1);
                *(float2*)&Cm[o1] = make_float2(v2, v3);
            }
        }
    }
}

#define SMEM_G (STAGES * 128 * TSTR * 4 * 2)   // 81920 bytes

template<int EPI, bool RND>
__global__ __launch_bounds__(128, 2) void gemm_tc(
    const float* __restrict__ A, int lda,
    const float* __restrict__ Bt, int ldb,
    float* __restrict__ Cm, int ldc,
    int K, int Nn, const float* __restrict__ bias)
{
    extern __shared__ uint32_t dynsm[];
    gemm128_body<EPI, RND>(dynsm, A, lda, Bt, ldb, Cm, ldc, K, Nn, bias,
                           nullptr, nullptr, blockIdx.y * 128, blockIdx.x * 128,
                           0, false);
}

// merged r,k,v projections + decay1 + gate1: z selects (z=3,4 are N=64 LoRA)
__global__ __launch_bounds__(128, 2) void gemm_rkv(
    const float* xr, const float* xk, const float* xv,
    const float* xw, const float* xg,
    const float* WrT, const float* WkT, const float* WvT,
    const float* dw1T, const float* gw1T,
    float* r, float* k, float* v, float* s1, float* s2)
{
    extern __shared__ uint32_t dynsm[];
    const int z = blockIdx.z;
    const int col0 = blockIdx.x * 128;
    const float* A;
    const float* Bt;
    float* Cm;
    int Nn, ldc, repi;
    bool rr;
    if (z < 3) {
        A  = (z == 0) ? xr : (z == 1) ? xk : xv;
        Bt = (z == 0) ? WrT : (z == 1) ? WkT : WvT;
        Cm = (z == 0) ? r : (z == 1) ? k : v;
        Nn = C_; ldc = C_; repi = 0; rr = false;
    } else {
        A  = (z == 3) ? xw : xg;
        Bt = (z == 3) ? dw1T : gw1T;
        Cm = (z == 3) ? s1 : s2;
        Nn = 64; ldc = 64; repi = 1; rr = true;
        if (col0 >= 64) return;
    }
    gemm128_body<-2, false>(dynsm, A, C_, Bt, C_, Cm, ldc, C_, Nn, nullptr,
                            nullptr, nullptr, blockIdx.y * 128, col0, repi, rr);
}

__global__ __launch_bounds__(128, 2) void gemm_dg2(
    const float* small1, const float* small2,
    const float* dw2T, const float* gw2T,
    float* w, float* g, const float* time_decay)
{
    extern __shared__ uint32_t dynsm[];
    const int z = blockIdx.z;
    gemm128_body<-2, false>(dynsm, (z == 0) ? small1 : small2, 64,
                            (z == 0) ? dw2T : gw2T, 64,
                            (z == 0) ? w : g, C_, 64, C_, time_decay,
                            nullptr, nullptr, blockIdx.y * 128, blockIdx.x * 128,
                            (z == 0) ? 2 : 0, false);
}

__global__ __launch_bounds__(128, 2) void gemm_mix(
    const float* __restrict__ lora, const float* __restrict__ w2T,
    const float* __restrict__ x, const float* __restrict__ xx,
    const float* m0, const float* m1, const float* m2, const float* m3, const float* m4,
    float* o0, float* o1, float* o2, float* o3, float* o4)
{
    extern __shared__ uint32_t dynsm[];
    const int z = blockIdx.z;
    const float* bias = (z == 0) ? m0 : (z == 1) ? m1 : (z == 2) ? m2 : (z == 3) ? m3 : m4;
    float* out = (z == 0) ? o0 : (z == 1) ? o1 : (z == 2) ? o2 : (z == 3) ? o3 : o4;
    gemm128_body<3, true>(dynsm, lora + z * DMIX, 160, w2T + z * DMIX, 160,
                          out, C_, DMIX, C_, bias, x, xx,
                          blockIdx.y * 128, blockIdx.x * 128, 0, false);
}

// ---- small tile: BM=64, BN=64, 128 threads (classic path) --------------------
template<int EPI, bool RND>
__device__ __forceinline__ void gemm64_body(
    uint32_t (*As)[64 * TSTR], uint32_t (*Bs)[64 * TSTR],
    const float* __restrict__ A, int lda,
    const float* __restrict__ Bt, int ldb,
    float* __restrict__ Cm, int ldc,
    int K, int Nn, const float* __restrict__ bias,
    int row0, int col0)
{
    const int tid = threadIdx.x;
    const int lane = tid & 31;
    const int wid = tid >> 5;
    const int wr = wid >> 1;
    const int wc = wid & 1;

    float4 ra[2], rb[2];

    auto loadAB = [&](int kc) {
        const int k0 = kc * 16;
        #pragma unroll
        for (int l = 0; l < 2; l++) {
            int e = tid + (l << 7);
            int r = e >> 2, c = e & 3;
            ra[l] = *(const float4*)&A[(long)(row0 + r) * lda + k0 + (c << 2)];
            int br = col0 + r;
            if (br < Nn)
                rb[l] = *(const float4*)&Bt[(long)br * ldb + k0 + (c << 2)];
            else
                rb[l] = make_float4(0.f, 0.f, 0.f, 0.f);
        }
    };
    auto storeAB = [&](int buf) {
        #pragma unroll
        for (int l = 0; l < 2; l++) {
            int e = tid + (l << 7);
            int r = e >> 2, c = e & 3;
            uint32_t* ap = &As[buf][r * TSTR + (c << 2)];
            ap[0] = f2tf32(ra[l].x); ap[1] = f2tf32(ra[l].y);
            ap[2] = f2tf32(ra[l].z); ap[3] = f2tf32(ra[l].w);
            uint32_t* bp = &Bs[buf][r * TSTR + (c << 2)];
            bp[0] = f2tf32(rb[l].x); bp[1] = f2tf32(rb[l].y);
            bp[2] = f2tf32(rb[l].z); bp[3] = f2tf32(rb[l].w);
        }
    };

    float acc[2][4][4];
    #pragma unroll
    for (int mi = 0; mi < 2; mi++)
        #pragma unroll
        for (int ni = 0; ni < 4; ni++)
            #pragma unroll
            for (int e = 0; e < 4; e++) acc[mi][ni][e] = 0.f;

    const int NKT = K >> 4;
    loadAB(0);
    storeAB(0);
    __syncthreads();

    const int lg = lane >> 2;
    const int lt = lane & 3;

    for (int kc = 0; kc < NKT; kc++) {
        const int cur = kc & 1;
        if (kc + 1 < NKT) loadAB(kc + 1);

        #pragma unroll
        for (int ks = 0; ks < 2; ks++) {
            const int k0 = (ks << 3) + lt;
            uint32_t af[2][4], bf[4][2];
            #pragma unroll
            for (int mi = 0; mi < 2; mi++) {
                int rm = wr * 32 + mi * 16 + lg;
                af[mi][0] = As[cur][rm * TSTR + k0];
                af[mi][1] = As[cur][(rm + 8) * TSTR + k0];
                af[mi][2] = As[cur][rm * TSTR + k0 + 4];
                af[mi][3] = As[cur][(rm + 8) * TSTR + k0 + 4];
            }
            #pragma unroll
            for (int ni = 0; ni < 4; ni++) {
                int cn = wc * 32 + ni * 8 + lg;
                bf[ni][0] = Bs[cur][cn * TSTR + k0];
                bf[ni][1] = Bs[cur][cn * TSTR + k0 + 4];
            }
            #pragma unroll
            for (int mi = 0; mi < 2; mi++)
                #pragma unroll
                for (int ni = 0; ni < 4; ni++)
                    mma1688(acc[mi][ni], af[mi], bf[ni]);
        }

        if (kc + 1 < NKT) storeAB(cur ^ 1);
        __syncthreads();
    }

    #pragma unroll
    for (int mi = 0; mi < 2; mi++) {
        int gr0 = row0 + wr * 32 + mi * 16 + lg;
        #pragma unroll
        for (int ni = 0; ni < 4; ni++) {
            int gc = col0 + wc * 32 + ni * 8 + 2 * lt;
            if (gc < Nn) {
                float v0 = acc[mi][ni][0], v1 = acc[mi][ni][1];
                float v2 = acc[mi][ni][2], v3 = acc[mi][ni][3];
                if (EPI == 1) {
                    v0 = tanhf(v0); v1 = tanhf(v1); v2 = tanhf(v2); v3 = tanhf(v3);
                }
                if (RND) {
                    v0 = rndt(v0); v1 = rndt(v1); v2 = rndt(v2); v3 = rndt(v3);
                }
                *(float2*)&Cm[(long)gr0 * ldc + gc] = make_float2(v0, v1);
                *(float2*)&Cm[(long)(gr0 + 8) * ldc + gc] = make_float2(v2, v3);
            }
        }
    }
}

template<int EPI, bool RND>
__global__ __launch_bounds__(128, 3) void gemm_tc64(
    const float* __restrict__ A, int lda,
    const float* __restrict__ Bt, int ldb,
    float* __restrict__ Cm, int ldc,
    int K, int Nn, const float* __restrict__ bias)
{
    __shared__ uint32_t As[2][64 * TSTR];
    __shared__ uint32_t Bs[2][64 * TSTR];
    gemm64_body<EPI, RND>(As, Bs, A, lda, Bt, ldb, Cm, ldc, K, Nn, bias,
                          blockIdx.y * 64, blockIdx.x * 64);
}

// ---------------- fused pre-pass: shift + all weight transposes --------------
struct TJob { const float* src; float* dst; int R, N, nbx, boff; };
struct TJobs { TJob j[10]; };

__global__ __launch_bounds__(256) void pre_kernel(
    const float4* __restrict__ x4, const float* __restrict__ maa_x,
    float4* __restrict__ xx4, float4* __restrict__ xxx4,
    TJobs js, int nshift)
{
    const int tid = threadIdx.x;
    if ((int)blockIdx.x < nshift) {
        long idx = (long)blockIdx.x * 256 + tid;
        const int C4 = C_ / 4;
        int c4 = (int)(idx % C4);
        long rt = idx / C4;
        int t = (int)(rt % T_);
        float4 xv = x4[idx];
        float4 xp = (t > 0) ? x4[idx - C4] : make_float4(0.f, 0.f, 0.f, 0.f);
        float4 mx = *(const float4*)&maa_x[c4 * 4];
        float4 d = make_float4(xp.x - xv.x, xp.y - xv.y, xp.z - xv.z, xp.w - xv.w);
        xx4[idx] = d;
        xxx4[idx] = make_float4(rndt(fmaf(d.x, mx.x, xv.x)), rndt(fmaf(d.y, mx.y, xv.y)),
                                rndt(fmaf(d.z, mx.z, xv.z)), rndt(fmaf(d.w, mx.w, xv.w)));
        return;
    }
    __shared__ float t[32][33];
    int b = blockIdx.x - nshift;
    int ji = 0;
    #pragma unroll
    for (int q = 1; q < 10; q++)
        if (b >= js.j[q].boff) ji = q;
    TJob jb = js.j[ji];
    int rem = b - jb.boff;
    int bx = (rem % jb.nbx) * 32;
    int by = (rem / jb.nbx) * 32;
    const int xq = tid & 31, yq = tid >> 5;
    #pragma unroll
    for (int i = 0; i < 32; i += 8) {
        int r = by + yq + i, n = bx + xq;
        if (r < jb.R && n < jb.N) t[yq + i][xq] = jb.src[(long)r * jb.N + n];
    }
    __syncthreads();
    #pragma unroll
    for (int i = 0; i < 32; i += 8) {
        int n = bx + yq + i, r = by + xq;
        if (n < jb.N && r < jb.R) jb.dst[(long)n * jb.R + r] = rndt(t[xq][yq + i]);
    }
}

// ---------------- chunked WKV6 -----------------------------------------------
__global__ __launch_bounds__(256) void wkv_chunkA(
    const float* __restrict__ r, const float* __restrict__ k,
    const float* __restrict__ v, const float* __restrict__ lw,
    const float* __restrict__ u,
    float* __restrict__ y, float* __restrict__ Dout,
    float* __restrict__ rpout, float* __restrict__ pLout)
{
    extern __shared__ float sm[];
    float* lp   = sm;
    float* bufA = lp + 65 * 64;
    float* rpT  = bufA + 64 * STRD;
    float* kpT  = rpT + 64 * STRD;
    float* kpp  = kpT + 64 * STRD;
    float* vsm  = kpp + 64 * STRD;
    float* dsm  = vsm + 64 * STRD;
    float* usm  = dsm + 64;

    const int tid = threadIdx.x;
    const int chunk = blockIdx.x;
    const int bh = chunk >> 5;
    const int c  = chunk & 31;
    const int b = bh >> 4, h = bh & 15;
    const long base = ((long)b * T_ + c * CHUNK) * C_ + h * 64;

    if (tid < 64) usm[tid] = u[h * 64 + tid];
    const int i  = tid & 63;
    const int tq = tid >> 6;

    #pragma unroll
    for (int e = 0; e < 16; e++) {
        int t = tq + 4 * e;
        bufA[t * STRD + i] = lw[base + (long)t * C_ + i];
    }
    __syncthreads();

    if (tid < 64) {
        float run = 0.f;
        for (int t = 0; t < 64; t++) {
            lp[t * 64 + tid] = run;
            run += bufA[t * STRD + tid];
        }
        lp[64 * 64 + tid] = run;
        pLout[(long)chunk * 64 + tid] = run;
    }
    __syncthreads();

    #pragma unroll
    for (int e = 0; e < 16; e++) {
        int t = tq + 4 * e;
        long gi = base + (long)t * C_ + i;
        float rr = r[gi], kk = k[gi];
        float lpti = lp[t * 64 + i];
        float lpn  = lpti + bufA[t * STRD + i];
        float lpL  = lp[64 * 64 + i];
        rpT[i * STRD + t] = rr * __expf(lpti);
        kpT[i * STRD + t] = kk * __expf(-lpn);
        kpp[t * STRD + i] = kk * __expf(lpL - lpn);
        vsm[t * STRD + i] = v[gi];
    }
    {
        int t = tid >> 2, q = tid & 3;
        long gb = base + (long)t * C_;
        float p = 0.f;
        #pragma unroll
        for (int ii = 0; ii < 16; ii++) {
            int ci = q * 16 + ii;
            p += r[gb + ci] * usm[ci] * k[gb + ci];
        }
        p += __shfl_xor_sync(0xffffffffu, p, 1);
        p += __shfl_xor_sync(0xffffffffu, p, 2);
        if (q == 0) dsm[t] = p;
    }
    __syncthreads();

    {
        float* rpg = rpout + (long)chunk * 64 * 64;
        #pragma unroll
        for (int e = 0; e < 16; e++) {
            int flat = tid + 256 * e;
            rpg[flat] = rpT[(flat >> 6) * STRD + (flat & 63)];
        }
    }

    {
        int t0 = (tid >> 4) * 4, s0 = (tid & 15) * 4;
        float acc[4][4];
        #pragma unroll
        for (int a = 0; a < 4; a++)
            #pragma unroll
            for (int bq = 0; bq < 4; bq++) acc[a][bq] = 0.f;
        for (int ii = 0; ii < 64; ii++) {
            float4 a4 = *(const float4*)&rpT[ii * STRD + t0];
            float4 b4 = *(const float4*)&kpT[ii * STRD + s0];
            float av[4] = { a4.x, a4.y, a4.z, a4.w };
            float bv[4] = { b4.x, b4.y, b4.z, b4.w };
            #pragma unroll
            for (int a = 0; a < 4; a++)
                #pragma unroll
                for (int bq = 0; bq < 4; bq++)
                    acc[a][bq] = fmaf(av[a], bv[bq], acc[a][bq]);
        }
        __syncthreads();
        #pragma unroll
        for (int a = 0; a < 4; a++)
            #pragma unroll
            for (int bq = 0; bq < 4; bq++) {
                int tt = t0 + a, ss = s0 + bq;
                float val = (tt > ss) ? acc[a][bq] : ((tt == ss) ? dsm[tt] : 0.f);
                bufA[ss * STRD + tt] = val;
            }
    }
    __syncthreads();

    {
        int t0 = (tid >> 4) * 4, j0 = (tid & 15) * 4;
        float acc[4][4];
        #pragma unroll
        for (int a = 0; a < 4; a++)
            #pragma unroll
            for (int bq = 0; bq < 4; bq++) acc[a][bq] = 0.f;
        for (int s = 0; s < 64; s++) {
            float4 a4 = *(const float4*)&bufA[s * STRD + t0];
            float4 b4 = *(const float4*)&vsm[s * STRD + j0];
            float av[4] = { a4.x, a4.y, a4.z, a4.w };
            float bv[4] = { b4.x, b4.y, b4.z, b4.w };
            #pragma unroll
            for (int a = 0; a < 4; a++)
                #pragma unroll
                for (int bq = 0; bq < 4; bq++)
                    acc[a][bq] = fmaf(av[a], bv[bq], acc[a][bq]);
        }
        #pragma unroll
        for (int a = 0; a < 4; a++) {
            float4 o = make_float4(acc[a][0], acc[a][1], acc[a][2], acc[a][3]);
            *(float4*)&y[base + (long)(t0 + a) * C_ + j0] = o;
        }
    }

    {
        int i0 = (tid >> 4) * 4, j0 = (tid & 15) * 4;
        float acc[4][4];
        #pragma unroll
        for (int a = 0; a < 4; a++)
            #pragma unroll
            for (int bq = 0; bq < 4; bq++) acc[a][bq] = 0.f;
        for (int s = 0; s < 64; s++) {
            float4 a4 = *(const float4*)&kpp[s * STRD + i0];
            float4 b4 = *(const float4*)&vsm[s * STRD + j0];
            float av[4] = { a4.x, a4.y, a4.z, a4.w };
            float bv[4] = { b4.x, b4.y, b4.z, b4.w };
            #pragma unroll
            for (int a = 0; a < 4; a++)
                #pragma unroll
                for (int bq = 0; bq < 4; bq++)
                    acc[a][bq] = fmaf(av[a], bv[bq], acc[a][bq]);
        }
        float* Dp = Dout + (long)chunk * 4096;
        #pragma unroll
        for (int a = 0; a < 4; a++) {
            float4 o = make_float4(acc[a][0], acc[a][1], acc[a][2], acc[a][3]);
            *(float4*)&Dp[(i0 + a) * 64 + j0] = o;
        }
    }
}

__global__ __launch_bounds__(256) void wkv_chunkB(
    const float* __restrict__ D, const float* __restrict__ pL,
    float* __restrict__ S)
{
    const int bh = blockIdx.x;
    const int tid = threadIdx.x;
    const int i = tid >> 2;
    const int jb = (tid & 3) * 16;
    float4 s0 = {0,0,0,0}, s1 = {0,0,0,0}, s2 = {0,0,0,0}, s3 = {0,0,0,0};
    for (int c = 0; c < G_; c++) {
        long chunk = (long)bh * G_ + c;
        long off = chunk * 4096 + i * 64 + jb;
        *(float4*)&S[off + 0]  = s0;
        *(float4*)&S[off + 4]  = s1;
        *(float4*)&S[off + 8]  = s2;
        *(float4*)&S[off + 12] = s3;
        float pl = __expf(pL[chunk * 64 + i]);
        float4 d0 = *(const float4*)&D[off + 0];
        float4 d1 = *(const float4*)&D[off + 4];
        float4 d2 = *(const float4*)&D[off + 8];
        float4 d3 = *(const float4*)&D[off + 12];
        s0 = make_float4(fmaf(pl, s0.x, d0.x), fmaf(pl, s0.y, d0.y), fmaf(pl, s0.z, d0.z), fmaf(pl, s0.w, d0.w));
        s1 = make_float4(fmaf(pl, s1.x, d1.x), fmaf(pl, s1.y, d1.y), fmaf(pl, s1.z, d1.z), fmaf(pl, s1.w, d1.w));
        s2 = make_float4(fmaf(pl, s2.x, d2.x), fmaf(pl, s2.y, d2.y), fmaf(pl, s2.z, d2.z), fmaf(pl, s2.w, d2.w));
        s3 = make_float4(fmaf(pl, s3.x, d3.x), fmaf(pl, s3.y, d3.y), fmaf(pl, s3.z, d3.z), fmaf(pl, s3.w, d3.w));
    }
}

__global__ __launch_bounds__(256) void wkv_chunkC(
    const float* __restrict__ rp, const float* __restrict__ S,
    float* __restrict__ y)
{
    __shared__ float rps[64 * 64];
    __shared__ float Ss[64 * 64];
    const int tid = threadIdx.x;
    const int chunk = blockIdx.x;
    const int bh = chunk >> 5;
    const int c  = chunk & 31;
    const int b = bh >> 4, h = bh & 15;
    const long base = ((long)b * T_ + c * CHUNK) * C_ + h * 64;

    const float* rpg = rp + (long)chunk * 4096;
    const float* Sg  = S  + (long)chunk * 4096;
    #pragma unroll
    for (int e = 0; e < 4; e++) {
        int f4 = tid + 256 * e;
        *(float4*)&rps[f4 * 4] = *(const float4*)&rpg[f4 * 4];
        *(float4*)&Ss[f4 * 4]  = *(const float4*)&Sg[f4 * 4];
    }
    __syncthreads();

    int t0 = (tid >> 4) * 4, j0 = (tid & 15) * 4;
    float acc[4][4];
    #pragma unroll
    for (int a = 0; a < 4; a++)
        #pragma unroll
        for (int bq = 0; bq < 4; bq++) acc[a][bq] = 0.f;
    for (int ii = 0; ii < 64; ii++) {
        float4 a4 = *(const float4*)&rps[ii * 64 + t0];
        float4 b4 = *(const float4*)&Ss[ii * 64 + j0];
        float av[4] = { a4.x, a4.y, a4.z, a4.w };
        float bv[4] = { b4.x, b4.y, b4.z, b4.w };
        #pragma unroll
        for (int a = 0; a < 4; a++)
            #pragma unroll
            for (int bq = 0; bq < 4; bq++)
                acc[a][bq] = fmaf(av[a], bv[bq], acc[a][bq]);
    }
    #pragma unroll
    for (int a = 0; a < 4; a++) {
        long yo = base + (long)(t0 + a) * C_ + j0;
        float4 cur = *(const float4*)&y[yo];
        cur.x += acc[a][0]; cur.y += acc[a][1];
        cur.z += acc[a][2]; cur.w += acc[a][3];
        *(float4*)&y[yo] = cur;
    }
}

// ---------------- GroupNorm over heads + gate multiply (z tf32-rounded) ------
__global__ __launch_bounds__(512) void gn_kernel(
    const float* __restrict__ y, const float* __restrict__ ln_g,
    const float* __restrict__ ln_b, const float* __restrict__ g,
    float* __restrict__ z)
{
    const int bt = blockIdx.x;
    const int warp = threadIdx.x >> 5;
    const int lane = threadIdx.x & 31;
    const long base = (long)bt * C_ + warp * 64;

    float a0 = y[base + lane];
    float a1 = y[base + 32 + lane];
    float sum = a0 + a1;
    float sq = a0 * a0 + a1 * a1;
    #pragma unroll
    for (int off = 16; off > 0; off >>= 1) {
        sum += __shfl_xor_sync(0xffffffffu, sum, off);
        sq  += __shfl_xor_sync(0xffffffffu, sq,  off);
    }
    float mu = sum * (1.f / 64.f);
    float var = sq * (1.f / 64.f) - mu * mu;
    float inv = rsqrtf(var + 6.4e-4f);

    int c0 = warp * 64 + lane;
    float z0 = (a0 - mu) * inv * ln_g[c0] + ln_b[c0];
    float z1 = (a1 - mu) * inv * ln_g[c0 + 32] + ln_b[c0 + 32];
    z[base + lane]      = rndt(z0 * g[base + lane]);
    z[base + 32 + lane] = rndt(z1 * g[base + 32 + lane]);
}

// ---------------- launcher ----------------------------------------------------
extern "C" void kernel_launch(void* const* d_in, const int* in_sizes, int n_in,
                              void* d_out, int out_size)
{
    const float* x          = (const float*)d_in[0];
    const float* maa_x      = (const float*)d_in[1];
    const float* maa_w      = (const float*)d_in[2];
    const float* maa_k      = (const float*)d_in[3];
    const float* maa_v      = (const float*)d_in[4];
    const float* maa_r      = (const float*)d_in[5];
    const float* maa_g      = (const float*)d_in[6];
    const float* maa_w1     = (const float*)d_in[7];
    const float* maa_w2     = (const float*)d_in[8];
    const float* Wr         = (const float*)d_in[9];
    const float* Wk         = (const float*)d_in[10];
    const float* Wv         = (const float*)d_in[11];
    const float* Wo         = (const float*)d_in[12];
    const float* gate_w1    = (const float*)d_in[13];
    const float* gate_w2    = (const float*)d_in[14];
    const float* time_decay = (const float*)d_in[15];
    const float* decay_w1   = (const float*)d_in[16];
    const float* decay_w2   = (const float*)d_in[17];
    const float* u          = (const float*)d_in[18];
    const float* ln_g       = (const float*)d_in[19];
    const float* ln_b       = (const float*)d_in[20];
    (void)in_sizes; (void)n_in; (void)out_size;

    float *p_xx, *p_xxx, *p_xw, *p_xk, *p_xv, *p_xr, *p_xg;
    float *p_r, *p_k, *p_v, *p_w, *p_g, *p_y, *p_z, *p_lora, *p_s1, *p_s2;
    float *p_D, *p_Sc, *p_rp, *p_pL;
    float *p_WrT, *p_WkT, *p_WvT, *p_WoT, *p_w1T, *p_w2T, *p_dw1T, *p_gw1T, *p_dw2T, *p_gw2T;
    cudaGetSymbolAddress((void**)&p_xx, g_xx);
    cudaGetSymbolAddress((void**)&p_xxx, g_xxx);
    cudaGetSymbolAddress((void**)&p_xw, g_xw);
    cudaGetSymbolAddress((void**)&p_xk, g_xk);
    cudaGetSymbolAddress((void**)&p_xv, g_xv);
    cudaGetSymbolAddress((void**)&p_xr, g_xr);
    cudaGetSymbolAddress((void**)&p_xg, g_xg);
    cudaGetSymbolAddress((void**)&p_r, g_r);
    cudaGetSymbolAddress((void**)&p_k, g_k);
    cudaGetSymbolAddress((void**)&p_v, g_v);
    cudaGetSymbolAddress((void**)&p_w, g_w);
    cudaGetSymbolAddress((void**)&p_g, g_g);
    cudaGetSymbolAddress((void**)&p_y, g_y);
    cudaGetSymbolAddress((void**)&p_z, g_z);
    cudaGetSymbolAddress((void**)&p_lora, g_lora);
    cudaGetSymbolAddress((void**)&p_s1, g_small);
    cudaGetSymbolAddress((void**)&p_s2, g_small2);
    cudaGetSymbolAddress((void**)&p_D, g_D);
    cudaGetSymbolAddress((void**)&p_Sc, g_Sc);
    cudaGetSymbolAddress((void**)&p_rp, g_rp);
    cudaGetSymbolAddress((void**)&p_pL, g_pL);
    cudaGetSymbolAddress((void**)&p_WrT, g_WrT);
    cudaGetSymbolAddress((void**)&p_WkT, g_WkT);
    cudaGetSymbolAddress((void**)&p_WvT, g_WvT);
    cudaGetSymbolAddress((void**)&p_WoT, g_WoT);
    cudaGetSymbolAddress((void**)&p_w1T, g_w1T);
    cudaGetSymbolAddress((void**)&p_w2T, g_w2T);
    cudaGetSymbolAddress((void**)&p_dw1T, g_dw1T);
    cudaGetSymbolAddress((void**)&p_gw1T, g_gw1T);
    cudaGetSymbolAddress((void**)&p_dw2T, g_dw2T);
    cudaGetSymbolAddress((void**)&p_gw2T, g_gw2T);

    const long total = BTC;
    const int M = B_ * T_;          // 8192
    const int gy = M / 128;         // 64
    const int gy64 = M / 64;        // 128

    const int SMEM_A = (65 * 64 + 5 * 64 * STRD + 128) * 4;
    cudaFuncSetAttribute(wkv_chunkA, cudaFuncAttributeMaxDynamicSharedMemorySize, SMEM_A);
    cudaFuncSetAttribute(gemm_rkv, cudaFuncAttributeMaxDynamicSharedMemorySize, SMEM_G);
    cudaFuncSetAttribute(gemm_mix, cudaFuncAttributeMaxDynamicSharedMemorySize, SMEM_G);
    cudaFuncSetAttribute(gemm_dg2, cudaFuncAttributeMaxDynamicSharedMemorySize, SMEM_G);
    cudaFuncSetAttribute((const void*)gemm_tc<0, false>,
                         cudaFuncAttributeMaxDynamicSharedMemorySize, SMEM_G);

    // transpose job table
    TJobs tj;
    int toff = 0;
    {
        const float* srcs[10] = { maa_w1, maa_w2, Wr, Wk, Wv, Wo,
                                  decay_w1, gate_w1, decay_w2, gate_w2 };
        float* dsts[10] = { p_w1T, p_w2T, p_WrT, p_WkT, p_WvT, p_WoT,
                            p_dw1T, p_gw1T, p_dw2T, p_gw2T };
        int Rs[10] = { 1024, 160, 1024, 1024, 1024, 1024, 1024, 1024, 64, 64 };
        int Ns[10] = { 160, 1024, 1024, 1024, 1024, 1024, 64, 64, 1024, 1024 };
        for (int q = 0; q < 10; q++) {
            int nbx = (Ns[q] + 31) / 32;
            int nby = (Rs[q] + 31) / 32;
            tj.j[q].src = srcs[q]; tj.j[q].dst = dsts[q];
            tj.j[q].R = Rs[q]; tj.j[q].N = Ns[q];
            tj.j[q].nbx = nbx; tj.j[q].boff = toff;
            toff += nbx * nby;
        }
    }
    const int nshift = (int)(total / 4 / 256);   // 8192

    // 0. fused shift + transposes (xxx + weights tf32-rounded)
    pre_kernel<<<nshift + toff, 256>>>((const float4*)x, maa_x,
        (float4*)p_xx, (float4*)p_xxx, tj, nshift);
    // 1. lora = tanh(xxx @ maa_w1), rounded
    gemm_tc64<1, true><<<dim3(3, gy64), 128>>>(p_xxx, C_, p_w1T, C_, p_lora, 160, C_, 160, nullptr);
    // 2. merged 5-branch mix GEMM (outputs rounded)
    gemm_mix<<<dim3(8, gy, 5), 128, SMEM_G>>>(p_lora, p_w2T, x, p_xx,
        maa_w, maa_k, maa_v, maa_r, maa_g,
        p_xw, p_xk, p_xv, p_xr, p_xg);
    // 3. merged r,k,v + decay1 + gate1 projections  <-- profiled by ncu
    gemm_rkv<<<dim3(8, gy, 5), 128, SMEM_G>>>(p_xr, p_xk, p_xv, p_xw, p_xg,
                                              p_WrT, p_WkT, p_WvT, p_dw1T, p_gw1T,
                                              p_r, p_k, p_v, p_s1, p_s2);
    // 4. merged decay2 + gate2
    gemm_dg2<<<dim3(8, gy, 2), 128, SMEM_G>>>(p_s1, p_s2, p_dw2T, p_gw2T, p_w, p_g, time_decay);
    // 5-7. chunked WKV6
    wkv_chunkA<<<NCHUNK, 256, SMEM_A>>>(p_r, p_k, p_v, p_w, u, p_y, p_D, p_rp, p_pL);
    wkv_chunkB<<<B_ * H_, 256>>>(p_D, p_pL, p_Sc);
    wkv_chunkC<<<NCHUNK, 256>>>(p_rp, p_Sc, p_y);
    // 8. GroupNorm + gate multiply (z rounded)
    gn_kernel<<<M, 512>>>(p_y, ln_g, ln_b, p_g, p_z);
    // 9. out = z @ Wo
    gemm_tc<0, false><<<dim3(8, gy), 128, SMEM_G>>>(p_z, C_, p_WoT, C_, (float*)d_out, C_, C_, C_, nullptr);
}

// round 14
// speedup vs baseline: 1.4948x; 1.0353x over previous
#include <cuda_runtime.h>
#include <cuda_bf16.h>
#include <cstdint>
#include <math.h>

// Problem constants
#define B_  4
#define T_  2048
#define C_  1024
#define H_  16
#define N_  64
#define DMIX 32

#define CHUNK 64
#define G_ 32
#define NCHUNK (B_*H_*G_)         // 2048
#define STRD 68

static const long BTC = (long)B_ * T_ * C_;   // 8388608

// ---------------- scratch (device globals; no runtime allocation) -------------
__device__ float g_xx [ (long)B_*T_*C_ ];
__device__ float g_xxx[ (long)B_*T_*C_ ];
__device__ float g_xw [ (long)B_*T_*C_ ];
__device__ float g_xk [ (long)B_*T_*C_ ];
__device__ float g_xv [ (long)B_*T_*C_ ];
__device__ float g_xr [ (long)B_*T_*C_ ];
__device__ float g_xg [ (long)B_*T_*C_ ];
__device__ float g_r  [ (long)B_*T_*C_ ];
__device__ float g_k  [ (long)B_*T_*C_ ];
__device__ float g_v  [ (long)B_*T_*C_ ];
__device__ float g_w  [ (long)B_*T_*C_ ];
__device__ float g_g  [ (long)B_*T_*C_ ];
__device__ float g_y  [ (long)B_*T_*C_ ];
__device__ float g_z  [ (long)B_*T_*C_ ];
__device__ float g_lora [ (long)B_*T_*5*DMIX ];
__device__ float g_small [ (long)B_*T_*64 ];
__device__ float g_small2[ (long)B_*T_*64 ];
__device__ float g_D  [ (long)NCHUNK*64*64 ];
__device__ float g_Sc [ (long)NCHUNK*64*64 ];
__device__ float g_rp [ (long)NCHUNK*64*64 ];
__device__ float g_pL [ (long)NCHUNK*64 ];
__device__ float g_WrT[ (long)C_*C_ ];
__device__ float g_WkT[ (long)C_*C_ ];
__device__ float g_WvT[ (long)C_*C_ ];
__device__ float g_WoT[ (long)C_*C_ ];
__device__ float g_w1T[ (long)160*C_ ];
__device__ float g_w2T[ (long)C_*160 ];
__device__ float g_dw1T[ (long)64*C_ ];
__device__ float g_gw1T[ (long)64*C_ ];
__device__ float g_dw2T[ (long)C_*64 ];
__device__ float g_gw2T[ (long)C_*64 ];

// ================= helpers ====================================================
#define TSTR 20
#define STAGES 3

__device__ __forceinline__ uint32_t f2tf32(float f) {
    uint32_t o;
    asm("cvt.rna.tf32.f32 %0, %1;" : "=r"(o) : "f"(f));
    return o;
}
__device__ __forceinline__ float rndt(float f) {
    return __uint_as_float(f2tf32(f));
}
__device__ __forceinline__ uint32_t smem_u32(const void* p) {
    uint32_t a;
    asm("{ .reg .u64 t; cvta.to.shared.u64 t, %1; cvt.u32.u64 %0, t; }"
        : "=r"(a) : "l"(p));
    return a;
}
#define CP_A16(dst, src) \
    asm volatile("cp.async.cg.shared.global [%0], [%1], 16;" :: "r"(dst), "l"(src))
#define CP_COMMIT() asm volatile("cp.async.commit_group;" ::: "memory")
#define CP_WAIT(n)  asm volatile("cp.async.wait_group %0;" :: "n"(n) : "memory")

__device__ __forceinline__ void mma1688(float* d, const uint32_t* a, const uint32_t* b) {
    asm volatile(
        "mma.sync.aligned.m16n8k8.row.col.f32.tf32.tf32.f32 "
        "{%0,%1,%2,%3}, {%4,%5,%6,%7}, {%8,%9}, {%0,%1,%2,%3};"
        : "+f"(d[0]), "+f"(d[1]), "+f"(d[2]), "+f"(d[3])
        : "r"(a[0]), "r"(a[1]), "r"(a[2]), "r"(a[3]), "r"(b[0]), "r"(b[1]));
}

// ---- 128x128 body: 256 threads, 8 warps (2x4), warp tile 64x32, cp.async -----
// Inputs MUST be pre-rounded tf32. EPI: 0 none, 1 tanh, 2 -exp(acc+bias),
// 3 xin+xxin*(bias+acc), -2 runtime repi (0/1/2). rrnd: runtime output rounding.
template<int EPI, bool RND>
__device__ __forceinline__ void gemm128_body(
    uint32_t* dynsm,
    const float* __restrict__ A, int lda,
    const float* __restrict__ Bt, int ldb,
    float* __restrict__ Cm, int ldc,
    int K, int Nn, const float* __restrict__ bias,
    const float* __restrict__ xin, const float* __restrict__ xxin,
    int row0, int col0, int repi, bool rrnd)
{
    const int tid = threadIdx.x;       // 0..255
    const int lane = tid & 31;
    const int wid = tid >> 5;          // 0..7
    const int wr = wid >> 2;           // 0..1
    const int wc = wid & 3;            // 0..3

    uint32_t* As = dynsm;
    uint32_t* Bs = dynsm + STAGES * 128 * TSTR;
    const uint32_t as0 = smem_u32(As);
    const uint32_t bs0 = smem_u32(Bs);

    auto issueStage = [&](int kc, int buf) {
        const int k0 = kc * 16;
        const uint32_t ao = as0 + buf * (128 * TSTR * 4);
        const uint32_t bo = bs0 + buf * (128 * TSTR * 4);
        #pragma unroll
        for (int l = 0; l < 2; l++) {
            int e = tid + (l << 8);
            int r = e >> 2, c = e & 3;
            uint32_t so = (uint32_t)(r * TSTR + (c << 2)) * 4u;
            CP_A16(ao + so, &A[(long)(row0 + r) * lda + k0 + (c << 2)]);
            CP_A16(bo + so, &Bt[(long)(col0 + r) * ldb + k0 + (c << 2)]);
        }
        CP_COMMIT();
    };

    float acc[4][4][4];
    #pragma unroll
    for (int mi = 0; mi < 4; mi++)
        #pragma unroll
        for (int ni = 0; ni < 4; ni++)
            #pragma unroll
            for (int e = 0; e < 4; e++) acc[mi][ni][e] = 0.f;

    const int NKT = K >> 4;
    issueStage(0, 0);
    if (NKT > 1) issueStage(1, 1);

    const int lg = lane >> 2;
    const int lt = lane & 3;

    for (int kc = 0; kc < NKT; kc++) {
        const int buf = kc % 3;
        if (kc + 2 < NKT) { CP_WAIT(1); } else { CP_WAIT(0); }
        __syncthreads();

        const uint32_t* Ab = As + buf * 128 * TSTR;
        const uint32_t* Bb = Bs + buf * 128 * TSTR;
        #pragma unroll
        for (int ks = 0; ks < 2; ks++) {
            const int k0 = (ks << 3) + lt;
            uint32_t af[4][4], bf[4][2];
            #pragma unroll
            for (int mi = 0; mi < 4; mi++) {
                int rm = wr * 64 + mi * 16 + lg;
                af[mi][0] = Ab[rm * TSTR + k0];
                af[mi][1] = Ab[(rm + 8) * TSTR + k0];
                af[mi][2] = Ab[rm * TSTR + k0 + 4];
                af[mi][3] = Ab[(rm + 8) * TSTR + k0 + 4];
            }
            #pragma unroll
            for (int ni = 0; ni < 4; ni++) {
                int cn = wc * 32 + ni * 8 + lg;
                bf[ni][0] = Bb[cn * TSTR + k0];
                bf[ni][1] = Bb[cn * TSTR + k0 + 4];
            }
            #pragma unroll
            for (int mi = 0; mi < 4; mi++)
                #pragma unroll
                for (int ni = 0; ni < 4; ni++)
                    mma1688(acc[mi][ni], af[mi], bf[ni]);
        }

        if (kc + 2 < NKT) issueStage(kc + 2, (kc + 2) % 3);
    }

    const int ep = (EPI == -2) ? repi : EPI;
    #pragma unroll
    for (int mi = 0; mi < 4; mi++) {
        int gr0 = row0 + wr * 64 + mi * 16 + lg;
        #pragma unroll
        for (int ni = 0; ni < 4; ni++) {
            int gc = col0 + wc * 32 + ni * 8 + 2 * lt;
            if (gc < Nn) {
                float v0 = acc[mi][ni][0], v1 = acc[mi][ni][1];
                float v2 = acc[mi][ni][2], v3 = acc[mi][ni][3];
                long o0 = (long)gr0 * ldc + gc;
                long o1 = (long)(gr0 + 8) * ldc + gc;
                if (ep == 1) {
                    v0 = tanhf(v0); v1 = tanhf(v1); v2 = tanhf(v2); v3 = tanhf(v3);
                } else if (ep == 2) {
                    float b0 = bias[gc], b1 = bias[gc + 1];
                    v0 = -expf(v0 + b0); v1 = -expf(v1 + b1);
                    v2 = -expf(v2 + b0); v3 = -expf(v3 + b1);
                } else if (ep == 3) {
                    float b0 = bias[gc], b1 = bias[gc + 1];
                    float2 x0 = *(const float2*)&xin[o0];
                    float2 x1 = *(const float2*)&xin[o1];
                    float2 d0 = *(const float2*)&xxin[o0];
                    float2 d1 = *(const float2*)&xxin[o1];
                    v0 = fmaf(d0.x, b0 + v0, x0.x);
                    v1 = fmaf(d0.y, b1 + v1, x0.y);
                    v2 = fmaf(d1.x, b0 + v2, x1.x);
                    v3 = fmaf(d1.y, b1 + v3, x1.y);
                }
                if (RND || rrnd) {
                    v0 = rndt(v0); v1 = rndt(v1); v2 = rndt(v2); v3 = rndt(v3);
                }
                *(float2*)&Cm[o0] = make_float2(v0, v1);
                *(float2*)&Cm[o1] = make_float2(v2, v3);
            }
        }
    }
}

#define SMEM_G (STAGES * 128 * TSTR * 4 * 2)   // 61440 bytes

template<int EPI, bool RND>
__global__ __launch_bounds__(256, 2) void gemm_tc(
    const float* __restrict__ A, int lda,
    const float* __restrict__ Bt, int ldb,
    float* __restrict__ Cm, int ldc,
    int K, int Nn, const float* __restrict__ bias)
{
    extern __shared__ uint32_t dynsm[];
    gemm128_body<EPI, RND>(dynsm, A, lda, Bt, ldb, Cm, ldc, K, Nn, bias,
                           nullptr, nullptr, blockIdx.y * 128, blockIdx.x * 128,
                           0, false);
}

// merged r,k,v projections + decay1 + gate1: z selects (z=3,4 are N=64 LoRA)
__global__ __launch_bounds__(256, 2) void gemm_rkv(
    const float* xr, const float* xk, const float* xv,
    const float* xw, const float* xg,
    const float* WrT, const float* WkT, const float* WvT,
    const float* dw1T, const float* gw1T,
    float* r, float* k, float* v, float* s1, float* s2)
{
    extern __shared__ uint32_t dynsm[];
    const int z = blockIdx.z;
    const int col0 = blockIdx.x * 128;
    const float* A;
    const float* Bt;
    float* Cm;
    int Nn, ldc, repi;
    bool rr;
    if (z < 3) {
        A  = (z == 0) ? xr : (z == 1) ? xk : xv;
        Bt = (z == 0) ? WrT : (z == 1) ? WkT : WvT;
        Cm = (z == 0) ? r : (z == 1) ? k : v;
        Nn = C_; ldc = C_; repi = 0; rr = false;
    } else {
        A  = (z == 3) ? xw : xg;
        Bt = (z == 3) ? dw1T : gw1T;
        Cm = (z == 3) ? s1 : s2;
        Nn = 64; ldc = 64; repi = 1; rr = true;
        if (col0 >= 64) return;
    }
    gemm128_body<-2, false>(dynsm, A, C_, Bt, C_, Cm, ldc, C_, Nn, nullptr,
                            nullptr, nullptr, blockIdx.y * 128, col0, repi, rr);
}

__global__ __launch_bounds__(256, 2) void gemm_dg2(
    const float* small1, const float* small2,
    const float* dw2T, const float* gw2T,
    float* w, float* g, const float* time_decay)
{
    extern __shared__ uint32_t dynsm[];
    const int z = blockIdx.z;
    gemm128_body<-2, false>(dynsm, (z == 0) ? small1 : small2, 64,
                            (z == 0) ? dw2T : gw2T, 64,
                            (z == 0) ? w : g, C_, 64, C_, time_decay,
                            nullptr, nullptr, blockIdx.y * 128, blockIdx.x * 128,
                            (z == 0) ? 2 : 0, false);
}

__global__ __launch_bounds__(256, 2) void gemm_mix(
    const float* __restrict__ lora, const float* __restrict__ w2T,
    const float* __restrict__ x, const float* __restrict__ xx,
    const float* m0, const float* m1, const float* m2, const float* m3, const float* m4,
    float* o0, float* o1, float* o2, float* o3, float* o4)
{
    extern __shared__ uint32_t dynsm[];
    const int z = blockIdx.z;
    const float* bias = (z == 0) ? m0 : (z == 1) ? m1 : (z == 2) ? m2 : (z == 3) ? m3 : m4;
    float* out = (z == 0) ? o0 : (z == 1) ? o1 : (z == 2) ? o2 : (z == 3) ? o3 : o4;
    gemm128_body<3, true>(dynsm, lora + z * DMIX, 160, w2T + z * DMIX, 160,
                          out, C_, DMIX, C_, bias, x, xx,
                          blockIdx.y * 128, blockIdx.x * 128, 0, false);
}

// ---- small tile: BM=64, BN=64, 128 threads (classic path) --------------------
template<int EPI, bool RND>
__device__ __forceinline__ void gemm64_body(
    uint32_t (*As)[64 * TSTR], uint32_t (*Bs)[64 * TSTR],
    const float* __restrict__ A, int lda,
    const float* __restrict__ Bt, int ldb,
    float* __restrict__ Cm, int ldc,
    int K, int Nn, const float* __restrict__ bias,
    int row0, int col0)
{
    const int tid = threadIdx.x;
    const int lane = tid & 31;
    const int wid = tid >> 5;
    const int wr = wid >> 1;
    const int wc = wid & 1;

    float4 ra[2], rb[2];

    auto loadAB = [&](int kc) {
        const int k0 = kc * 16;
        #pragma unroll
        for (int l = 0; l < 2; l++) {
            int e = tid + (l << 7);
            int r = e >> 2, c = e & 3;
            ra[l] = *(const float4*)&A[(long)(row0 + r) * lda + k0 + (c << 2)];
            int br = col0 + r;
            if (br < Nn)
                rb[l] = *(const float4*)&Bt[(long)br * ldb + k0 + (c << 2)];
            else
                rb[l] = make_float4(0.f, 0.f, 0.f, 0.f);
        }
    };
    auto storeAB = [&](int buf) {
        #pragma unroll
        for (int l = 0; l < 2; l++) {
            int e = tid + (l << 7);
            int r = e >> 2, c = e & 3;
            uint32_t* ap = &As[buf][r * TSTR + (c << 2)];
            ap[0] = f2tf32(ra[l].x); ap[1] = f2tf32(ra[l].y);
            ap[2] = f2tf32(ra[l].z); ap[3] = f2tf32(ra[l].w);
            uint32_t* bp = &Bs[buf][r * TSTR + (c << 2)];
            bp[0] = f2tf32(rb[l].x); bp[1] = f2tf32(rb[l].y);
            bp[2] = f2tf32(rb[l].z); bp[3] = f2tf32(rb[l].w);
        }
    };

    float acc[2][4][4];
    #pragma unroll
    for (int mi = 0; mi < 2; mi++)
        #pragma unroll
        for (int ni = 0; ni < 4; ni++)
            #pragma unroll
            for (int e = 0; e < 4; e++) acc[mi][ni][e] = 0.f;

    const int NKT = K >> 4;
    loadAB(0);
    storeAB(0);
    __syncthreads();

    const int lg = lane >> 2;
    const int lt = lane & 3;

    for (int kc = 0; kc < NKT; kc++) {
        const int cur = kc & 1;
        if (kc + 1 < NKT) loadAB(kc + 1);

        #pragma unroll
        for (int ks = 0; ks < 2; ks++) {
            const int k0 = (ks << 3) + lt;
            uint32_t af[2][4], bf[4][2];
            #pragma unroll
            for (int mi = 0; mi < 2; mi++) {
                int rm = wr * 32 + mi * 16 + lg;
                af[mi][0] = As[cur][rm * TSTR + k0];
                af[mi][1] = As[cur][(rm + 8) * TSTR + k0];
                af[mi][2] = As[cur][rm * TSTR + k0 + 4];
                af[mi][3] = As[cur][(rm + 8) * TSTR + k0 + 4];
            }
            #pragma unroll
            for (int ni = 0; ni < 4; ni++) {
                int cn = wc * 32 + ni * 8 + lg;
                bf[ni][0] = Bs[cur][cn * TSTR + k0];
                bf[ni][1] = Bs[cur][cn * TSTR + k0 + 4];
            }
            #pragma unroll
            for (int mi = 0; mi < 2; mi++)
                #pragma unroll
                for (int ni = 0; ni < 4; ni++)
                    mma1688(acc[mi][ni], af[mi], bf[ni]);
        }

        if (kc + 1 < NKT) storeAB(cur ^ 1);
        __syncthreads();
    }

    #pragma unroll
    for (int mi = 0; mi < 2; mi++) {
        int gr0 = row0 + wr * 32 + mi * 16 + lg;
        #pragma unroll
        for (int ni = 0; ni < 4; ni++) {
            int gc = col0 + wc * 32 + ni * 8 + 2 * lt;
            if (gc < Nn) {
                float v0 = acc[mi][ni][0], v1 = acc[mi][ni][1];
                float v2 = acc[mi][ni][2], v3 = acc[mi][ni][3];
                if (EPI == 1) {
                    v0 = tanhf(v0); v1 = tanhf(v1); v2 = tanhf(v2); v3 = tanhf(v3);
                }
                if (RND) {
                    v0 = rndt(v0); v1 = rndt(v1); v2 = rndt(v2); v3 = rndt(v3);
                }
                *(float2*)&Cm[(long)gr0 * ldc + gc] = make_float2(v0, v1);
                *(float2*)&Cm[(long)(gr0 + 8) * ldc + gc] = make_float2(v2, v3);
            }
        }
    }
}

template<int EPI, bool RND>
__global__ __launch_bounds__(128, 3) void gemm_tc64(
    const float* __restrict__ A, int lda,
    const float* __restrict__ Bt, int ldb,
    float* __restrict__ Cm, int ldc,
    int K, int Nn, const float* __restrict__ bias)
{
    __shared__ uint32_t As[2][64 * TSTR];
    __shared__ uint32_t Bs[2][64 * TSTR];
    gemm64_body<EPI, RND>(As, Bs, A, lda, Bt, ldb, Cm, ldc, K, Nn, bias,
                          blockIdx.y * 64, blockIdx.x * 64);
}

// ---------------- fused pre-pass: shift + all weight transposes --------------
struct TJob { const float* src; float* dst; int R, N, nbx, boff; };
struct TJobs { TJob j[10]; };

__global__ __launch_bounds__(256) void pre_kernel(
    const float4* __restrict__ x4, const float* __restrict__ maa_x,
    float4* __restrict__ xx4, float4* __restrict__ xxx4,
    TJobs js, int nshift)
{
    const int tid = threadIdx.x;
    if ((int)blockIdx.x < nshift) {
        long idx = (long)blockIdx.x * 256 + tid;
        const int C4 = C_ / 4;
        int c4 = (int)(idx % C4);
        long rt = idx / C4;
        int t = (int)(rt % T_);
        float4 xv = x4[idx];
        float4 xp = (t > 0) ? x4[idx - C4] : make_float4(0.f, 0.f, 0.f, 0.f);
        float4 mx = *(const float4*)&maa_x[c4 * 4];
        float4 d = make_float4(xp.x - xv.x, xp.y - xv.y, xp.z - xv.z, xp.w - xv.w);
        xx4[idx] = d;
        xxx4[idx] = make_float4(rndt(fmaf(d.x, mx.x, xv.x)), rndt(fmaf(d.y, mx.y, xv.y)),
                                rndt(fmaf(d.z, mx.z, xv.z)), rndt(fmaf(d.w, mx.w, xv.w)));
        return;
    }
    __shared__ float t[32][33];
    int b = blockIdx.x - nshift;
    int ji = 0;
    #pragma unroll
    for (int q = 1; q < 10; q++)
        if (b >= js.j[q].boff) ji = q;
    TJob jb = js.j[ji];
    int rem = b - jb.boff;
    int bx = (rem % jb.nbx) * 32;
    int by = (rem / jb.nbx) * 32;
    const int xq = tid & 31, yq = tid >> 5;
    #pragma unroll
    for (int i = 0; i < 32; i += 8) {
        int r = by + yq + i, n = bx + xq;
        if (r < jb.R && n < jb.N) t[yq + i][xq] = jb.src[(long)r * jb.N + n];
    }
    __syncthreads();
    #pragma unroll
    for (int i = 0; i < 32; i += 8) {
        int n = bx + yq + i, r = by + xq;
        if (n < jb.N && r < jb.R) jb.dst[(long)n * jb.R + r] = rndt(t[xq][yq + i]);
    }
}

// ---------------- chunked WKV6 -----------------------------------------------
__global__ __launch_bounds__(256) void wkv_chunkA(
    const float* __restrict__ r, const float* __restrict__ k,
    const float* __restrict__ v, const float* __restrict__ lw,
    const float* __restrict__ u,
    float* __restrict__ y, float* __restrict__ Dout,
    float* __restrict__ rpout, float* __restrict__ pLout)
{
    extern __shared__ float sm[];
    float* lp   = sm;
    float* bufA = lp + 65 * 64;
    float* rpT  = bufA + 64 * STRD;
    float* kpT  = rpT + 64 * STRD;
    float* kpp  = kpT + 64 * STRD;
    float* vsm  = kpp + 64 * STRD;
    float* dsm  = vsm + 64 * STRD;
    float* usm  = dsm + 64;

    const int tid = threadIdx.x;
    const int chunk = blockIdx.x;
    const int bh = chunk >> 5;
    const int c  = chunk & 31;
    const int b = bh >> 4, h = bh & 15;
    const long base = ((long)b * T_ + c * CHUNK) * C_ + h * 64;

    if (tid < 64) usm[tid] = u[h * 64 + tid];
    const int i  = tid & 63;
    const int tq = tid >> 6;

    #pragma unroll
    for (int e = 0; e < 16; e++) {
        int t = tq + 4 * e;
        bufA[t * STRD + i] = lw[base + (long)t * C_ + i];
    }
    __syncthreads();

    if (tid < 64) {
        float run = 0.f;
        for (int t = 0; t < 64; t++) {
            lp[t * 64 + tid] = run;
            run += bufA[t * STRD + tid];
        }
        lp[64 * 64 + tid] = run;
        pLout[(long)chunk * 64 + tid] = run;
    }
    __syncthreads();

    #pragma unroll
    for (int e = 0; e < 16; e++) {
        int t = tq + 4 * e;
        long gi = base + (long)t * C_ + i;
        float rr = r[gi], kk = k[gi];
        float lpti = lp[t * 64 + i];
        float lpn  = lpti + bufA[t * STRD + i];
        float lpL  = lp[64 * 64 + i];
        rpT[i * STRD + t] = rr * __expf(lpti);
        kpT[i * STRD + t] = kk * __expf(-lpn);
        kpp[t * STRD + i] = kk * __expf(lpL - lpn);
        vsm[t * STRD + i] = v[gi];
    }
    {
        int t = tid >> 2, q = tid & 3;
        long gb = base + (long)t * C_;
        float p = 0.f;
        #pragma unroll
        for (int ii = 0; ii < 16; ii++) {
            int ci = q * 16 + ii;
            p += r[gb + ci] * usm[ci] * k[gb + ci];
        }
        p += __shfl_xor_sync(0xffffffffu, p, 1);
        p += __shfl_xor_sync(0xffffffffu, p, 2);
        if (q == 0) dsm[t] = p;
    }
    __syncthreads();

    {
        float* rpg = rpout + (long)chunk * 64 * 64;
        #pragma unroll
        for (int e = 0; e < 16; e++) {
            int flat = tid + 256 * e;
            rpg[flat] = rpT[(flat >> 6) * STRD + (flat & 63)];
        }
    }

    {
        int t0 = (tid >> 4) * 4, s0 = (tid & 15) * 4;
        float acc[4][4];
        #pragma unroll
        for (int a = 0; a < 4; a++)
            #pragma unroll
            for (int bq = 0; bq < 4; bq++) acc[a][bq] = 0.f;
        for (int ii = 0; ii < 64; ii++) {
            float4 a4 = *(const float4*)&rpT[ii * STRD + t0];
            float4 b4 = *(const float4*)&kpT[ii * STRD + s0];
            float av[4] = { a4.x, a4.y, a4.z, a4.w };
            float bv[4] = { b4.x, b4.y, b4.z, b4.w };
            #pragma unroll
            for (int a = 0; a < 4; a++)
                #pragma unroll
                for (int bq = 0; bq < 4; bq++)
                    acc[a][bq] = fmaf(av[a], bv[bq], acc[a][bq]);
        }
        __syncthreads();
        #pragma unroll
        for (int a = 0; a < 4; a++)
            #pragma unroll
            for (int bq = 0; bq < 4; bq++) {
                int tt = t0 + a, ss = s0 + bq;
                float val = (tt > ss) ? acc[a][bq] : ((tt == ss) ? dsm[tt] : 0.f);
                bufA[ss * STRD + tt] = val;
            }
    }
    __syncthreads();

    {
        int t0 = (tid >> 4) * 4, j0 = (tid & 15) * 4;
        float acc[4][4];
        #pragma unroll
        for (int a = 0; a < 4; a++)
            #pragma unroll
            for (int bq = 0; bq < 4; bq++) acc[a][bq] = 0.f;
        for (int s = 0; s < 64; s++) {
            float4 a4 = *(const float4*)&bufA[s * STRD + t0];
            float4 b4 = *(const float4*)&vsm[s * STRD + j0];
            float av[4] = { a4.x, a4.y, a4.z, a4.w };
            float bv[4] = { b4.x, b4.y, b4.z, b4.w };
            #pragma unroll
            for (int a = 0; a < 4; a++)
                #pragma unroll
                for (int bq = 0; bq < 4; bq++)
                    acc[a][bq] = fmaf(av[a], bv[bq], acc[a][bq]);
        }
        #pragma unroll
        for (int a = 0; a < 4; a++) {
            float4 o = make_float4(acc[a][0], acc[a][1], acc[a][2], acc[a][3]);
            *(float4*)&y[base + (long)(t0 + a) * C_ + j0] = o;
        }
    }

    {
        int i0 = (tid >> 4) * 4, j0 = (tid & 15) * 4;
        float acc[4][4];
        #pragma unroll
        for (int a = 0; a < 4; a++)
            #pragma unroll
            for (int bq = 0; bq < 4; bq++) acc[a][bq] = 0.f;
        for (int s = 0; s < 64; s++) {
            float4 a4 = *(const float4*)&kpp[s * STRD + i0];
            float4 b4 = *(const float4*)&vsm[s * STRD + j0];
            float av[4] = { a4.x, a4.y, a4.z, a4.w };
            float bv[4] = { b4.x, b4.y, b4.z, b4.w };
            #pragma unroll
            for (int a = 0; a < 4; a++)
                #pragma unroll
                for (int bq = 0; bq < 4; bq++)
                    acc[a][bq] = fmaf(av[a], bv[bq], acc[a][bq]);
        }
        float* Dp = Dout + (long)chunk * 4096;
        #pragma unroll
        for (int a = 0; a < 4; a++) {
            float4 o = make_float4(acc[a][0], acc[a][1], acc[a][2], acc[a][3]);
            *(float4*)&Dp[(i0 + a) * 64 + j0] = o;
        }
    }
}

__global__ __launch_bounds__(256) void wkv_chunkB(
    const float* __restrict__ D, const float* __restrict__ pL,
    float* __restrict__ S)
{
    const int bh = blockIdx.x;
    const int tid = threadIdx.x;
    const int i = tid >> 2;
    const int jb = (tid & 3) * 16;
    float4 s0 = {0,0,0,0}, s1 = {0,0,0,0}, s2 = {0,0,0,0}, s3 = {0,0,0,0};
    for (int c = 0; c < G_; c++) {
        long chunk = (long)bh * G_ + c;
        long off = chunk * 4096 + i * 64 + jb;
        *(float4*)&S[off + 0]  = s0;
        *(float4*)&S[off + 4]  = s1;
        *(float4*)&S[off + 8]  = s2;
        *(float4*)&S[off + 12] = s3;
        float pl = __expf(pL[chunk * 64 + i]);
        float4 d0 = *(const float4*)&D[off + 0];
        float4 d1 = *(const float4*)&D[off + 4];
        float4 d2 = *(const float4*)&D[off + 8];
        float4 d3 = *(const float4*)&D[off + 12];
        s0 = make_float4(fmaf(pl, s0.x, d0.x), fmaf(pl, s0.y, d0.y), fmaf(pl, s0.z, d0.z), fmaf(pl, s0.w, d0.w));
        s1 = make_float4(fmaf(pl, s1.x, d1.x), fmaf(pl, s1.y, d1.y), fmaf(pl, s1.z, d1.z), fmaf(pl, s1.w, d1.w));
        s2 = make_float4(fmaf(pl, s2.x, d2.x), fmaf(pl, s2.y, d2.y), fmaf(pl, s2.z, d2.z), fmaf(pl, s2.w, d2.w));
        s3 = make_float4(fmaf(pl, s3.x, d3.x), fmaf(pl, s3.y, d3.y), fmaf(pl, s3.z, d3.z), fmaf(pl, s3.w, d3.w));
    }
}

__global__ __launch_bounds__(256) void wkv_chunkC(
    const float* __restrict__ rp, const float* __restrict__ S,
    float* __restrict__ y)
{
    __shared__ float rps[64 * 64];
    __shared__ float Ss[64 * 64];
    const int tid = threadIdx.x;
    const int chunk = blockIdx.x;
    const int bh = chunk >> 5;
    const int c  = chunk & 31;
    const int b = bh >> 4, h = bh & 15;
    const long base = ((long)b * T_ + c * CHUNK) * C_ + h * 64;

    const float* rpg = rp + (long)chunk * 4096;
    const float* Sg  = S  + (long)chunk * 4096;
    #pragma unroll
    for (int e = 0; e < 4; e++) {
        int f4 = tid + 256 * e;
        *(float4*)&rps[f4 * 4] = *(const float4*)&rpg[f4 * 4];
        *(float4*)&Ss[f4 * 4]  = *(const float4*)&Sg[f4 * 4];
    }
    __syncthreads();

    int t0 = (tid >> 4) * 4, j0 = (tid & 15) * 4;
    float acc[4][4];
    #pragma unroll
    for (int a = 0; a < 4; a++)
        #pragma unroll
        for (int bq = 0; bq < 4; bq++) acc[a][bq] = 0.f;
    for (int ii = 0; ii < 64; ii++) {
        float4 a4 = *(const float4*)&rps[ii * 64 + t0];
        float4 b4 = *(const float4*)&Ss[ii * 64 + j0];
        float av[4] = { a4.x, a4.y, a4.z, a4.w };
        float bv[4] = { b4.x, b4.y, b4.z, b4.w };
        #pragma unroll
        for (int a = 0; a < 4; a++)
            #pragma unroll
            for (int bq = 0; bq < 4; bq++)
                acc[a][bq] = fmaf(av[a], bv[bq], acc[a][bq]);
    }
    #pragma unroll
    for (int a = 0; a < 4; a++) {
        long yo = base + (long)(t0 + a) * C_ + j0;
        float4 cur = *(const float4*)&y[yo];
        cur.x += acc[a][0]; cur.y += acc[a][1];
        cur.z += acc[a][2]; cur.w += acc[a][3];
        *(float4*)&y[yo] = cur;
    }
}

// ---------------- GroupNorm over heads + gate multiply (z tf32-rounded) ------
__global__ __launch_bounds__(512) void gn_kernel(
    const float* __restrict__ y, const float* __restrict__ ln_g,
    const float* __restrict__ ln_b, const float* __restrict__ g,
    float* __restrict__ z)
{
    const int bt = blockIdx.x;
    const int warp = threadIdx.x >> 5;
    const int lane = threadIdx.x & 31;
    const long base = (long)bt * C_ + warp * 64;

    float a0 = y[base + lane];
    float a1 = y[base + 32 + lane];
    float sum = a0 + a1;
    float sq = a0 * a0 + a1 * a1;
    #pragma unroll
    for (int off = 16; off > 0; off >>= 1) {
        sum += __shfl_xor_sync(0xffffffffu, sum, off);
        sq  += __shfl_xor_sync(0xffffffffu, sq,  off);
    }
    float mu = sum * (1.f / 64.f);
    float var = sq * (1.f / 64.f) - mu * mu;
    float inv = rsqrtf(var + 6.4e-4f);

    int c0 = warp * 64 + lane;
    float z0 = (a0 - mu) * inv * ln_g[c0] + ln_b[c0];
    float z1 = (a1 - mu) * inv * ln_g[c0 + 32] + ln_b[c0 + 32];
    z[base + lane]      = rndt(z0 * g[base + lane]);
    z[base + 32 + lane] = rndt(z1 * g[base + 32 + lane]);
}

// ---------------- launcher ----------------------------------------------------
extern "C" void kernel_launch(void* const* d_in, const int* in_sizes, int n_in,
                              void* d_out, int out_size)
{
    const float* x          = (const float*)d_in[0];
    const float* maa_x      = (const float*)d_in[1];
    const float* maa_w      = (const float*)d_in[2];
    const float* maa_k      = (const float*)d_in[3];
    const float* maa_v      = (const float*)d_in[4];
    const float* maa_r      = (const float*)d_in[5];
    const float* maa_g      = (const float*)d_in[6];
    const float* maa_w1     = (const float*)d_in[7];
    const float* maa_w2     = (const float*)d_in[8];
    const float* Wr         = (const float*)d_in[9];
    const float* Wk         = (const float*)d_in[10];
    const float* Wv         = (const float*)d_in[11];
    const float* Wo         = (const float*)d_in[12];
    const float* gate_w1    = (const float*)d_in[13];
    const float* gate_w2    = (const float*)d_in[14];
    const float* time_decay = (const float*)d_in[15];
    const float* decay_w1   = (const float*)d_in[16];
    const float* decay_w2   = (const float*)d_in[17];
    const float* u          = (const float*)d_in[18];
    const float* ln_g       = (const float*)d_in[19];
    const float* ln_b       = (const float*)d_in[20];
    (void)in_sizes; (void)n_in; (void)out_size;

    float *p_xx, *p_xxx, *p_xw, *p_xk, *p_xv, *p_xr, *p_xg;
    float *p_r, *p_k, *p_v, *p_w, *p_g, *p_y, *p_z, *p_lora, *p_s1, *p_s2;
    float *p_D, *p_Sc, *p_rp, *p_pL;
    float *p_WrT, *p_WkT, *p_WvT, *p_WoT, *p_w1T, *p_w2T, *p_dw1T, *p_gw1T, *p_dw2T, *p_gw2T;
    cudaGetSymbolAddress((void**)&p_xx, g_xx);
    cudaGetSymbolAddress((void**)&p_xxx, g_xxx);
    cudaGetSymbolAddress((void**)&p_xw, g_xw);
    cudaGetSymbolAddress((void**)&p_xk, g_xk);
    cudaGetSymbolAddress((void**)&p_xv, g_xv);
    cudaGetSymbolAddress((void**)&p_xr, g_xr);
    cudaGetSymbolAddress((void**)&p_xg, g_xg);
    cudaGetSymbolAddress((void**)&p_r, g_r);
    cudaGetSymbolAddress((void**)&p_k, g_k);
    cudaGetSymbolAddress((void**)&p_v, g_v);
    cudaGetSymbolAddress((void**)&p_w, g_w);
    cudaGetSymbolAddress((void**)&p_g, g_g);
    cudaGetSymbolAddress((void**)&p_y, g_y);
    cudaGetSymbolAddress((void**)&p_z, g_z);
    cudaGetSymbolAddress((void**)&p_lora, g_lora);
    cudaGetSymbolAddress((void**)&p_s1, g_small);
    cudaGetSymbolAddress((void**)&p_s2, g_small2);
    cudaGetSymbolAddress((void**)&p_D, g_D);
    cudaGetSymbolAddress((void**)&p_Sc, g_Sc);
    cudaGetSymbolAddress((void**)&p_rp, g_rp);
    cudaGetSymbolAddress((void**)&p_pL, g_pL);
    cudaGetSymbolAddress((void**)&p_WrT, g_WrT);
    cudaGetSymbolAddress((void**)&p_WkT, g_WkT);
    cudaGetSymbolAddress((void**)&p_WvT, g_WvT);
    cudaGetSymbolAddress((void**)&p_WoT, g_WoT);
    cudaGetSymbolAddress((void**)&p_w1T, g_w1T);
    cudaGetSymbolAddress((void**)&p_w2T, g_w2T);
    cudaGetSymbolAddress((void**)&p_dw1T, g_dw1T);
    cudaGetSymbolAddress((void**)&p_gw1T, g_gw1T);
    cudaGetSymbolAddress((void**)&p_dw2T, g_dw2T);
    cudaGetSymbolAddress((void**)&p_gw2T, g_gw2T);

    const long total = BTC;
    const int M = B_ * T_;          // 8192
    const int gy = M / 128;         // 64
    const int gy64 = M / 64;        // 128

    const int SMEM_A = (65 * 64 + 5 * 64 * STRD + 128) * 4;
    cudaFuncSetAttribute(wkv_chunkA, cudaFuncAttributeMaxDynamicSharedMemorySize, SMEM_A);
    cudaFuncSetAttribute(gemm_rkv, cudaFuncAttributeMaxDynamicSharedMemorySize, SMEM_G);
    cudaFuncSetAttribute(gemm_mix, cudaFuncAttributeMaxDynamicSharedMemorySize, SMEM_G);
    cudaFuncSetAttribute(gemm_dg2, cudaFuncAttributeMaxDynamicSharedMemorySize, SMEM_G);
    cudaFuncSetAttribute((const void*)gemm_tc<0, false>,
                         cudaFuncAttributeMaxDynamicSharedMemorySize, SMEM_G);

    // transpose job table
    TJobs tj;
    int toff = 0;
    {
        const float* srcs[10] = { maa_w1, maa_w2, Wr, Wk, Wv, Wo,
                                  decay_w1, gate_w1, decay_w2, gate_w2 };
        float* dsts[10] = { p_w1T, p_w2T, p_WrT, p_WkT, p_WvT, p_WoT,
                            p_dw1T, p_gw1T, p_dw2T, p_gw2T };
        int Rs[10] = { 1024, 160, 1024, 1024, 1024, 1024, 1024, 1024, 64, 64 };
        int Ns[10] = { 160, 1024, 1024, 1024, 1024, 1024, 64, 64, 1024, 1024 };
        for (int q = 0; q < 10; q++) {
            int nbx = (Ns[q] + 31) / 32;
            int nby = (Rs[q] + 31) / 32;
            tj.j[q].src = srcs[q]; tj.j[q].dst = dsts[q];
            tj.j[q].R = Rs[q]; tj.j[q].N = Ns[q];
            tj.j[q].nbx = nbx; tj.j[q].boff = toff;
            toff += nbx * nby;
        }
    }
    const int nshift = (int)(total / 4 / 256);   // 8192

    // 0. fused shift + transposes (xxx + weights tf32-rounded)
    pre_kernel<<<nshift + toff, 256>>>((const float4*)x, maa_x,
        (float4*)p_xx, (float4*)p_xxx, tj, nshift);
    // 1. lora = tanh(xxx @ maa_w1), rounded
    gemm_tc64<1, true><<<dim3(3, gy64), 128>>>(p_xxx, C_, p_w1T, C_, p_lora, 160, C_, 160, nullptr);
    // 2. merged 5-branch mix GEMM (outputs rounded)
    gemm_mix<<<dim3(8, gy, 5), 256, SMEM_G>>>(p_lora, p_w2T, x, p_xx,
        maa_w, maa_k, maa_v, maa_r, maa_g,
        p_xw, p_xk, p_xv, p_xr, p_xg);
    // 3. merged r,k,v + decay1 + gate1 projections  <-- profiled by ncu
    gemm_rkv<<<dim3(8, gy, 5), 256, SMEM_G>>>(p_xr, p_xk, p_xv, p_xw, p_xg,
                                              p_WrT, p_WkT, p_WvT, p_dw1T, p_gw1T,
                                              p_r, p_k, p_v, p_s1, p_s2);
    // 4. merged decay2 + gate2
    gemm_dg2<<<dim3(8, gy, 2), 256, SMEM_G>>>(p_s1, p_s2, p_dw2T, p_gw2T, p_w, p_g, time_decay);
    // 5-7. chunked WKV6
    wkv_chunkA<<<NCHUNK, 256, SMEM_A>>>(p_r, p_k, p_v, p_w, u, p_y, p_D, p_rp, p_pL);
    wkv_chunkB<<<B_ * H_, 256>>>(p_D, p_pL, p_Sc);
    wkv_chunkC<<<NCHUNK, 256>>>(p_rp, p_Sc, p_y);
    // 8. GroupNorm + gate multiply (z rounded)
    gn_kernel<<<M, 512>>>(p_y, ln_g, ln_b, p_g, p_z);
    // 9. out = z @ Wo
    gemm_tc<0, false><<<dim3(8, gy), 256, SMEM_G>>>(p_z, C_, p_WoT, C_, (float*)d_out, C_, C_, C_, nullptr);
}

// round 15
// speedup vs baseline: 1.5840x; 1.0597x over previous
#include <cuda_runtime.h>
#include <cuda_bf16.h>
#include <cstdint>
#include <math.h>

// Problem constants
#define B_  4
#define T_  2048
#define C_  1024
#define H_  16
#define N_  64
#define DMIX 32

#define CHUNK 64
#define G_ 32
#define NCHUNK (B_*H_*G_)         // 2048
#define STRD 68

static const long BTC = (long)B_ * T_ * C_;   // 8388608

// ---------------- scratch (device globals; no runtime allocation) -------------
__device__ float g_xx [ (long)B_*T_*C_ ];
__device__ float g_xxx[ (long)B_*T_*C_ ];
__device__ float g_xw [ (long)B_*T_*C_ ];
__device__ float g_xk [ (long)B_*T_*C_ ];
__device__ float g_xv [ (long)B_*T_*C_ ];
__device__ float g_xr [ (long)B_*T_*C_ ];
__device__ float g_xg [ (long)B_*T_*C_ ];
__device__ float g_r  [ (long)B_*T_*C_ ];
__device__ float g_k  [ (long)B_*T_*C_ ];
__device__ float g_v  [ (long)B_*T_*C_ ];
__device__ float g_w  [ (long)B_*T_*C_ ];
__device__ float g_g  [ (long)B_*T_*C_ ];
__device__ float g_y  [ (long)B_*T_*C_ ];
__device__ float g_z  [ (long)B_*T_*C_ ];
__device__ float g_lora [ (long)B_*T_*5*DMIX ];
__device__ float g_small [ (long)B_*T_*64 ];
__device__ float g_small2[ (long)B_*T_*64 ];
__device__ float g_D  [ (long)NCHUNK*64*64 ];
__device__ float g_Sc [ (long)NCHUNK*64*64 ];
__device__ float g_rp [ (long)NCHUNK*64*64 ];
__device__ float g_pL [ (long)NCHUNK*64 ];
__device__ float g_WrT[ (long)C_*C_ ];
__device__ float g_WkT[ (long)C_*C_ ];
__device__ float g_WvT[ (long)C_*C_ ];
__device__ float g_WoT[ (long)C_*C_ ];
__device__ float g_w1T[ (long)160*C_ ];
__device__ float g_w2T[ (long)C_*160 ];
__device__ float g_dw1T[ (long)64*C_ ];
__device__ float g_gw1T[ (long)64*C_ ];
__device__ float g_dw2T[ (long)C_*64 ];
__device__ float g_gw2T[ (long)C_*64 ];

// ================= helpers ====================================================
#define TSTR 20
#define STAGES 3

__device__ __forceinline__ uint32_t f2tf32(float f) {
    uint32_t o;
    asm("cvt.rna.tf32.f32 %0, %1;" : "=r"(o) : "f"(f));
    return o;
}
__device__ __forceinline__ float rndt(float f) {
    return __uint_as_float(f2tf32(f));
}
__device__ __forceinline__ uint32_t smem_u32(const void* p) {
    uint32_t a;
    asm("{ .reg .u64 t; cvta.to.shared.u64 t, %1; cvt.u32.u64 %0, t; }"
        : "=r"(a) : "l"(p));
    return a;
}
#define CP_A16(dst, src) \
    asm volatile("cp.async.cg.shared.global [%0], [%1], 16;" :: "r"(dst), "l"(src))
#define CP_COMMIT() asm volatile("cp.async.commit_group;" ::: "memory")
#define CP_WAIT(n)  asm volatile("cp.async.wait_group %0;" :: "n"(n) : "memory")

__device__ __forceinline__ void mma1688(float* d, const uint32_t* a, const uint32_t* b) {
    asm volatile(
        "mma.sync.aligned.m16n8k8.row.col.f32.tf32.tf32.f32 "
        "{%0,%1,%2,%3}, {%4,%5,%6,%7}, {%8,%9}, {%0,%1,%2,%3};"
        : "+f"(d[0]), "+f"(d[1]), "+f"(d[2]), "+f"(d[3])
        : "r"(a[0]), "r"(a[1]), "r"(a[2]), "r"(a[3]), "r"(b[0]), "r"(b[1]));
}

// ---- 128x128 body, geometry templated on TH --------------------------------
// TH=128: 4 warps 2x2, warp tile 64x64 (best for K=1024 compute-bound).
// TH=256: 8 warps 2x4, warp tile 64x32 (best for small-K memory-bound).
// Inputs MUST be pre-rounded tf32. EPI: 0 none, 1 tanh, 2 -exp(acc+bias),
// 3 xin+xxin*(bias+acc), -2 runtime repi (0/1/2). rrnd: runtime output rounding.
template<int TH, int EPI, bool RND>
__device__ __forceinline__ void gemm128_body(
    uint32_t* dynsm,
    const float* __restrict__ A, int lda,
    const float* __restrict__ Bt, int ldb,
    float* __restrict__ Cm, int ldc,
    int K, int Nn, const float* __restrict__ bias,
    const float* __restrict__ xin, const float* __restrict__ xxin,
    int row0, int col0, int repi, bool rrnd)
{
    constexpr int NI  = (TH == 256) ? 4 : 8;      // n-subtiles per warp
    constexpr int WCW = (TH == 256) ? 32 : 64;    // warp col width
    constexpr int LPT = 512 / TH;                 // float4 loads/thread/tile

    const int tid = threadIdx.x;
    const int lane = tid & 31;
    const int wid = tid >> 5;
    const int wr = (TH == 256) ? (wid >> 2) : (wid >> 1);
    const int wc = (TH == 256) ? (wid & 3) : (wid & 1);

    uint32_t* As = dynsm;
    uint32_t* Bs = dynsm + STAGES * 128 * TSTR;
    const uint32_t as0 = smem_u32(As);
    const uint32_t bs0 = smem_u32(Bs);

    auto issueStage = [&](int kc, int buf) {
        const int k0 = kc * 16;
        const uint32_t ao = as0 + buf * (128 * TSTR * 4);
        const uint32_t bo = bs0 + buf * (128 * TSTR * 4);
        #pragma unroll
        for (int l = 0; l < LPT; l++) {
            int e = tid + l * TH;
            int r = e >> 2, c = e & 3;
            uint32_t so = (uint32_t)(r * TSTR + (c << 2)) * 4u;
            CP_A16(ao + so, &A[(long)(row0 + r) * lda + k0 + (c << 2)]);
            CP_A16(bo + so, &Bt[(long)(col0 + r) * ldb + k0 + (c << 2)]);
        }
        CP_COMMIT();
    };

    float acc[4][NI][4];
    #pragma unroll
    for (int mi = 0; mi < 4; mi++)
        #pragma unroll
        for (int ni = 0; ni < NI; ni++)
            #pragma unroll
            for (int e = 0; e < 4; e++) acc[mi][ni][e] = 0.f;

    const int NKT = K >> 4;
    issueStage(0, 0);
    if (NKT > 1) issueStage(1, 1);

    const int lg = lane >> 2;
    const int lt = lane & 3;

    for (int kc = 0; kc < NKT; kc++) {
        const int buf = kc % 3;
        if (kc + 2 < NKT) { CP_WAIT(1); } else { CP_WAIT(0); }
        __syncthreads();

        const uint32_t* Ab = As + buf * 128 * TSTR;
        const uint32_t* Bb = Bs + buf * 128 * TSTR;
        #pragma unroll
        for (int ks = 0; ks < 2; ks++) {
            const int k0 = (ks << 3) + lt;
            uint32_t af[4][4], bf[NI][2];
            #pragma unroll
            for (int mi = 0; mi < 4; mi++) {
                int rm = wr * 64 + mi * 16 + lg;
                af[mi][0] = Ab[rm * TSTR + k0];
                af[mi][1] = Ab[(rm + 8) * TSTR + k0];
                af[mi][2] = Ab[rm * TSTR + k0 + 4];
                af[mi][3] = Ab[(rm + 8) * TSTR + k0 + 4];
            }
            #pragma unroll
            for (int ni = 0; ni < NI; ni++) {
                int cn = wc * WCW + ni * 8 + lg;
                bf[ni][0] = Bb[cn * TSTR + k0];
                bf[ni][1] = Bb[cn * TSTR + k0 + 4];
            }
            #pragma unroll
            for (int mi = 0; mi < 4; mi++)
                #pragma unroll
                for (int ni = 0; ni < NI; ni++)
                    mma1688(acc[mi][ni], af[mi], bf[ni]);
        }

        if (kc + 2 < NKT) issueStage(kc + 2, (kc + 2) % 3);
    }

    const int ep = (EPI == -2) ? repi : EPI;
    #pragma unroll
    for (int mi = 0; mi < 4; mi++) {
        int gr0 = row0 + wr * 64 + mi * 16 + lg;
        #pragma unroll
        for (int ni = 0; ni < NI; ni++) {
            int gc = col0 + wc * WCW + ni * 8 + 2 * lt;
            if (gc < Nn) {
                float v0 = acc[mi][ni][0], v1 = acc[mi][ni][1];
                float v2 = acc[mi][ni][2], v3 = acc[mi][ni][3];
                long o0 = (long)gr0 * ldc + gc;
                long o1 = (long)(gr0 + 8) * ldc + gc;
                if (ep == 1) {
                    v0 = tanhf(v0); v1 = tanhf(v1); v2 = tanhf(v2); v3 = tanhf(v3);
                } else if (ep == 2) {
                    float b0 = bias[gc], b1 = bias[gc + 1];
                    v0 = -expf(v0 + b0); v1 = -expf(v1 + b1);
                    v2 = -expf(v2 + b0); v3 = -expf(v3 + b1);
                } else if (ep == 3) {
                    float b0 = bias[gc], b1 = bias[gc + 1];
                    float2 x0 = *(const float2*)&xin[o0];
                    float2 x1 = *(const float2*)&xin[o1];
                    float2 d0 = *(const float2*)&xxin[o0];
                    float2 d1 = *(const float2*)&xxin[o1];
                    v0 = fmaf(d0.x, b0 + v0, x0.x);
                    v1 = fmaf(d0.y, b1 + v1, x0.y);
                    v2 = fmaf(d1.x, b0 + v2, x1.x);
                    v3 = fmaf(d1.y, b1 + v3, x1.y);
                }
                if (RND || rrnd) {
                    v0 = rndt(v0); v1 = rndt(v1); v2 = rndt(v2); v3 = rndt(v3);
                }
                *(float2*)&Cm[o0] = make_float2(v0, v1);
                *(float2*)&Cm[o1] = make_float2(v2, v3);
            }
        }
    }
}

#define SMEM_G (STAGES * 128 * TSTR * 4 * 2)   // 61440 bytes

// Wo projection: K=1024 compute-bound -> 128 threads
template<int EPI, bool RND>
__global__ __launch_bounds__(128, 2) void gemm_tc(
    const float* __restrict__ A, int lda,
    const float* __restrict__ Bt, int ldb,
    float* __restrict__ Cm, int ldc,
    int K, int Nn, const float* __restrict__ bias)
{
    extern __shared__ uint32_t dynsm[];
    gemm128_body<128, EPI, RND>(dynsm, A, lda, Bt, ldb, Cm, ldc, K, Nn, bias,
                                nullptr, nullptr, blockIdx.y * 128, blockIdx.x * 128,
                                0, false);
}

// merged r,k,v + decay1 + gate1: K=1024 compute-bound -> 128 threads
__global__ __launch_bounds__(128, 2) void gemm_rkv(
    const float* xr, const float* xk, const float* xv,
    const float* xw, const float* xg,
    const float* WrT, const float* WkT, const float* WvT,
    const float* dw1T, const float* gw1T,
    float* r, float* k, float* v, float* s1, float* s2)
{
    extern __shared__ uint32_t dynsm[];
    const int z = blockIdx.z;
    const int col0 = blockIdx.x * 128;
    const float* A;
    const float* Bt;
    float* Cm;
    int Nn, ldc, repi;
    bool rr;
    if (z < 3) {
        A  = (z == 0) ? xr : (z == 1) ? xk : xv;
        Bt = (z == 0) ? WrT : (z == 1) ? WkT : WvT;
        Cm = (z == 0) ? r : (z == 1) ? k : v;
        Nn = C_; ldc = C_; repi = 0; rr = false;
    } else {
        A  = (z == 3) ? xw : xg;
        Bt = (z == 3) ? dw1T : gw1T;
        Cm = (z == 3) ? s1 : s2;
        Nn = 64; ldc = 64; repi = 1; rr = true;
        if (col0 >= 64) return;
    }
    gemm128_body<128, -2, false>(dynsm, A, C_, Bt, C_, Cm, ldc, C_, Nn, nullptr,
                                 nullptr, nullptr, blockIdx.y * 128, col0, repi, rr);
}

// merged decay2 + gate2: K=64 memory-bound -> 256 threads
__global__ __launch_bounds__(256, 2) void gemm_dg2(
    const float* small1, const float* small2,
    const float* dw2T, const float* gw2T,
    float* w, float* g, const float* time_decay)
{
    extern __shared__ uint32_t dynsm[];
    const int z = blockIdx.z;
    gemm128_body<256, -2, false>(dynsm, (z == 0) ? small1 : small2, 64,
                                 (z == 0) ? dw2T : gw2T, 64,
                                 (z == 0) ? w : g, C_, 64, C_, time_decay,
                                 nullptr, nullptr, blockIdx.y * 128, blockIdx.x * 128,
                                 (z == 0) ? 2 : 0, false);
}

// merged 5-branch mix: K=32 memory-bound -> 256 threads
__global__ __launch_bounds__(256, 2) void gemm_mix(
    const float* __restrict__ lora, const float* __restrict__ w2T,
    const float* __restrict__ x, const float* __restrict__ xx,
    const float* m0, const float* m1, const float* m2, const float* m3, const float* m4,
    float* o0, float* o1, float* o2, float* o3, float* o4)
{
    extern __shared__ uint32_t dynsm[];
    const int z = blockIdx.z;
    const float* bias = (z == 0) ? m0 : (z == 1) ? m1 : (z == 2) ? m2 : (z == 3) ? m3 : m4;
    float* out = (z == 0) ? o0 : (z == 1) ? o1 : (z == 2) ? o2 : (z == 3) ? o3 : o4;
    gemm128_body<256, 3, true>(dynsm, lora + z * DMIX, 160, w2T + z * DMIX, 160,
                               out, C_, DMIX, C_, bias, x, xx,
                               blockIdx.y * 128, blockIdx.x * 128, 0, false);
}

// ---- small tile: BM=64, BN=64, 128 threads (classic path) --------------------
template<int EPI, bool RND>
__device__ __forceinline__ void gemm64_body(
    uint32_t (*As)[64 * TSTR], uint32_t (*Bs)[64 * TSTR],
    const float* __restrict__ A, int lda,
    const float* __restrict__ Bt, int ldb,
    float* __restrict__ Cm, int ldc,
    int K, int Nn, const float* __restrict__ bias,
    int row0, int col0)
{
    const int tid = threadIdx.x;
    const int lane = tid & 31;
    const int wid = tid >> 5;
    const int wr = wid >> 1;
    const int wc = wid & 1;

    float4 ra[2], rb[2];

    auto loadAB = [&](int kc) {
        const int k0 = kc * 16;
        #pragma unroll
        for (int l = 0; l < 2; l++) {
            int e = tid + (l << 7);
            int r = e >> 2, c = e & 3;
            ra[l] = *(const float4*)&A[(long)(row0 + r) * lda + k0 + (c << 2)];
            int br = col0 + r;
            if (br < Nn)
                rb[l] = *(const float4*)&Bt[(long)br * ldb + k0 + (c << 2)];
            else
                rb[l] = make_float4(0.f, 0.f, 0.f, 0.f);
        }
    };
    auto storeAB = [&](int buf) {
        #pragma unroll
        for (int l = 0; l < 2; l++) {
            int e = tid + (l << 7);
            int r = e >> 2, c = e & 3;
            uint32_t* ap = &As[buf][r * TSTR + (c << 2)];
            ap[0] = f2tf32(ra[l].x); ap[1] = f2tf32(ra[l].y);
            ap[2] = f2tf32(ra[l].z); ap[3] = f2tf32(ra[l].w);
            uint32_t* bp = &Bs[buf][r * TSTR + (c << 2)];
            bp[0] = f2tf32(rb[l].x); bp[1] = f2tf32(rb[l].y);
            bp[2] = f2tf32(rb[l].z); bp[3] = f2tf32(rb[l].w);
        }
    };

    float acc[2][4][4];
    #pragma unroll
    for (int mi = 0; mi < 2; mi++)
        #pragma unroll
        for (int ni = 0; ni < 4; ni++)
            #pragma unroll
            for (int e = 0; e < 4; e++) acc[mi][ni][e] = 0.f;

    const int NKT = K >> 4;
    loadAB(0);
    storeAB(0);
    __syncthreads();

    const int lg = lane >> 2;
    const int lt = lane & 3;

    for (int kc = 0; kc < NKT; kc++) {
        const int cur = kc & 1;
        if (kc + 1 < NKT) loadAB(kc + 1);

        #pragma unroll
        for (int ks = 0; ks < 2; ks++) {
            const int k0 = (ks << 3) + lt;
            uint32_t af[2][4], bf[4][2];
            #pragma unroll
            for (int mi = 0; mi < 2; mi++) {
                int rm = wr * 32 + mi * 16 + lg;
                af[mi][0] = As[cur][rm * TSTR + k0];
                af[mi][1] = As[cur][(rm + 8) * TSTR + k0];
                af[mi][2] = As[cur][rm * TSTR + k0 + 4];
                af[mi][3] = As[cur][(rm + 8) * TSTR + k0 + 4];
            }
            #pragma unroll
            for (int ni = 0; ni < 4; ni++) {
                int cn = wc * 32 + ni * 8 + lg;
                bf[ni][0] = Bs[cur][cn * TSTR + k0];
                bf[ni][1] = Bs[cur][cn * TSTR + k0 + 4];
            }
            #pragma unroll
            for (int mi = 0; mi < 2; mi++)
                #pragma unroll
                for (int ni = 0; ni < 4; ni++)
                    mma1688(acc[mi][ni], af[mi], bf[ni]);
        }

        if (kc + 1 < NKT) storeAB(cur ^ 1);
        __syncthreads();
    }

    #pragma unroll
    for (int mi = 0; mi < 2; mi++) {
        int gr0 = row0 + wr * 32 + mi * 16 + lg;
        #pragma unroll
        for (int ni = 0; ni < 4; ni++) {
            int gc = col0 + wc * 32 + ni * 8 + 2 * lt;
            if (gc < Nn) {
                float v0 = acc[mi][ni][0], v1 = acc[mi][ni][1];
                float v2 = acc[mi][ni][2], v3 = acc[mi][ni][3];
                if (EPI == 1) {
                    v0 = tanhf(v0); v1 = tanhf(v1); v2 = tanhf(v2); v3 = tanhf(v3);
                }
                if (RND) {
                    v0 = rndt(v0); v1 = rndt(v1); v2 = rndt(v2); v3 = rndt(v3);
                }
                *(float2*)&Cm[(long)gr0 * ldc + gc] = make_float2(v0, v1);
                *(float2*)&Cm[(long)(gr0 + 8) * ldc + gc] = make_float2(v2, v3);
            }
        }
    }
}

template<int EPI, bool RND>
__global__ __launch_bounds__(128, 3) void gemm_tc64(
    const float* __restrict__ A, int lda,
    const float* __restrict__ Bt, int ldb,
    float* __restrict__ Cm, int ldc,
    int K, int Nn, const float* __restrict__ bias)
{
    __shared__ uint32_t As[2][64 * TSTR];
    __shared__ uint32_t Bs[2][64 * TSTR];
    gemm64_body<EPI, RND>(As, Bs, A, lda, Bt, ldb, Cm, ldc, K, Nn, bias,
                          blockIdx.y * 64, blockIdx.x * 64);
}

// ---------------- fused pre-pass: shift + all weight transposes --------------
struct TJob { const float* src; float* dst; int R, N, nbx, boff; };
struct TJobs { TJob j[10]; };

__global__ __launch_bounds__(256) void pre_kernel(
    const float4* __restrict__ x4, const float* __restrict__ maa_x,
    float4* __restrict__ xx4, float4* __restrict__ xxx4,
    TJobs js, int nshift)
{
    const int tid = threadIdx.x;
    if ((int)blockIdx.x < nshift) {
        long idx = (long)blockIdx.x * 256 + tid;
        const int C4 = C_ / 4;
        int c4 = (int)(idx % C4);
        long rt = idx / C4;
        int t = (int)(rt % T_);
        float4 xv = x4[idx];
        float4 xp = (t > 0) ? x4[idx - C4] : make_float4(0.f, 0.f, 0.f, 0.f);
        float4 mx = *(const float4*)&maa_x[c4 * 4];
        float4 d = make_float4(xp.x - xv.x, xp.y - xv.y, xp.z - xv.z, xp.w - xv.w);
        xx4[idx] = d;
        xxx4[idx] = make_float4(rndt(fmaf(d.x, mx.x, xv.x)), rndt(fmaf(d.y, mx.y, xv.y)),
                                rndt(fmaf(d.z, mx.z, xv.z)), rndt(fmaf(d.w, mx.w, xv.w)));
        return;
    }
    __shared__ float t[32][33];
    int b = blockIdx.x - nshift;
    int ji = 0;
    #pragma unroll
    for (int q = 1; q < 10; q++)
        if (b >= js.j[q].boff) ji = q;
    TJob jb = js.j[ji];
    int rem = b - jb.boff;
    int bx = (rem % jb.nbx) * 32;
    int by = (rem / jb.nbx) * 32;
    const int xq = tid & 31, yq = tid >> 5;
    #pragma unroll
    for (int i = 0; i < 32; i += 8) {
        int r = by + yq + i, n = bx + xq;
        if (r < jb.R && n < jb.N) t[yq + i][xq] = jb.src[(long)r * jb.N + n];
    }
    __syncthreads();
    #pragma unroll
    for (int i = 0; i < 32; i += 8) {
        int n = bx + yq + i, r = by + xq;
        if (n < jb.N && r < jb.R) jb.dst[(long)n * jb.R + r] = rndt(t[xq][yq + i]);
    }
}

// ---------------- chunked WKV6 -----------------------------------------------
__global__ __launch_bounds__(256) void wkv_chunkA(
    const float* __restrict__ r, const float* __restrict__ k,
    const float* __restrict__ v, const float* __restrict__ lw,
    const float* __restrict__ u,
    float* __restrict__ y, float* __restrict__ Dout,
    float* __restrict__ rpout, float* __restrict__ pLout)
{
    extern __shared__ float sm[];
    float* lp   = sm;
    float* bufA = lp + 65 * 64;
    float* rpT  = bufA + 64 * STRD;
    float* kpT  = rpT + 64 * STRD;
    float* kpp  = kpT + 64 * STRD;
    float* vsm  = kpp + 64 * STRD;
    float* dsm  = vsm + 64 * STRD;
    float* usm  = dsm + 64;

    const int tid = threadIdx.x;
    const int chunk = blockIdx.x;
    const int bh = chunk >> 5;
    const int c  = chunk & 31;
    const int b = bh >> 4, h = bh & 15;
    const long base = ((long)b * T_ + c * CHUNK) * C_ + h * 64;

    if (tid < 64) usm[tid] = u[h * 64 + tid];
    const int i  = tid & 63;
    const int tq = tid >> 6;

    #pragma unroll
    for (int e = 0; e < 16; e++) {
        int t = tq + 4 * e;
        bufA[t * STRD + i] = lw[base + (long)t * C_ + i];
    }
    __syncthreads();

    if (tid < 64) {
        float run = 0.f;
        for (int t = 0; t < 64; t++) {
            lp[t * 64 + tid] = run;
            run += bufA[t * STRD + tid];
        }
        lp[64 * 64 + tid] = run;
        pLout[(long)chunk * 64 + tid] = run;
    }
    __syncthreads();

    #pragma unroll
    for (int e = 0; e < 16; e++) {
        int t = tq + 4 * e;
        long gi = base + (long)t * C_ + i;
        float rr = r[gi], kk = k[gi];
        float lpti = lp[t * 64 + i];
        float lpn  = lpti + bufA[t * STRD + i];
        float lpL  = lp[64 * 64 + i];
        rpT[i * STRD + t] = rr * __expf(lpti);
        kpT[i * STRD + t] = kk * __expf(-lpn);
        kpp[t * STRD + i] = kk * __expf(lpL - lpn);
        vsm[t * STRD + i] = v[gi];
    }
    {
        int t = tid >> 2, q = tid & 3;
        long gb = base + (long)t * C_;
        float p = 0.f;
        #pragma unroll
        for (int ii = 0; ii < 16; ii++) {
            int ci = q * 16 + ii;
            p += r[gb + ci] * usm[ci] * k[gb + ci];
        }
        p += __shfl_xor_sync(0xffffffffu, p, 1);
        p += __shfl_xor_sync(0xffffffffu, p, 2);
        if (q == 0) dsm[t] = p;
    }
    __syncthreads();

    {
        float* rpg = rpout + (long)chunk * 64 * 64;
        #pragma unroll
        for (int e = 0; e < 16; e++) {
            int flat = tid + 256 * e;
            rpg[flat] = rpT[(flat >> 6) * STRD + (flat & 63)];
        }
    }

    {
        int t0 = (tid >> 4) * 4, s0 = (tid & 15) * 4;
        float acc[4][4];
        #pragma unroll
        for (int a = 0; a < 4; a++)
            #pragma unroll
            for (int bq = 0; bq < 4; bq++) acc[a][bq] = 0.f;
        for (int ii = 0; ii < 64; ii++) {
            float4 a4 = *(const float4*)&rpT[ii * STRD + t0];
            float4 b4 = *(const float4*)&kpT[ii * STRD + s0];
            float av[4] = { a4.x, a4.y, a4.z, a4.w };
            float bv[4] = { b4.x, b4.y, b4.z, b4.w };
            #pragma unroll
            for (int a = 0; a < 4; a++)
                #pragma unroll
                for (int bq = 0; bq < 4; bq++)
                    acc[a][bq] = fmaf(av[a], bv[bq], acc[a][bq]);
        }
        __syncthreads();
        #pragma unroll
        for (int a = 0; a < 4; a++)
            #pragma unroll
            for (int bq = 0; bq < 4; bq++) {
                int tt = t0 + a, ss = s0 + bq;
                float val = (tt > ss) ? acc[a][bq] : ((tt == ss) ? dsm[tt] : 0.f);
                bufA[ss * STRD + tt] = val;
            }
    }
    __syncthreads();

    {
        int t0 = (tid >> 4) * 4, j0 = (tid & 15) * 4;
        float acc[4][4];
        #pragma unroll
        for (int a = 0; a < 4; a++)
            #pragma unroll
            for (int bq = 0; bq < 4; bq++) acc[a][bq] = 0.f;
        for (int s = 0; s < 64; s++) {
            float4 a4 = *(const float4*)&bufA[s * STRD + t0];
            float4 b4 = *(const float4*)&vsm[s * STRD + j0];
            float av[4] = { a4.x, a4.y, a4.z, a4.w };
            float bv[4] = { b4.x, b4.y, b4.z, b4.w };
            #pragma unroll
            for (int a = 0; a < 4; a++)
                #pragma unroll
                for (int bq = 0; bq < 4; bq++)
                    acc[a][bq] = fmaf(av[a], bv[bq], acc[a][bq]);
        }
        #pragma unroll
        for (int a = 0; a < 4; a++) {
            float4 o = make_float4(acc[a][0], acc[a][1], acc[a][2], acc[a][3]);
            *(float4*)&y[base + (long)(t0 + a) * C_ + j0] = o;
        }
    }

    {
        int i0 = (tid >> 4) * 4, j0 = (tid & 15) * 4;
        float acc[4][4];
        #pragma unroll
        for (int a = 0; a < 4; a++)
            #pragma unroll
            for (int bq = 0; bq < 4; bq++) acc[a][bq] = 0.f;
        for (int s = 0; s < 64; s++) {
            float4 a4 = *(const float4*)&kpp[s * STRD + i0];
            float4 b4 = *(const float4*)&vsm[s * STRD + j0];
            float av[4] = { a4.x, a4.y, a4.z, a4.w };
            float bv[4] = { b4.x, b4.y, b4.z, b4.w };
            #pragma unroll
            for (int a = 0; a < 4; a++)
                #pragma unroll
                for (int bq = 0; bq < 4; bq++)
                    acc[a][bq] = fmaf(av[a], bv[bq], acc[a][bq]);
        }
        float* Dp = Dout + (long)chunk * 4096;
        #pragma unroll
        for (int a = 0; a < 4; a++) {
            float4 o = make_float4(acc[a][0], acc[a][1], acc[a][2], acc[a][3]);
            *(float4*)&Dp[(i0 + a) * 64 + j0] = o;
        }
    }
}

__global__ __launch_bounds__(256) void wkv_chunkB(
    const float* __restrict__ D, const float* __restrict__ pL,
    float* __restrict__ S)
{
    const int bh = blockIdx.x;
    const int tid = threadIdx.x;
    const int i = tid >> 2;
    const int jb = (tid & 3) * 16;
    float4 s0 = {0,0,0,0}, s1 = {0,0,0,0}, s2 = {0,0,0,0}, s3 = {0,0,0,0};
    for (int c = 0; c < G_; c++) {
        long chunk = (long)bh * G_ + c;
        long off = chunk * 4096 + i * 64 + jb;
        *(float4*)&S[off + 0]  = s0;
        *(float4*)&S[off + 4]  = s1;
        *(float4*)&S[off + 8]  = s2;
        *(float4*)&S[off + 12] = s3;
        float pl = __expf(pL[chunk * 64 + i]);
        float4 d0 = *(const float4*)&D[off + 0];
        float4 d1 = *(const float4*)&D[off + 4];
        float4 d2 = *(const float4*)&D[off + 8];
        float4 d3 = *(const float4*)&D[off + 12];
        s0 = make_float4(fmaf(pl, s0.x, d0.x), fmaf(pl, s0.y, d0.y), fmaf(pl, s0.z, d0.z), fmaf(pl, s0.w, d0.w));
        s1 = make_float4(fmaf(pl, s1.x, d1.x), fmaf(pl, s1.y, d1.y), fmaf(pl, s1.z, d1.z), fmaf(pl, s1.w, d1.w));
        s2 = make_float4(fmaf(pl, s2.x, d2.x), fmaf(pl, s2.y, d2.y), fmaf(pl, s2.z, d2.z), fmaf(pl, s2.w, d2.w));
        s3 = make_float4(fmaf(pl, s3.x, d3.x), fmaf(pl, s3.y, d3.y), fmaf(pl, s3.z, d3.z), fmaf(pl, s3.w, d3.w));
    }
}

__global__ __launch_bounds__(256) void wkv_chunkC(
    const float* __restrict__ rp, const float* __restrict__ S,
    float* __restrict__ y)
{
    __shared__ float rps[64 * 64];
    __shared__ float Ss[64 * 64];
    const int tid = threadIdx.x;
    const int chunk = blockIdx.x;
    const int bh = chunk >> 5;
    const int c  = chunk & 31;
    const int b = bh >> 4, h = bh & 15;
    const long base = ((long)b * T_ + c * CHUNK) * C_ + h * 64;

    const float* rpg = rp + (long)chunk * 4096;
    const float* Sg  = S  + (long)chunk * 4096;
    #pragma unroll
    for (int e = 0; e < 4; e++) {
        int f4 = tid + 256 * e;
        *(float4*)&rps[f4 * 4] = *(const float4*)&rpg[f4 * 4];
        *(float4*)&Ss[f4 * 4]  = *(const float4*)&Sg[f4 * 4];
    }
    __syncthreads();

    int t0 = (tid >> 4) * 4, j0 = (tid & 15) * 4;
    float acc[4][4];
    #pragma unroll
    for (int a = 0; a < 4; a++)
        #pragma unroll
        for (int bq = 0; bq < 4; bq++) acc[a][bq] = 0.f;
    for (int ii = 0; ii < 64; ii++) {
        float4 a4 = *(const float4*)&rps[ii * 64 + t0];
        float4 b4 = *(const float4*)&Ss[ii * 64 + j0];
        float av[4] = { a4.x, a4.y, a4.z, a4.w };
        float bv[4] = { b4.x, b4.y, b4.z, b4.w };
        #pragma unroll
        for (int a = 0; a < 4; a++)
            #pragma unroll
            for (int bq = 0; bq < 4; bq++)
                acc[a][bq] = fmaf(av[a], bv[bq], acc[a][bq]);
    }
    #pragma unroll
    for (int a = 0; a < 4; a++) {
        long yo = base + (long)(t0 + a) * C_ + j0;
        float4 cur = *(const float4*)&y[yo];
        cur.x += acc[a][0]; cur.y += acc[a][1];
        cur.z += acc[a][2]; cur.w += acc[a][3];
        *(float4*)&y[yo] = cur;
    }
}

// ---------------- GroupNorm over heads + gate multiply (z tf32-rounded) ------
__global__ __launch_bounds__(512) void gn_kernel(
    const float* __restrict__ y, const float* __restrict__ ln_g,
    const float* __restrict__ ln_b, const float* __restrict__ g,
    float* __restrict__ z)
{
    const int bt = blockIdx.x;
    const int warp = threadIdx.x >> 5;
    const int lane = threadIdx.x & 31;
    const long base = (long)bt * C_ + warp * 64;

    float a0 = y[base + lane];
    float a1 = y[base + 32 + lane];
    float sum = a0 + a1;
    float sq = a0 * a0 + a1 * a1;
    #pragma unroll
    for (int off = 16; off > 0; off >>= 1) {
        sum += __shfl_xor_sync(0xffffffffu, sum, off);
        sq  += __shfl_xor_sync(0xffffffffu, sq,  off);
    }
    float mu = sum * (1.f / 64.f);
    float var = sq * (1.f / 64.f) - mu * mu;
    float inv = rsqrtf(var + 6.4e-4f);

    int c0 = warp * 64 + lane;
    float z0 = (a0 - mu) * inv * ln_g[c0] + ln_b[c0];
    float z1 = (a1 - mu) * inv * ln_g[c0 + 32] + ln_b[c0 + 32];
    z[base + lane]      = rndt(z0 * g[base + lane]);
    z[base + 32 + lane] = rndt(z1 * g[base + 32 + lane]);
}

// ---------------- launcher ----------------------------------------------------
extern "C" void kernel_launch(void* const* d_in, const int* in_sizes, int n_in,
                              void* d_out, int out_size)
{
    const float* x          = (const float*)d_in[0];
    const float* maa_x      = (const float*)d_in[1];
    const float* maa_w      = (const float*)d_in[2];
    const float* maa_k      = (const float*)d_in[3];
    const float* maa_v      = (const float*)d_in[4];
    const float* maa_r      = (const float*)d_in[5];
    const float* maa_g      = (const float*)d_in[6];
    const float* maa_w1     = (const float*)d_in[7];
    const float* maa_w2     = (const float*)d_in[8];
    const float* Wr         = (const float*)d_in[9];
    const float* Wk         = (const float*)d_in[10];
    const float* Wv         = (const float*)d_in[11];
    const float* Wo         = (const float*)d_in[12];
    const float* gate_w1    = (const float*)d_in[13];
    const float* gate_w2    = (const float*)d_in[14];
    const float* time_decay = (const float*)d_in[15];
    const float* decay_w1   = (const float*)d_in[16];
    const float* decay_w2   = (const float*)d_in[17];
    const float* u          = (const float*)d_in[18];
    const float* ln_g       = (const float*)d_in[19];
    const float* ln_b       = (const float*)d_in[20];
    (void)in_sizes; (void)n_in; (void)out_size;

    float *p_xx, *p_xxx, *p_xw, *p_xk, *p_xv, *p_xr, *p_xg;
    float *p_r, *p_k, *p_v, *p_w, *p_g, *p_y, *p_z, *p_lora, *p_s1, *p_s2;
    float *p_D, *p_Sc, *p_rp, *p_pL;
    float *p_WrT, *p_WkT, *p_WvT, *p_WoT, *p_w1T, *p_w2T, *p_dw1T, *p_gw1T, *p_dw2T, *p_gw2T;
    cudaGetSymbolAddress((void**)&p_xx, g_xx);
    cudaGetSymbolAddress((void**)&p_xxx, g_xxx);
    cudaGetSymbolAddress((void**)&p_xw, g_xw);
    cudaGetSymbolAddress((void**)&p_xk, g_xk);
    cudaGetSymbolAddress((void**)&p_xv, g_xv);
    cudaGetSymbolAddress((void**)&p_xr, g_xr);
    cudaGetSymbolAddress((void**)&p_xg, g_xg);
    cudaGetSymbolAddress((void**)&p_r, g_r);
    cudaGetSymbolAddress((void**)&p_k, g_k);
    cudaGetSymbolAddress((void**)&p_v, g_v);
    cudaGetSymbolAddress((void**)&p_w, g_w);
    cudaGetSymbolAddress((void**)&p_g, g_g);
    cudaGetSymbolAddress((void**)&p_y, g_y);
    cudaGetSymbolAddress((void**)&p_z, g_z);
    cudaGetSymbolAddress((void**)&p_lora, g_lora);
    cudaGetSymbolAddress((void**)&p_s1, g_small);
    cudaGetSymbolAddress((void**)&p_s2, g_small2);
    cudaGetSymbolAddress((void**)&p_D, g_D);
    cudaGetSymbolAddress((void**)&p_Sc, g_Sc);
    cudaGetSymbolAddress((void**)&p_rp, g_rp);
    cudaGetSymbolAddress((void**)&p_pL, g_pL);
    cudaGetSymbolAddress((void**)&p_WrT, g_WrT);
    cudaGetSymbolAddress((void**)&p_WkT, g_WkT);
    cudaGetSymbolAddress((void**)&p_WvT, g_WvT);
    cudaGetSymbolAddress((void**)&p_WoT, g_WoT);
    cudaGetSymbolAddress((void**)&p_w1T, g_w1T);
    cudaGetSymbolAddress((void**)&p_w2T, g_w2T);
    cudaGetSymbolAddress((void**)&p_dw1T, g_dw1T);
    cudaGetSymbolAddress((void**)&p_gw1T, g_gw1T);
    cudaGetSymbolAddress((void**)&p_dw2T, g_dw2T);
    cudaGetSymbolAddress((void**)&p_gw2T, g_gw2T);

    const long total = BTC;
    const int M = B_ * T_;          // 8192
    const int gy = M / 128;         // 64
    const int gy64 = M / 64;        // 128

    const int SMEM_A = (65 * 64 + 5 * 64 * STRD + 128) * 4;
    cudaFuncSetAttribute(wkv_chunkA, cudaFuncAttributeMaxDynamicSharedMemorySize, SMEM_A);
    cudaFuncSetAttribute(gemm_rkv, cudaFuncAttributeMaxDynamicSharedMemorySize, SMEM_G);
    cudaFuncSetAttribute(gemm_mix, cudaFuncAttributeMaxDynamicSharedMemorySize, SMEM_G);
    cudaFuncSetAttribute(gemm_dg2, cudaFuncAttributeMaxDynamicSharedMemorySize, SMEM_G);
    cudaFuncSetAttribute((const void*)gemm_tc<0, false>,
                         cudaFuncAttributeMaxDynamicSharedMemorySize, SMEM_G);

    // transpose job table
    TJobs tj;
    int toff = 0;
    {
        const float* srcs[10] = { maa_w1, maa_w2, Wr, Wk, Wv, Wo,
                                  decay_w1, gate_w1, decay_w2, gate_w2 };
        float* dsts[10] = { p_w1T, p_w2T, p_WrT, p_WkT, p_WvT, p_WoT,
                            p_dw1T, p_gw1T, p_dw2T, p_gw2T };
        int Rs[10] = { 1024, 160, 1024, 1024, 1024, 1024, 1024, 1024, 64, 64 };
        int Ns[10] = { 160, 1024, 1024, 1024, 1024, 1024, 64, 64, 1024, 1024 };
        for (int q = 0; q < 10; q++) {
            int nbx = (Ns[q] + 31) / 32;
            int nby = (Rs[q] + 31) / 32;
            tj.j[q].src = srcs[q]; tj.j[q].dst = dsts[q];
            tj.j[q].R = Rs[q]; tj.j[q].N = Ns[q];
            tj.j[q].nbx = nbx; tj.j[q].boff = toff;
            toff += nbx * nby;
        }
    }
    const int nshift = (int)(total / 4 / 256);   // 8192

    // 0. fused shift + transposes (xxx + weights tf32-rounded)
    pre_kernel<<<nshift + toff, 256>>>((const float4*)x, maa_x,
        (float4*)p_xx, (float4*)p_xxx, tj, nshift);
    // 1. lora = tanh(xxx @ maa_w1), rounded
    gemm_tc64<1, true><<<dim3(3, gy64), 128>>>(p_xxx, C_, p_w1T, C_, p_lora, 160, C_, 160, nullptr);
    // 2. merged 5-branch mix GEMM (256 thr, outputs rounded)
    gemm_mix<<<dim3(8, gy, 5), 256, SMEM_G>>>(p_lora, p_w2T, x, p_xx,
        maa_w, maa_k, maa_v, maa_r, maa_g,
        p_xw, p_xk, p_xv, p_xr, p_xg);
    // 3. merged r,k,v + decay1 + gate1 (128 thr)  <-- profiled by ncu
    gemm_rkv<<<dim3(8, gy, 5), 128, SMEM_G>>>(p_xr, p_xk, p_xv, p_xw, p_xg,
                                              p_WrT, p_WkT, p_WvT, p_dw1T, p_gw1T,
                                              p_r, p_k, p_v, p_s1, p_s2);
    // 4. merged decay2 + gate2 (256 thr)
    gemm_dg2<<<dim3(8, gy, 2), 256, SMEM_G>>>(p_s1, p_s2, p_dw2T, p_gw2T, p_w, p_g, time_decay);
    // 5-7. chunked WKV6
    wkv_chunkA<<<NCHUNK, 256, SMEM_A>>>(p_r, p_k, p_v, p_w, u, p_y, p_D, p_rp, p_pL);
    wkv_chunkB<<<B_ * H_, 256>>>(p_D, p_pL, p_Sc);
    wkv_chunkC<<<NCHUNK, 256>>>(p_rp, p_Sc, p_y);
    // 8. GroupNorm + gate multiply (z rounded)
    gn_kernel<<<M, 512>>>(p_y, ln_g, ln_b, p_g, p_z);
    // 9. out = z @ Wo (128 thr)
    gemm_tc<0, false><<<dim3(8, gy), 128, SMEM_G>>>(p_z, C_, p_WoT, C_, (float*)d_out, C_, C_, C_, nullptr);
}

// round 16
// speedup vs baseline: 1.5920x; 1.0051x over previous
#include <cuda_runtime.h>
#include <cuda_bf16.h>
#include <cstdint>
#include <math.h>

// Problem constants
#define B_  4
#define T_  2048
#define C_  1024
#define H_  16
#define N_  64
#define DMIX 32

#define CHUNK 64
#define G_ 32
#define NCHUNK (B_*H_*G_)         // 2048
#define STRD 68

static const long BTC = (long)B_ * T_ * C_;   // 8388608

// ---------------- scratch (device globals; no runtime allocation) -------------
__device__ float g_xx [ (long)B_*T_*C_ ];
__device__ float g_xxx[ (long)B_*T_*C_ ];
__device__ float g_xw [ (long)B_*T_*C_ ];
__device__ float g_xk [ (long)B_*T_*C_ ];
__device__ float g_xv [ (long)B_*T_*C_ ];
__device__ float g_xr [ (long)B_*T_*C_ ];
__device__ float g_xg [ (long)B_*T_*C_ ];
__device__ float g_r  [ (long)B_*T_*C_ ];
__device__ float g_k  [ (long)B_*T_*C_ ];
__device__ float g_v  [ (long)B_*T_*C_ ];
__device__ float g_w  [ (long)B_*T_*C_ ];
__device__ float g_g  [ (long)B_*T_*C_ ];
__device__ float g_y  [ (long)B_*T_*C_ ];
__device__ float g_z  [ (long)B_*T_*C_ ];
__device__ float g_lora [ (long)B_*T_*5*DMIX ];
__device__ float g_small [ (long)B_*T_*64 ];
__device__ float g_small2[ (long)B_*T_*64 ];
__device__ float g_D  [ (long)NCHUNK*64*64 ];
__device__ float g_Sc [ (long)NCHUNK*64*64 ];
__device__ float g_rp [ (long)NCHUNK*64*64 ];
__device__ float g_pL [ (long)NCHUNK*64 ];
__device__ float g_WrT[ (long)C_*C_ ];
__device__ float g_WkT[ (long)C_*C_ ];
__device__ float g_WvT[ (long)C_*C_ ];
__device__ float g_WoT[ (long)C_*C_ ];
__device__ float g_w1T[ (long)160*C_ ];
__device__ float g_w2T[ (long)C_*160 ];
__device__ float g_dw1T[ (long)64*C_ ];
__device__ float g_gw1T[ (long)64*C_ ];
__device__ float g_dw2T[ (long)C_*64 ];
__device__ float g_gw2T[ (long)C_*64 ];

// ================= helpers ====================================================
#define TSTR 20
#define STAGES 3

__device__ __forceinline__ uint32_t f2tf32(float f) {
    uint32_t o;
    asm("cvt.rna.tf32.f32 %0, %1;" : "=r"(o) : "f"(f));
    return o;
}
__device__ __forceinline__ float rndt(float f) {
    return __uint_as_float(f2tf32(f));
}
__device__ __forceinline__ uint32_t smem_u32(const void* p) {
    uint32_t a;
    asm("{ .reg .u64 t; cvta.to.shared.u64 t, %1; cvt.u32.u64 %0, t; }"
        : "=r"(a) : "l"(p));
    return a;
}
#define CP_A16(dst, src) \
    asm volatile("cp.async.cg.shared.global [%0], [%1], 16;" :: "r"(dst), "l"(src))
#define CP_COMMIT() asm volatile("cp.async.commit_group;" ::: "memory")
#define CP_WAIT(n)  asm volatile("cp.async.wait_group %0;" :: "n"(n) : "memory")

__device__ __forceinline__ void mma1688(float* d, const uint32_t* a, const uint32_t* b) {
    asm volatile(
        "mma.sync.aligned.m16n8k8.row.col.f32.tf32.tf32.f32 "
        "{%0,%1,%2,%3}, {%4,%5,%6,%7}, {%8,%9}, {%0,%1,%2,%3};"
        : "+f"(d[0]), "+f"(d[1]), "+f"(d[2]), "+f"(d[3])
        : "r"(a[0]), "r"(a[1]), "r"(a[2]), "r"(a[3]), "r"(b[0]), "r"(b[1]));
}

// ---- 128x128 body, geometry templated on TH --------------------------------
// TH=128: 4 warps 2x2, warp tile 64x64 (best for K=1024 compute-bound).
// TH=256: 8 warps 2x4, warp tile 64x32 (best for small-K memory-bound).
// Inputs MUST be pre-rounded tf32. EPI: 0 none, 1 tanh, 2 -exp(acc+bias),
// 3 xin+xxin*(bias+acc), -2 runtime repi (0/1/2). rrnd: runtime output rounding.
template<int TH, int EPI, bool RND>
__device__ __forceinline__ void gemm128_body(
    uint32_t* dynsm,
    const float* __restrict__ A, int lda,
    const float* __restrict__ Bt, int ldb,
    float* __restrict__ Cm, int ldc,
    int K, int Nn, const float* __restrict__ bias,
    const float* __restrict__ xin, const float* __restrict__ xxin,
    int row0, int col0, int repi, bool rrnd)
{
    constexpr int NI  = (TH == 256) ? 4 : 8;      // n-subtiles per warp
    constexpr int WCW = (TH == 256) ? 32 : 64;    // warp col width
    constexpr int LPT = 512 / TH;                 // float4 loads/thread/tile

    const int tid = threadIdx.x;
    const int lane = tid & 31;
    const int wid = tid >> 5;
    const int wr = (TH == 256) ? (wid >> 2) : (wid >> 1);
    const int wc = (TH == 256) ? (wid & 3) : (wid & 1);

    uint32_t* As = dynsm;
    uint32_t* Bs = dynsm + STAGES * 128 * TSTR;
    const uint32_t as0 = smem_u32(As);
    const uint32_t bs0 = smem_u32(Bs);

    auto issueStage = [&](int kc, int buf) {
        const int k0 = kc * 16;
        const uint32_t ao = as0 + buf * (128 * TSTR * 4);
        const uint32_t bo = bs0 + buf * (128 * TSTR * 4);
        #pragma unroll
        for (int l = 0; l < LPT; l++) {
            int e = tid + l * TH;
            int r = e >> 2, c = e & 3;
            uint32_t so = (uint32_t)(r * TSTR + (c << 2)) * 4u;
            CP_A16(ao + so, &A[(long)(row0 + r) * lda + k0 + (c << 2)]);
            CP_A16(bo + so, &Bt[(long)(col0 + r) * ldb + k0 + (c << 2)]);
        }
        CP_COMMIT();
    };

    float acc[4][NI][4];
    #pragma unroll
    for (int mi = 0; mi < 4; mi++)
        #pragma unroll
        for (int ni = 0; ni < NI; ni++)
            #pragma unroll
            for (int e = 0; e < 4; e++) acc[mi][ni][e] = 0.f;

    const int NKT = K >> 4;
    issueStage(0, 0);
    if (NKT > 1) issueStage(1, 1);

    const int lg = lane >> 2;
    const int lt = lane & 3;

    for (int kc = 0; kc < NKT; kc++) {
        const int buf = kc % 3;
        if (kc + 2 < NKT) { CP_WAIT(1); } else { CP_WAIT(0); }
        __syncthreads();

        const uint32_t* Ab = As + buf * 128 * TSTR;
        const uint32_t* Bb = Bs + buf * 128 * TSTR;
        #pragma unroll
        for (int ks = 0; ks < 2; ks++) {
            const int k0 = (ks << 3) + lt;
            uint32_t af[4][4], bf[NI][2];
            #pragma unroll
            for (int mi = 0; mi < 4; mi++) {
                int rm = wr * 64 + mi * 16 + lg;
                af[mi][0] = Ab[rm * TSTR + k0];
                af[mi][1] = Ab[(rm + 8) * TSTR + k0];
                af[mi][2] = Ab[rm * TSTR + k0 + 4];
                af[mi][3] = Ab[(rm + 8) * TSTR + k0 + 4];
            }
            #pragma unroll
            for (int ni = 0; ni < NI; ni++) {
                int cn = wc * WCW + ni * 8 + lg;
                bf[ni][0] = Bb[cn * TSTR + k0];
                bf[ni][1] = Bb[cn * TSTR + k0 + 4];
            }
            #pragma unroll
            for (int mi = 0; mi < 4; mi++)
                #pragma unroll
                for (int ni = 0; ni < NI; ni++)
                    mma1688(acc[mi][ni], af[mi], bf[ni]);
        }

        if (kc + 2 < NKT) issueStage(kc + 2, (kc + 2) % 3);
    }

    const int ep = (EPI == -2) ? repi : EPI;
    #pragma unroll
    for (int mi = 0; mi < 4; mi++) {
        int gr0 = row0 + wr * 64 + mi * 16 + lg;
        #pragma unroll
        for (int ni = 0; ni < NI; ni++) {
            int gc = col0 + wc * WCW + ni * 8 + 2 * lt;
            if (gc < Nn) {
                float v0 = acc[mi][ni][0], v1 = acc[mi][ni][1];
                float v2 = acc[mi][ni][2], v3 = acc[mi][ni][3];
                long o0 = (long)gr0 * ldc + gc;
                long o1 = (long)(gr0 + 8) * ldc + gc;
                if (ep == 1) {
                    v0 = tanhf(v0); v1 = tanhf(v1); v2 = tanhf(v2); v3 = tanhf(v3);
                } else if (ep == 2) {
                    float b0 = bias[gc], b1 = bias[gc + 1];
                    v0 = -expf(v0 + b0); v1 = -expf(v1 + b1);
                    v2 = -expf(v2 + b0); v3 = -expf(v3 + b1);
                } else if (ep == 3) {
                    float b0 = bias[gc], b1 = bias[gc + 1];
                    float2 x0 = *(const float2*)&xin[o0];
                    float2 x1 = *(const float2*)&xin[o1];
                    float2 d0 = *(const float2*)&xxin[o0];
                    float2 d1 = *(const float2*)&xxin[o1];
                    v0 = fmaf(d0.x, b0 + v0, x0.x);
                    v1 = fmaf(d0.y, b1 + v1, x0.y);
                    v2 = fmaf(d1.x, b0 + v2, x1.x);
                    v3 = fmaf(d1.y, b1 + v3, x1.y);
                }
                if (RND || rrnd) {
                    v0 = rndt(v0); v1 = rndt(v1); v2 = rndt(v2); v3 = rndt(v3);
                }
                *(float2*)&Cm[o0] = make_float2(v0, v1);
                *(float2*)&Cm[o1] = make_float2(v2, v3);
            }
        }
    }
}

#define SMEM_G (STAGES * 128 * TSTR * 4 * 2)   // 61440 bytes

// Wo projection: K=1024 compute-bound -> 128 threads
template<int EPI, bool RND>
__global__ __launch_bounds__(128, 2) void gemm_tc(
    const float* __restrict__ A, int lda,
    const float* __restrict__ Bt, int ldb,
    float* __restrict__ Cm, int ldc,
    int K, int Nn, const float* __restrict__ bias)
{
    extern __shared__ uint32_t dynsm[];
    gemm128_body<128, EPI, RND>(dynsm, A, lda, Bt, ldb, Cm, ldc, K, Nn, bias,
                                nullptr, nullptr, blockIdx.y * 128, blockIdx.x * 128,
                                0, false);
}

// merged r,k,v + decay1 + gate1, flattened 1D grid (no no-op CTAs):
// blocks [0,1536): z = b>>9 (rkv), tile = b&511 -> col0=(tile&7)*128, row0=(tile>>3)*128
// blocks [1536,1664): LoRA z=3,4: col0=0, row0=(e&63)*128
__global__ __launch_bounds__(128, 2) void gemm_rkv(
    const float* xr, const float* xk, const float* xv,
    const float* xw, const float* xg,
    const float* WrT, const float* WkT, const float* WvT,
    const float* dw1T, const float* gw1T,
    float* r, float* k, float* v, float* s1, float* s2)
{
    extern __shared__ uint32_t dynsm[];
    const int b = blockIdx.x;
    int z, col0, row0;
    if (b < 1536) {
        z = b >> 9;
        int t = b & 511;
        col0 = (t & 7) * 128;
        row0 = (t >> 3) * 128;
    } else {
        int e = b - 1536;
        z = 3 + (e >> 6);
        col0 = 0;
        row0 = (e & 63) * 128;
    }
    const float* A;
    const float* Bt;
    float* Cm;
    int Nn, ldc, repi;
    bool rr;
    if (z < 3) {
        A  = (z == 0) ? xr : (z == 1) ? xk : xv;
        Bt = (z == 0) ? WrT : (z == 1) ? WkT : WvT;
        Cm = (z == 0) ? r : (z == 1) ? k : v;
        Nn = C_; ldc = C_; repi = 0; rr = false;
    } else {
        A  = (z == 3) ? xw : xg;
        Bt = (z == 3) ? dw1T : gw1T;
        Cm = (z == 3) ? s1 : s2;
        Nn = 64; ldc = 64; repi = 1; rr = true;
    }
    gemm128_body<128, -2, false>(dynsm, A, C_, Bt, C_, Cm, ldc, C_, Nn, nullptr,
                                 nullptr, nullptr, row0, col0, repi, rr);
}

// merged decay2 + gate2: K=64 memory-bound -> 256 threads
__global__ __launch_bounds__(256, 2) void gemm_dg2(
    const float* small1, const float* small2,
    const float* dw2T, const float* gw2T,
    float* w, float* g, const float* time_decay)
{
    extern __shared__ uint32_t dynsm[];
    const int z = blockIdx.z;
    gemm128_body<256, -2, false>(dynsm, (z == 0) ? small1 : small2, 64,
                                 (z == 0) ? dw2T : gw2T, 64,
                                 (z == 0) ? w : g, C_, 64, C_, time_decay,
                                 nullptr, nullptr, blockIdx.y * 128, blockIdx.x * 128,
                                 (z == 0) ? 2 : 0, false);
}

// merged 5-branch mix: K=32 memory-bound -> 256 threads
__global__ __launch_bounds__(256, 2) void gemm_mix(
    const float* __restrict__ lora, const float* __restrict__ w2T,
    const float* __restrict__ x, const float* __restrict__ xx,
    const float* m0, const float* m1, const float* m2, const float* m3, const float* m4,
    float* o0, float* o1, float* o2, float* o3, float* o4)
{
    extern __shared__ uint32_t dynsm[];
    const int z = blockIdx.z;
    const float* bias = (z == 0) ? m0 : (z == 1) ? m1 : (z == 2) ? m2 : (z == 3) ? m3 : m4;
    float* out = (z == 0) ? o0 : (z == 1) ? o1 : (z == 2) ? o2 : (z == 3) ? o3 : o4;
    gemm128_body<256, 3, true>(dynsm, lora + z * DMIX, 160, w2T + z * DMIX, 160,
                               out, C_, DMIX, C_, bias, x, xx,
                               blockIdx.y * 128, blockIdx.x * 128, 0, false);
}

// ---- small tile: BM=64, BN=64, 128 threads (classic path) --------------------
template<int EPI, bool RND>
__device__ __forceinline__ void gemm64_body(
    uint32_t (*As)[64 * TSTR], uint32_t (*Bs)[64 * TSTR],
    const float* __restrict__ A, int lda,
    const float* __restrict__ Bt, int ldb,
    float* __restrict__ Cm, int ldc,
    int K, int Nn, const float* __restrict__ bias,
    int row0, int col0)
{
    const int tid = threadIdx.x;
    const int lane = tid & 31;
    const int wid = tid >> 5;
    const int wr = wid >> 1;
    const int wc = wid & 1;

    float4 ra[2], rb[2];

    auto loadAB = [&](int kc) {
        const int k0 = kc * 16;
        #pragma unroll
        for (int l = 0; l < 2; l++) {
            int e = tid + (l << 7);
            int r = e >> 2, c = e & 3;
            ra[l] = *(const float4*)&A[(long)(row0 + r) * lda + k0 + (c << 2)];
            int br = col0 + r;
            if (br < Nn)
                rb[l] = *(const float4*)&Bt[(long)br * ldb + k0 + (c << 2)];
            else
                rb[l] = make_float4(0.f, 0.f, 0.f, 0.f);
        }
    };
    auto storeAB = [&](int buf) {
        #pragma unroll
        for (int l = 0; l < 2; l++) {
            int e = tid + (l << 7);
            int r = e >> 2, c = e & 3;
            uint32_t* ap = &As[buf][r * TSTR + (c << 2)];
            ap[0] = f2tf32(ra[l].x); ap[1] = f2tf32(ra[l].y);
            ap[2] = f2tf32(ra[l].z); ap[3] = f2tf32(ra[l].w);
            uint32_t* bp = &Bs[buf][r * TSTR + (c << 2)];
            bp[0] = f2tf32(rb[l].x); bp[1] = f2tf32(rb[l].y);
            bp[2] = f2tf32(rb[l].z); bp[3] = f2tf32(rb[l].w);
        }
    };

    float acc[2][4][4];
    #pragma unroll
    for (int mi = 0; mi < 2; mi++)
        #pragma unroll
        for (int ni = 0; ni < 4; ni++)
            #pragma unroll
            for (int e = 0; e < 4; e++) acc[mi][ni][e] = 0.f;

    const int NKT = K >> 4;
    loadAB(0);
    storeAB(0);
    __syncthreads();

    const int lg = lane >> 2;
    const int lt = lane & 3;

    for (int kc = 0; kc < NKT; kc++) {
        const int cur = kc & 1;
        if (kc + 1 < NKT) loadAB(kc + 1);

        #pragma unroll
        for (int ks = 0; ks < 2; ks++) {
            const int k0 = (ks << 3) + lt;
            uint32_t af[2][4], bf[4][2];
            #pragma unroll
            for (int mi = 0; mi < 2; mi++) {
                int rm = wr * 32 + mi * 16 + lg;
                af[mi][0] = As[cur][rm * TSTR + k0];
                af[mi][1] = As[cur][(rm + 8) * TSTR + k0];
                af[mi][2] = As[cur][rm * TSTR + k0 + 4];
                af[mi][3] = As[cur][(rm + 8) * TSTR + k0 + 4];
            }
            #pragma unroll
            for (int ni = 0; ni < 4; ni++) {
                int cn = wc * 32 + ni * 8 + lg;
                bf[ni][0] = Bs[cur][cn * TSTR + k0];
                bf[ni][1] = Bs[cur][cn * TSTR + k0 + 4];
            }
            #pragma unroll
            for (int mi = 0; mi < 2; mi++)
                #pragma unroll
                for (int ni = 0; ni < 4; ni++)
                    mma1688(acc[mi][ni], af[mi], bf[ni]);
        }

        if (kc + 1 < NKT) storeAB(cur ^ 1);
        __syncthreads();
    }

    #pragma unroll
    for (int mi = 0; mi < 2; mi++) {
        int gr0 = row0 + wr * 32 + mi * 16 + lg;
        #pragma unroll
        for (int ni = 0; ni < 4; ni++) {
            int gc = col0 + wc * 32 + ni * 8 + 2 * lt;
            if (gc < Nn) {
                float v0 = acc[mi][ni][0], v1 = acc[mi][ni][1];
                float v2 = acc[mi][ni][2], v3 = acc[mi][ni][3];
                if (EPI == 1) {
                    v0 = tanhf(v0); v1 = tanhf(v1); v2 = tanhf(v2); v3 = tanhf(v3);
                }
                if (RND) {
                    v0 = rndt(v0); v1 = rndt(v1); v2 = rndt(v2); v3 = rndt(v3);
                }
                *(float2*)&Cm[(long)gr0 * ldc + gc] = make_float2(v0, v1);
                *(float2*)&Cm[(long)(gr0 + 8) * ldc + gc] = make_float2(v2, v3);
            }
        }
    }
}

template<int EPI, bool RND>
__global__ __launch_bounds__(128, 3) void gemm_tc64(
    const float* __restrict__ A, int lda,
    const float* __restrict__ Bt, int ldb,
    float* __restrict__ Cm, int ldc,
    int K, int Nn, const float* __restrict__ bias)
{
    __shared__ uint32_t As[2][64 * TSTR];
    __shared__ uint32_t Bs[2][64 * TSTR];
    gemm64_body<EPI, RND>(As, Bs, A, lda, Bt, ldb, Cm, ldc, K, Nn, bias,
                          blockIdx.y * 64, blockIdx.x * 64);
}

// ---------------- fused pre-pass: shift + all weight transposes --------------
struct TJob { const float* src; float* dst; int R, N, nbx, boff; };
struct TJobs { TJob j[10]; };

__global__ __launch_bounds__(256) void pre_kernel(
    const float4* __restrict__ x4, const float* __restrict__ maa_x,
    float4* __restrict__ xx4, float4* __restrict__ xxx4,
    TJobs js, int nshift)
{
    const int tid = threadIdx.x;
    if ((int)blockIdx.x < nshift) {
        long idx = (long)blockIdx.x * 256 + tid;
        const int C4 = C_ / 4;
        int c4 = (int)(idx % C4);
        long rt = idx / C4;
        int t = (int)(rt % T_);
        float4 xv = x4[idx];
        float4 xp = (t > 0) ? x4[idx - C4] : make_float4(0.f, 0.f, 0.f, 0.f);
        float4 mx = *(const float4*)&maa_x[c4 * 4];
        float4 d = make_float4(xp.x - xv.x, xp.y - xv.y, xp.z - xv.z, xp.w - xv.w);
        xx4[idx] = d;
        xxx4[idx] = make_float4(rndt(fmaf(d.x, mx.x, xv.x)), rndt(fmaf(d.y, mx.y, xv.y)),
                                rndt(fmaf(d.z, mx.z, xv.z)), rndt(fmaf(d.w, mx.w, xv.w)));
        return;
    }
    __shared__ float t[32][33];
    int b = blockIdx.x - nshift;
    int ji = 0;
    #pragma unroll
    for (int q = 1; q < 10; q++)
        if (b >= js.j[q].boff) ji = q;
    TJob jb = js.j[ji];
    int rem = b - jb.boff;
    int bx = (rem % jb.nbx) * 32;
    int by = (rem / jb.nbx) * 32;
    const int xq = tid & 31, yq = tid >> 5;
    #pragma unroll
    for (int i = 0; i < 32; i += 8) {
        int r = by + yq + i, n = bx + xq;
        if (r < jb.R && n < jb.N) t[yq + i][xq] = jb.src[(long)r * jb.N + n];
    }
    __syncthreads();
    #pragma unroll
    for (int i = 0; i < 32; i += 8) {
        int n = bx + yq + i, r = by + xq;
        if (n < jb.N && r < jb.R) jb.dst[(long)n * jb.R + r] = rndt(t[xq][yq + i]);
    }
}

// ---------------- chunked WKV6 -----------------------------------------------
__global__ __launch_bounds__(256, 2) void wkv_chunkA(
    const float* __restrict__ r, const float* __restrict__ k,
    const float* __restrict__ v, const float* __restrict__ lw,
    const float* __restrict__ u,
    float* __restrict__ y, float* __restrict__ Dout,
    float* __restrict__ rpout, float* __restrict__ pLout)
{
    extern __shared__ float sm[];
    float* lp   = sm;
    float* bufA = lp + 65 * 64;
    float* rpT  = bufA + 64 * STRD;
    float* kpT  = rpT + 64 * STRD;
    float* kpp  = kpT + 64 * STRD;
    float* vsm  = kpp + 64 * STRD;
    float* dsm  = vsm + 64 * STRD;
    float* usm  = dsm + 64;

    const int tid = threadIdx.x;
    const int chunk = blockIdx.x;
    const int bh = chunk >> 5;
    const int c  = chunk & 31;
    const int b = bh >> 4, h = bh & 15;
    const long base = ((long)b * T_ + c * CHUNK) * C_ + h * 64;

    if (tid < 64) usm[tid] = u[h * 64 + tid];
    const int i  = tid & 63;
    const int tq = tid >> 6;

    #pragma unroll
    for (int e = 0; e < 16; e++) {
        int t = tq + 4 * e;
        bufA[t * STRD + i] = lw[base + (long)t * C_ + i];
    }
    __syncthreads();

    if (tid < 64) {
        float run = 0.f;
        for (int t = 0; t < 64; t++) {
            lp[t * 64 + tid] = run;
            run += bufA[t * STRD + tid];
        }
        lp[64 * 64 + tid] = run;
        pLout[(long)chunk * 64 + tid] = run;
    }
    __syncthreads();

    #pragma unroll
    for (int e = 0; e < 16; e++) {
        int t = tq + 4 * e;
        long gi = base + (long)t * C_ + i;
        float rr = r[gi], kk = k[gi];
        float lpti = lp[t * 64 + i];
        float lpn  = lpti + bufA[t * STRD + i];
        float lpL  = lp[64 * 64 + i];
        rpT[i * STRD + t] = rr * __expf(lpti);
        kpT[i * STRD + t] = kk * __expf(-lpn);
        kpp[t * STRD + i] = kk * __expf(lpL - lpn);
        vsm[t * STRD + i] = v[gi];
    }
    {
        int t = tid >> 2, q = tid & 3;
        long gb = base + (long)t * C_;
        float p = 0.f;
        #pragma unroll
        for (int ii = 0; ii < 16; ii++) {
            int ci = q * 16 + ii;
            p += r[gb + ci] * usm[ci] * k[gb + ci];
        }
        p += __shfl_xor_sync(0xffffffffu, p, 1);
        p += __shfl_xor_sync(0xffffffffu, p, 2);
        if (q == 0) dsm[t] = p;
    }
    __syncthreads();

    {
        float* rpg = rpout + (long)chunk * 64 * 64;
        #pragma unroll
        for (int e = 0; e < 16; e++) {
            int flat = tid + 256 * e;
            rpg[flat] = rpT[(flat >> 6) * STRD + (flat & 63)];
        }
    }

    {
        int t0 = (tid >> 4) * 4, s0 = (tid & 15) * 4;
        float acc[4][4];
        #pragma unroll
        for (int a = 0; a < 4; a++)
            #pragma unroll
            for (int bq = 0; bq < 4; bq++) acc[a][bq] = 0.f;
        for (int ii = 0; ii < 64; ii++) {
            float4 a4 = *(const float4*)&rpT[ii * STRD + t0];
            float4 b4 = *(const float4*)&kpT[ii * STRD + s0];
            float av[4] = { a4.x, a4.y, a4.z, a4.w };
            float bv[4] = { b4.x, b4.y, b4.z, b4.w };
            #pragma unroll
            for (int a = 0; a < 4; a++)
                #pragma unroll
                for (int bq = 0; bq < 4; bq++)
                    acc[a][bq] = fmaf(av[a], bv[bq], acc[a][bq]);
        }
        __syncthreads();
        #pragma unroll
        for (int a = 0; a < 4; a++)
            #pragma unroll
            for (int bq = 0; bq < 4; bq++) {
                int tt = t0 + a, ss = s0 + bq;
                float val = (tt > ss) ? acc[a][bq] : ((tt == ss) ? dsm[tt] : 0.f);
                bufA[ss * STRD + tt] = val;
            }
    }
    __syncthreads();

    {
        int t0 = (tid >> 4) * 4, j0 = (tid & 15) * 4;
        float acc[4][4];
        #pragma unroll
        for (int a = 0; a < 4; a++)
            #pragma unroll
            for (int bq = 0; bq < 4; bq++) acc[a][bq] = 0.f;
        for (int s = 0; s < 64; s++) {
            float4 a4 = *(const float4*)&bufA[s * STRD + t0];
            float4 b4 = *(const float4*)&vsm[s * STRD + j0];
            float av[4] = { a4.x, a4.y, a4.z, a4.w };
            float bv[4] = { b4.x, b4.y, b4.z, b4.w };
            #pragma unroll
            for (int a = 0; a < 4; a++)
                #pragma unroll
                for (int bq = 0; bq < 4; bq++)
                    acc[a][bq] = fmaf(av[a], bv[bq], acc[a][bq]);
        }
        #pragma unroll
        for (int a = 0; a < 4; a++) {
            float4 o = make_float4(acc[a][0], acc[a][1], acc[a][2], acc[a][3]);
            *(float4*)&y[base + (long)(t0 + a) * C_ + j0] = o;
        }
    }

    {
        int i0 = (tid >> 4) * 4, j0 = (tid & 15) * 4;
        float acc[4][4];
        #pragma unroll
        for (int a = 0; a < 4; a++)
            #pragma unroll
            for (int bq = 0; bq < 4; bq++) acc[a][bq] = 0.f;
        for (int s = 0; s < 64; s++) {
            float4 a4 = *(const float4*)&kpp[s * STRD + i0];
            float4 b4 = *(const float4*)&vsm[s * STRD + j0];
            float av[4] = { a4.x, a4.y, a4.z, a4.w };
            float bv[4] = { b4.x, b4.y, b4.z, b4.w };
            #pragma unroll
            for (int a = 0; a < 4; a++)
                #pragma unroll
                for (int bq = 0; bq < 4; bq++)
                    acc[a][bq] = fmaf(av[a], bv[bq], acc[a][bq]);
        }
        float* Dp = Dout + (long)chunk * 4096;
        #pragma unroll
        for (int a = 0; a < 4; a++) {
            float4 o = make_float4(acc[a][0], acc[a][1], acc[a][2], acc[a][3]);
            *(float4*)&Dp[(i0 + a) * 64 + j0] = o;
        }
    }
}

__global__ __launch_bounds__(256) void wkv_chunkB(
    const float* __restrict__ D, const float* __restrict__ pL,
    float* __restrict__ S)
{
    const int bh = blockIdx.x;
    const int tid = threadIdx.x;
    const int i = tid >> 2;
    const int jb = (tid & 3) * 16;
    float4 s0 = {0,0,0,0}, s1 = {0,0,0,0}, s2 = {0,0,0,0}, s3 = {0,0,0,0};
    for (int c = 0; c < G_; c++) {
        long chunk = (long)bh * G_ + c;
        long off = chunk * 4096 + i * 64 + jb;
        *(float4*)&S[off + 0]  = s0;
        *(float4*)&S[off + 4]  = s1;
        *(float4*)&S[off + 8]  = s2;
        *(float4*)&S[off + 12] = s3;
        float pl = __expf(pL[chunk * 64 + i]);
        float4 d0 = *(const float4*)&D[off + 0];
        float4 d1 = *(const float4*)&D[off + 4];
        float4 d2 = *(const float4*)&D[off + 8];
        float4 d3 = *(const float4*)&D[off + 12];
        s0 = make_float4(fmaf(pl, s0.x, d0.x), fmaf(pl, s0.y, d0.y), fmaf(pl, s0.z, d0.z), fmaf(pl, s0.w, d0.w));
        s1 = make_float4(fmaf(pl, s1.x, d1.x), fmaf(pl, s1.y, d1.y), fmaf(pl, s1.z, d1.z), fmaf(pl, s1.w, d1.w));
        s2 = make_float4(fmaf(pl, s2.x, d2.x), fmaf(pl, s2.y, d2.y), fmaf(pl, s2.z, d2.z), fmaf(pl, s2.w, d2.w));
        s3 = make_float4(fmaf(pl, s3.x, d3.x), fmaf(pl, s3.y, d3.y), fmaf(pl, s3.z, d3.z), fmaf(pl, s3.w, d3.w));
    }
}

__global__ __launch_bounds__(256) void wkv_chunkC(
    const float* __restrict__ rp, const float* __restrict__ S,
    float* __restrict__ y)
{
    __shared__ float rps[64 * 64];
    __shared__ float Ss[64 * 64];
    const int tid = threadIdx.x;
    const int chunk = blockIdx.x;
    const int bh = chunk >> 5;
    const int c  = chunk & 31;
    const int b = bh >> 4, h = bh & 15;
    const long base = ((long)b * T_ + c * CHUNK) * C_ + h * 64;

    const float* rpg = rp + (long)chunk * 4096;
    const float* Sg  = S  + (long)chunk * 4096;
    #pragma unroll
    for (int e = 0; e < 4; e++) {
        int f4 = tid + 256 * e;
        *(float4*)&rps[f4 * 4] = *(const float4*)&rpg[f4 * 4];
        *(float4*)&Ss[f4 * 4]  = *(const float4*)&Sg[f4 * 4];
    }
    __syncthreads();

    int t0 = (tid >> 4) * 4, j0 = (tid & 15) * 4;
    float acc[4][4];
    #pragma unroll
    for (int a = 0; a < 4; a++)
        #pragma unroll
        for (int bq = 0; bq < 4; bq++) acc[a][bq] = 0.f;
    for (int ii = 0; ii < 64; ii++) {
        float4 a4 = *(const float4*)&rps[ii * 64 + t0];
        float4 b4 = *(const float4*)&Ss[ii * 64 + j0];
        float av[4] = { a4.x, a4.y, a4.z, a4.w };
        float bv[4] = { b4.x, b4.y, b4.z, b4.w };
        #pragma unroll
        for (int a = 0; a < 4; a++)
            #pragma unroll
            for (int bq = 0; bq < 4; bq++)
                acc[a][bq] = fmaf(av[a], bv[bq], acc[a][bq]);
    }
    #pragma unroll
    for (int a = 0; a < 4; a++) {
        long yo = base + (long)(t0 + a) * C_ + j0;
        float4 cur = *(const float4*)&y[yo];
        cur.x += acc[a][0]; cur.y += acc[a][1];
        cur.z += acc[a][2]; cur.w += acc[a][3];
        *(float4*)&y[yo] = cur;
    }
}

// ---------------- GroupNorm over heads + gate multiply (z tf32-rounded) ------
__global__ __launch_bounds__(512) void gn_kernel(
    const float* __restrict__ y, const float* __restrict__ ln_g,
    const float* __restrict__ ln_b, const float* __restrict__ g,
    float* __restrict__ z)
{
    const int bt = blockIdx.x;
    const int warp = threadIdx.x >> 5;
    const int lane = threadIdx.x & 31;
    const long base = (long)bt * C_ + warp * 64;

    float a0 = y[base + lane];
    float a1 = y[base + 32 + lane];
    float sum = a0 + a1;
    float sq = a0 * a0 + a1 * a1;
    #pragma unroll
    for (int off = 16; off > 0; off >>= 1) {
        sum += __shfl_xor_sync(0xffffffffu, sum, off);
        sq  += __shfl_xor_sync(0xffffffffu, sq,  off);
    }
    float mu = sum * (1.f / 64.f);
    float var = sq * (1.f / 64.f) - mu * mu;
    float inv = rsqrtf(var + 6.4e-4f);

    int c0 = warp * 64 + lane;
    float z0 = (a0 - mu) * inv * ln_g[c0] + ln_b[c0];
    float z1 = (a1 - mu) * inv * ln_g[c0 + 32] + ln_b[c0 + 32];
    z[base + lane]      = rndt(z0 * g[base + lane]);
    z[base + 32 + lane] = rndt(z1 * g[base + 32 + lane]);
}

// ---------------- launcher ----------------------------------------------------
extern "C" void kernel_launch(void* const* d_in, const int* in_sizes, int n_in,
                              void* d_out, int out_size)
{
    const float* x          = (const float*)d_in[0];
    const float* maa_x      = (const float*)d_in[1];
    const float* maa_w      = (const float*)d_in[2];
    const float* maa_k      = (const float*)d_in[3];
    const float* maa_v      = (const float*)d_in[4];
    const float* maa_r      = (const float*)d_in[5];
    const float* maa_g      = (const float*)d_in[6];
    const float* maa_w1     = (const float*)d_in[7];
    const float* maa_w2     = (const float*)d_in[8];
    const float* Wr         = (const float*)d_in[9];
    const float* Wk         = (const float*)d_in[10];
    const float* Wv         = (const float*)d_in[11];
    const float* Wo         = (const float*)d_in[12];
    const float* gate_w1    = (const float*)d_in[13];
    const float* gate_w2    = (const float*)d_in[14];
    const float* time_decay = (const float*)d_in[15];
    const float* decay_w1   = (const float*)d_in[16];
    const float* decay_w2   = (const float*)d_in[17];
    const float* u          = (const float*)d_in[18];
    const float* ln_g       = (const float*)d_in[19];
    const float* ln_b       = (const float*)d_in[20];
    (void)in_sizes; (void)n_in; (void)out_size;

    float *p_xx, *p_xxx, *p_xw, *p_xk, *p_xv, *p_xr, *p_xg;
    float *p_r, *p_k, *p_v, *p_w, *p_g, *p_y, *p_z, *p_lora, *p_s1, *p_s2;
    float *p_D, *p_Sc, *p_rp, *p_pL;
    float *p_WrT, *p_WkT, *p_WvT, *p_WoT, *p_w1T, *p_w2T, *p_dw1T, *p_gw1T, *p_dw2T, *p_gw2T;
    cudaGetSymbolAddress((void**)&p_xx, g_xx);
    cudaGetSymbolAddress((void**)&p_xxx, g_xxx);
    cudaGetSymbolAddress((void**)&p_xw, g_xw);
    cudaGetSymbolAddress((void**)&p_xk, g_xk);
    cudaGetSymbolAddress((void**)&p_xv, g_xv);
    cudaGetSymbolAddress((void**)&p_xr, g_xr);
    cudaGetSymbolAddress((void**)&p_xg, g_xg);
    cudaGetSymbolAddress((void**)&p_r, g_r);
    cudaGetSymbolAddress((void**)&p_k, g_k);
    cudaGetSymbolAddress((void**)&p_v, g_v);
    cudaGetSymbolAddress((void**)&p_w, g_w);
    cudaGetSymbolAddress((void**)&p_g, g_g);
    cudaGetSymbolAddress((void**)&p_y, g_y);
    cudaGetSymbolAddress((void**)&p_z, g_z);
    cudaGetSymbolAddress((void**)&p_lora, g_lora);
    cudaGetSymbolAddress((void**)&p_s1, g_small);
    cudaGetSymbolAddress((void**)&p_s2, g_small2);
    cudaGetSymbolAddress((void**)&p_D, g_D);
    cudaGetSymbolAddress((void**)&p_Sc, g_Sc);
    cudaGetSymbolAddress((void**)&p_rp, g_rp);
    cudaGetSymbolAddress((void**)&p_pL, g_pL);
    cudaGetSymbolAddress((void**)&p_WrT, g_WrT);
    cudaGetSymbolAddress((void**)&p_WkT, g_WkT);
    cudaGetSymbolAddress((void**)&p_WvT, g_WvT);
    cudaGetSymbolAddress((void**)&p_WoT, g_WoT);
    cudaGetSymbolAddress((void**)&p_w1T, g_w1T);
    cudaGetSymbolAddress((void**)&p_w2T, g_w2T);
    cudaGetSymbolAddress((void**)&p_dw1T, g_dw1T);
    cudaGetSymbolAddress((void**)&p_gw1T, g_gw1T);
    cudaGetSymbolAddress((void**)&p_dw2T, g_dw2T);
    cudaGetSymbolAddress((void**)&p_gw2T, g_gw2T);

    const long total = BTC;
    const int M = B_ * T_;          // 8192
    const int gy = M / 128;         // 64
    const int gy64 = M / 64;        // 128

    const int SMEM_A = (65 * 64 + 5 * 64 * STRD + 128) * 4;
    cudaFuncSetAttribute(wkv_chunkA, cudaFuncAttributeMaxDynamicSharedMemorySize, SMEM_A);
    cudaFuncSetAttribute(gemm_rkv, cudaFuncAttributeMaxDynamicSharedMemorySize, SMEM_G);
    cudaFuncSetAttribute(gemm_mix, cudaFuncAttributeMaxDynamicSharedMemorySize, SMEM_G);
    cudaFuncSetAttribute(gemm_dg2, cudaFuncAttributeMaxDynamicSharedMemorySize, SMEM_G);
    cudaFuncSetAttribute((const void*)gemm_tc<0, false>,
                         cudaFuncAttributeMaxDynamicSharedMemorySize, SMEM_G);

    // transpose job table
    TJobs tj;
    int toff = 0;
    {
        const float* srcs[10] = { maa_w1, maa_w2, Wr, Wk, Wv, Wo,
                                  decay_w1, gate_w1, decay_w2, gate_w2 };
        float* dsts[10] = { p_w1T, p_w2T, p_WrT, p_WkT, p_WvT, p_WoT,
                            p_dw1T, p_gw1T, p_dw2T, p_gw2T };
        int Rs[10] = { 1024, 160, 1024, 1024, 1024, 1024, 1024, 1024, 64, 64 };
        int Ns[10] = { 160, 1024, 1024, 1024, 1024, 1024, 64, 64, 1024, 1024 };
        for (int q = 0; q < 10; q++) {
            int nbx = (Ns[q] + 31) / 32;
            int nby = (Rs[q] + 31) / 32;
            tj.j[q].src = srcs[q]; tj.j[q].dst = dsts[q];
            tj.j[q].R = Rs[q]; tj.j[q].N = Ns[q];
            tj.j[q].nbx = nbx; tj.j[q].boff = toff;
            toff += nbx * nby;
        }
    }
    const int nshift = (int)(total / 4 / 256);   // 8192

    // 0. fused shift + transposes (xxx + weights tf32-rounded)
    pre_kernel<<<nshift + toff, 256>>>((const float4*)x, maa_x,
        (float4*)p_xx, (float4*)p_xxx, tj, nshift);
    // 1. lora = tanh(xxx @ maa_w1), rounded
    gemm_tc64<1, true><<<dim3(3, gy64), 128>>>(p_xxx, C_, p_w1T, C_, p_lora, 160, C_, 160, nullptr);
    // 2. merged 5-branch mix GEMM (256 thr, outputs rounded)
    gemm_mix<<<dim3(8, gy, 5), 256, SMEM_G>>>(p_lora, p_w2T, x, p_xx,
        maa_w, maa_k, maa_v, maa_r, maa_g,
        p_xw, p_xk, p_xv, p_xr, p_xg);
    // 3. merged r,k,v + decay1 + gate1, flattened grid (128 thr) <-- profiled
    gemm_rkv<<<1664, 128, SMEM_G>>>(p_xr, p_xk, p_xv, p_xw, p_xg,
                                    p_WrT, p_WkT, p_WvT, p_dw1T, p_gw1T,
                                    p_r, p_k, p_v, p_s1, p_s2);
    // 4. merged decay2 + gate2 (256 thr)
    gemm_dg2<<<dim3(8, gy, 2), 256, SMEM_G>>>(p_s1, p_s2, p_dw2T, p_gw2T, p_w, p_g, time_decay);
    // 5-7. chunked WKV6 (chunkA now 2 CTAs/SM)
    wkv_chunkA<<<NCHUNK, 256, SMEM_A>>>(p_r, p_k, p_v, p_w, u, p_y, p_D, p_rp, p_pL);
    wkv_chunkB<<<B_ * H_, 256>>>(p_D, p_pL, p_Sc);
    wkv_chunkC<<<NCHUNK, 256>>>(p_rp, p_Sc, p_y);
    // 8. GroupNorm + gate multiply (z rounded)
    gn_kernel<<<M, 512>>>(p_y, ln_g, ln_b, p_g, p_z);
    // 9. out = z @ Wo (128 thr)
    gemm_tc<0, false><<<dim3(8, gy), 128, SMEM_G>>>(p_z, C_, p_WoT, C_, (float*)d_out, C_, C_, C_, nullptr);
}

// round 17
// speedup vs baseline: 1.6159x; 1.0150x over previous
#include <cuda_runtime.h>
#include <cuda_bf16.h>
#include <cstdint>
#include <math.h>

// Problem constants
#define B_  4
#define T_  2048
#define C_  1024
#define H_  16
#define N_  64
#define DMIX 32

#define CHUNK 64
#define G_ 32
#define NCHUNK (B_*H_*G_)         // 2048
#define STRD 68

static const long BTC = (long)B_ * T_ * C_;   // 8388608

// ---------------- scratch (device globals; no runtime allocation) -------------
__device__ float g_xx [ (long)B_*T_*C_ ];
__device__ float g_xxx[ (long)B_*T_*C_ ];
__device__ float g_xw [ (long)B_*T_*C_ ];
__device__ float g_xk [ (long)B_*T_*C_ ];
__device__ float g_xv [ (long)B_*T_*C_ ];
__device__ float g_xr [ (long)B_*T_*C_ ];
__device__ float g_xg [ (long)B_*T_*C_ ];
__device__ float g_r  [ (long)B_*T_*C_ ];
__device__ float g_k  [ (long)B_*T_*C_ ];
__device__ float g_v  [ (long)B_*T_*C_ ];
__device__ float g_w  [ (long)B_*T_*C_ ];
__device__ float g_g  [ (long)B_*T_*C_ ];
__device__ float g_y  [ (long)B_*T_*C_ ];
__device__ float g_z  [ (long)B_*T_*C_ ];
__device__ float g_lora [ (long)B_*T_*5*DMIX ];
__device__ float g_small [ (long)B_*T_*64 ];
__device__ float g_small2[ (long)B_*T_*64 ];
__device__ float g_D  [ (long)NCHUNK*64*64 ];
__device__ float g_Sc [ (long)NCHUNK*64*64 ];
__device__ float g_rp [ (long)NCHUNK*64*64 ];
__device__ float g_pL [ (long)NCHUNK*64 ];
__device__ float g_WrT[ (long)C_*C_ ];
__device__ float g_WkT[ (long)C_*C_ ];
__device__ float g_WvT[ (long)C_*C_ ];
__device__ float g_WoT[ (long)C_*C_ ];
__device__ float g_w1T[ (long)160*C_ ];
__device__ float g_w2T[ (long)C_*160 ];
__device__ float g_dw1T[ (long)64*C_ ];
__device__ float g_gw1T[ (long)64*C_ ];
__device__ float g_dw2T[ (long)C_*64 ];
__device__ float g_gw2T[ (long)C_*64 ];

// ================= helpers ====================================================
#define TSTR 20
#define STAGES 3

__device__ __forceinline__ uint32_t f2tf32(float f) {
    uint32_t o;
    asm("cvt.rna.tf32.f32 %0, %1;" : "=r"(o) : "f"(f));
    return o;
}
__device__ __forceinline__ float rndt(float f) {
    return __uint_as_float(f2tf32(f));
}
__device__ __forceinline__ uint32_t smem_u32(const void* p) {
    uint32_t a;
    asm("{ .reg .u64 t; cvta.to.shared.u64 t, %1; cvt.u32.u64 %0, t; }"
        : "=r"(a) : "l"(p));
    return a;
}
#define CP_A16(dst, src) \
    asm volatile("cp.async.cg.shared.global [%0], [%1], 16;" :: "r"(dst), "l"(src))
#define CP_COMMIT() asm volatile("cp.async.commit_group;" ::: "memory")
#define CP_WAIT(n)  asm volatile("cp.async.wait_group %0;" :: "n"(n) : "memory")

__device__ __forceinline__ void mma1688(float* d, const uint32_t* a, const uint32_t* b) {
    asm volatile(
        "mma.sync.aligned.m16n8k8.row.col.f32.tf32.tf32.f32 "
        "{%0,%1,%2,%3}, {%4,%5,%6,%7}, {%8,%9}, {%0,%1,%2,%3};"
        : "+f"(d[0]), "+f"(d[1]), "+f"(d[2]), "+f"(d[3])
        : "r"(a[0]), "r"(a[1]), "r"(a[2]), "r"(a[3]), "r"(b[0]), "r"(b[1]));
}

// ---- 128x128 body, geometry templated on TH --------------------------------
// TH=128: 4 warps 2x2, warp tile 64x64 (best for K=1024 compute-bound).
// TH=256: 8 warps 2x4, warp tile 64x32 (best for small-K memory-bound).
// Inputs MUST be pre-rounded tf32. EPI: 0 none, 1 tanh, 2 -exp(acc+bias),
// 3 xin+xxin*(bias+acc), -2 runtime repi (0/1/2). rrnd: runtime output rounding.
template<int TH, int EPI, bool RND>
__device__ __forceinline__ void gemm128_body(
    uint32_t* dynsm,
    const float* __restrict__ A, int lda,
    const float* __restrict__ Bt, int ldb,
    float* __restrict__ Cm, int ldc,
    int K, int Nn, const float* __restrict__ bias,
    const float* __restrict__ xin, const float* __restrict__ xxin,
    int row0, int col0, int repi, bool rrnd)
{
    constexpr int NI  = (TH == 256) ? 4 : 8;
    constexpr int WCW = (TH == 256) ? 32 : 64;
    constexpr int LPT = 512 / TH;

    const int tid = threadIdx.x;
    const int lane = tid & 31;
    const int wid = tid >> 5;
    const int wr = (TH == 256) ? (wid >> 2) : (wid >> 1);
    const int wc = (TH == 256) ? (wid & 3) : (wid & 1);

    uint32_t* As = dynsm;
    uint32_t* Bs = dynsm + STAGES * 128 * TSTR;
    const uint32_t as0 = smem_u32(As);
    const uint32_t bs0 = smem_u32(Bs);

    auto issueStage = [&](int kc, int buf) {
        const int k0 = kc * 16;
        const uint32_t ao = as0 + buf * (128 * TSTR * 4);
        const uint32_t bo = bs0 + buf * (128 * TSTR * 4);
        #pragma unroll
        for (int l = 0; l < LPT; l++) {
            int e = tid + l * TH;
            int r = e >> 2, c = e & 3;
            uint32_t so = (uint32_t)(r * TSTR + (c << 2)) * 4u;
            CP_A16(ao + so, &A[(long)(row0 + r) * lda + k0 + (c << 2)]);
            CP_A16(bo + so, &Bt[(long)(col0 + r) * ldb + k0 + (c << 2)]);
        }
        CP_COMMIT();
    };

    float acc[4][NI][4];
    #pragma unroll
    for (int mi = 0; mi < 4; mi++)
        #pragma unroll
        for (int ni = 0; ni < NI; ni++)
            #pragma unroll
            for (int e = 0; e < 4; e++) acc[mi][ni][e] = 0.f;

    const int NKT = K >> 4;
    issueStage(0, 0);
    if (NKT > 1) issueStage(1, 1);

    const int lg = lane >> 2;
    const int lt = lane & 3;

    for (int kc = 0; kc < NKT; kc++) {
        const int buf = kc % 3;
        if (kc + 2 < NKT) { CP_WAIT(1); } else { CP_WAIT(0); }
        __syncthreads();

        const uint32_t* Ab = As + buf * 128 * TSTR;
        const uint32_t* Bb = Bs + buf * 128 * TSTR;
        #pragma unroll
        for (int ks = 0; ks < 2; ks++) {
            const int k0 = (ks << 3) + lt;
            uint32_t af[4][4], bf[NI][2];
            #pragma unroll
            for (int mi = 0; mi < 4; mi++) {
                int rm = wr * 64 + mi * 16 + lg;
                af[mi][0] = Ab[rm * TSTR + k0];
                af[mi][1] = Ab[(rm + 8) * TSTR + k0];
                af[mi][2] = Ab[rm * TSTR + k0 + 4];
                af[mi][3] = Ab[(rm + 8) * TSTR + k0 + 4];
            }
            #pragma unroll
            for (int ni = 0; ni < NI; ni++) {
                int cn = wc * WCW + ni * 8 + lg;
                bf[ni][0] = Bb[cn * TSTR + k0];
                bf[ni][1] = Bb[cn * TSTR + k0 + 4];
            }
            #pragma unroll
            for (int mi = 0; mi < 4; mi++)
                #pragma unroll
                for (int ni = 0; ni < NI; ni++)
                    mma1688(acc[mi][ni], af[mi], bf[ni]);
        }

        if (kc + 2 < NKT) issueStage(kc + 2, (kc + 2) % 3);
    }

    const int ep = (EPI == -2) ? repi : EPI;
    #pragma unroll
    for (int mi = 0; mi < 4; mi++) {
        int gr0 = row0 + wr * 64 + mi * 16 + lg;
        #pragma unroll
        for (int ni = 0; ni < NI; ni++) {
            int gc = col0 + wc * WCW + ni * 8 + 2 * lt;
            if (gc < Nn) {
                float v0 = acc[mi][ni][0], v1 = acc[mi][ni][1];
                float v2 = acc[mi][ni][2], v3 = acc[mi][ni][3];
                long o0 = (long)gr0 * ldc + gc;
                long o1 = (long)(gr0 + 8) * ldc + gc;
                if (ep == 1) {
                    v0 = tanhf(v0); v1 = tanhf(v1); v2 = tanhf(v2); v3 = tanhf(v3);
                } else if (ep == 2) {
                    float b0 = bias[gc], b1 = bias[gc + 1];
                    v0 = -expf(v0 + b0); v1 = -expf(v1 + b1);
                    v2 = -expf(v2 + b0); v3 = -expf(v3 + b1);
                } else if (ep == 3) {
                    float b0 = bias[gc], b1 = bias[gc + 1];
                    float2 x0 = *(const float2*)&xin[o0];
                    float2 x1 = *(const float2*)&xin[o1];
                    float2 d0 = *(const float2*)&xxin[o0];
                    float2 d1 = *(const float2*)&xxin[o1];
                    v0 = fmaf(d0.x, b0 + v0, x0.x);
                    v1 = fmaf(d0.y, b1 + v1, x0.y);
                    v2 = fmaf(d1.x, b0 + v2, x1.x);
                    v3 = fmaf(d1.y, b1 + v3, x1.y);
                }
                if (RND || rrnd) {
                    v0 = rndt(v0); v1 = rndt(v1); v2 = rndt(v2); v3 = rndt(v3);
                }
                *(float2*)&Cm[o0] = make_float2(v0, v1);
                *(float2*)&Cm[o1] = make_float2(v2, v3);
            }
        }
    }
}

#define SMEM_G (STAGES * 128 * TSTR * 4 * 2)   // 61440 bytes

// Wo projection: K=1024 compute-bound -> 128 threads
template<int EPI, bool RND>
__global__ __launch_bounds__(128, 2) void gemm_tc(
    const float* __restrict__ A, int lda,
    const float* __restrict__ Bt, int ldb,
    float* __restrict__ Cm, int ldc,
    int K, int Nn, const float* __restrict__ bias)
{
    extern __shared__ uint32_t dynsm[];
    gemm128_body<128, EPI, RND>(dynsm, A, lda, Bt, ldb, Cm, ldc, K, Nn, bias,
                                nullptr, nullptr, blockIdx.y * 128, blockIdx.x * 128,
                                0, false);
}

// lora = tanh(xxx @ w1T^T), N=160, K=1024 -> 128-thread cp.async body
__global__ __launch_bounds__(128, 2) void gemm_lora(
    const float* __restrict__ xxx, const float* __restrict__ w1T,
    float* __restrict__ lora)
{
    extern __shared__ uint32_t dynsm[];
    gemm128_body<128, 1, true>(dynsm, xxx, C_, w1T, C_, lora, 160, C_, 160,
                               nullptr, nullptr, nullptr,
                               blockIdx.y * 128, blockIdx.x * 128, 0, false);
}

// merged r,k,v + decay1 + gate1, flattened 1D grid
__global__ __launch_bounds__(128, 2) void gemm_rkv(
    const float* xr, const float* xk, const float* xv,
    const float* xw, const float* xg,
    const float* WrT, const float* WkT, const float* WvT,
    const float* dw1T, const float* gw1T,
    float* r, float* k, float* v, float* s1, float* s2)
{
    extern __shared__ uint32_t dynsm[];
    const int b = blockIdx.x;
    int z, col0, row0;
    if (b < 1536) {
        z = b >> 9;
        int t = b & 511;
        col0 = (t & 7) * 128;
        row0 = (t >> 3) * 128;
    } else {
        int e = b - 1536;
        z = 3 + (e >> 6);
        col0 = 0;
        row0 = (e & 63) * 128;
    }
    const float* A;
    const float* Bt;
    float* Cm;
    int Nn, ldc, repi;
    bool rr;
    if (z < 3) {
        A  = (z == 0) ? xr : (z == 1) ? xk : xv;
        Bt = (z == 0) ? WrT : (z == 1) ? WkT : WvT;
        Cm = (z == 0) ? r : (z == 1) ? k : v;
        Nn = C_; ldc = C_; repi = 0; rr = false;
    } else {
        A  = (z == 3) ? xw : xg;
        Bt = (z == 3) ? dw1T : gw1T;
        Cm = (z == 3) ? s1 : s2;
        Nn = 64; ldc = 64; repi = 1; rr = true;
    }
    gemm128_body<128, -2, false>(dynsm, A, C_, Bt, C_, Cm, ldc, C_, Nn, nullptr,
                                 nullptr, nullptr, row0, col0, repi, rr);
}

// merged decay2 + gate2: K=64 memory-bound -> 256 threads
__global__ __launch_bounds__(256, 2) void gemm_dg2(
    const float* small1, const float* small2,
    const float* dw2T, const float* gw2T,
    float* w, float* g, const float* time_decay)
{
    extern __shared__ uint32_t dynsm[];
    const int z = blockIdx.z;
    gemm128_body<256, -2, false>(dynsm, (z == 0) ? small1 : small2, 64,
                                 (z == 0) ? dw2T : gw2T, 64,
                                 (z == 0) ? w : g, C_, 64, C_, time_decay,
                                 nullptr, nullptr, blockIdx.y * 128, blockIdx.x * 128,
                                 (z == 0) ? 2 : 0, false);
}

// merged 5-branch mix: K=32 memory-bound -> 256 threads
__global__ __launch_bounds__(256, 2) void gemm_mix(
    const float* __restrict__ lora, const float* __restrict__ w2T,
    const float* __restrict__ x, const float* __restrict__ xx,
    const float* m0, const float* m1, const float* m2, const float* m3, const float* m4,
    float* o0, float* o1, float* o2, float* o3, float* o4)
{
    extern __shared__ uint32_t dynsm[];
    const int z = blockIdx.z;
    const float* bias = (z == 0) ? m0 : (z == 1) ? m1 : (z == 2) ? m2 : (z == 3) ? m3 : m4;
    float* out = (z == 0) ? o0 : (z == 1) ? o1 : (z == 2) ? o2 : (z == 3) ? o3 : o4;
    gemm128_body<256, 3, true>(dynsm, lora + z * DMIX, 160, w2T + z * DMIX, 160,
                               out, C_, DMIX, C_, bias, x, xx,
                               blockIdx.y * 128, blockIdx.x * 128, 0, false);
}

// ---------------- fused pre-pass: shift + all weight transposes --------------
struct TJob { const float* src; float* dst; int R, N, nbx, boff; };
struct TJobs { TJob j[10]; };

__global__ __launch_bounds__(256) void pre_kernel(
    const float4* __restrict__ x4, const float* __restrict__ maa_x,
    float4* __restrict__ xx4, float4* __restrict__ xxx4,
    TJobs js, int nshift)
{
    const int tid = threadIdx.x;
    if ((int)blockIdx.x < nshift) {
        long idx = (long)blockIdx.x * 256 + tid;
        const int C4 = C_ / 4;
        int c4 = (int)(idx % C4);
        long rt = idx / C4;
        int t = (int)(rt % T_);
        float4 xv = x4[idx];
        float4 xp = (t > 0) ? x4[idx - C4] : make_float4(0.f, 0.f, 0.f, 0.f);
        float4 mx = *(const float4*)&maa_x[c4 * 4];
        float4 d = make_float4(xp.x - xv.x, xp.y - xv.y, xp.z - xv.z, xp.w - xv.w);
        xx4[idx] = d;
        xxx4[idx] = make_float4(rndt(fmaf(d.x, mx.x, xv.x)), rndt(fmaf(d.y, mx.y, xv.y)),
                                rndt(fmaf(d.z, mx.z, xv.z)), rndt(fmaf(d.w, mx.w, xv.w)));
        return;
    }
    __shared__ float t[32][33];
    int b = blockIdx.x - nshift;
    int ji = 0;
    #pragma unroll
    for (int q = 1; q < 10; q++)
        if (b >= js.j[q].boff) ji = q;
    TJob jb = js.j[ji];
    int rem = b - jb.boff;
    int bx = (rem % jb.nbx) * 32;
    int by = (rem / jb.nbx) * 32;
    const int xq = tid & 31, yq = tid >> 5;
    #pragma unroll
    for (int i = 0; i < 32; i += 8) {
        int r = by + yq + i, n = bx + xq;
        if (r < jb.R && n < jb.N) t[yq + i][xq] = jb.src[(long)r * jb.N + n];
    }
    __syncthreads();
    #pragma unroll
    for (int i = 0; i < 32; i += 8) {
        int n = bx + yq + i, r = by + xq;
        if (n < jb.N && r < jb.R) jb.dst[(long)n * jb.R + r] = rndt(t[xq][yq + i]);
    }
}

// ---------------- chunked WKV6 -----------------------------------------------
__global__ __launch_bounds__(256, 2) void wkv_chunkA(
    const float* __restrict__ r, const float* __restrict__ k,
    const float* __restrict__ v, const float* __restrict__ lw,
    const float* __restrict__ u,
    float* __restrict__ y, float* __restrict__ Dout,
    float* __restrict__ rpout, float* __restrict__ pLout)
{
    extern __shared__ float sm[];
    float* lp   = sm;
    float* bufA = lp + 65 * 64;
    float* rpT  = bufA + 64 * STRD;
    float* kpT  = rpT + 64 * STRD;
    float* kpp  = kpT + 64 * STRD;
    float* vsm  = kpp + 64 * STRD;
    float* dsm  = vsm + 64 * STRD;
    float* usm  = dsm + 64;

    const int tid = threadIdx.x;
    const int chunk = blockIdx.x;
    const int bh = chunk >> 5;
    const int c  = chunk & 31;
    const int b = bh >> 4, h = bh & 15;
    const long base = ((long)b * T_ + c * CHUNK) * C_ + h * 64;

    if (tid < 64) usm[tid] = u[h * 64 + tid];
    const int i  = tid & 63;
    const int tq = tid >> 6;

    #pragma unroll
    for (int e = 0; e < 16; e++) {
        int t = tq + 4 * e;
        bufA[t * STRD + i] = lw[base + (long)t * C_ + i];
    }
    __syncthreads();

    if (tid < 64) {
        float run = 0.f;
        for (int t = 0; t < 64; t++) {
            lp[t * 64 + tid] = run;
            run += bufA[t * STRD + tid];
        }
        lp[64 * 64 + tid] = run;
        pLout[(long)chunk * 64 + tid] = run;
    }
    __syncthreads();

    #pragma unroll
    for (int e = 0; e < 16; e++) {
        int t = tq + 4 * e;
        long gi = base + (long)t * C_ + i;
        float rr = r[gi], kk = k[gi];
        float lpti = lp[t * 64 + i];
        float lpn  = lpti + bufA[t * STRD + i];
        float lpL  = lp[64 * 64 + i];
        rpT[i * STRD + t] = rr * __expf(lpti);
        kpT[i * STRD + t] = kk * __expf(-lpn);
        kpp[t * STRD + i] = kk * __expf(lpL - lpn);
        vsm[t * STRD + i] = v[gi];
    }
    {
        int t = tid >> 2, q = tid & 3;
        long gb = base + (long)t * C_;
        float p = 0.f;
        #pragma unroll
        for (int ii = 0; ii < 16; ii++) {
            int ci = q * 16 + ii;
            p += r[gb + ci] * usm[ci] * k[gb + ci];
        }
        p += __shfl_xor_sync(0xffffffffu, p, 1);
        p += __shfl_xor_sync(0xffffffffu, p, 2);
        if (q == 0) dsm[t] = p;
    }
    __syncthreads();

    {
        float* rpg = rpout + (long)chunk * 64 * 64;
        #pragma unroll
        for (int e = 0; e < 16; e++) {
            int flat = tid + 256 * e;
            rpg[flat] = rpT[(flat >> 6) * STRD + (flat & 63)];
        }
    }

    {
        int t0 = (tid >> 4) * 4, s0 = (tid & 15) * 4;
        float acc[4][4];
        #pragma unroll
        for (int a = 0; a < 4; a++)
            #pragma unroll
            for (int bq = 0; bq < 4; bq++) acc[a][bq] = 0.f;
        for (int ii = 0; ii < 64; ii++) {
            float4 a4 = *(const float4*)&rpT[ii * STRD + t0];
            float4 b4 = *(const float4*)&kpT[ii * STRD + s0];
            float av[4] = { a4.x, a4.y, a4.z, a4.w };
            float bv[4] = { b4.x, b4.y, b4.z, b4.w };
            #pragma unroll
            for (int a = 0; a < 4; a++)
                #pragma unroll
                for (int bq = 0; bq < 4; bq++)
                    acc[a][bq] = fmaf(av[a], bv[bq], acc[a][bq]);
        }
        __syncthreads();
        #pragma unroll
        for (int a = 0; a < 4; a++)
            #pragma unroll
            for (int bq = 0; bq < 4; bq++) {
                int tt = t0 + a, ss = s0 + bq;
                float val = (tt > ss) ? acc[a][bq] : ((tt == ss) ? dsm[tt] : 0.f);
                bufA[ss * STRD + tt] = val;
            }
    }
    __syncthreads();

    {
        int t0 = (tid >> 4) * 4, j0 = (tid & 15) * 4;
        float acc[4][4];
        #pragma unroll
        for (int a = 0; a < 4; a++)
            #pragma unroll
            for (int bq = 0; bq < 4; bq++) acc[a][bq] = 0.f;
        for (int s = 0; s < 64; s++) {
            float4 a4 = *(const float4*)&bufA[s * STRD + t0];
            float4 b4 = *(const float4*)&vsm[s * STRD + j0];
            float av[4] = { a4.x, a4.y, a4.z, a4.w };
            float bv[4] = { b4.x, b4.y, b4.z, b4.w };
            #pragma unroll
            for (int a = 0; a < 4; a++)
                #pragma unroll
                for (int bq = 0; bq < 4; bq++)
                    acc[a][bq] = fmaf(av[a], bv[bq], acc[a][bq]);
        }
        #pragma unroll
        for (int a = 0; a < 4; a++) {
            float4 o = make_float4(acc[a][0], acc[a][1], acc[a][2], acc[a][3]);
            *(float4*)&y[base + (long)(t0 + a) * C_ + j0] = o;
        }
    }

    {
        int i0 = (tid >> 4) * 4, j0 = (tid & 15) * 4;
        float acc[4][4];
        #pragma unroll
        for (int a = 0; a < 4; a++)
            #pragma unroll
            for (int bq = 0; bq < 4; bq++) acc[a][bq] = 0.f;
        for (int s = 0; s < 64; s++) {
            float4 a4 = *(const float4*)&kpp[s * STRD + i0];
            float4 b4 = *(const float4*)&vsm[s * STRD + j0];
            float av[4] = { a4.x, a4.y, a4.z, a4.w };
            float bv[4] = { b4.x, b4.y, b4.z, b4.w };
            #pragma unroll
            for (int a = 0; a < 4; a++)
                #pragma unroll
                for (int bq = 0; bq < 4; bq++)
                    acc[a][bq] = fmaf(av[a], bv[bq], acc[a][bq]);
        }
        float* Dp = Dout + (long)chunk * 4096;
        #pragma unroll
        for (int a = 0; a < 4; a++) {
            float4 o = make_float4(acc[a][0], acc[a][1], acc[a][2], acc[a][3]);
            *(float4*)&Dp[(i0 + a) * 64 + j0] = o;
        }
    }
}

__global__ __launch_bounds__(256) void wkv_chunkB(
    const float* __restrict__ D, const float* __restrict__ pL,
    float* __restrict__ S)
{
    const int bh = blockIdx.x;
    const int tid = threadIdx.x;
    const int i = tid >> 2;
    const int jb = (tid & 3) * 16;
    float4 s0 = {0,0,0,0}, s1 = {0,0,0,0}, s2 = {0,0,0,0}, s3 = {0,0,0,0};
    for (int c = 0; c < G_; c++) {
        long chunk = (long)bh * G_ + c;
        long off = chunk * 4096 + i * 64 + jb;
        *(float4*)&S[off + 0]  = s0;
        *(float4*)&S[off + 4]  = s1;
        *(float4*)&S[off + 8]  = s2;
        *(float4*)&S[off + 12] = s3;
        float pl = __expf(pL[chunk * 64 + i]);
        float4 d0 = *(const float4*)&D[off + 0];
        float4 d1 = *(const float4*)&D[off + 4];
        float4 d2 = *(const float4*)&D[off + 8];
        float4 d3 = *(const float4*)&D[off + 12];
        s0 = make_float4(fmaf(pl, s0.x, d0.x), fmaf(pl, s0.y, d0.y), fmaf(pl, s0.z, d0.z), fmaf(pl, s0.w, d0.w));
        s1 = make_float4(fmaf(pl, s1.x, d1.x), fmaf(pl, s1.y, d1.y), fmaf(pl, s1.z, d1.z), fmaf(pl, s1.w, d1.w));
        s2 = make_float4(fmaf(pl, s2.x, d2.x), fmaf(pl, s2.y, d2.y), fmaf(pl, s2.z, d2.z), fmaf(pl, s2.w, d2.w));
        s3 = make_float4(fmaf(pl, s3.x, d3.x), fmaf(pl, s3.y, d3.y), fmaf(pl, s3.z, d3.z), fmaf(pl, s3.w, d3.w));
    }
}

// chunkC fused with GroupNorm + gate: writes z directly.
__global__ __launch_bounds__(256) void wkv_chunkC(
    const float* __restrict__ rp, const float* __restrict__ S,
    const float* __restrict__ y,
    const float* __restrict__ ln_g, const float* __restrict__ ln_b,
    const float* __restrict__ g, float* __restrict__ z)
{
    __shared__ float rps[64 * 64];
    __shared__ float Ss[64 * 64];
    const int tid = threadIdx.x;
    const int chunk = blockIdx.x;
    const int bh = chunk >> 5;
    const int c  = chunk & 31;
    const int b = bh >> 4, h = bh & 15;
    const long base = ((long)b * T_ + c * CHUNK) * C_ + h * 64;

    const float* rpg = rp + (long)chunk * 4096;
    const float* Sg  = S  + (long)chunk * 4096;
    #pragma unroll
    for (int e = 0; e < 4; e++) {
        int f4 = tid + 256 * e;
        *(float4*)&rps[f4 * 4] = *(const float4*)&rpg[f4 * 4];
        *(float4*)&Ss[f4 * 4]  = *(const float4*)&Sg[f4 * 4];
    }
    __syncthreads();

    int t0 = (tid >> 4) * 4, j0 = (tid & 15) * 4;
    float acc[4][4];
    #pragma unroll
    for (int a = 0; a < 4; a++)
        #pragma unroll
        for (int bq = 0; bq < 4; bq++) acc[a][bq] = 0.f;
    for (int ii = 0; ii < 64; ii++) {
        float4 a4 = *(const float4*)&rps[ii * 64 + t0];
        float4 b4 = *(const float4*)&Ss[ii * 64 + j0];
        float av[4] = { a4.x, a4.y, a4.z, a4.w };
        float bv[4] = { b4.x, b4.y, b4.z, b4.w };
        #pragma unroll
        for (int a = 0; a < 4; a++)
            #pragma unroll
            for (int bq = 0; bq < 4; bq++)
                acc[a][bq] = fmaf(av[a], bv[bq], acc[a][bq]);
    }

    // final y = intra (from global) + inter (acc); then GroupNorm over j (head
    // dim, 64 values per t-row = 16 lanes x 4) + gate multiply -> z.
    const float lg0 = ln_g[h * 64 + j0],     lg1 = ln_g[h * 64 + j0 + 1];
    const float lg2 = ln_g[h * 64 + j0 + 2], lg3 = ln_g[h * 64 + j0 + 3];
    const float lb0 = ln_b[h * 64 + j0],     lb1 = ln_b[h * 64 + j0 + 1];
    const float lb2 = ln_b[h * 64 + j0 + 2], lb3 = ln_b[h * 64 + j0 + 3];

    #pragma unroll
    for (int a = 0; a < 4; a++) {
        long yo = base + (long)(t0 + a) * C_ + j0;
        float4 cur = *(const float4*)&y[yo];
        float y0 = cur.x + acc[a][0];
        float y1 = cur.y + acc[a][1];
        float y2 = cur.z + acc[a][2];
        float y3 = cur.w + acc[a][3];

        float s  = y0 + y1 + y2 + y3;
        float sq = y0 * y0 + y1 * y1 + y2 * y2 + y3 * y3;
        #pragma unroll
        for (int off = 1; off < 16; off <<= 1) {
            s  += __shfl_xor_sync(0xffffffffu, s,  off);
            sq += __shfl_xor_sync(0xffffffffu, sq, off);
        }
        float mu  = s * (1.f / 64.f);
        float var = sq * (1.f / 64.f) - mu * mu;
        float inv = rsqrtf(var + 6.4e-4f);

        float4 gg = *(const float4*)&g[yo];
        float4 o;
        o.x = rndt((y0 - mu) * inv * lg0 + lb0) ;
        o.y = rndt((y1 - mu) * inv * lg1 + lb1) ;
        o.z = rndt((y2 - mu) * inv * lg2 + lb2) ;
        o.w = rndt((y3 - mu) * inv * lg3 + lb3) ;
        o.x = rndt(o.x * gg.x);
        o.y = rndt(o.y * gg.y);
        o.z = rndt(o.z * gg.z);
        o.w = rndt(o.w * gg.w);
        *(float4*)&z[yo] = o;
    }
}

// ---------------- launcher ----------------------------------------------------
extern "C" void kernel_launch(void* const* d_in, const int* in_sizes, int n_in,
                              void* d_out, int out_size)
{
    const float* x          = (const float*)d_in[0];
    const float* maa_x      = (const float*)d_in[1];
    const float* maa_w      = (const float*)d_in[2];
    const float* maa_k      = (const float*)d_in[3];
    const float* maa_v      = (const float*)d_in[4];
    const float* maa_r      = (const float*)d_in[5];
    const float* maa_g      = (const float*)d_in[6];
    const float* maa_w1     = (const float*)d_in[7];
    const float* maa_w2     = (const float*)d_in[8];
    const float* Wr         = (const float*)d_in[9];
    const float* Wk         = (const float*)d_in[10];
    const float* Wv         = (const float*)d_in[11];
    const float* Wo         = (const float*)d_in[12];
    const float* gate_w1    = (const float*)d_in[13];
    const float* gate_w2    = (const float*)d_in[14];
    const float* time_decay = (const float*)d_in[15];
    const float* decay_w1   = (const float*)d_in[16];
    const float* decay_w2   = (const float*)d_in[17];
    const float* u          = (const float*)d_in[18];
    const float* ln_g       = (const float*)d_in[19];
    const float* ln_b       = (const float*)d_in[20];
    (void)in_sizes; (void)n_in; (void)out_size;

    float *p_xx, *p_xxx, *p_xw, *p_xk, *p_xv, *p_xr, *p_xg;
    float *p_r, *p_k, *p_v, *p_w, *p_g, *p_y, *p_z, *p_lora, *p_s1, *p_s2;
    float *p_D, *p_Sc, *p_rp, *p_pL;
    float *p_WrT, *p_WkT, *p_WvT, *p_WoT, *p_w1T, *p_w2T, *p_dw1T, *p_gw1T, *p_dw2T, *p_gw2T;
    cudaGetSymbolAddress((void**)&p_xx, g_xx);
    cudaGetSymbolAddress((void**)&p_xxx, g_xxx);
    cudaGetSymbolAddress((void**)&p_xw, g_xw);
    cudaGetSymbolAddress((void**)&p_xk, g_xk);
    cudaGetSymbolAddress((void**)&p_xv, g_xv);
    cudaGetSymbolAddress((void**)&p_xr, g_xr);
    cudaGetSymbolAddress((void**)&p_xg, g_xg);
    cudaGetSymbolAddress((void**)&p_r, g_r);
    cudaGetSymbolAddress((void**)&p_k, g_k);
    cudaGetSymbolAddress((void**)&p_v, g_v);
    cudaGetSymbolAddress((void**)&p_w, g_w);
    cudaGetSymbolAddress((void**)&p_g, g_g);
    cudaGetSymbolAddress((void**)&p_y, g_y);
    cudaGetSymbolAddress((void**)&p_z, g_z);
    cudaGetSymbolAddress((void**)&p_lora, g_lora);
    cudaGetSymbolAddress((void**)&p_s1, g_small);
    cudaGetSymbolAddress((void**)&p_s2, g_small2);
    cudaGetSymbolAddress((void**)&p_D, g_D);
    cudaGetSymbolAddress((void**)&p_Sc, g_Sc);
    cudaGetSymbolAddress((void**)&p_rp, g_rp);
    cudaGetSymbolAddress((void**)&p_pL, g_pL);
    cudaGetSymbolAddress((void**)&p_WrT, g_WrT);
    cudaGetSymbolAddress((void**)&p_WkT, g_WkT);
    cudaGetSymbolAddress((void**)&p_WvT, g_WvT);
    cudaGetSymbolAddress((void**)&p_WoT, g_WoT);
    cudaGetSymbolAddress((void**)&p_w1T, g_w1T);
    cudaGetSymbolAddress((void**)&p_w2T, g_w2T);
    cudaGetSymbolAddress((void**)&p_dw1T, g_dw1T);
    cudaGetSymbolAddress((void**)&p_gw1T, g_gw1T);
    cudaGetSymbolAddress((void**)&p_dw2T, g_dw2T);
    cudaGetSymbolAddress((void**)&p_gw2T, g_gw2T);

    const long total = BTC;
    const int M = B_ * T_;          // 8192
    const int gy = M / 128;         // 64

    const int SMEM_A = (65 * 64 + 5 * 64 * STRD + 128) * 4;
    cudaFuncSetAttribute(wkv_chunkA, cudaFuncAttributeMaxDynamicSharedMemorySize, SMEM_A);
    cudaFuncSetAttribute(gemm_rkv, cudaFuncAttributeMaxDynamicSharedMemorySize, SMEM_G);
    cudaFuncSetAttribute(gemm_mix, cudaFuncAttributeMaxDynamicSharedMemorySize, SMEM_G);
    cudaFuncSetAttribute(gemm_dg2, cudaFuncAttributeMaxDynamicSharedMemorySize, SMEM_G);
    cudaFuncSetAttribute(gemm_lora, cudaFuncAttributeMaxDynamicSharedMemorySize, SMEM_G);
    cudaFuncSetAttribute((const void*)gemm_tc<0, false>,
                         cudaFuncAttributeMaxDynamicSharedMemorySize, SMEM_G);

    // transpose job table
    TJobs tj;
    int toff = 0;
    {
        const float* srcs[10] = { maa_w1, maa_w2, Wr, Wk, Wv, Wo,
                                  decay_w1, gate_w1, decay_w2, gate_w2 };
        float* dsts[10] = { p_w1T, p_w2T, p_WrT, p_WkT, p_WvT, p_WoT,
                            p_dw1T, p_gw1T, p_dw2T, p_gw2T };
        int Rs[10] = { 1024, 160, 1024, 1024, 1024, 1024, 1024, 1024, 64, 64 };
        int Ns[10] = { 160, 1024, 1024, 1024, 1024, 1024, 64, 64, 1024, 1024 };
        for (int q = 0; q < 10; q++) {
            int nbx = (Ns[q] + 31) / 32;
            int nby = (Rs[q] + 31) / 32;
            tj.j[q].src = srcs[q]; tj.j[q].dst = dsts[q];
            tj.j[q].R = Rs[q]; tj.j[q].N = Ns[q];
            tj.j[q].nbx = nbx; tj.j[q].boff = toff;
            toff += nbx * nby;
        }
    }
    const int nshift = (int)(total / 4 / 256);   // 8192

    // 0. fused shift + transposes (xxx + weights tf32-rounded)
    pre_kernel<<<nshift + toff, 256>>>((const float4*)x, maa_x,
        (float4*)p_xx, (float4*)p_xxx, tj, nshift);
    // 1. lora = tanh(xxx @ maa_w1)  (cp.async 128-body, N=160)
    gemm_lora<<<dim3(2, gy), 128, SMEM_G>>>(p_xxx, p_w1T, p_lora);
    // 2. merged 5-branch mix GEMM (256 thr, outputs rounded)
    gemm_mix<<<dim3(8, gy, 5), 256, SMEM_G>>>(p_lora, p_w2T, x, p_xx,
        maa_w, maa_k, maa_v, maa_r, maa_g,
        p_xw, p_xk, p_xv, p_xr, p_xg);
    // 3. merged r,k,v + decay1 + gate1, flattened grid (128 thr) <-- profiled
    gemm_rkv<<<1664, 128, SMEM_G>>>(p_xr, p_xk, p_xv, p_xw, p_xg,
                                    p_WrT, p_WkT, p_WvT, p_dw1T, p_gw1T,
                                    p_r, p_k, p_v, p_s1, p_s2);
    // 4. merged decay2 + gate2 (256 thr)
    gemm_dg2<<<dim3(8, gy, 2), 256, SMEM_G>>>(p_s1, p_s2, p_dw2T, p_gw2T, p_w, p_g, time_decay);
    // 5-7. chunked WKV6; chunkC fuses GroupNorm+gate -> z
    wkv_chunkA<<<NCHUNK, 256, SMEM_A>>>(p_r, p_k, p_v, p_w, u, p_y, p_D, p_rp, p_pL);
    wkv_chunkB<<<B_ * H_, 256>>>(p_D, p_pL, p_Sc);
    wkv_chunkC<<<NCHUNK, 256>>>(p_rp, p_Sc, p_y, ln_g, ln_b, p_g, p_z);
    // 8. out = z @ Wo (128 thr)
    gemm_tc<0, false><<<dim3(8, gy), 128, SMEM_G>>>(p_z, C_, p_WoT, C_, (float*)d_out, C_, C_, C_, nullptr);
}